// round 2
// baseline (speedup 1.0000x reference)
#include <cuda_runtime.h>
#include <math.h>

// Problem dims
#define Bn   128
#define Tn   20
#define Vn   12000
#define En   512
#define Hn   512
#define VISn 512

typedef unsigned long long ull;

__device__ __forceinline__ void fma2(ull &d, ull a, ull b) {
    asm("fma.rn.f32x2 %0, %1, %2, %0;" : "+l"(d) : "l"(a), "l"(b));
}
__device__ __forceinline__ float lo32(ull v) { return __uint_as_float((unsigned)(v & 0xffffffffu)); }
__device__ __forceinline__ float hi32(ull v) { return __uint_as_float((unsigned)(v >> 32)); }

// ---------------- scratch (device globals; no runtime allocation) ----------------
__device__ float g_fT[Bn * 49 * VISn];            // transposed conv features
__device__ float g_fv[Bn * 49 * VISn];            // att_fc output (pre-normalize)
__device__ float g_features_all[Bn * 64 * VISn];  // normalized fv ++ eng tokens
__device__ float g_we[Bn * Tn * En];              // word embeddings
__device__ float g_att_fea[Bn * 64 * VISn];       // features_all @ att_vw_w.T
__device__ float g_att_h[Bn * Tn * VISn];         // we @ att_hw_w.T
__device__ float g_x[Bn * Tn * 1024];             // [feas_seq | we] concat (K=1024)
__device__ float g_xg[Bn * Tn * 4 * Hn];          // precomputed input gates
__device__ float g_c[Bn * Hn];                    // LSTM cell state
__device__ float g_h0[Bn * Hn];                   // zero h for step 0
__device__ float g_hs[Bn * Tn * Hn];              // hidden states [B,T,H] (b-major rows: (b*T+t))
__device__ float g_bias2[4 * Hn];                 // b_ih + b_hh
__device__ float g_part[8 * Bn * VISn];           // split-K partials for img GEMM

// ---------------- main GEMM: C[M,N] = A[M,K] @ B[N,K]^T  (packed f32x2) ----------------
// 128x128 tile, BK=16, 256 threads, double-buffered smem, 8x8 microtile.
// mode 0: C = acc + bias     mode 2: masked fc epilogue (zero where lengths[row/T] < row%T)
__global__ __launch_bounds__(256)
void gemm128(const float* __restrict__ A, int lda,
             const float* __restrict__ Bw, int ldb,
             float* __restrict__ C, int ldc,
             const float* __restrict__ bias,
             int M, int N, int K, int mode, const int* __restrict__ lengths)
{
    __shared__ __align__(16) float  As[2][16][128];
    __shared__ __align__(16) float2 Bs[2][16][128];   // duplicated (b,b) pairs

    const int tid = threadIdx.x;
    const int tx  = tid & 15;           // n microtile
    const int ty  = tid >> 4;           // m microtile
    const int m0  = blockIdx.y * 128;
    const int n0  = blockIdx.x * 128;

    const int lr = tid >> 1;            // tile row loaded by this thread (0..127)
    const int lk = (tid & 1) * 8;       // k offset (two float4)

    const bool av = (m0 + lr) < M;
    const bool bv = (n0 + lr) < N;
    const float* Ap = A  + (long)(m0 + lr) * lda + lk;
    const float* Bp = Bw + (long)(n0 + lr) * ldb + lk;

    const int NP = K >> 4;
    const float4 z4 = make_float4(0.f, 0.f, 0.f, 0.f);

    float4 ra0, ra1, rb0, rb1;

    // prologue: panel 0 -> buf 0
    ra0 = av ? *(const float4*)(Ap + 0) : z4;
    ra1 = av ? *(const float4*)(Ap + 4) : z4;
    rb0 = bv ? *(const float4*)(Bp + 0) : z4;
    rb1 = bv ? *(const float4*)(Bp + 4) : z4;
    {
        As[0][lk+0][lr] = ra0.x; As[0][lk+1][lr] = ra0.y;
        As[0][lk+2][lr] = ra0.z; As[0][lk+3][lr] = ra0.w;
        As[0][lk+4][lr] = ra1.x; As[0][lk+5][lr] = ra1.y;
        As[0][lk+6][lr] = ra1.z; As[0][lk+7][lr] = ra1.w;
        Bs[0][lk+0][lr] = make_float2(rb0.x, rb0.x);
        Bs[0][lk+1][lr] = make_float2(rb0.y, rb0.y);
        Bs[0][lk+2][lr] = make_float2(rb0.z, rb0.z);
        Bs[0][lk+3][lr] = make_float2(rb0.w, rb0.w);
        Bs[0][lk+4][lr] = make_float2(rb1.x, rb1.x);
        Bs[0][lk+5][lr] = make_float2(rb1.y, rb1.y);
        Bs[0][lk+6][lr] = make_float2(rb1.z, rb1.z);
        Bs[0][lk+7][lr] = make_float2(rb1.w, rb1.w);
    }
    __syncthreads();

    ull acc[4][8];
    #pragma unroll
    for (int i = 0; i < 4; i++)
        #pragma unroll
        for (int j = 0; j < 8; j++) acc[i][j] = 0ull;

    for (int p = 0; p < NP; p++) {
        const int buf = p & 1;
        const bool more = (p + 1) < NP;
        if (more) {
            const float* Apn = Ap + (p + 1) * 16;
            const float* Bpn = Bp + (p + 1) * 16;
            ra0 = av ? *(const float4*)(Apn + 0) : z4;
            ra1 = av ? *(const float4*)(Apn + 4) : z4;
            rb0 = bv ? *(const float4*)(Bpn + 0) : z4;
            rb1 = bv ? *(const float4*)(Bpn + 4) : z4;
        }

        #pragma unroll
        for (int kk = 0; kk < 16; kk++) {
            const ulonglong2* ap = (const ulonglong2*)&As[buf][kk][ty * 8];
            ulonglong2 A01 = ap[0], A23 = ap[1];
            ull aa[4] = {A01.x, A01.y, A23.x, A23.y};
            const ulonglong2* bp = (const ulonglong2*)&Bs[buf][kk][tx * 8];
            ulonglong2 q0 = bp[0], q1 = bp[1], q2 = bp[2], q3 = bp[3];
            ull bb[8] = {q0.x, q0.y, q1.x, q1.y, q2.x, q2.y, q3.x, q3.y};
            #pragma unroll
            for (int mp = 0; mp < 4; mp++)
                #pragma unroll
                for (int j = 0; j < 8; j++)
                    fma2(acc[mp][j], aa[mp], bb[j]);
        }

        if (more) {
            const int nb = buf ^ 1;
            As[nb][lk+0][lr] = ra0.x; As[nb][lk+1][lr] = ra0.y;
            As[nb][lk+2][lr] = ra0.z; As[nb][lk+3][lr] = ra0.w;
            As[nb][lk+4][lr] = ra1.x; As[nb][lk+5][lr] = ra1.y;
            As[nb][lk+6][lr] = ra1.z; As[nb][lk+7][lr] = ra1.w;
            Bs[nb][lk+0][lr] = make_float2(rb0.x, rb0.x);
            Bs[nb][lk+1][lr] = make_float2(rb0.y, rb0.y);
            Bs[nb][lk+2][lr] = make_float2(rb0.z, rb0.z);
            Bs[nb][lk+3][lr] = make_float2(rb0.w, rb0.w);
            Bs[nb][lk+4][lr] = make_float2(rb1.x, rb1.x);
            Bs[nb][lk+5][lr] = make_float2(rb1.y, rb1.y);
            Bs[nb][lk+6][lr] = make_float2(rb1.z, rb1.z);
            Bs[nb][lk+7][lr] = make_float2(rb1.w, rb1.w);
        }
        __syncthreads();
    }

    // epilogue
    #pragma unroll
    for (int mp = 0; mp < 4; mp++) {
        const int r0 = m0 + ty * 8 + mp * 2;
        const int r1 = r0 + 1;
        bool keep0 = true, keep1 = true;
        if (mode == 2) {
            keep0 = (r0 < M) && (lengths[r0 / Tn] >= (r0 % Tn));
            keep1 = (r1 < M) && (lengths[r1 / Tn] >= (r1 % Tn));
        }
        #pragma unroll
        for (int j = 0; j < 8; j++) {
            const int col = n0 + tx * 8 + j;
            if (col >= N) continue;
            const float bj = bias ? bias[col] : 0.f;
            float vlo = lo32(acc[mp][j]) + bj;
            float vhi = hi32(acc[mp][j]) + bj;
            if (mode == 2) { if (!keep0) vlo = 0.f; if (!keep1) vhi = 0.f; }
            if (r0 < M) C[(long)r0 * ldc + col] = vlo;
            if (r1 < M) C[(long)r1 * ldc + col] = vhi;
        }
    }
}

// ---------------- split-K GEMM for img (M=128, N=512, K=2048, lda=ldb=2048) ----------------
__global__ __launch_bounds__(256)
void sgemm_splitk(const float* __restrict__ A, const float* __restrict__ Bw)
{
    __shared__ float As[16][64];
    __shared__ float Bs[16][64];
    const int tid = threadIdx.x;
    const int tx = tid & 15, ty = tid >> 4;
    const int n0 = blockIdx.x * 64, m0 = blockIdx.y * 64;
    const int kbase = blockIdx.z * 256;

    const int lr = tid >> 2, lk = (tid & 3) * 4;
    const float* Ap = A  + (long)(m0 + lr) * 2048 + kbase + lk;
    const float* Bp = Bw + (long)(n0 + lr) * 2048 + kbase + lk;

    float acc[4][4] = {};
    for (int k0 = 0; k0 < 256; k0 += 16) {
        float4 avv = *(const float4*)(Ap + k0);
        float4 bvv = *(const float4*)(Bp + k0);
        __syncthreads();
        As[lk+0][lr] = avv.x; As[lk+1][lr] = avv.y; As[lk+2][lr] = avv.z; As[lk+3][lr] = avv.w;
        Bs[lk+0][lr] = bvv.x; Bs[lk+1][lr] = bvv.y; Bs[lk+2][lr] = bvv.z; Bs[lk+3][lr] = bvv.w;
        __syncthreads();
        #pragma unroll
        for (int kk = 0; kk < 16; kk++) {
            float a[4], b[4];
            #pragma unroll
            for (int i = 0; i < 4; i++) a[i] = As[kk][ty * 4 + i];
            #pragma unroll
            for (int j = 0; j < 4; j++) b[j] = Bs[kk][tx * 4 + j];
            #pragma unroll
            for (int i = 0; i < 4; i++)
                #pragma unroll
                for (int j = 0; j < 4; j++) acc[i][j] += a[i] * b[j];
        }
    }
    float* Cp = g_part + (long)blockIdx.z * Bn * VISn;
    #pragma unroll
    for (int i = 0; i < 4; i++)
        #pragma unroll
        for (int j = 0; j < 4; j++)
            Cp[(long)(m0 + ty * 4 + i) * VISn + n0 + tx * 4 + j] = acc[i][j];
}

__global__ void k_img_reduce(const float* __restrict__ img_b) {
    int b = blockIdx.x, v = threadIdx.x;     // 128 x 512
    float s = img_b[v];
    #pragma unroll
    for (int k = 0; k < 8; k++) s += g_part[((long)k * Bn + b) * VISn + v];
    g_x[(long)(b * Tn) * 1024 + v] = s;      // feas_seq step 0
}

// ---------------- small prep kernels ----------------
__global__ void k_init_state() {
    int i = blockIdx.x * blockDim.x + threadIdx.x;
    if (i < Bn * Hn) { g_c[i] = 0.f; g_h0[i] = 0.f; }
}
__global__ void k_bias2(const float* __restrict__ b_ih, const float* __restrict__ b_hh) {
    int i = blockIdx.x * blockDim.x + threadIdx.x;
    if (i < 4 * Hn) g_bias2[i] = b_ih[i] + b_hh[i];
}
__global__ void k_transpose_f(const float* __restrict__ features) {
    int bp = blockIdx.x;                 // b*49+p
    int b = bp / 49, p = bp % 49;
    int v = threadIdx.x;
    g_fT[(long)bp * 512 + v] = features[((long)b * 512 + v) * 49 + p];
}
__global__ void k_normalize() {
    int row = blockIdx.x;
    int b = row / 49, p = row % 49;
    const float* x = g_fv + (long)row * 512;
    __shared__ float red[8];
    int tid = threadIdx.x, lane = tid & 31, wid = tid >> 5;
    float s = 0.f;
    for (int v = tid; v < 512; v += 256) { float t = x[v]; s += t * t; }
    #pragma unroll
    for (int o = 16; o; o >>= 1) s += __shfl_xor_sync(0xffffffffu, s, o);
    if (lane == 0) red[wid] = s;
    __syncthreads();
    if (tid == 0) {
        float sum = 0.f;
        #pragma unroll
        for (int w = 0; w < 8; w++) sum += red[w];
        red[0] = 1.f / fmaxf(sqrtf(sum), 1e-12f);
    }
    __syncthreads();
    float inv = red[0];
    float* o = g_features_all + ((long)b * 64 + p) * 512;
    for (int v = tid; v < 512; v += 256) o[v] = x[v] * inv;
}
__global__ void k_copy_eng(const float* __restrict__ eng) {
    int bj = blockIdx.x;
    int b = bj / 15, j = bj % 15;
    int v = threadIdx.x;
    g_features_all[((long)b * 64 + 49 + j) * 512 + v] = eng[(long)bj * 512 + v];
}
// embedding gather -> g_we AND concat slot g_x[:, 512:]
__global__ void k_embed(const int* __restrict__ captions, const float* __restrict__ embed_w) {
    int r = blockIdx.x;                  // b*T+t
    int idx = captions[r];
    float v = embed_w[(long)idx * 512 + threadIdx.x];
    g_we[(long)r * 512 + threadIdx.x] = v;
    g_x[(long)r * 1024 + 512 + threadIdx.x] = v;
}

// ---------------- fused attention -> g_x[:, :512] rows t=1..19 ----------------
__global__ __launch_bounds__(512)
void k_attention(const float* __restrict__ att_bias, const float* __restrict__ att_w) {
    int t = blockIdx.x, b = blockIdx.y;
    __shared__ float hh[512], ws[512], sb[64], sout[64];
    int tid = threadIdx.x, lane = tid & 31, wid = tid >> 5;

    hh[tid] = g_att_h[((long)b * Tn + t) * 512 + tid];
    ws[tid] = att_w[tid];
    if (tid < 64) sb[tid] = att_bias[tid];
    __syncthreads();

    for (int n = wid; n < 64; n += 16) {
        const float* fea = g_att_fea + ((long)b * 64 + n) * 512;
        float bn = sb[n], s = 0.f;
        for (int v = lane; v < 512; v += 32)
            s += fmaxf(fea[v] + hh[v] + bn, 0.f) * ws[v];
        #pragma unroll
        for (int o = 16; o; o >>= 1) s += __shfl_xor_sync(0xffffffffu, s, o);
        if (lane == 0) sout[n] = s;
    }
    __syncthreads();

    if (tid == 0) {
        float mx = sout[0];
        for (int n = 1; n < 64; n++) mx = fmaxf(mx, sout[n]);
        float sum = 0.f;
        for (int n = 0; n < 64; n++) { float e = __expf(sout[n] - mx); sout[n] = e; sum += e; }
        float inv = 1.f / sum;
        for (int n = 0; n < 64; n++) sout[n] *= inv;
    }
    __syncthreads();

    float acc = 0.f;
    const float* fa = g_features_all + (long)b * 64 * 512 + tid;
    #pragma unroll 8
    for (int n = 0; n < 64; n++) acc += sout[n] * fa[(long)n * 512];
    g_x[((long)b * Tn + (t + 1)) * 1024 + tid] = acc;
}

// ---------------- fused LSTM step (packed f32x2 inner product) ----------------
// grid: (Hn/16 = 32, Bn/32 = 4); 256 threads.
__global__ __launch_bounds__(256)
void k_lstm_step(const float* __restrict__ w_hh,
                 const float* __restrict__ hprev, int hstride, int t)
{
    __shared__ __align__(16) float2 Hs[16][32];       // duplicated (h,h)
    __shared__ __align__(16) float  Ws[16][64];
    __shared__ float Gs[32][65];

    int tid = threadIdx.x;
    int tx = tid & 15, ty = tid >> 4;
    int hc0 = blockIdx.x * 16;
    int b0  = blockIdx.y * 32;

    ull acc[2][2] = {{0ull, 0ull}, {0ull, 0ull}};

    for (int k0 = 0; k0 < Hn; k0 += 16) {
        __syncthreads();
        for (int i = tid; i < 32 * 16; i += 256) {
            int r = i >> 4, k = i & 15;
            float v = hprev[(long)(b0 + r) * hstride + k0 + k];
            Hs[k][r] = make_float2(v, v);
        }
        for (int i = tid; i < 64 * 16; i += 256) {
            int v = i >> 4, k = i & 15;
            int j = (v >> 4) * Hn + hc0 + (v & 15);
            Ws[k][v] = w_hh[(long)j * Hn + k0 + k];
        }
        __syncthreads();
        #pragma unroll
        for (int kk = 0; kk < 16; kk++) {
            ull a0 = *(const ull*)&Hs[kk][ty * 2 + 0];
            ull a1 = *(const ull*)&Hs[kk][ty * 2 + 1];
            ulonglong2 bq = *(const ulonglong2*)&Ws[kk][tx * 4];
            fma2(acc[0][0], a0, bq.x); fma2(acc[0][1], a0, bq.y);
            fma2(acc[1][0], a1, bq.x); fma2(acc[1][1], a1, bq.y);
        }
    }

    #pragma unroll
    for (int mi = 0; mi < 2; mi++) {
        int m = ty * 2 + mi;
        #pragma unroll
        for (int pj = 0; pj < 2; pj++) {
            int v0 = tx * 4 + pj * 2;
            int j0 = (v0 >> 4) * Hn + hc0 + (v0 & 15);
            const float* xg = g_xg + ((long)(b0 + m) * Tn + t) * (4 * Hn);
            Gs[m][v0 + 0] = lo32(acc[mi][pj]) + xg[j0];
            Gs[m][v0 + 1] = hi32(acc[mi][pj]) + xg[j0 + 1];
        }
    }
    __syncthreads();

    for (int p = tid; p < 32 * 16; p += 256) {
        int r = p >> 4, l = p & 15;
        int b = b0 + r, hcol = hc0 + l;
        float gi = Gs[r][l +  0];
        float gf = Gs[r][l + 16];
        float gg = Gs[r][l + 32];
        float go = Gs[r][l + 48];
        float co = g_c[(long)b * Hn + hcol];
        float si = 1.f / (1.f + __expf(-gi));
        float sf = 1.f / (1.f + __expf(-gf));
        float so = 1.f / (1.f + __expf(-go));
        float cn = sf * co + si * tanhf(gg);
        float hn = so * tanhf(cn);
        g_c[(long)b * Hn + hcol] = cn;
        g_hs[((long)b * Tn + t) * Hn + hcol] = hn;
    }
}

// ---------------- launch ----------------
static inline dim3 g128(int M, int N) { return dim3((N + 127) / 128, (M + 127) / 128); }

extern "C" void kernel_launch(void* const* d_in, const int* in_sizes, int n_in,
                              void* d_out, int out_size)
{
    const float* feature_0 = (const float*)d_in[0];
    const float* features  = (const float*)d_in[1];
    const float* eng       = (const float*)d_in[2];
    const int*   captions  = (const int*)  d_in[3];
    const int*   lengths   = (const int*)  d_in[4];
    const float* embed_w   = (const float*)d_in[5];
    const float* w_ih      = (const float*)d_in[6];
    const float* w_hh      = (const float*)d_in[7];
    const float* b_ih      = (const float*)d_in[8];
    const float* b_hh      = (const float*)d_in[9];
    const float* fc_w      = (const float*)d_in[10];
    const float* fc_b      = (const float*)d_in[11];
    const float* att_vw_w  = (const float*)d_in[12];
    const float* att_hw_w  = (const float*)d_in[13];
    const float* att_bias  = (const float*)d_in[14];
    const float* att_w_w   = (const float*)d_in[15];
    const float* att_fc_w  = (const float*)d_in[16];
    const float* att_fc_b  = (const float*)d_in[17];
    const float* img_w     = (const float*)d_in[18];
    const float* img_b     = (const float*)d_in[19];
    float* out = (float*)d_out;

    float* p_fT    = nullptr; cudaGetSymbolAddress((void**)&p_fT,    g_fT);
    float* p_fv    = nullptr; cudaGetSymbolAddress((void**)&p_fv,    g_fv);
    float* p_fall  = nullptr; cudaGetSymbolAddress((void**)&p_fall,  g_features_all);
    float* p_we    = nullptr; cudaGetSymbolAddress((void**)&p_we,    g_we);
    float* p_afea  = nullptr; cudaGetSymbolAddress((void**)&p_afea,  g_att_fea);
    float* p_ah    = nullptr; cudaGetSymbolAddress((void**)&p_ah,    g_att_h);
    float* p_x     = nullptr; cudaGetSymbolAddress((void**)&p_x,     g_x);
    float* p_xg    = nullptr; cudaGetSymbolAddress((void**)&p_xg,    g_xg);
    float* p_h0    = nullptr; cudaGetSymbolAddress((void**)&p_h0,    g_h0);
    float* p_hs    = nullptr; cudaGetSymbolAddress((void**)&p_hs,    g_hs);
    float* p_bias2 = nullptr; cudaGetSymbolAddress((void**)&p_bias2, g_bias2);

    // prep
    k_init_state<<<(Bn * Hn + 511) / 512, 512>>>();
    k_bias2<<<(4 * Hn + 255) / 256, 256>>>(b_ih, b_hh);
    k_transpose_f<<<Bn * 49, 512>>>(features);
    k_embed<<<Bn * Tn, 512>>>(captions, embed_w);
    k_copy_eng<<<Bn * 15, 512>>>(eng);

    // att_fc: fv = fT @ att_fc_w.T + b   (6272 x 512 x 512)
    gemm128<<<g128(Bn * 49, 512), 256>>>(p_fT, 512, att_fc_w, 512,
        p_fv, 512, att_fc_b, Bn * 49, 512, 512, 0, nullptr);
    k_normalize<<<Bn * 49, 256>>>();

    // img (split-K): feature_0 @ img_w.T -> partials -> g_x rows t=0
    sgemm_splitk<<<dim3(8, 2, 8), 256>>>(feature_0, img_w);
    k_img_reduce<<<Bn, 512>>>(img_b);

    // att_fea = features_all @ att_vw_w.T   (8192 x 512 x 512)
    gemm128<<<g128(Bn * 64, 512), 256>>>(p_fall, 512, att_vw_w, 512,
        p_afea, 512, nullptr, Bn * 64, 512, 512, 0, nullptr);

    // att_h = we @ att_hw_w.T   (2560 x 512 x 512)
    gemm128<<<g128(Bn * Tn, 512), 256>>>(p_we, 512, att_hw_w, 512,
        p_ah, 512, nullptr, Bn * Tn, 512, 512, 0, nullptr);

    // fused attention -> g_x[:, :512] rows t=1..19
    k_attention<<<dim3(Tn - 1, Bn), 512>>>(att_bias, att_w_w);

    // xg = [feas|we] @ w_ih.T + (b_ih+b_hh)   (2560 x 2048 x 1024, single fused GEMM)
    gemm128<<<g128(Bn * Tn, 4 * Hn), 256>>>(p_x, 1024, w_ih, 1024,
        p_xg, 4 * Hn, p_bias2, Bn * Tn, 4 * Hn, 1024, 0, nullptr);

    // LSTM recurrence (only h @ w_hh.T serial)
    for (int t = 0; t < Tn; t++) {
        const float* hprev = (t == 0) ? p_h0 : (p_hs + (long)(t - 1) * Hn);
        int hstride = (t == 0) ? Hn : Tn * Hn;
        k_lstm_step<<<dim3(Hn / 16, Bn / 32), 256>>>(w_hh, hprev, hstride, t);
    }

    // logits + mask: out = hs @ fc_w.T + fc_b   (2560 x 12000 x 512)
    gemm128<<<g128(Bn * Tn, Vn), 256>>>(p_hs, 512, fc_w, 512,
        out, Vn, fc_b, Bn * Tn, Vn, 512, 2, lengths);
}

// round 4
// speedup vs baseline: 2.7464x; 2.7464x over previous
#include <cuda_runtime.h>
#include <cuda_bf16.h>
#include <cstdint>
#include <math.h>

// Problem dims
#define Bn   128
#define Tn   20
#define Vn   12000
#define En   512
#define Hn   512
#define VISn 512

// ===================== PTX helpers (sm_100 baseline, no 'a' features) =====================
__device__ __forceinline__ uint32_t smem_u32(const void* p) {
    uint32_t a;
    asm("{ .reg .u64 t; cvta.to.shared.u64 t, %1; cvt.u32.u64 %0, t; }" : "=r"(a) : "l"(p));
    return a;
}
#define CP_ASYNC16(dst, src) \
    asm volatile("cp.async.cg.shared.global [%0], [%1], 16;" :: "r"(dst), "l"(src) : "memory")
#define CP_COMMIT() asm volatile("cp.async.commit_group;" ::: "memory")
#define CP_WAIT0()  asm volatile("cp.async.wait_group 0;" ::: "memory")
#define CP_WAIT1()  asm volatile("cp.async.wait_group 1;" ::: "memory")

__device__ __forceinline__ void ldsm4(uint32_t* r, uint32_t addr) {
    asm volatile("ldmatrix.sync.aligned.m8n8.x4.shared.b16 {%0,%1,%2,%3}, [%4];"
        : "=r"(r[0]), "=r"(r[1]), "=r"(r[2]), "=r"(r[3]) : "r"(addr));
}
__device__ __forceinline__ void mma16816(float* c, const uint32_t* a, const uint32_t* b) {
    asm volatile("mma.sync.aligned.m16n8k16.row.col.f32.bf16.bf16.f32 "
        "{%0,%1,%2,%3}, {%4,%5,%6,%7}, {%8,%9}, {%0,%1,%2,%3};"
        : "+f"(c[0]), "+f"(c[1]), "+f"(c[2]), "+f"(c[3])
        : "r"(a[0]), "r"(a[1]), "r"(a[2]), "r"(a[3]), "r"(b[0]), "r"(b[1]));
}

// ===================== scratch (device globals) =====================
__device__ float g_fv[Bn * 49 * VISn];
__device__ float g_features_all[Bn * 64 * VISn];
__device__ float g_att_fea[Bn * 64 * VISn];
__device__ float g_att_h[Bn * Tn * VISn];
__device__ float g_xg[Bn * Tn * 4 * Hn];
__device__ float g_c[Bn * Hn];
__device__ float g_h0[Bn * Hn];
__device__ float g_hs[Bn * Tn * Hn];
__device__ float g_bias2[4 * Hn];
__device__ float g_part[8 * Bn * VISn];

// bf16 split pairs (hi, lo)
__device__ __nv_bfloat16 g_fT_h[Bn * 49 * VISn],   g_fT_l[Bn * 49 * VISn];
__device__ __nv_bfloat16 g_fall_h[Bn * 64 * VISn], g_fall_l[Bn * 64 * VISn];
__device__ __nv_bfloat16 g_we_h[Bn * Tn * En],     g_we_l[Bn * Tn * En];
__device__ __nv_bfloat16 g_x_h[Bn * Tn * 1024],    g_x_l[Bn * Tn * 1024];
__device__ __nv_bfloat16 g_hs_h[Bn * Tn * Hn],     g_hs_l[Bn * Tn * Hn];
__device__ __nv_bfloat16 g_wfc1_h[VISn * VISn],    g_wfc1_l[VISn * VISn];
__device__ __nv_bfloat16 g_wvw_h[VISn * VISn],     g_wvw_l[VISn * VISn];
__device__ __nv_bfloat16 g_whw_h[VISn * En],       g_whw_l[VISn * En];
__device__ __nv_bfloat16 g_wih_h[4 * Hn * 1024],   g_wih_l[4 * Hn * 1024];
__device__ __nv_bfloat16 g_wfc_h[Vn * Hn],         g_wfc_l[Vn * Hn];

__device__ __forceinline__ void split_write(float v, __nv_bfloat16* h, __nv_bfloat16* l, long i) {
    __nv_bfloat16 hi = __float2bfloat16(v);
    h[i] = hi;
    l[i] = __float2bfloat16(v - __bfloat162float(hi));
}

// ===================== tensor-core GEMM via mma.sync =====================
// C[M,N] = (Ah+Al)[M,K] @ (Bh+Bl)[N,K]^T, 3 bf16 products, fp32 accum.
// 128x128 tile, BK=32, 8 warps (2x4), cp.async double buffer.
// smem tile layout: [128 rows][stride 40 bf16] (80B rows -> conflict-free ldmatrix)
#define ROWB   80                    // bytes per smem row
#define TILEB  (128 * ROWB)          // 10240 B per tile
#define STAGEB (4 * TILEB)           // Ah, Al, Bh, Bl
#define MG_SMEM (2 * STAGEB)         // 81920 B

__global__ __launch_bounds__(256, 1)
void mma_gemm(const __nv_bfloat16* __restrict__ Ah, const __nv_bfloat16* __restrict__ Al,
              const __nv_bfloat16* __restrict__ Bh, const __nv_bfloat16* __restrict__ Bl,
              float* __restrict__ C, int ldc, const float* __restrict__ bias,
              int M, int N, int K, int mode, const int* __restrict__ lengths)
{
    extern __shared__ __align__(16) char smem[];
    const uint32_t sbase = smem_u32(smem);

    const int tid = threadIdx.x, wid = tid >> 5, lane = tid & 31;
    const int m0 = blockIdx.y * 128, n0 = blockIdx.x * 128;
    const int wm = wid & 1, wn = wid >> 1;        // 2 x 4 warp grid

    const int NC = K >> 5;                        // chunks of K=32

    // per-thread load mapping: 2 chunks of 16B per tile per stage
    // chunk ch = tid + i*256 : row = ch>>2 (0..127), kq = ch&3
    auto issue = [&](int c) {
        const int buf = c & 1;
        const long kc = (long)c * 32;
        #pragma unroll
        for (int ti = 0; ti < 4; ti++) {
            const __nv_bfloat16* S = (ti == 0) ? Ah : (ti == 1) ? Al : (ti == 2) ? Bh : Bl;
            const int  rb  = (ti < 2) ? m0 : n0;
            const bool isB = (ti >= 2);
            #pragma unroll
            for (int i = 0; i < 2; i++) {
                int ch = tid + i * 256;
                int row = ch >> 2, kq = ch & 3;
                int gr = rb + row;
                if (isB && gr >= N) gr = N - 1;   // clamp; garbage cols masked at store
                const __nv_bfloat16* src = S + (long)gr * K + kc + kq * 8;
                uint32_t dst = sbase + buf * STAGEB + ti * TILEB + row * ROWB + kq * 16;
                CP_ASYNC16(dst, src);
            }
        }
        CP_COMMIT();
    };

    float acc[4][4][4];
    #pragma unroll
    for (int mi = 0; mi < 4; mi++)
        #pragma unroll
        for (int ni = 0; ni < 4; ni++)
            #pragma unroll
            for (int q = 0; q < 4; q++) acc[mi][ni][q] = 0.f;

    // fragment smem addresses (relative offsets within a tile)
    const uint32_t a_off = (uint32_t)((wm * 64 + (lane & 15)) * ROWB + (lane >> 4) * 8 * 2);
    const uint32_t b_off = (uint32_t)((wn * 32 + ((lane >> 4) & 1) * 8 + (lane & 7)) * ROWB
                                      + ((lane >> 3) & 1) * 8 * 2);

    issue(0);

    for (int c = 0; c < NC; c++) {
        if (c + 1 < NC) { issue(c + 1); CP_WAIT1(); }
        else            { CP_WAIT0(); }
        __syncthreads();

        const uint32_t tb = sbase + (c & 1) * STAGEB;
        #pragma unroll
        for (int kk = 0; kk < 2; kk++) {
            const uint32_t kba = kk * 32;         // bytes: k16 step = 16 elems * 2B
            uint32_t ah[4][4], al[4][4], bh[4][2], bl[4][2];
            #pragma unroll
            for (int mi = 0; mi < 4; mi++) {
                ldsm4(ah[mi], tb + 0 * TILEB + a_off + mi * 16 * ROWB + kba);
                ldsm4(al[mi], tb + 1 * TILEB + a_off + mi * 16 * ROWB + kba);
            }
            #pragma unroll
            for (int nip = 0; nip < 2; nip++) {
                uint32_t t4[4];
                ldsm4(t4, tb + 2 * TILEB + b_off + nip * 16 * ROWB + kba);
                bh[2*nip][0] = t4[0]; bh[2*nip][1] = t4[1];
                bh[2*nip+1][0] = t4[2]; bh[2*nip+1][1] = t4[3];
                ldsm4(t4, tb + 3 * TILEB + b_off + nip * 16 * ROWB + kba);
                bl[2*nip][0] = t4[0]; bl[2*nip][1] = t4[1];
                bl[2*nip+1][0] = t4[2]; bl[2*nip+1][1] = t4[3];
            }
            #pragma unroll
            for (int mi = 0; mi < 4; mi++)
                #pragma unroll
                for (int ni = 0; ni < 4; ni++) {
                    mma16816(acc[mi][ni], ah[mi], bh[ni]);
                    mma16816(acc[mi][ni], ah[mi], bl[ni]);
                    mma16816(acc[mi][ni], al[mi], bh[ni]);
                }
        }
        __syncthreads();
    }

    // epilogue: direct stores (8B per thread-row-segment, sector-aligned)
    #pragma unroll
    for (int mi = 0; mi < 4; mi++) {
        const int r0 = m0 + wm * 64 + mi * 16 + (lane >> 2);
        const int r1 = r0 + 8;
        bool keep0 = true, keep1 = true;
        if (mode == 2) {
            keep0 = (lengths[r0 / Tn] >= (r0 % Tn));
            keep1 = (lengths[r1 / Tn] >= (r1 % Tn));
        }
        #pragma unroll
        for (int ni = 0; ni < 4; ni++) {
            const int col = n0 + wn * 32 + ni * 8 + (lane & 3) * 2;
            if (col >= N) continue;
            float b0 = 0.f, b1 = 0.f;
            if (bias) { b0 = bias[col]; b1 = bias[col + 1]; }
            float v0 = acc[mi][ni][0] + b0, v1 = acc[mi][ni][1] + b1;
            float v2 = acc[mi][ni][2] + b0, v3 = acc[mi][ni][3] + b1;
            if (mode == 2) {
                if (!keep0) { v0 = 0.f; v1 = 0.f; }
                if (!keep1) { v2 = 0.f; v3 = 0.f; }
            }
            *(float2*)(C + (long)r0 * ldc + col) = make_float2(v0, v1);
            *(float2*)(C + (long)r1 * ldc + col) = make_float2(v2, v3);
        }
    }
}

// ===================== split-K fp32 GEMM for img (M=128, K=2048) =====================
__global__ __launch_bounds__(256)
void sgemm_splitk(const float* __restrict__ A, const float* __restrict__ Bw)
{
    __shared__ float As[16][64];
    __shared__ float Bs[16][64];
    const int tid = threadIdx.x;
    const int tx = tid & 15, ty = tid >> 4;
    const int n0 = blockIdx.x * 64, m0 = blockIdx.y * 64;
    const int kbase = blockIdx.z * 256;
    const int lr = tid >> 2, lk = (tid & 3) * 4;
    const float* Ap = A  + (long)(m0 + lr) * 2048 + kbase + lk;
    const float* Bp = Bw + (long)(n0 + lr) * 2048 + kbase + lk;

    float acc[4][4] = {};
    for (int k0 = 0; k0 < 256; k0 += 16) {
        float4 avv = *(const float4*)(Ap + k0);
        float4 bvv = *(const float4*)(Bp + k0);
        __syncthreads();
        As[lk+0][lr] = avv.x; As[lk+1][lr] = avv.y; As[lk+2][lr] = avv.z; As[lk+3][lr] = avv.w;
        Bs[lk+0][lr] = bvv.x; Bs[lk+1][lr] = bvv.y; Bs[lk+2][lr] = bvv.z; Bs[lk+3][lr] = bvv.w;
        __syncthreads();
        #pragma unroll
        for (int kk = 0; kk < 16; kk++) {
            float a[4], b[4];
            #pragma unroll
            for (int i = 0; i < 4; i++) a[i] = As[kk][ty * 4 + i];
            #pragma unroll
            for (int j = 0; j < 4; j++) b[j] = Bs[kk][tx * 4 + j];
            #pragma unroll
            for (int i = 0; i < 4; i++)
                #pragma unroll
                for (int j = 0; j < 4; j++) acc[i][j] += a[i] * b[j];
        }
    }
    float* Cp = g_part + (long)blockIdx.z * Bn * VISn;
    #pragma unroll
    for (int i = 0; i < 4; i++)
        #pragma unroll
        for (int j = 0; j < 4; j++)
            Cp[(long)(m0 + ty * 4 + i) * VISn + n0 + tx * 4 + j] = acc[i][j];
}

__global__ void k_img_reduce(const float* __restrict__ img_b) {
    int b = blockIdx.x, v = threadIdx.x;
    float s = img_b[v];
    #pragma unroll
    for (int k = 0; k < 8; k++) s += g_part[((long)k * Bn + b) * VISn + v];
    split_write(s, g_x_h, g_x_l, (long)(b * Tn) * 1024 + v);
}

// ===================== prep kernels =====================
__global__ void k_init_state() {
    int i = blockIdx.x * blockDim.x + threadIdx.x;
    if (i < Bn * Hn) { g_c[i] = 0.f; g_h0[i] = 0.f; }
}
__global__ void k_bias2(const float* __restrict__ b_ih, const float* __restrict__ b_hh) {
    int i = blockIdx.x * blockDim.x + threadIdx.x;
    if (i < 4 * Hn) g_bias2[i] = b_ih[i] + b_hh[i];
}
__global__ void k_cvt(const float* __restrict__ x, __nv_bfloat16* __restrict__ h,
                      __nv_bfloat16* __restrict__ l, int n) {
    int i = blockIdx.x * blockDim.x + threadIdx.x;
    if (i < n) split_write(x[i], h, l, i);
}
__global__ void k_transpose_f(const float* __restrict__ features) {
    int bp = blockIdx.x;
    int b = bp / 49, p = bp % 49;
    int v = threadIdx.x;
    float val = features[((long)b * 512 + v) * 49 + p];
    split_write(val, g_fT_h, g_fT_l, (long)bp * 512 + v);
}
__global__ void k_normalize() {
    int row = blockIdx.x;
    int b = row / 49, p = row % 49;
    const float* x = g_fv + (long)row * 512;
    __shared__ float red[8];
    int tid = threadIdx.x, lane = tid & 31, wid = tid >> 5;
    float s = 0.f;
    for (int v = tid; v < 512; v += 256) { float t = x[v]; s += t * t; }
    #pragma unroll
    for (int o = 16; o; o >>= 1) s += __shfl_xor_sync(0xffffffffu, s, o);
    if (lane == 0) red[wid] = s;
    __syncthreads();
    if (tid == 0) {
        float sum = 0.f;
        #pragma unroll
        for (int w = 0; w < 8; w++) sum += red[w];
        red[0] = 1.f / fmaxf(sqrtf(sum), 1e-12f);
    }
    __syncthreads();
    float inv = red[0];
    long o = ((long)b * 64 + p) * 512;
    for (int v = tid; v < 512; v += 256) {
        float val = x[v] * inv;
        g_features_all[o + v] = val;
        split_write(val, g_fall_h, g_fall_l, o + v);
    }
}
__global__ void k_copy_eng(const float* __restrict__ eng) {
    int bj = blockIdx.x;
    int b = bj / 15, j = bj % 15;
    int v = threadIdx.x;
    float val = eng[(long)bj * 512 + v];
    long o = ((long)b * 64 + 49 + j) * 512 + v;
    g_features_all[o] = val;
    split_write(val, g_fall_h, g_fall_l, o);
}
__global__ void k_embed(const int* __restrict__ captions, const float* __restrict__ embed_w) {
    int r = blockIdx.x;
    int idx = captions[r];
    float v = embed_w[(long)idx * 512 + threadIdx.x];
    split_write(v, g_we_h, g_we_l, (long)r * 512 + threadIdx.x);
    split_write(v, g_x_h,  g_x_l,  (long)r * 1024 + 512 + threadIdx.x);
}

// ===================== fused attention =====================
__global__ __launch_bounds__(512)
void k_attention(const float* __restrict__ att_bias, const float* __restrict__ att_w) {
    int t = blockIdx.x, b = blockIdx.y;
    __shared__ float hh[512], ws[512], sbv[64], sout[64];
    int tid = threadIdx.x, lane = tid & 31, wid = tid >> 5;

    hh[tid] = g_att_h[((long)b * Tn + t) * 512 + tid];
    ws[tid] = att_w[tid];
    if (tid < 64) sbv[tid] = att_bias[tid];
    __syncthreads();

    for (int n = wid; n < 64; n += 16) {
        const float* fea = g_att_fea + ((long)b * 64 + n) * 512;
        float bn = sbv[n], s = 0.f;
        for (int v = lane; v < 512; v += 32)
            s += fmaxf(fea[v] + hh[v] + bn, 0.f) * ws[v];
        #pragma unroll
        for (int o = 16; o; o >>= 1) s += __shfl_xor_sync(0xffffffffu, s, o);
        if (lane == 0) sout[n] = s;
    }
    __syncthreads();

    if (tid == 0) {
        float mx = sout[0];
        for (int n = 1; n < 64; n++) mx = fmaxf(mx, sout[n]);
        float sum = 0.f;
        for (int n = 0; n < 64; n++) { float e = __expf(sout[n] - mx); sout[n] = e; sum += e; }
        float inv = 1.f / sum;
        for (int n = 0; n < 64; n++) sout[n] *= inv;
    }
    __syncthreads();

    float acc = 0.f;
    const float* fa = g_features_all + (long)b * 64 * 512 + tid;
    #pragma unroll 8
    for (int n = 0; n < 64; n++) acc += sout[n] * fa[(long)n * 512];
    split_write(acc, g_x_h, g_x_l, ((long)b * Tn + (t + 1)) * 1024 + tid);
}

// ===================== fused LSTM step (fp32 SIMT) =====================
__global__ __launch_bounds__(256)
void k_lstm_step(const float* __restrict__ w_hh,
                 const float* __restrict__ hprev, int hstride, int t)
{
    __shared__ float Hs[16][32];
    __shared__ float Ws[16][64];
    __shared__ float Gs[32][65];

    int tid = threadIdx.x;
    int tx = tid & 15, ty = tid >> 4;
    int hc0 = blockIdx.x * 16;
    int b0  = blockIdx.y * 32;

    float acc[2][4] = {};

    for (int k0 = 0; k0 < Hn; k0 += 16) {
        __syncthreads();
        for (int i = tid; i < 32 * 16; i += 256) {
            int r = i >> 4, k = i & 15;
            Hs[k][r] = hprev[(long)(b0 + r) * hstride + k0 + k];
        }
        for (int i = tid; i < 64 * 16; i += 256) {
            int v = i >> 4, k = i & 15;
            int j = (v >> 4) * Hn + hc0 + (v & 15);
            Ws[k][v] = w_hh[(long)j * Hn + k0 + k];
        }
        __syncthreads();
        #pragma unroll
        for (int kk = 0; kk < 16; kk++) {
            float a0 = Hs[kk][ty * 2 + 0];
            float a1 = Hs[kk][ty * 2 + 1];
            float bb[4];
            #pragma unroll
            for (int j = 0; j < 4; j++) bb[j] = Ws[kk][tx * 4 + j];
            #pragma unroll
            for (int j = 0; j < 4; j++) { acc[0][j] += a0 * bb[j]; acc[1][j] += a1 * bb[j]; }
        }
    }

    #pragma unroll
    for (int mi = 0; mi < 2; mi++) {
        int m = ty * 2 + mi;
        #pragma unroll
        for (int ni = 0; ni < 4; ni++) {
            int v = tx * 4 + ni;
            int j = (v >> 4) * Hn + hc0 + (v & 15);
            Gs[m][v] = acc[mi][ni] + g_xg[((long)(b0 + m) * Tn + t) * (4 * Hn) + j];
        }
    }
    __syncthreads();

    for (int p = tid; p < 32 * 16; p += 256) {
        int r = p >> 4, l = p & 15;
        int b = b0 + r, hcol = hc0 + l;
        float gi = Gs[r][l +  0];
        float gf = Gs[r][l + 16];
        float gg = Gs[r][l + 32];
        float go = Gs[r][l + 48];
        float co = g_c[(long)b * Hn + hcol];
        float si = 1.f / (1.f + __expf(-gi));
        float sf = 1.f / (1.f + __expf(-gf));
        float so = 1.f / (1.f + __expf(-go));
        float cn = sf * co + si * tanhf(gg);
        float hn = so * tanhf(cn);
        g_c[(long)b * Hn + hcol] = cn;
        long oi = ((long)b * Tn + t) * Hn + hcol;
        g_hs[oi] = hn;
        split_write(hn, g_hs_h, g_hs_l, oi);
    }
}

// ===================== launch =====================
static inline dim3 tgrid(int M, int N) { return dim3((N + 127) / 128, M / 128); }

extern "C" void kernel_launch(void* const* d_in, const int* in_sizes, int n_in,
                              void* d_out, int out_size)
{
    const float* feature_0 = (const float*)d_in[0];
    const float* features  = (const float*)d_in[1];
    const float* eng       = (const float*)d_in[2];
    const int*   captions  = (const int*)  d_in[3];
    const int*   lengths   = (const int*)  d_in[4];
    const float* embed_w   = (const float*)d_in[5];
    const float* w_ih      = (const float*)d_in[6];
    const float* w_hh      = (const float*)d_in[7];
    const float* b_ih      = (const float*)d_in[8];
    const float* b_hh      = (const float*)d_in[9];
    const float* fc_w      = (const float*)d_in[10];
    const float* fc_b      = (const float*)d_in[11];
    const float* att_vw_w  = (const float*)d_in[12];
    const float* att_hw_w  = (const float*)d_in[13];
    const float* att_bias  = (const float*)d_in[14];
    const float* att_w_w   = (const float*)d_in[15];
    const float* att_fc_w  = (const float*)d_in[16];
    const float* att_fc_b  = (const float*)d_in[17];
    const float* img_w     = (const float*)d_in[18];
    const float* img_b     = (const float*)d_in[19];
    float* out = (float*)d_out;

    static bool smem_set = false;
    if (!smem_set) {
        cudaFuncSetAttribute(mma_gemm, cudaFuncAttributeMaxDynamicSharedMemorySize, MG_SMEM);
        smem_set = true;
    }

    #define SYM(p, s) float* p = nullptr; cudaGetSymbolAddress((void**)&p, s)
    SYM(p_fv, g_fv); SYM(p_ah, g_att_h); SYM(p_xg, g_xg);
    SYM(p_h0, g_h0); SYM(p_hs, g_hs); SYM(p_bias2, g_bias2);
    #undef SYM
    #define BSYM(p, s) __nv_bfloat16* p = nullptr; cudaGetSymbolAddress((void**)&p, s)
    BSYM(p_fT_h, g_fT_h);     BSYM(p_fT_l, g_fT_l);
    BSYM(p_fall_h, g_fall_h); BSYM(p_fall_l, g_fall_l);
    BSYM(p_we_h, g_we_h);     BSYM(p_we_l, g_we_l);
    BSYM(p_x_h, g_x_h);       BSYM(p_x_l, g_x_l);
    BSYM(p_hs_h, g_hs_h);     BSYM(p_hs_l, g_hs_l);
    BSYM(p_wfc1_h, g_wfc1_h); BSYM(p_wfc1_l, g_wfc1_l);
    BSYM(p_wvw_h, g_wvw_h);   BSYM(p_wvw_l, g_wvw_l);
    BSYM(p_whw_h, g_whw_h);   BSYM(p_whw_l, g_whw_l);
    BSYM(p_wih_h, g_wih_h);   BSYM(p_wih_l, g_wih_l);
    BSYM(p_wfc_h, g_wfc_h);   BSYM(p_wfc_l, g_wfc_l);
    #undef BSYM
    float* p_afea = nullptr; cudaGetSymbolAddress((void**)&p_afea, g_att_fea);

    // prep + weight conversions
    k_init_state<<<(Bn * Hn + 511) / 512, 512>>>();
    k_bias2<<<(4 * Hn + 255) / 256, 256>>>(b_ih, b_hh);
    k_cvt<<<(512 * 512 + 255) / 256, 256>>>(att_fc_w, p_wfc1_h, p_wfc1_l, 512 * 512);
    k_cvt<<<(512 * 512 + 255) / 256, 256>>>(att_vw_w, p_wvw_h, p_wvw_l, 512 * 512);
    k_cvt<<<(512 * 512 + 255) / 256, 256>>>(att_hw_w, p_whw_h, p_whw_l, 512 * 512);
    k_cvt<<<(2048 * 1024 + 255) / 256, 256>>>(w_ih, p_wih_h, p_wih_l, 2048 * 1024);
    k_cvt<<<(Vn * 512 + 255) / 256, 256>>>(fc_w, p_wfc_h, p_wfc_l, Vn * 512);
    k_transpose_f<<<Bn * 49, 512>>>(features);
    k_embed<<<Bn * Tn, 512>>>(captions, embed_w);

    // att_fc: fv = fT @ att_fc_w.T + b   (6272 x 512 x 512)
    mma_gemm<<<tgrid(Bn * 49, 512), 256, MG_SMEM>>>(p_fT_h, p_fT_l, p_wfc1_h, p_wfc1_l,
        p_fv, 512, att_fc_b, Bn * 49, 512, 512, 0, nullptr);
    k_normalize<<<Bn * 49, 256>>>();
    k_copy_eng<<<Bn * 15, 512>>>(eng);

    // img (split-K fp32): feature_0 @ img_w.T -> g_x rows t=0
    sgemm_splitk<<<dim3(8, 2, 8), 256>>>(feature_0, img_w);
    k_img_reduce<<<Bn, 512>>>(img_b);

    // att_fea = features_all @ att_vw_w.T   (8192 x 512 x 512)
    mma_gemm<<<tgrid(Bn * 64, 512), 256, MG_SMEM>>>(p_fall_h, p_fall_l, p_wvw_h, p_wvw_l,
        p_afea, 512, nullptr, Bn * 64, 512, 512, 0, nullptr);

    // att_h = we @ att_hw_w.T   (2560 x 512 x 512)
    mma_gemm<<<tgrid(Bn * Tn, 512), 256, MG_SMEM>>>(p_we_h, p_we_l, p_whw_h, p_whw_l,
        p_ah, 512, nullptr, Bn * Tn, 512, 512, 0, nullptr);

    // fused attention -> g_x feas part rows t=1..19
    k_attention<<<dim3(Tn - 1, Bn), 512>>>(att_bias, att_w_w);

    // xg = [feas|we] @ w_ih.T + (b_ih+b_hh)   (2560 x 2048 x 1024)
    mma_gemm<<<tgrid(Bn * Tn, 4 * Hn), 256, MG_SMEM>>>(p_x_h, p_x_l, p_wih_h, p_wih_l,
        p_xg, 4 * Hn, p_bias2, Bn * Tn, 4 * Hn, 1024, 0, nullptr);

    // LSTM recurrence (only h @ w_hh.T serial)
    for (int t = 0; t < Tn; t++) {
        const float* hprev = (t == 0) ? p_h0 : (p_hs + (long)(t - 1) * Hn);
        int hstride = (t == 0) ? Hn : Tn * Hn;
        k_lstm_step<<<dim3(Hn / 16, Bn / 32), 256>>>(w_hh, hprev, hstride, t);
    }

    // logits + mask: out = hs @ fc_w.T + fc_b   (2560 x 12000 x 512)
    mma_gemm<<<tgrid(Bn * Tn, Vn), 256, MG_SMEM>>>(p_hs_h, p_hs_l, p_wfc_h, p_wfc_l,
        out, Vn, fc_b, Bn * Tn, Vn, 512, 2, lengths);
}

// round 5
// speedup vs baseline: 4.3924x; 1.5993x over previous
#include <cuda_runtime.h>
#include <cuda_bf16.h>
#include <cstdint>
#include <math.h>

// Problem dims
#define Bn   128
#define Tn   20
#define Vn   12000
#define En   512
#define Hn   512
#define VISn 512

// ===================== PTX helpers (sm_100 baseline) =====================
__device__ __forceinline__ uint32_t smem_u32(const void* p) {
    uint32_t a;
    asm("{ .reg .u64 t; cvta.to.shared.u64 t, %1; cvt.u32.u64 %0, t; }" : "=r"(a) : "l"(p));
    return a;
}
#define CP_ASYNC16(dst, src) \
    asm volatile("cp.async.cg.shared.global [%0], [%1], 16;" :: "r"(dst), "l"(src) : "memory")
#define CP_COMMIT() asm volatile("cp.async.commit_group;" ::: "memory")
#define CP_WAIT2()  asm volatile("cp.async.wait_group 2;" ::: "memory")

__device__ __forceinline__ void ldsm4(uint32_t* r, uint32_t addr) {
    asm volatile("ldmatrix.sync.aligned.m8n8.x4.shared.b16 {%0,%1,%2,%3}, [%4];"
        : "=r"(r[0]), "=r"(r[1]), "=r"(r[2]), "=r"(r[3]) : "r"(addr));
}
__device__ __forceinline__ void mma16816(float* c, const uint32_t* a, const uint32_t* b) {
    asm volatile("mma.sync.aligned.m16n8k16.row.col.f32.bf16.bf16.f32 "
        "{%0,%1,%2,%3}, {%4,%5,%6,%7}, {%8,%9}, {%0,%1,%2,%3};"
        : "+f"(c[0]), "+f"(c[1]), "+f"(c[2]), "+f"(c[3])
        : "r"(a[0]), "r"(a[1]), "r"(a[2]), "r"(a[3]), "r"(b[0]), "r"(b[1]));
}

// ===================== scratch (device globals) =====================
__device__ float g_fv[Bn * 49 * VISn];
__device__ float g_features_all[Bn * 64 * VISn];
__device__ float g_att_fea[Bn * 64 * VISn];
__device__ float g_att_h[Bn * Tn * VISn];
__device__ float g_xg[Bn * Tn * 4 * Hn];
__device__ float g_c[Bn * Hn];
__device__ float g_bias2[4 * Hn];
__device__ float g_part[8 * Bn * VISn];

// bf16 split pairs (hi, lo)
__device__ __nv_bfloat16 g_fT_h[Bn * 49 * VISn],   g_fT_l[Bn * 49 * VISn];
__device__ __nv_bfloat16 g_fall_h[Bn * 64 * VISn], g_fall_l[Bn * 64 * VISn];
__device__ __nv_bfloat16 g_we_h[Bn * Tn * En],     g_we_l[Bn * Tn * En];
__device__ __nv_bfloat16 g_x_h[Bn * Tn * 1024],    g_x_l[Bn * Tn * 1024];
__device__ __nv_bfloat16 g_hs_h[Bn * Tn * Hn],     g_hs_l[Bn * Tn * Hn];
__device__ __nv_bfloat16 g_wfc1_h[VISn * VISn],    g_wfc1_l[VISn * VISn];
__device__ __nv_bfloat16 g_wvw_h[VISn * VISn],     g_wvw_l[VISn * VISn];
__device__ __nv_bfloat16 g_whw_h[VISn * En],       g_whw_l[VISn * En];
__device__ __nv_bfloat16 g_wih_h[4 * Hn * 1024],   g_wih_l[4 * Hn * 1024];
__device__ __nv_bfloat16 g_wfc_h[Vn * Hn],         g_wfc_l[Vn * Hn];
__device__ __nv_bfloat16 g_whh_h[4 * Hn * Hn],     g_whh_l[4 * Hn * Hn];

__device__ __forceinline__ void split_write(float v, __nv_bfloat16* h, __nv_bfloat16* l, long i) {
    __nv_bfloat16 hi = __float2bfloat16(v);
    h[i] = hi;
    l[i] = __float2bfloat16(v - __bfloat162float(hi));
}

// ===================== tensor-core GEMM via mma.sync (4-stage ring) =====================
// C[M,N] = (Ah+Al)[M,K] @ (Bh+Bl)[N,K]^T, 3 bf16 products, fp32 accum.
// 128x128 tile, BK=32, 8 warps (2x4), 4-stage cp.async ring, 1 sync/chunk.
#define ROWB   80
#define TILEB  (128 * ROWB)          // 10240 B
#define STAGEB (4 * TILEB)           // 40960 B
#define NSTG   4
#define MG_SMEM (NSTG * STAGEB)      // 163840 B

__global__ __launch_bounds__(256, 1)
void mma_gemm(const __nv_bfloat16* __restrict__ Ah, const __nv_bfloat16* __restrict__ Al,
              const __nv_bfloat16* __restrict__ Bh, const __nv_bfloat16* __restrict__ Bl,
              float* __restrict__ C, int ldc, const float* __restrict__ bias,
              int M, int N, int K, int mode, const int* __restrict__ lengths)
{
    extern __shared__ __align__(16) char smem[];
    const uint32_t sbase = smem_u32(smem);

    const int tid = threadIdx.x, wid = tid >> 5, lane = tid & 31;
    const int m0 = blockIdx.y * 128, n0 = blockIdx.x * 128;
    const int wm = wid & 1, wn = wid >> 1;

    const int NC = K >> 5;

    auto issue = [&](int c) {
        if (c < NC) {
            const long kc = (long)c * 32;
            const uint32_t sb = sbase + (c & (NSTG - 1)) * STAGEB;
            #pragma unroll
            for (int ti = 0; ti < 4; ti++) {
                const __nv_bfloat16* S = (ti == 0) ? Ah : (ti == 1) ? Al : (ti == 2) ? Bh : Bl;
                const int  rb  = (ti < 2) ? m0 : n0;
                const bool isB = (ti >= 2);
                #pragma unroll
                for (int i = 0; i < 2; i++) {
                    int ch = tid + i * 256;
                    int row = ch >> 2, kq = ch & 3;
                    int gr = rb + row;
                    if (isB && gr >= N) gr = N - 1;
                    const __nv_bfloat16* src = S + (long)gr * K + kc + kq * 8;
                    CP_ASYNC16(sb + ti * TILEB + row * ROWB + kq * 16, src);
                }
            }
        }
        CP_COMMIT();
    };

    float acc[4][4][4];
    #pragma unroll
    for (int mi = 0; mi < 4; mi++)
        #pragma unroll
        for (int ni = 0; ni < 4; ni++)
            #pragma unroll
            for (int q = 0; q < 4; q++) acc[mi][ni][q] = 0.f;

    const uint32_t a_off = (uint32_t)((wm * 64 + (lane & 15)) * ROWB + (lane >> 4) * 16);
    const uint32_t b_off = (uint32_t)((wn * 32 + ((lane >> 4) & 1) * 8 + (lane & 7)) * ROWB
                                      + ((lane >> 3) & 1) * 16);

    issue(0); issue(1); issue(2);

    for (int c = 0; c < NC; c++) {
        CP_WAIT2();
        __syncthreads();
        issue(c + 3);

        const uint32_t tb = sbase + (c & (NSTG - 1)) * STAGEB;
        #pragma unroll
        for (int kk = 0; kk < 2; kk++) {
            const uint32_t kba = kk * 32;
            uint32_t ah[4][4], al[4][4], bh[4][2], bl[4][2];
            #pragma unroll
            for (int mi = 0; mi < 4; mi++) {
                ldsm4(ah[mi], tb + 0 * TILEB + a_off + mi * 16 * ROWB + kba);
                ldsm4(al[mi], tb + 1 * TILEB + a_off + mi * 16 * ROWB + kba);
            }
            #pragma unroll
            for (int nip = 0; nip < 2; nip++) {
                uint32_t t4[4];
                ldsm4(t4, tb + 2 * TILEB + b_off + nip * 16 * ROWB + kba);
                bh[2*nip][0] = t4[0]; bh[2*nip][1] = t4[1];
                bh[2*nip+1][0] = t4[2]; bh[2*nip+1][1] = t4[3];
                ldsm4(t4, tb + 3 * TILEB + b_off + nip * 16 * ROWB + kba);
                bl[2*nip][0] = t4[0]; bl[2*nip][1] = t4[1];
                bl[2*nip+1][0] = t4[2]; bl[2*nip+1][1] = t4[3];
            }
            #pragma unroll
            for (int mi = 0; mi < 4; mi++)
                #pragma unroll
                for (int ni = 0; ni < 4; ni++) {
                    mma16816(acc[mi][ni], ah[mi], bh[ni]);
                    mma16816(acc[mi][ni], ah[mi], bl[ni]);
                    mma16816(acc[mi][ni], al[mi], bh[ni]);
                }
        }
    }

    #pragma unroll
    for (int mi = 0; mi < 4; mi++) {
        const int r0 = m0 + wm * 64 + mi * 16 + (lane >> 2);
        const int r1 = r0 + 8;
        bool keep0 = true, keep1 = true;
        if (mode == 2) {
            keep0 = (lengths[r0 / Tn] >= (r0 % Tn));
            keep1 = (lengths[r1 / Tn] >= (r1 % Tn));
        }
        #pragma unroll
        for (int ni = 0; ni < 4; ni++) {
            const int col = n0 + wn * 32 + ni * 8 + (lane & 3) * 2;
            if (col >= N) continue;
            float b0 = 0.f, b1 = 0.f;
            if (bias) { b0 = bias[col]; b1 = bias[col + 1]; }
            float v0 = acc[mi][ni][0] + b0, v1 = acc[mi][ni][1] + b1;
            float v2 = acc[mi][ni][2] + b0, v3 = acc[mi][ni][3] + b1;
            if (mode == 2) {
                if (!keep0) { v0 = 0.f; v1 = 0.f; }
                if (!keep1) { v2 = 0.f; v3 = 0.f; }
            }
            *(float2*)(C + (long)r0 * ldc + col) = make_float2(v0, v1);
            *(float2*)(C + (long)r1 * ldc + col) = make_float2(v2, v3);
        }
    }
}

// ===================== LSTM step t>=1: tensor-core h@w_hh + fused gates =====================
// grid 32 CTAs (16 hcols each, all 4 gates), 256 threads (8 warps, 2x4).
// A = h_{t-1} split (128 x 512), B = permuted w_hh rows (64 = 4 gates x 16 hcols).
#define L_ATILE (128 * ROWB)         // 10240
#define L_BTILE (64 * ROWB)          // 5120
#define L_STAGE (2 * L_ATILE + 2 * L_BTILE)  // 30720
#define L_SMEM  (NSTG * L_STAGE)     // 122880

__global__ __launch_bounds__(256, 1)
void k_lstm_mma(int t)
{
    extern __shared__ __align__(16) char smem[];
    const uint32_t sbase = smem_u32(smem);
    const int tid = threadIdx.x, wid = tid >> 5, lane = tid & 31;
    const int h0 = blockIdx.x * 16;
    const int wm = wid & 1, wn = wid >> 1;       // wn = gate index
    const int NC = 16;                           // K=512 / 32

    auto issue = [&](int c) {
        if (c < NC) {
            const long kc = (long)c * 32;
            const uint32_t sb = sbase + (c & (NSTG - 1)) * L_STAGE;
            #pragma unroll
            for (int s = 0; s < 2; s++) {        // A: h hi/lo
                const __nv_bfloat16* S = s ? g_hs_l : g_hs_h;
                #pragma unroll
                for (int i = 0; i < 2; i++) {
                    int ch = tid + i * 256;
                    int row = ch >> 2, kq = ch & 3;   // row = batch
                    const __nv_bfloat16* src = S + ((long)row * Tn + (t - 1)) * Hn + kc + kq * 8;
                    CP_ASYNC16(sb + s * L_ATILE + row * ROWB + kq * 16, src);
                }
            }
            #pragma unroll
            for (int s = 0; s < 2; s++) {        // B: w_hh hi/lo, permuted rows
                const __nv_bfloat16* S = s ? g_whh_l : g_whh_h;
                int row = tid >> 2, kq = tid & 3;     // row 0..63
                int j = (row >> 4) * 512 + h0 + (row & 15);
                const __nv_bfloat16* src = S + (long)j * Hn + kc + kq * 8;
                CP_ASYNC16(sb + 2 * L_ATILE + s * L_BTILE + row * ROWB + kq * 16, src);
            }
        }
        CP_COMMIT();
    };

    float acc[4][2][4];
    #pragma unroll
    for (int mi = 0; mi < 4; mi++)
        #pragma unroll
        for (int ni = 0; ni < 2; ni++)
            #pragma unroll
            for (int q = 0; q < 4; q++) acc[mi][ni][q] = 0.f;

    const uint32_t a_off = (uint32_t)((wm * 64 + (lane & 15)) * ROWB + (lane >> 4) * 16);
    const uint32_t b_off = (uint32_t)((wn * 16 + ((lane >> 4) & 1) * 8 + (lane & 7)) * ROWB
                                      + ((lane >> 3) & 1) * 16);

    issue(0); issue(1); issue(2);

    for (int c = 0; c < NC; c++) {
        CP_WAIT2();
        __syncthreads();
        issue(c + 3);

        const uint32_t tb = sbase + (c & (NSTG - 1)) * L_STAGE;
        #pragma unroll
        for (int kk = 0; kk < 2; kk++) {
            const uint32_t kba = kk * 32;
            uint32_t ah[4][4], al[4][4], bh[2][2], bl[2][2];
            #pragma unroll
            for (int mi = 0; mi < 4; mi++) {
                ldsm4(ah[mi], tb + 0 * L_ATILE + a_off + mi * 16 * ROWB + kba);
                ldsm4(al[mi], tb + 1 * L_ATILE + a_off + mi * 16 * ROWB + kba);
            }
            {
                uint32_t t4[4];
                ldsm4(t4, tb + 2 * L_ATILE + b_off + kba);
                bh[0][0] = t4[0]; bh[0][1] = t4[1]; bh[1][0] = t4[2]; bh[1][1] = t4[3];
                ldsm4(t4, tb + 2 * L_ATILE + L_BTILE + b_off + kba);
                bl[0][0] = t4[0]; bl[0][1] = t4[1]; bl[1][0] = t4[2]; bl[1][1] = t4[3];
            }
            #pragma unroll
            for (int mi = 0; mi < 4; mi++)
                #pragma unroll
                for (int ni = 0; ni < 2; ni++) {
                    mma16816(acc[mi][ni], ah[mi], bh[ni]);
                    mma16816(acc[mi][ni], ah[mi], bl[ni]);
                    mma16816(acc[mi][ni], al[mi], bh[ni]);
                }
        }
    }

    // stage gates to smem (reuse ring buffers), then fused pointwise
    __syncthreads();
    float* Gs = (float*)smem;                    // [128][68]
    #pragma unroll
    for (int mi = 0; mi < 4; mi++) {
        const int r0 = wm * 64 + mi * 16 + (lane >> 2);
        const int r1 = r0 + 8;
        #pragma unroll
        for (int ni = 0; ni < 2; ni++) {
            const int cl = wn * 16 + ni * 8 + (lane & 3) * 2;
            Gs[r0 * 68 + cl]     = acc[mi][ni][0];
            Gs[r0 * 68 + cl + 1] = acc[mi][ni][1];
            Gs[r1 * 68 + cl]     = acc[mi][ni][2];
            Gs[r1 * 68 + cl + 1] = acc[mi][ni][3];
        }
    }
    __syncthreads();

    for (int p = tid; p < 128 * 16; p += 256) {
        const int b = p >> 4, l = p & 15;
        const int hcol = h0 + l;
        const float* xg = g_xg + ((long)b * Tn + t) * 2048;
        float gi = Gs[b * 68 + 0 * 16 + l] + xg[0 * 512 + hcol];
        float gf = Gs[b * 68 + 1 * 16 + l] + xg[1 * 512 + hcol];
        float gg = Gs[b * 68 + 2 * 16 + l] + xg[2 * 512 + hcol];
        float go = Gs[b * 68 + 3 * 16 + l] + xg[3 * 512 + hcol];
        float co = g_c[b * 512 + hcol];
        float si = 1.f / (1.f + __expf(-gi));
        float sf = 1.f / (1.f + __expf(-gf));
        float so = 1.f / (1.f + __expf(-go));
        float cn = sf * co + si * tanhf(gg);
        float hn = so * tanhf(cn);
        g_c[b * 512 + hcol] = cn;
        split_write(hn, g_hs_h, g_hs_l, ((long)b * Tn + t) * 512 + hcol);
    }
}

// LSTM step 0: h=0, c=0 -> gates = xg only
__global__ void k_lstm_t0()
{
    int i = blockIdx.x * blockDim.x + threadIdx.x;
    if (i >= Bn * Hn) return;
    int b = i >> 9, hcol = i & 511;
    const float* xg = g_xg + ((long)b * Tn) * 2048;
    float gi = xg[hcol], gf = xg[512 + hcol], gg = xg[1024 + hcol], go = xg[1536 + hcol];
    (void)gf;
    float si = 1.f / (1.f + __expf(-gi));
    float so = 1.f / (1.f + __expf(-go));
    float cn = si * tanhf(gg);
    float hn = so * tanhf(cn);
    g_c[i] = cn;
    split_write(hn, g_hs_h, g_hs_l, ((long)b * Tn) * 512 + hcol);
}

// ===================== split-K fp32 GEMM for img (M=128, K=2048) =====================
__global__ __launch_bounds__(256)
void sgemm_splitk(const float* __restrict__ A, const float* __restrict__ Bw)
{
    __shared__ float As[16][64];
    __shared__ float Bs[16][64];
    const int tid = threadIdx.x;
    const int tx = tid & 15, ty = tid >> 4;
    const int n0 = blockIdx.x * 64, m0 = blockIdx.y * 64;
    const int kbase = blockIdx.z * 256;
    const int lr = tid >> 2, lk = (tid & 3) * 4;
    const float* Ap = A  + (long)(m0 + lr) * 2048 + kbase + lk;
    const float* Bp = Bw + (long)(n0 + lr) * 2048 + kbase + lk;

    float acc[4][4] = {};
    for (int k0 = 0; k0 < 256; k0 += 16) {
        float4 avv = *(const float4*)(Ap + k0);
        float4 bvv = *(const float4*)(Bp + k0);
        __syncthreads();
        As[lk+0][lr] = avv.x; As[lk+1][lr] = avv.y; As[lk+2][lr] = avv.z; As[lk+3][lr] = avv.w;
        Bs[lk+0][lr] = bvv.x; Bs[lk+1][lr] = bvv.y; Bs[lk+2][lr] = bvv.z; Bs[lk+3][lr] = bvv.w;
        __syncthreads();
        #pragma unroll
        for (int kk = 0; kk < 16; kk++) {
            float a[4], b[4];
            #pragma unroll
            for (int i = 0; i < 4; i++) a[i] = As[kk][ty * 4 + i];
            #pragma unroll
            for (int j = 0; j < 4; j++) b[j] = Bs[kk][tx * 4 + j];
            #pragma unroll
            for (int i = 0; i < 4; i++)
                #pragma unroll
                for (int j = 0; j < 4; j++) acc[i][j] += a[i] * b[j];
        }
    }
    float* Cp = g_part + (long)blockIdx.z * Bn * VISn;
    #pragma unroll
    for (int i = 0; i < 4; i++)
        #pragma unroll
        for (int j = 0; j < 4; j++)
            Cp[(long)(m0 + ty * 4 + i) * VISn + n0 + tx * 4 + j] = acc[i][j];
}

__global__ void k_img_reduce(const float* __restrict__ img_b) {
    int b = blockIdx.x, v = threadIdx.x;
    float s = img_b[v];
    #pragma unroll
    for (int k = 0; k < 8; k++) s += g_part[((long)k * Bn + b) * VISn + v];
    split_write(s, g_x_h, g_x_l, (long)(b * Tn) * 1024 + v);
}

// ===================== prep kernels =====================
__global__ void k_bias2(const float* __restrict__ b_ih, const float* __restrict__ b_hh) {
    int i = blockIdx.x * blockDim.x + threadIdx.x;
    if (i < 4 * Hn) g_bias2[i] = b_ih[i] + b_hh[i];
}
__global__ void k_cvt(const float* __restrict__ x, __nv_bfloat16* __restrict__ h,
                      __nv_bfloat16* __restrict__ l, int n) {
    int i = blockIdx.x * blockDim.x + threadIdx.x;
    if (i < n) split_write(x[i], h, l, i);
}
__global__ void k_transpose_f(const float* __restrict__ features) {
    int bp = blockIdx.x;
    int b = bp / 49, p = bp % 49;
    int v = threadIdx.x;
    float val = features[((long)b * 512 + v) * 49 + p];
    split_write(val, g_fT_h, g_fT_l, (long)bp * 512 + v);
}
__global__ void k_normalize() {
    int row = blockIdx.x;
    int b = row / 49, p = row % 49;
    const float* x = g_fv + (long)row * 512;
    __shared__ float red[8];
    int tid = threadIdx.x, lane = tid & 31, wid = tid >> 5;
    float s = 0.f;
    for (int v = tid; v < 512; v += 256) { float t = x[v]; s += t * t; }
    #pragma unroll
    for (int o = 16; o; o >>= 1) s += __shfl_xor_sync(0xffffffffu, s, o);
    if (lane == 0) red[wid] = s;
    __syncthreads();
    if (tid == 0) {
        float sum = 0.f;
        #pragma unroll
        for (int w = 0; w < 8; w++) sum += red[w];
        red[0] = 1.f / fmaxf(sqrtf(sum), 1e-12f);
    }
    __syncthreads();
    float inv = red[0];
    long o = ((long)b * 64 + p) * 512;
    for (int v = tid; v < 512; v += 256) {
        float val = x[v] * inv;
        g_features_all[o + v] = val;
        split_write(val, g_fall_h, g_fall_l, o + v);
    }
}
__global__ void k_copy_eng(const float* __restrict__ eng) {
    int bj = blockIdx.x;
    int b = bj / 15, j = bj % 15;
    int v = threadIdx.x;
    float val = eng[(long)bj * 512 + v];
    long o = ((long)b * 64 + 49 + j) * 512 + v;
    g_features_all[o] = val;
    split_write(val, g_fall_h, g_fall_l, o);
}
__global__ void k_embed(const int* __restrict__ captions, const float* __restrict__ embed_w) {
    int r = blockIdx.x;
    int idx = captions[r];
    float v = embed_w[(long)idx * 512 + threadIdx.x];
    split_write(v, g_we_h, g_we_l, (long)r * 512 + threadIdx.x);
    split_write(v, g_x_h,  g_x_l,  (long)r * 1024 + 512 + threadIdx.x);
}

// ===================== fused attention =====================
__global__ __launch_bounds__(512)
void k_attention(const float* __restrict__ att_bias, const float* __restrict__ att_w) {
    int t = blockIdx.x, b = blockIdx.y;
    __shared__ float hh[512], ws[512], sbv[64], sout[64];
    int tid = threadIdx.x, lane = tid & 31, wid = tid >> 5;

    hh[tid] = g_att_h[((long)b * Tn + t) * 512 + tid];
    ws[tid] = att_w[tid];
    if (tid < 64) sbv[tid] = att_bias[tid];
    __syncthreads();

    for (int n = wid; n < 64; n += 16) {
        const float* fea = g_att_fea + ((long)b * 64 + n) * 512;
        float bn = sbv[n], s = 0.f;
        for (int v = lane; v < 512; v += 32)
            s += fmaxf(fea[v] + hh[v] + bn, 0.f) * ws[v];
        #pragma unroll
        for (int o = 16; o; o >>= 1) s += __shfl_xor_sync(0xffffffffu, s, o);
        if (lane == 0) sout[n] = s;
    }
    __syncthreads();

    if (tid == 0) {
        float mx = sout[0];
        for (int n = 1; n < 64; n++) mx = fmaxf(mx, sout[n]);
        float sum = 0.f;
        for (int n = 0; n < 64; n++) { float e = __expf(sout[n] - mx); sout[n] = e; sum += e; }
        float inv = 1.f / sum;
        for (int n = 0; n < 64; n++) sout[n] *= inv;
    }
    __syncthreads();

    float acc = 0.f;
    const float* fa = g_features_all + (long)b * 64 * 512 + tid;
    #pragma unroll 8
    for (int n = 0; n < 64; n++) acc += sout[n] * fa[(long)n * 512];
    split_write(acc, g_x_h, g_x_l, ((long)b * Tn + (t + 1)) * 1024 + tid);
}

// ===================== launch =====================
static inline dim3 tgrid(int M, int N) { return dim3((N + 127) / 128, M / 128); }

extern "C" void kernel_launch(void* const* d_in, const int* in_sizes, int n_in,
                              void* d_out, int out_size)
{
    const float* feature_0 = (const float*)d_in[0];
    const float* features  = (const float*)d_in[1];
    const float* eng       = (const float*)d_in[2];
    const int*   captions  = (const int*)  d_in[3];
    const int*   lengths   = (const int*)  d_in[4];
    const float* embed_w   = (const float*)d_in[5];
    const float* w_ih      = (const float*)d_in[6];
    const float* w_hh      = (const float*)d_in[7];
    const float* b_ih      = (const float*)d_in[8];
    const float* b_hh      = (const float*)d_in[9];
    const float* fc_w      = (const float*)d_in[10];
    const float* fc_b      = (const float*)d_in[11];
    const float* att_vw_w  = (const float*)d_in[12];
    const float* att_hw_w  = (const float*)d_in[13];
    const float* att_bias  = (const float*)d_in[14];
    const float* att_w_w   = (const float*)d_in[15];
    const float* att_fc_w  = (const float*)d_in[16];
    const float* att_fc_b  = (const float*)d_in[17];
    const float* img_w     = (const float*)d_in[18];
    const float* img_b     = (const float*)d_in[19];
    float* out = (float*)d_out;

    static bool smem_set = false;
    if (!smem_set) {
        cudaFuncSetAttribute(mma_gemm,   cudaFuncAttributeMaxDynamicSharedMemorySize, MG_SMEM);
        cudaFuncSetAttribute(k_lstm_mma, cudaFuncAttributeMaxDynamicSharedMemorySize, L_SMEM);
        smem_set = true;
    }

    float* p_fv = nullptr;    cudaGetSymbolAddress((void**)&p_fv,    g_fv);
    float* p_ah = nullptr;    cudaGetSymbolAddress((void**)&p_ah,    g_att_h);
    float* p_xg = nullptr;    cudaGetSymbolAddress((void**)&p_xg,    g_xg);
    float* p_bias2 = nullptr; cudaGetSymbolAddress((void**)&p_bias2, g_bias2);
    float* p_afea = nullptr;  cudaGetSymbolAddress((void**)&p_afea,  g_att_fea);
    #define BSYM(p, s) __nv_bfloat16* p = nullptr; cudaGetSymbolAddress((void**)&p, s)
    BSYM(p_fT_h, g_fT_h);     BSYM(p_fT_l, g_fT_l);
    BSYM(p_fall_h, g_fall_h); BSYM(p_fall_l, g_fall_l);
    BSYM(p_we_h, g_we_h);     BSYM(p_we_l, g_we_l);
    BSYM(p_x_h, g_x_h);       BSYM(p_x_l, g_x_l);
    BSYM(p_hs_h, g_hs_h);     BSYM(p_hs_l, g_hs_l);
    BSYM(p_wfc1_h, g_wfc1_h); BSYM(p_wfc1_l, g_wfc1_l);
    BSYM(p_wvw_h, g_wvw_h);   BSYM(p_wvw_l, g_wvw_l);
    BSYM(p_whw_h, g_whw_h);   BSYM(p_whw_l, g_whw_l);
    BSYM(p_wih_h, g_wih_h);   BSYM(p_wih_l, g_wih_l);
    BSYM(p_wfc_h, g_wfc_h);   BSYM(p_wfc_l, g_wfc_l);
    BSYM(p_whh_h, g_whh_h);   BSYM(p_whh_l, g_whh_l);
    #undef BSYM

    // launches 1..5 (so launch #6 — the att_fc mma_gemm — is the ncu-profiled one)
    k_bias2<<<(4 * Hn + 255) / 256, 256>>>(b_ih, b_hh);
    k_cvt<<<(512 * 512 + 255) / 256, 256>>>(att_fc_w, p_wfc1_h, p_wfc1_l, 512 * 512);
    k_transpose_f<<<Bn * 49, 512>>>(features);
    k_embed<<<Bn * Tn, 512>>>(captions, embed_w);
    k_cvt<<<(512 * 512 + 255) / 256, 256>>>(att_vw_w, p_wvw_h, p_wvw_l, 512 * 512);

    // #6: att_fc: fv = fT @ att_fc_w.T + b   (6272 x 512 x 512)
    mma_gemm<<<tgrid(Bn * 49, 512), 256, MG_SMEM>>>(p_fT_h, p_fT_l, p_wfc1_h, p_wfc1_l,
        p_fv, 512, att_fc_b, Bn * 49, 512, 512, 0, nullptr);

    // remaining conversions + prep
    k_cvt<<<(512 * 512 + 255) / 256, 256>>>(att_hw_w, p_whw_h, p_whw_l, 512 * 512);
    k_cvt<<<(2048 * 1024 + 255) / 256, 256>>>(w_ih, p_wih_h, p_wih_l, 2048 * 1024);
    k_cvt<<<(Vn * 512 + 255) / 256, 256>>>(fc_w, p_wfc_h, p_wfc_l, Vn * 512);
    k_cvt<<<(2048 * 512 + 255) / 256, 256>>>(w_hh, p_whh_h, p_whh_l, 2048 * 512);
    k_normalize<<<Bn * 49, 256>>>();
    k_copy_eng<<<Bn * 15, 512>>>(eng);

    // img (split-K fp32): feature_0 @ img_w.T -> g_x rows t=0
    sgemm_splitk<<<dim3(8, 2, 8), 256>>>(feature_0, img_w);
    k_img_reduce<<<Bn, 512>>>(img_b);

    // att_fea = features_all @ att_vw_w.T   (8192 x 512 x 512)
    mma_gemm<<<tgrid(Bn * 64, 512), 256, MG_SMEM>>>(p_fall_h, p_fall_l, p_wvw_h, p_wvw_l,
        p_afea, 512, nullptr, Bn * 64, 512, 512, 0, nullptr);

    // att_h = we @ att_hw_w.T   (2560 x 512 x 512)
    mma_gemm<<<tgrid(Bn * Tn, 512), 256, MG_SMEM>>>(p_we_h, p_we_l, p_whw_h, p_whw_l,
        p_ah, 512, nullptr, Bn * Tn, 512, 512, 0, nullptr);

    // fused attention -> g_x feas part rows t=1..19
    k_attention<<<dim3(Tn - 1, Bn), 512>>>(att_bias, att_w_w);

    // xg = [feas|we] @ w_ih.T + (b_ih+b_hh)   (2560 x 2048 x 1024)
    mma_gemm<<<tgrid(Bn * Tn, 4 * Hn), 256, MG_SMEM>>>(p_x_h, p_x_l, p_wih_h, p_wih_l,
        p_xg, 4 * Hn, p_bias2, Bn * Tn, 4 * Hn, 1024, 0, nullptr);

    // LSTM recurrence: step 0 pointwise, steps 1..19 tensor-core
    k_lstm_t0<<<(Bn * Hn + 255) / 256, 256>>>();
    for (int t = 1; t < Tn; t++)
        k_lstm_mma<<<32, 256, L_SMEM>>>(t);

    // logits + mask: out = hs @ fc_w.T + fc_b   (2560 x 12000 x 512)
    mma_gemm<<<tgrid(Bn * Tn, Vn), 256, MG_SMEM>>>(p_hs_h, p_hs_l, p_wfc_h, p_wfc_l,
        out, Vn, fc_b, Bn * Tn, Vn, 512, 2, lengths);
}

// round 6
// speedup vs baseline: 5.2662x; 1.1990x over previous
#include <cuda_runtime.h>
#include <cuda_fp16.h>
#include <cstdint>
#include <math.h>

// Problem dims
#define Bn   128
#define Tn   20
#define Vn   12000
#define En   512
#define Hn   512
#define VISn 512

// ===================== PTX helpers (sm_100 baseline) =====================
__device__ __forceinline__ uint32_t smem_u32(const void* p) {
    uint32_t a;
    asm("{ .reg .u64 t; cvta.to.shared.u64 t, %1; cvt.u32.u64 %0, t; }" : "=r"(a) : "l"(p));
    return a;
}
#define CP_ASYNC16(dst, src) \
    asm volatile("cp.async.cg.shared.global [%0], [%1], 16;" :: "r"(dst), "l"(src) : "memory")
#define CP_COMMIT() asm volatile("cp.async.commit_group;" ::: "memory")
#define CP_WAIT2()  asm volatile("cp.async.wait_group 2;" ::: "memory")

__device__ __forceinline__ void ldsm4(uint32_t* r, uint32_t addr) {
    asm volatile("ldmatrix.sync.aligned.m8n8.x4.shared.b16 {%0,%1,%2,%3}, [%4];"
        : "=r"(r[0]), "=r"(r[1]), "=r"(r[2]), "=r"(r[3]) : "r"(addr));
}
__device__ __forceinline__ void mma16816(float* c, const uint32_t* a, const uint32_t* b) {
    asm volatile("mma.sync.aligned.m16n8k16.row.col.f32.f16.f16.f32 "
        "{%0,%1,%2,%3}, {%4,%5,%6,%7}, {%8,%9}, {%0,%1,%2,%3};"
        : "+f"(c[0]), "+f"(c[1]), "+f"(c[2]), "+f"(c[3])
        : "r"(a[0]), "r"(a[1]), "r"(a[2]), "r"(a[3]), "r"(b[0]), "r"(b[1]));
}

// ===================== scratch (device globals) =====================
__device__ float g_fv[Bn * 49 * VISn];
__device__ float g_features_all[Bn * 64 * VISn];
__device__ float g_att_fea[Bn * 64 * VISn];
__device__ float g_att_h[Bn * Tn * VISn];
__device__ float g_xg[Bn * Tn * 4 * Hn];
__device__ float g_c[Bn * Hn];
__device__ float g_bias2[4 * Hn];
__device__ float g_part[8 * Bn * VISn];

// activations: fp16 split pairs (hi, lo)
__device__ __half g_fT_h[Bn * 49 * VISn],   g_fT_l[Bn * 49 * VISn];
__device__ __half g_fall_h[Bn * 64 * VISn], g_fall_l[Bn * 64 * VISn];
__device__ __half g_we_h[Bn * Tn * En],     g_we_l[Bn * Tn * En];
__device__ __half g_x_h[Bn * Tn * 1024],    g_x_l[Bn * Tn * 1024];
__device__ __half g_hs_h[Bn * Tn * Hn],     g_hs_l[Bn * Tn * Hn];
// weights: single fp16
__device__ __half g_wfc1[VISn * VISn];
__device__ __half g_wvw[VISn * VISn];
__device__ __half g_whw[VISn * En];
__device__ __half g_wih[4 * Hn * 1024];
__device__ __half g_wfc[Vn * Hn];
__device__ __half g_whh[4 * Hn * Hn];

__device__ __forceinline__ void split_write16(float v, __half* h, __half* l, long i) {
    __half hi = __float2half_rn(v);
    h[i] = hi;
    l[i] = __float2half_rn(v - __half2float(hi));
}

// ===================== tensor-core GEMM via mma.sync (fp16 2-product) =====================
// C[M,N] = (Ah+Al)[M,K] @ B[N,K]^T, fp32 accum. 128x128 tile, BK=32, 8 warps (2x4).
// 4-stage cp.async ring, 1 sync/chunk.  mode 0: +bias  mode 2: masked fc epilogue.
#define ROWB   80
#define TILEB  (128 * ROWB)          // 10240 B
#define STAGEB (3 * TILEB)           // 30720 B (Ah, Al, B)
#define NSTG   4
#define MG_SMEM (NSTG * STAGEB)      // 122880 B

__global__ __launch_bounds__(256, 1)
void mma_gemm(const __half* __restrict__ Ah, const __half* __restrict__ Al,
              const __half* __restrict__ Bw,
              float* __restrict__ C, int ldc, const float* __restrict__ bias,
              int M, int N, int K, int mode, const int* __restrict__ lengths)
{
    extern __shared__ __align__(16) char smem[];
    const uint32_t sbase = smem_u32(smem);

    const int tid = threadIdx.x, wid = tid >> 5, lane = tid & 31;
    const int m0 = blockIdx.y * 128, n0 = blockIdx.x * 128;
    const int wm = wid & 1, wn = wid >> 1;

    const int NC = K >> 5;

    auto issue = [&](int c) {
        if (c < NC) {
            const long kc = (long)c * 32;
            const uint32_t sb = sbase + (c & (NSTG - 1)) * STAGEB;
            #pragma unroll
            for (int ti = 0; ti < 3; ti++) {
                const __half* S = (ti == 0) ? Ah : (ti == 1) ? Al : Bw;
                const int  rb  = (ti < 2) ? m0 : n0;
                const bool isB = (ti == 2);
                #pragma unroll
                for (int i = 0; i < 2; i++) {
                    int ch = tid + i * 256;
                    int row = ch >> 2, kq = ch & 3;
                    int gr = rb + row;
                    if (isB && gr >= N) gr = N - 1;
                    const __half* src = S + (long)gr * K + kc + kq * 8;
                    CP_ASYNC16(sb + ti * TILEB + row * ROWB + kq * 16, src);
                }
            }
        }
        CP_COMMIT();
    };

    float acc[4][4][4];
    #pragma unroll
    for (int mi = 0; mi < 4; mi++)
        #pragma unroll
        for (int ni = 0; ni < 4; ni++)
            #pragma unroll
            for (int q = 0; q < 4; q++) acc[mi][ni][q] = 0.f;

    const uint32_t a_off = (uint32_t)((wm * 64 + (lane & 15)) * ROWB + (lane >> 4) * 16);
    const uint32_t b_off = (uint32_t)((wn * 32 + ((lane >> 4) & 1) * 8 + (lane & 7)) * ROWB
                                      + ((lane >> 3) & 1) * 16);

    issue(0); issue(1); issue(2);

    for (int c = 0; c < NC; c++) {
        CP_WAIT2();
        __syncthreads();
        issue(c + 3);

        const uint32_t tb = sbase + (c & (NSTG - 1)) * STAGEB;
        #pragma unroll
        for (int kk = 0; kk < 2; kk++) {
            const uint32_t kba = kk * 32;
            uint32_t ah[4][4], al[4][4], bb[4][2];
            #pragma unroll
            for (int mi = 0; mi < 4; mi++) {
                ldsm4(ah[mi], tb + 0 * TILEB + a_off + mi * 16 * ROWB + kba);
                ldsm4(al[mi], tb + 1 * TILEB + a_off + mi * 16 * ROWB + kba);
            }
            #pragma unroll
            for (int nip = 0; nip < 2; nip++) {
                uint32_t t4[4];
                ldsm4(t4, tb + 2 * TILEB + b_off + nip * 16 * ROWB + kba);
                bb[2*nip][0] = t4[0]; bb[2*nip][1] = t4[1];
                bb[2*nip+1][0] = t4[2]; bb[2*nip+1][1] = t4[3];
            }
            #pragma unroll
            for (int mi = 0; mi < 4; mi++)
                #pragma unroll
                for (int ni = 0; ni < 4; ni++) {
                    mma16816(acc[mi][ni], ah[mi], bb[ni]);
                    mma16816(acc[mi][ni], al[mi], bb[ni]);
                }
        }
    }

    #pragma unroll
    for (int mi = 0; mi < 4; mi++) {
        const int r0 = m0 + wm * 64 + mi * 16 + (lane >> 2);
        const int r1 = r0 + 8;
        bool keep0 = true, keep1 = true;
        if (mode == 2) {
            keep0 = (lengths[r0 / Tn] >= (r0 % Tn));
            keep1 = (lengths[r1 / Tn] >= (r1 % Tn));
        }
        #pragma unroll
        for (int ni = 0; ni < 4; ni++) {
            const int col = n0 + wn * 32 + ni * 8 + (lane & 3) * 2;
            if (col >= N) continue;
            float b0 = 0.f, b1 = 0.f;
            if (bias) { b0 = bias[col]; b1 = bias[col + 1]; }
            float v0 = acc[mi][ni][0] + b0, v1 = acc[mi][ni][1] + b1;
            float v2 = acc[mi][ni][2] + b0, v3 = acc[mi][ni][3] + b1;
            if (mode == 2) {
                if (!keep0) { v0 = 0.f; v1 = 0.f; }
                if (!keep1) { v2 = 0.f; v3 = 0.f; }
            }
            *(float2*)(C + (long)r0 * ldc + col) = make_float2(v0, v1);
            *(float2*)(C + (long)r1 * ldc + col) = make_float2(v2, v3);
        }
    }
}

// ===================== LSTM step t>=1: tensor-core h@w_hh + fused gates =====================
// grid 32 CTAs (16 hcols x 4 gates each), 256 threads (8 warps, 2x4).
#define L_ATILE (128 * ROWB)                 // 10240
#define L_BTILE (64 * ROWB)                  // 5120
#define L_STAGE (2 * L_ATILE + L_BTILE)      // 25600
#define L_SMEM  (NSTG * L_STAGE)             // 102400

__global__ __launch_bounds__(256, 1)
void k_lstm_mma(int t)
{
    extern __shared__ __align__(16) char smem[];
    const uint32_t sbase = smem_u32(smem);
    const int tid = threadIdx.x, wid = tid >> 5, lane = tid & 31;
    const int h0 = blockIdx.x * 16;
    const int wm = wid & 1, wn = wid >> 1;       // wn = gate index
    const int NC = 16;

    auto issue = [&](int c) {
        if (c < NC) {
            const long kc = (long)c * 32;
            const uint32_t sb = sbase + (c & (NSTG - 1)) * L_STAGE;
            #pragma unroll
            for (int s = 0; s < 2; s++) {        // A: h hi/lo
                const __half* S = s ? g_hs_l : g_hs_h;
                #pragma unroll
                for (int i = 0; i < 2; i++) {
                    int ch = tid + i * 256;
                    int row = ch >> 2, kq = ch & 3;
                    const __half* src = S + ((long)row * Tn + (t - 1)) * Hn + kc + kq * 8;
                    CP_ASYNC16(sb + s * L_ATILE + row * ROWB + kq * 16, src);
                }
            }
            {                                    // B: w_hh, permuted rows
                int row = tid >> 2, kq = tid & 3;
                int j = (row >> 4) * 512 + h0 + (row & 15);
                const __half* src = g_whh + (long)j * Hn + kc + kq * 8;
                CP_ASYNC16(sb + 2 * L_ATILE + row * ROWB + kq * 16, src);
            }
        }
        CP_COMMIT();
    };

    float acc[4][2][4];
    #pragma unroll
    for (int mi = 0; mi < 4; mi++)
        #pragma unroll
        for (int ni = 0; ni < 2; ni++)
            #pragma unroll
            for (int q = 0; q < 4; q++) acc[mi][ni][q] = 0.f;

    const uint32_t a_off = (uint32_t)((wm * 64 + (lane & 15)) * ROWB + (lane >> 4) * 16);
    const uint32_t b_off = (uint32_t)((wn * 16 + ((lane >> 4) & 1) * 8 + (lane & 7)) * ROWB
                                      + ((lane >> 3) & 1) * 16);

    issue(0); issue(1); issue(2);

    for (int c = 0; c < NC; c++) {
        CP_WAIT2();
        __syncthreads();
        issue(c + 3);

        const uint32_t tb = sbase + (c & (NSTG - 1)) * L_STAGE;
        #pragma unroll
        for (int kk = 0; kk < 2; kk++) {
            const uint32_t kba = kk * 32;
            uint32_t ah[4][4], al[4][4], bb[2][2];
            #pragma unroll
            for (int mi = 0; mi < 4; mi++) {
                ldsm4(ah[mi], tb + 0 * L_ATILE + a_off + mi * 16 * ROWB + kba);
                ldsm4(al[mi], tb + 1 * L_ATILE + a_off + mi * 16 * ROWB + kba);
            }
            {
                uint32_t t4[4];
                ldsm4(t4, tb + 2 * L_ATILE + b_off + kba);
                bb[0][0] = t4[0]; bb[0][1] = t4[1]; bb[1][0] = t4[2]; bb[1][1] = t4[3];
            }
            #pragma unroll
            for (int mi = 0; mi < 4; mi++)
                #pragma unroll
                for (int ni = 0; ni < 2; ni++) {
                    mma16816(acc[mi][ni], ah[mi], bb[ni]);
                    mma16816(acc[mi][ni], al[mi], bb[ni]);
                }
        }
    }

    // stage gates, fused pointwise
    __syncthreads();
    float* Gs = (float*)smem;                    // [128][68]
    #pragma unroll
    for (int mi = 0; mi < 4; mi++) {
        const int r0 = wm * 64 + mi * 16 + (lane >> 2);
        const int r1 = r0 + 8;
        #pragma unroll
        for (int ni = 0; ni < 2; ni++) {
            const int cl = wn * 16 + ni * 8 + (lane & 3) * 2;
            Gs[r0 * 68 + cl]     = acc[mi][ni][0];
            Gs[r0 * 68 + cl + 1] = acc[mi][ni][1];
            Gs[r1 * 68 + cl]     = acc[mi][ni][2];
            Gs[r1 * 68 + cl + 1] = acc[mi][ni][3];
        }
    }
    __syncthreads();

    for (int p = tid; p < 128 * 16; p += 256) {
        const int b = p >> 4, l = p & 15;
        const int hcol = h0 + l;
        const float* xg = g_xg + ((long)b * Tn + t) * 2048;
        float gi = Gs[b * 68 + 0 * 16 + l] + xg[0 * 512 + hcol];
        float gf = Gs[b * 68 + 1 * 16 + l] + xg[1 * 512 + hcol];
        float gg = Gs[b * 68 + 2 * 16 + l] + xg[2 * 512 + hcol];
        float go = Gs[b * 68 + 3 * 16 + l] + xg[3 * 512 + hcol];
        float co = g_c[b * 512 + hcol];
        float si = 1.f / (1.f + __expf(-gi));
        float sf = 1.f / (1.f + __expf(-gf));
        float so = 1.f / (1.f + __expf(-go));
        float cn = sf * co + si * tanhf(gg);
        float hn = so * tanhf(cn);
        g_c[b * 512 + hcol] = cn;
        split_write16(hn, g_hs_h, g_hs_l, ((long)b * Tn + t) * 512 + hcol);
    }
}

// LSTM step 0: h=0, c=0 -> gates = xg only
__global__ void k_lstm_t0()
{
    int i = blockIdx.x * blockDim.x + threadIdx.x;
    if (i >= Bn * Hn) return;
    int b = i >> 9, hcol = i & 511;
    const float* xg = g_xg + ((long)b * Tn) * 2048;
    float gi = xg[hcol], gg = xg[1024 + hcol], go = xg[1536 + hcol];
    float si = 1.f / (1.f + __expf(-gi));
    float so = 1.f / (1.f + __expf(-go));
    float cn = si * tanhf(gg);
    float hn = so * tanhf(cn);
    g_c[i] = cn;
    split_write16(hn, g_hs_h, g_hs_l, ((long)b * Tn) * 512 + hcol);
}

// ===================== split-K fp32 GEMM for img (M=128, K=2048) =====================
__global__ __launch_bounds__(256)
void sgemm_splitk(const float* __restrict__ A, const float* __restrict__ Bw)
{
    __shared__ float As[16][64];
    __shared__ float Bs[16][64];
    const int tid = threadIdx.x;
    const int tx = tid & 15, ty = tid >> 4;
    const int n0 = blockIdx.x * 64, m0 = blockIdx.y * 64;
    const int kbase = blockIdx.z * 256;
    const int lr = tid >> 2, lk = (tid & 3) * 4;
    const float* Ap = A  + (long)(m0 + lr) * 2048 + kbase + lk;
    const float* Bp = Bw + (long)(n0 + lr) * 2048 + kbase + lk;

    float acc[4][4] = {};
    for (int k0 = 0; k0 < 256; k0 += 16) {
        float4 avv = *(const float4*)(Ap + k0);
        float4 bvv = *(const float4*)(Bp + k0);
        __syncthreads();
        As[lk+0][lr] = avv.x; As[lk+1][lr] = avv.y; As[lk+2][lr] = avv.z; As[lk+3][lr] = avv.w;
        Bs[lk+0][lr] = bvv.x; Bs[lk+1][lr] = bvv.y; Bs[lk+2][lr] = bvv.z; Bs[lk+3][lr] = bvv.w;
        __syncthreads();
        #pragma unroll
        for (int kk = 0; kk < 16; kk++) {
            float a[4], b[4];
            #pragma unroll
            for (int i = 0; i < 4; i++) a[i] = As[kk][ty * 4 + i];
            #pragma unroll
            for (int j = 0; j < 4; j++) b[j] = Bs[kk][tx * 4 + j];
            #pragma unroll
            for (int i = 0; i < 4; i++)
                #pragma unroll
                for (int j = 0; j < 4; j++) acc[i][j] += a[i] * b[j];
        }
    }
    float* Cp = g_part + (long)blockIdx.z * Bn * VISn;
    #pragma unroll
    for (int i = 0; i < 4; i++)
        #pragma unroll
        for (int j = 0; j < 4; j++)
            Cp[(long)(m0 + ty * 4 + i) * VISn + n0 + tx * 4 + j] = acc[i][j];
}

__global__ void k_img_reduce(const float* __restrict__ img_b) {
    int b = blockIdx.x, v = threadIdx.x;
    float s = img_b[v];
    #pragma unroll
    for (int k = 0; k < 8; k++) s += g_part[((long)k * Bn + b) * VISn + v];
    split_write16(s, g_x_h, g_x_l, (long)(b * Tn) * 1024 + v);
}

// ===================== prep kernels =====================
__global__ void k_bias2(const float* __restrict__ b_ih, const float* __restrict__ b_hh) {
    int i = blockIdx.x * blockDim.x + threadIdx.x;
    if (i < 4 * Hn) g_bias2[i] = b_ih[i] + b_hh[i];
}
__global__ void k_cvt16(const float* __restrict__ x, __half* __restrict__ h, int n) {
    int i = blockIdx.x * blockDim.x + threadIdx.x;
    if (i < n) h[i] = __float2half_rn(x[i]);
}
__global__ void k_transpose_f(const float* __restrict__ features) {
    int bp = blockIdx.x;
    int b = bp / 49, p = bp % 49;
    int v = threadIdx.x;
    float val = features[((long)b * 512 + v) * 49 + p];
    split_write16(val, g_fT_h, g_fT_l, (long)bp * 512 + v);
}
__global__ void k_normalize() {
    int row = blockIdx.x;
    int b = row / 49, p = row % 49;
    const float* x = g_fv + (long)row * 512;
    __shared__ float red[8];
    int tid = threadIdx.x, lane = tid & 31, wid = tid >> 5;
    float s = 0.f;
    for (int v = tid; v < 512; v += 256) { float t = x[v]; s += t * t; }
    #pragma unroll
    for (int o = 16; o; o >>= 1) s += __shfl_xor_sync(0xffffffffu, s, o);
    if (lane == 0) red[wid] = s;
    __syncthreads();
    if (tid == 0) {
        float sum = 0.f;
        #pragma unroll
        for (int w = 0; w < 8; w++) sum += red[w];
        red[0] = 1.f / fmaxf(sqrtf(sum), 1e-12f);
    }
    __syncthreads();
    float inv = red[0];
    long o = ((long)b * 64 + p) * 512;
    for (int v = tid; v < 512; v += 256) {
        float val = x[v] * inv;
        g_features_all[o + v] = val;
        split_write16(val, g_fall_h, g_fall_l, o + v);
    }
}
__global__ void k_copy_eng(const float* __restrict__ eng) {
    int bj = blockIdx.x;
    int b = bj / 15, j = bj % 15;
    int v = threadIdx.x;
    float val = eng[(long)bj * 512 + v];
    long o = ((long)b * 64 + 49 + j) * 512 + v;
    g_features_all[o] = val;
    split_write16(val, g_fall_h, g_fall_l, o);
}
__global__ void k_embed(const int* __restrict__ captions, const float* __restrict__ embed_w) {
    int r = blockIdx.x;
    int idx = captions[r];
    float v = embed_w[(long)idx * 512 + threadIdx.x];
    split_write16(v, g_we_h, g_we_l, (long)r * 512 + threadIdx.x);
    split_write16(v, g_x_h,  g_x_l,  (long)r * 1024 + 512 + threadIdx.x);
}

// ===================== fused attention =====================
__global__ __launch_bounds__(512)
void k_attention(const float* __restrict__ att_bias, const float* __restrict__ att_w) {
    int t = blockIdx.x, b = blockIdx.y;
    __shared__ float hh[512], ws[512], sbv[64], sout[64];
    int tid = threadIdx.x, lane = tid & 31, wid = tid >> 5;

    hh[tid] = g_att_h[((long)b * Tn + t) * 512 + tid];
    ws[tid] = att_w[tid];
    if (tid < 64) sbv[tid] = att_bias[tid];
    __syncthreads();

    for (int n = wid; n < 64; n += 16) {
        const float* fea = g_att_fea + ((long)b * 64 + n) * 512;
        float bn = sbv[n], s = 0.f;
        for (int v = lane; v < 512; v += 32)
            s += fmaxf(fea[v] + hh[v] + bn, 0.f) * ws[v];
        #pragma unroll
        for (int o = 16; o; o >>= 1) s += __shfl_xor_sync(0xffffffffu, s, o);
        if (lane == 0) sout[n] = s;
    }
    __syncthreads();

    if (tid == 0) {
        float mx = sout[0];
        for (int n = 1; n < 64; n++) mx = fmaxf(mx, sout[n]);
        float sum = 0.f;
        for (int n = 0; n < 64; n++) { float e = __expf(sout[n] - mx); sout[n] = e; sum += e; }
        float inv = 1.f / sum;
        for (int n = 0; n < 64; n++) sout[n] *= inv;
    }
    __syncthreads();

    float acc = 0.f;
    const float* fa = g_features_all + (long)b * 64 * 512 + tid;
    #pragma unroll 8
    for (int n = 0; n < 64; n++) acc += sout[n] * fa[(long)n * 512];
    split_write16(acc, g_x_h, g_x_l, ((long)b * Tn + (t + 1)) * 1024 + tid);
}

// ===================== launch =====================
static inline dim3 tgrid(int M, int N) { return dim3((N + 127) / 128, M / 128); }

extern "C" void kernel_launch(void* const* d_in, const int* in_sizes, int n_in,
                              void* d_out, int out_size)
{
    const float* feature_0 = (const float*)d_in[0];
    const float* features  = (const float*)d_in[1];
    const float* eng       = (const float*)d_in[2];
    const int*   captions  = (const int*)  d_in[3];
    const int*   lengths   = (const int*)  d_in[4];
    const float* embed_w   = (const float*)d_in[5];
    const float* w_ih      = (const float*)d_in[6];
    const float* w_hh      = (const float*)d_in[7];
    const float* b_ih      = (const float*)d_in[8];
    const float* b_hh      = (const float*)d_in[9];
    const float* fc_w      = (const float*)d_in[10];
    const float* fc_b      = (const float*)d_in[11];
    const float* att_vw_w  = (const float*)d_in[12];
    const float* att_hw_w  = (const float*)d_in[13];
    const float* att_bias  = (const float*)d_in[14];
    const float* att_w_w   = (const float*)d_in[15];
    const float* att_fc_w  = (const float*)d_in[16];
    const float* att_fc_b  = (const float*)d_in[17];
    const float* img_w     = (const float*)d_in[18];
    const float* img_b     = (const float*)d_in[19];
    float* out = (float*)d_out;

    static bool smem_set = false;
    if (!smem_set) {
        cudaFuncSetAttribute(mma_gemm,   cudaFuncAttributeMaxDynamicSharedMemorySize, MG_SMEM);
        cudaFuncSetAttribute(k_lstm_mma, cudaFuncAttributeMaxDynamicSharedMemorySize, L_SMEM);
        smem_set = true;
    }

    float* p_fv = nullptr;    cudaGetSymbolAddress((void**)&p_fv,    g_fv);
    float* p_ah = nullptr;    cudaGetSymbolAddress((void**)&p_ah,    g_att_h);
    float* p_xg = nullptr;    cudaGetSymbolAddress((void**)&p_xg,    g_xg);
    float* p_bias2 = nullptr; cudaGetSymbolAddress((void**)&p_bias2, g_bias2);
    float* p_afea = nullptr;  cudaGetSymbolAddress((void**)&p_afea,  g_att_fea);
    #define HSYM(p, s) __half* p = nullptr; cudaGetSymbolAddress((void**)&p, s)
    HSYM(p_fT_h, g_fT_h);     HSYM(p_fT_l, g_fT_l);
    HSYM(p_fall_h, g_fall_h); HSYM(p_fall_l, g_fall_l);
    HSYM(p_we_h, g_we_h);     HSYM(p_we_l, g_we_l);
    HSYM(p_x_h, g_x_h);       HSYM(p_x_l, g_x_l);
    HSYM(p_hs_h, g_hs_h);     HSYM(p_hs_l, g_hs_l);
    HSYM(p_wfc1, g_wfc1);     HSYM(p_wvw, g_wvw);
    HSYM(p_whw, g_whw);       HSYM(p_wih, g_wih);
    HSYM(p_wfc, g_wfc);       HSYM(p_whh, g_whh);
    #undef HSYM

    // launches 1-3: dependencies of the att_fc GEMM; #4 = mma_gemm (ncu profile slot)
    k_cvt16<<<(512 * 512 + 255) / 256, 256>>>(att_fc_w, p_wfc1, 512 * 512);
    k_transpose_f<<<Bn * 49, 512>>>(features);
    k_bias2<<<(4 * Hn + 255) / 256, 256>>>(b_ih, b_hh);

    // #4: att_fc: fv = fT @ att_fc_w.T + b   (6272 x 512 x 512)
    mma_gemm<<<tgrid(Bn * 49, 512), 256, MG_SMEM>>>(p_fT_h, p_fT_l, p_wfc1,
        p_fv, 512, att_fc_b, Bn * 49, 512, 512, 0, nullptr);

    // remaining conversions + prep
    k_embed<<<Bn * Tn, 512>>>(captions, embed_w);
    k_cvt16<<<(512 * 512 + 255) / 256, 256>>>(att_vw_w, p_wvw, 512 * 512);
    k_cvt16<<<(512 * 512 + 255) / 256, 256>>>(att_hw_w, p_whw, 512 * 512);
    k_cvt16<<<(2048 * 1024 + 255) / 256, 256>>>(w_ih, p_wih, 2048 * 1024);
    k_cvt16<<<(Vn * 512 + 255) / 256, 256>>>(fc_w, p_wfc, Vn * 512);
    k_cvt16<<<(2048 * 512 + 255) / 256, 256>>>(w_hh, p_whh, 2048 * 512);
    k_normalize<<<Bn * 49, 256>>>();
    k_copy_eng<<<Bn * 15, 512>>>(eng);

    // img (split-K fp32): feature_0 @ img_w.T -> g_x rows t=0
    sgemm_splitk<<<dim3(8, 2, 8), 256>>>(feature_0, img_w);
    k_img_reduce<<<Bn, 512>>>(img_b);

    // att_fea = features_all @ att_vw_w.T   (8192 x 512 x 512)
    mma_gemm<<<tgrid(Bn * 64, 512), 256, MG_SMEM>>>(p_fall_h, p_fall_l, p_wvw,
        p_afea, 512, nullptr, Bn * 64, 512, 512, 0, nullptr);

    // att_h = we @ att_hw_w.T   (2560 x 512 x 512)
    mma_gemm<<<tgrid(Bn * Tn, 512), 256, MG_SMEM>>>(p_we_h, p_we_l, p_whw,
        p_ah, 512, nullptr, Bn * Tn, 512, 512, 0, nullptr);

    // fused attention -> g_x feas part rows t=1..19
    k_attention<<<dim3(Tn - 1, Bn), 512>>>(att_bias, att_w_w);

    // xg = [feas|we] @ w_ih.T + (b_ih+b_hh)   (2560 x 2048 x 1024)
    mma_gemm<<<tgrid(Bn * Tn, 4 * Hn), 256, MG_SMEM>>>(p_x_h, p_x_l, p_wih,
        p_xg, 4 * Hn, p_bias2, Bn * Tn, 4 * Hn, 1024, 0, nullptr);

    // LSTM recurrence: step 0 pointwise, steps 1..19 tensor-core
    k_lstm_t0<<<(Bn * Hn + 255) / 256, 256>>>();
    for (int t = 1; t < Tn; t++)
        k_lstm_mma<<<32, 256, L_SMEM>>>(t);

    // logits + mask: out = hs @ fc_w.T + fc_b   (2560 x 12000 x 512)
    mma_gemm<<<tgrid(Bn * Tn, Vn), 256, MG_SMEM>>>(p_hs_h, p_hs_l, p_wfc,
        out, Vn, fc_b, Bn * Tn, Vn, 512, 2, lengths);
}

// round 7
// speedup vs baseline: 5.6551x; 1.0738x over previous
#include <cuda_runtime.h>
#include <cuda_fp16.h>
#include <cstdint>
#include <math.h>

// Problem dims
#define Bn   128
#define Tn   20
#define Vn   12000
#define En   512
#define Hn   512
#define VISn 512

// ===================== PTX helpers (sm_100 baseline) =====================
__device__ __forceinline__ uint32_t smem_u32(const void* p) {
    uint32_t a;
    asm("{ .reg .u64 t; cvta.to.shared.u64 t, %1; cvt.u32.u64 %0, t; }" : "=r"(a) : "l"(p));
    return a;
}
#define CP_ASYNC16(dst, src) \
    asm volatile("cp.async.cg.shared.global [%0], [%1], 16;" :: "r"(dst), "l"(src) : "memory")
#define CP_COMMIT() asm volatile("cp.async.commit_group;" ::: "memory")
#define CP_WAIT1()  asm volatile("cp.async.wait_group 1;" ::: "memory")
#define CP_WAIT2()  asm volatile("cp.async.wait_group 2;" ::: "memory")

__device__ __forceinline__ void ldsm4(uint32_t* r, uint32_t addr) {
    asm volatile("ldmatrix.sync.aligned.m8n8.x4.shared.b16 {%0,%1,%2,%3}, [%4];"
        : "=r"(r[0]), "=r"(r[1]), "=r"(r[2]), "=r"(r[3]) : "r"(addr));
}
__device__ __forceinline__ void mma16816(float* c, const uint32_t* a, const uint32_t* b) {
    asm volatile("mma.sync.aligned.m16n8k16.row.col.f32.f16.f16.f32 "
        "{%0,%1,%2,%3}, {%4,%5,%6,%7}, {%8,%9}, {%0,%1,%2,%3};"
        : "+f"(c[0]), "+f"(c[1]), "+f"(c[2]), "+f"(c[3])
        : "r"(a[0]), "r"(a[1]), "r"(a[2]), "r"(a[3]), "r"(b[0]), "r"(b[1]));
}

// ===================== scratch (device globals) =====================
__device__ float g_fv[Bn * 49 * VISn];
__device__ float g_features_all[Bn * 64 * VISn];
__device__ float g_att_fea[Bn * 64 * VISn];
__device__ float g_att_h[Bn * Tn * VISn];
__device__ float g_xg[Bn * Tn * 4 * Hn];
__device__ float g_c[Bn * Hn];
__device__ float g_bias2[4 * Hn];
__device__ float g_part[8 * Bn * VISn];

// activations: fp16 split pairs (hi, lo)
__device__ __half g_fT_h[Bn * 49 * VISn],   g_fT_l[Bn * 49 * VISn];
__device__ __half g_fall_h[Bn * 64 * VISn], g_fall_l[Bn * 64 * VISn];
__device__ __half g_we_h[Bn * Tn * En],     g_we_l[Bn * Tn * En];
__device__ __half g_x_h[Bn * Tn * 1024],    g_x_l[Bn * Tn * 1024];
__device__ __half g_hs_h[Bn * Tn * Hn],     g_hs_l[Bn * Tn * Hn];
// weights: single fp16
__device__ __half g_wfc1[VISn * VISn];
__device__ __half g_wvw[VISn * VISn];
__device__ __half g_whw[VISn * En];
__device__ __half g_wih[4 * Hn * 1024];
__device__ __half g_wfc[Vn * Hn];
__device__ __half g_whh[4 * Hn * Hn];

__device__ __forceinline__ void split_write16(float v, __half* h, __half* l, long i) {
    __half hi = __float2half_rn(v);
    h[i] = hi;
    l[i] = __float2half_rn(v - __half2float(hi));
}

// ===================== tensor-core GEMM via mma.sync (fp16 2-product) =====================
// C[M,N] = (Ah+Al)[M,K] @ B[N,K]^T, fp32 accum. 128x128 tile, BK=32, 8 warps (2x4).
// 3-stage cp.async ring -> 92160 B smem -> 2 CTAs/SM (16 warps/SM).
#define ROWB   80
#define TILEB  (128 * ROWB)          // 10240 B
#define STAGEB (3 * TILEB)           // 30720 B (Ah, Al, B)
#define G_NSTG 3
#define MG_SMEM (G_NSTG * STAGEB)    // 92160 B

__global__ __launch_bounds__(256, 2)
void mma_gemm(const __half* __restrict__ Ah, const __half* __restrict__ Al,
              const __half* __restrict__ Bw,
              float* __restrict__ C, int ldc, const float* __restrict__ bias,
              int M, int N, int K, int mode, const int* __restrict__ lengths)
{
    extern __shared__ __align__(16) char smem[];
    const uint32_t sbase = smem_u32(smem);

    const int tid = threadIdx.x, wid = tid >> 5, lane = tid & 31;
    const int m0 = blockIdx.y * 128, n0 = blockIdx.x * 128;
    const int wm = wid & 1, wn = wid >> 1;

    const int NC = K >> 5;

    auto stage_of = [](int c) { return (c % G_NSTG); };

    auto issue = [&](int c) {
        if (c < NC) {
            const long kc = (long)c * 32;
            const uint32_t sb = sbase + stage_of(c) * STAGEB;
            #pragma unroll
            for (int ti = 0; ti < 3; ti++) {
                const __half* S = (ti == 0) ? Ah : (ti == 1) ? Al : Bw;
                const int  rb  = (ti < 2) ? m0 : n0;
                const bool isB = (ti == 2);
                #pragma unroll
                for (int i = 0; i < 2; i++) {
                    int ch = tid + i * 256;
                    int row = ch >> 2, kq = ch & 3;
                    int gr = rb + row;
                    if (isB && gr >= N) gr = N - 1;
                    const __half* src = S + (long)gr * K + kc + kq * 8;
                    CP_ASYNC16(sb + ti * TILEB + row * ROWB + kq * 16, src);
                }
            }
        }
        CP_COMMIT();
    };

    float acc[4][4][4];
    #pragma unroll
    for (int mi = 0; mi < 4; mi++)
        #pragma unroll
        for (int ni = 0; ni < 4; ni++)
            #pragma unroll
            for (int q = 0; q < 4; q++) acc[mi][ni][q] = 0.f;

    const uint32_t a_off = (uint32_t)((wm * 64 + (lane & 15)) * ROWB + (lane >> 4) * 16);
    const uint32_t b_off = (uint32_t)((wn * 32 + ((lane >> 4) & 1) * 8 + (lane & 7)) * ROWB
                                      + ((lane >> 3) & 1) * 16);

    issue(0); issue(1);

    for (int c = 0; c < NC; c++) {
        CP_WAIT1();
        __syncthreads();
        issue(c + 2);

        const uint32_t tb = sbase + stage_of(c) * STAGEB;
        #pragma unroll
        for (int kk = 0; kk < 2; kk++) {
            const uint32_t kba = kk * 32;
            uint32_t ah[4][4], al[4][4], bb[4][2];
            #pragma unroll
            for (int mi = 0; mi < 4; mi++) {
                ldsm4(ah[mi], tb + 0 * TILEB + a_off + mi * 16 * ROWB + kba);
                ldsm4(al[mi], tb + 1 * TILEB + a_off + mi * 16 * ROWB + kba);
            }
            #pragma unroll
            for (int nip = 0; nip < 2; nip++) {
                uint32_t t4[4];
                ldsm4(t4, tb + 2 * TILEB + b_off + nip * 16 * ROWB + kba);
                bb[2*nip][0] = t4[0]; bb[2*nip][1] = t4[1];
                bb[2*nip+1][0] = t4[2]; bb[2*nip+1][1] = t4[3];
            }
            #pragma unroll
            for (int mi = 0; mi < 4; mi++)
                #pragma unroll
                for (int ni = 0; ni < 4; ni++) {
                    mma16816(acc[mi][ni], ah[mi], bb[ni]);
                    mma16816(acc[mi][ni], al[mi], bb[ni]);
                }
        }
        __syncthreads();
    }

    #pragma unroll
    for (int mi = 0; mi < 4; mi++) {
        const int r0 = m0 + wm * 64 + mi * 16 + (lane >> 2);
        const int r1 = r0 + 8;
        bool keep0 = true, keep1 = true;
        if (mode == 2) {
            keep0 = (lengths[r0 / Tn] >= (r0 % Tn));
            keep1 = (lengths[r1 / Tn] >= (r1 % Tn));
        }
        #pragma unroll
        for (int ni = 0; ni < 4; ni++) {
            const int col = n0 + wn * 32 + ni * 8 + (lane & 3) * 2;
            if (col >= N) continue;
            float b0 = 0.f, b1 = 0.f;
            if (bias) { b0 = bias[col]; b1 = bias[col + 1]; }
            float v0 = acc[mi][ni][0] + b0, v1 = acc[mi][ni][1] + b1;
            float v2 = acc[mi][ni][2] + b0, v3 = acc[mi][ni][3] + b1;
            if (mode == 2) {
                if (!keep0) { v0 = 0.f; v1 = 0.f; }
                if (!keep1) { v2 = 0.f; v3 = 0.f; }
            }
            *(float2*)(C + (long)r0 * ldc + col) = make_float2(v0, v1);
            *(float2*)(C + (long)r1 * ldc + col) = make_float2(v2, v3);
        }
    }
}

// ===================== LSTM step t>=1: tensor-core h@w_hh + fused gates =====================
// grid 32 CTAs (16 hcols x 4 gates each), 256 threads (8 warps, 2x4). 4-stage ring.
#define L_ATILE (128 * ROWB)                 // 10240
#define L_BTILE (64 * ROWB)                  // 5120
#define L_STAGE (2 * L_ATILE + L_BTILE)      // 25600
#define L_NSTG  4
#define L_SMEM  (L_NSTG * L_STAGE)           // 102400

__global__ __launch_bounds__(256, 1)
void k_lstm_mma(int t)
{
    extern __shared__ __align__(16) char smem[];
    const uint32_t sbase = smem_u32(smem);
    const int tid = threadIdx.x, wid = tid >> 5, lane = tid & 31;
    const int h0 = blockIdx.x * 16;
    const int wm = wid & 1, wn = wid >> 1;       // wn = gate index
    const int NC = 16;

    auto issue = [&](int c) {
        if (c < NC) {
            const long kc = (long)c * 32;
            const uint32_t sb = sbase + (c & (L_NSTG - 1)) * L_STAGE;
            #pragma unroll
            for (int s = 0; s < 2; s++) {        // A: h hi/lo
                const __half* S = s ? g_hs_l : g_hs_h;
                #pragma unroll
                for (int i = 0; i < 2; i++) {
                    int ch = tid + i * 256;
                    int row = ch >> 2, kq = ch & 3;
                    const __half* src = S + ((long)row * Tn + (t - 1)) * Hn + kc + kq * 8;
                    CP_ASYNC16(sb + s * L_ATILE + row * ROWB + kq * 16, src);
                }
            }
            {                                    // B: w_hh, permuted rows
                int row = tid >> 2, kq = tid & 3;
                int j = (row >> 4) * 512 + h0 + (row & 15);
                const __half* src = g_whh + (long)j * Hn + kc + kq * 8;
                CP_ASYNC16(sb + 2 * L_ATILE + row * ROWB + kq * 16, src);
            }
        }
        CP_COMMIT();
    };

    float acc[4][2][4];
    #pragma unroll
    for (int mi = 0; mi < 4; mi++)
        #pragma unroll
        for (int ni = 0; ni < 2; ni++)
            #pragma unroll
            for (int q = 0; q < 4; q++) acc[mi][ni][q] = 0.f;

    const uint32_t a_off = (uint32_t)((wm * 64 + (lane & 15)) * ROWB + (lane >> 4) * 16);
    const uint32_t b_off = (uint32_t)((wn * 16 + ((lane >> 4) & 1) * 8 + (lane & 7)) * ROWB
                                      + ((lane >> 3) & 1) * 16);

    issue(0); issue(1); issue(2);

    for (int c = 0; c < NC; c++) {
        CP_WAIT2();
        __syncthreads();
        issue(c + 3);

        const uint32_t tb = sbase + (c & (L_NSTG - 1)) * L_STAGE;
        #pragma unroll
        for (int kk = 0; kk < 2; kk++) {
            const uint32_t kba = kk * 32;
            uint32_t ah[4][4], al[4][4], bb[2][2];
            #pragma unroll
            for (int mi = 0; mi < 4; mi++) {
                ldsm4(ah[mi], tb + 0 * L_ATILE + a_off + mi * 16 * ROWB + kba);
                ldsm4(al[mi], tb + 1 * L_ATILE + a_off + mi * 16 * ROWB + kba);
            }
            {
                uint32_t t4[4];
                ldsm4(t4, tb + 2 * L_ATILE + b_off + kba);
                bb[0][0] = t4[0]; bb[0][1] = t4[1]; bb[1][0] = t4[2]; bb[1][1] = t4[3];
            }
            #pragma unroll
            for (int mi = 0; mi < 4; mi++)
                #pragma unroll
                for (int ni = 0; ni < 2; ni++) {
                    mma16816(acc[mi][ni], ah[mi], bb[ni]);
                    mma16816(acc[mi][ni], al[mi], bb[ni]);
                }
        }
    }

    // stage gates, fused pointwise
    __syncthreads();
    float* Gs = (float*)smem;                    // [128][68]
    #pragma unroll
    for (int mi = 0; mi < 4; mi++) {
        const int r0 = wm * 64 + mi * 16 + (lane >> 2);
        const int r1 = r0 + 8;
        #pragma unroll
        for (int ni = 0; ni < 2; ni++) {
            const int cl = wn * 16 + ni * 8 + (lane & 3) * 2;
            Gs[r0 * 68 + cl]     = acc[mi][ni][0];
            Gs[r0 * 68 + cl + 1] = acc[mi][ni][1];
            Gs[r1 * 68 + cl]     = acc[mi][ni][2];
            Gs[r1 * 68 + cl + 1] = acc[mi][ni][3];
        }
    }
    __syncthreads();

    for (int p = tid; p < 128 * 16; p += 256) {
        const int b = p >> 4, l = p & 15;
        const int hcol = h0 + l;
        const float* xg = g_xg + ((long)b * Tn + t) * 2048;
        float gi = Gs[b * 68 + 0 * 16 + l] + xg[0 * 512 + hcol];
        float gf = Gs[b * 68 + 1 * 16 + l] + xg[1 * 512 + hcol];
        float gg = Gs[b * 68 + 2 * 16 + l] + xg[2 * 512 + hcol];
        float go = Gs[b * 68 + 3 * 16 + l] + xg[3 * 512 + hcol];
        float co = g_c[b * 512 + hcol];
        float si = 1.f / (1.f + __expf(-gi));
        float sf = 1.f / (1.f + __expf(-gf));
        float so = 1.f / (1.f + __expf(-go));
        float cn = sf * co + si * tanhf(gg);
        float hn = so * tanhf(cn);
        g_c[b * 512 + hcol] = cn;
        split_write16(hn, g_hs_h, g_hs_l, ((long)b * Tn + t) * 512 + hcol);
    }
}

// LSTM step 0: h=0, c=0 -> gates = xg only
__global__ void k_lstm_t0()
{
    int i = blockIdx.x * blockDim.x + threadIdx.x;
    if (i >= Bn * Hn) return;
    int b = i >> 9, hcol = i & 511;
    const float* xg = g_xg + ((long)b * Tn) * 2048;
    float gi = xg[hcol], gg = xg[1024 + hcol], go = xg[1536 + hcol];
    float si = 1.f / (1.f + __expf(-gi));
    float so = 1.f / (1.f + __expf(-go));
    float cn = si * tanhf(gg);
    float hn = so * tanhf(cn);
    g_c[i] = cn;
    split_write16(hn, g_hs_h, g_hs_l, ((long)b * Tn) * 512 + hcol);
}

// ===================== split-K fp32 GEMM for img (M=128, K=2048) =====================
__global__ __launch_bounds__(256)
void sgemm_splitk(const float* __restrict__ A, const float* __restrict__ Bw)
{
    __shared__ float As[16][64];
    __shared__ float Bs[16][64];
    const int tid = threadIdx.x;
    const int tx = tid & 15, ty = tid >> 4;
    const int n0 = blockIdx.x * 64, m0 = blockIdx.y * 64;
    const int kbase = blockIdx.z * 256;
    const int lr = tid >> 2, lk = (tid & 3) * 4;
    const float* Ap = A  + (long)(m0 + lr) * 2048 + kbase + lk;
    const float* Bp = Bw + (long)(n0 + lr) * 2048 + kbase + lk;

    float acc[4][4] = {};
    for (int k0 = 0; k0 < 256; k0 += 16) {
        float4 avv = *(const float4*)(Ap + k0);
        float4 bvv = *(const float4*)(Bp + k0);
        __syncthreads();
        As[lk+0][lr] = avv.x; As[lk+1][lr] = avv.y; As[lk+2][lr] = avv.z; As[lk+3][lr] = avv.w;
        Bs[lk+0][lr] = bvv.x; Bs[lk+1][lr] = bvv.y; Bs[lk+2][lr] = bvv.z; Bs[lk+3][lr] = bvv.w;
        __syncthreads();
        #pragma unroll
        for (int kk = 0; kk < 16; kk++) {
            float a[4], b[4];
            #pragma unroll
            for (int i = 0; i < 4; i++) a[i] = As[kk][ty * 4 + i];
            #pragma unroll
            for (int j = 0; j < 4; j++) b[j] = Bs[kk][tx * 4 + j];
            #pragma unroll
            for (int i = 0; i < 4; i++)
                #pragma unroll
                for (int j = 0; j < 4; j++) acc[i][j] += a[i] * b[j];
        }
    }
    float* Cp = g_part + (long)blockIdx.z * Bn * VISn;
    #pragma unroll
    for (int i = 0; i < 4; i++)
        #pragma unroll
        for (int j = 0; j < 4; j++)
            Cp[(long)(m0 + ty * 4 + i) * VISn + n0 + tx * 4 + j] = acc[i][j];
}

__global__ void k_img_reduce(const float* __restrict__ img_b) {
    int b = blockIdx.x, v = threadIdx.x;
    float s = img_b[v];
    #pragma unroll
    for (int k = 0; k < 8; k++) s += g_part[((long)k * Bn + b) * VISn + v];
    split_write16(s, g_x_h, g_x_l, (long)(b * Tn) * 1024 + v);
}

// ===================== prep kernels =====================
__global__ void k_bias2(const float* __restrict__ b_ih, const float* __restrict__ b_hh) {
    int i = blockIdx.x * blockDim.x + threadIdx.x;
    if (i < 4 * Hn) g_bias2[i] = b_ih[i] + b_hh[i];
}
__global__ void k_cvt16(const float* __restrict__ x, __half* __restrict__ h, int n) {
    int i = blockIdx.x * blockDim.x + threadIdx.x;
    if (i < n) h[i] = __float2half_rn(x[i]);
}
__global__ void k_transpose_f(const float* __restrict__ features) {
    int bp = blockIdx.x;
    int b = bp / 49, p = bp % 49;
    int v = threadIdx.x;
    float val = features[((long)b * 512 + v) * 49 + p];
    split_write16(val, g_fT_h, g_fT_l, (long)bp * 512 + v);
}
__global__ void k_normalize() {
    int row = blockIdx.x;
    int b = row / 49, p = row % 49;
    const float* x = g_fv + (long)row * 512;
    __shared__ float red[8];
    int tid = threadIdx.x, lane = tid & 31, wid = tid >> 5;
    float s = 0.f;
    for (int v = tid; v < 512; v += 256) { float t = x[v]; s += t * t; }
    #pragma unroll
    for (int o = 16; o; o >>= 1) s += __shfl_xor_sync(0xffffffffu, s, o);
    if (lane == 0) red[wid] = s;
    __syncthreads();
    if (tid == 0) {
        float sum = 0.f;
        #pragma unroll
        for (int w = 0; w < 8; w++) sum += red[w];
        red[0] = 1.f / fmaxf(sqrtf(sum), 1e-12f);
    }
    __syncthreads();
    float inv = red[0];
    long o = ((long)b * 64 + p) * 512;
    for (int v = tid; v < 512; v += 256) {
        float val = x[v] * inv;
        g_features_all[o + v] = val;
        split_write16(val, g_fall_h, g_fall_l, o + v);
    }
}
__global__ void k_copy_eng(const float* __restrict__ eng) {
    int bj = blockIdx.x;
    int b = bj / 15, j = bj % 15;
    int v = threadIdx.x;
    float val = eng[(long)bj * 512 + v];
    long o = ((long)b * 64 + 49 + j) * 512 + v;
    g_features_all[o] = val;
    split_write16(val, g_fall_h, g_fall_l, o);
}
__global__ void k_embed(const int* __restrict__ captions, const float* __restrict__ embed_w) {
    int r = blockIdx.x;
    int idx = captions[r];
    float v = embed_w[(long)idx * 512 + threadIdx.x];
    split_write16(v, g_we_h, g_we_l, (long)r * 512 + threadIdx.x);
    split_write16(v, g_x_h,  g_x_l,  (long)r * 1024 + 512 + threadIdx.x);
}

// ===================== fused attention =====================
__global__ __launch_bounds__(512)
void k_attention(const float* __restrict__ att_bias, const float* __restrict__ att_w) {
    int t = blockIdx.x, b = blockIdx.y;
    __shared__ float hh[512], ws[512], sbv[64], sout[64];
    int tid = threadIdx.x, lane = tid & 31, wid = tid >> 5;

    hh[tid] = g_att_h[((long)b * Tn + t) * 512 + tid];
    ws[tid] = att_w[tid];
    if (tid < 64) sbv[tid] = att_bias[tid];
    __syncthreads();

    for (int n = wid; n < 64; n += 16) {
        const float* fea = g_att_fea + ((long)b * 64 + n) * 512;
        float bn = sbv[n], s = 0.f;
        for (int v = lane; v < 512; v += 32)
            s += fmaxf(fea[v] + hh[v] + bn, 0.f) * ws[v];
        #pragma unroll
        for (int o = 16; o; o >>= 1) s += __shfl_xor_sync(0xffffffffu, s, o);
        if (lane == 0) sout[n] = s;
    }
    __syncthreads();

    if (tid == 0) {
        float mx = sout[0];
        for (int n = 1; n < 64; n++) mx = fmaxf(mx, sout[n]);
        float sum = 0.f;
        for (int n = 0; n < 64; n++) { float e = __expf(sout[n] - mx); sout[n] = e; sum += e; }
        float inv = 1.f / sum;
        for (int n = 0; n < 64; n++) sout[n] *= inv;
    }
    __syncthreads();

    float acc = 0.f;
    const float* fa = g_features_all + (long)b * 64 * 512 + tid;
    #pragma unroll 8
    for (int n = 0; n < 64; n++) acc += sout[n] * fa[(long)n * 512];
    split_write16(acc, g_x_h, g_x_l, ((long)b * Tn + (t + 1)) * 1024 + tid);
}

// ===================== launch =====================
static inline dim3 tgrid(int M, int N) { return dim3((N + 127) / 128, M / 128); }

extern "C" void kernel_launch(void* const* d_in, const int* in_sizes, int n_in,
                              void* d_out, int out_size)
{
    const float* feature_0 = (const float*)d_in[0];
    const float* features  = (const float*)d_in[1];
    const float* eng       = (const float*)d_in[2];
    const int*   captions  = (const int*)  d_in[3];
    const int*   lengths   = (const int*)  d_in[4];
    const float* embed_w   = (const float*)d_in[5];
    const float* w_ih      = (const float*)d_in[6];
    const float* w_hh      = (const float*)d_in[7];
    const float* b_ih      = (const float*)d_in[8];
    const float* b_hh      = (const float*)d_in[9];
    const float* fc_w      = (const float*)d_in[10];
    const float* fc_b      = (const float*)d_in[11];
    const float* att_vw_w  = (const float*)d_in[12];
    const float* att_hw_w  = (const float*)d_in[13];
    const float* att_bias  = (const float*)d_in[14];
    const float* att_w_w   = (const float*)d_in[15];
    const float* att_fc_w  = (const float*)d_in[16];
    const float* att_fc_b  = (const float*)d_in[17];
    const float* img_w     = (const float*)d_in[18];
    const float* img_b     = (const float*)d_in[19];
    float* out = (float*)d_out;

    static bool smem_set = false;
    if (!smem_set) {
        cudaFuncSetAttribute(mma_gemm,   cudaFuncAttributeMaxDynamicSharedMemorySize, MG_SMEM);
        cudaFuncSetAttribute(k_lstm_mma, cudaFuncAttributeMaxDynamicSharedMemorySize, L_SMEM);
        smem_set = true;
    }

    float* p_fv = nullptr;    cudaGetSymbolAddress((void**)&p_fv,    g_fv);
    float* p_ah = nullptr;    cudaGetSymbolAddress((void**)&p_ah,    g_att_h);
    float* p_xg = nullptr;    cudaGetSymbolAddress((void**)&p_xg,    g_xg);
    float* p_bias2 = nullptr; cudaGetSymbolAddress((void**)&p_bias2, g_bias2);
    float* p_afea = nullptr;  cudaGetSymbolAddress((void**)&p_afea,  g_att_fea);
    #define HSYM(p, s) __half* p = nullptr; cudaGetSymbolAddress((void**)&p, s)
    HSYM(p_fT_h, g_fT_h);     HSYM(p_fT_l, g_fT_l);
    HSYM(p_fall_h, g_fall_h); HSYM(p_fall_l, g_fall_l);
    HSYM(p_we_h, g_we_h);     HSYM(p_we_l, g_we_l);
    HSYM(p_x_h, g_x_h);       HSYM(p_x_l, g_x_l);
    HSYM(p_hs_h, g_hs_h);     HSYM(p_hs_l, g_hs_l);
    HSYM(p_wfc1, g_wfc1);     HSYM(p_wvw, g_wvw);
    HSYM(p_whw, g_whw);       HSYM(p_wih, g_wih);
    HSYM(p_wfc, g_wfc);       HSYM(p_whh, g_whh);
    #undef HSYM

    // launches 1-3: dependencies of the att_fc GEMM; #4 = mma_gemm (ncu profile slot)
    k_cvt16<<<(512 * 512 + 255) / 256, 256>>>(att_fc_w, p_wfc1, 512 * 512);
    k_transpose_f<<<Bn * 49, 512>>>(features);
    k_bias2<<<(4 * Hn + 255) / 256, 256>>>(b_ih, b_hh);

    // #4: att_fc: fv = fT @ att_fc_w.T + b   (6272 x 512 x 512)
    mma_gemm<<<tgrid(Bn * 49, 512), 256, MG_SMEM>>>(p_fT_h, p_fT_l, p_wfc1,
        p_fv, 512, att_fc_b, Bn * 49, 512, 512, 0, nullptr);

    // remaining conversions + prep
    k_embed<<<Bn * Tn, 512>>>(captions, embed_w);
    k_cvt16<<<(512 * 512 + 255) / 256, 256>>>(att_vw_w, p_wvw, 512 * 512);
    k_cvt16<<<(512 * 512 + 255) / 256, 256>>>(att_hw_w, p_whw, 512 * 512);
    k_cvt16<<<(2048 * 1024 + 255) / 256, 256>>>(w_ih, p_wih, 2048 * 1024);
    k_cvt16<<<(Vn * 512 + 255) / 256, 256>>>(fc_w, p_wfc, Vn * 512);
    k_cvt16<<<(2048 * 512 + 255) / 256, 256>>>(w_hh, p_whh, 2048 * 512);
    k_normalize<<<Bn * 49, 256>>>();
    k_copy_eng<<<Bn * 15, 512>>>(eng);

    // img (split-K fp32): feature_0 @ img_w.T -> g_x rows t=0
    sgemm_splitk<<<dim3(8, 2, 8), 256>>>(feature_0, img_w);
    k_img_reduce<<<Bn, 512>>>(img_b);

    // att_fea = features_all @ att_vw_w.T   (8192 x 512 x 512)
    mma_gemm<<<tgrid(Bn * 64, 512), 256, MG_SMEM>>>(p_fall_h, p_fall_l, p_wvw,
        p_afea, 512, nullptr, Bn * 64, 512, 512, 0, nullptr);

    // att_h = we @ att_hw_w.T   (2560 x 512 x 512)
    mma_gemm<<<tgrid(Bn * Tn, 512), 256, MG_SMEM>>>(p_we_h, p_we_l, p_whw,
        p_ah, 512, nullptr, Bn * Tn, 512, 512, 0, nullptr);

    // fused attention -> g_x feas part rows t=1..19
    k_attention<<<dim3(Tn - 1, Bn), 512>>>(att_bias, att_w_w);

    // xg = [feas|we] @ w_ih.T + (b_ih+b_hh)   (2560 x 2048 x 1024)
    mma_gemm<<<tgrid(Bn * Tn, 4 * Hn), 256, MG_SMEM>>>(p_x_h, p_x_l, p_wih,
        p_xg, 4 * Hn, p_bias2, Bn * Tn, 4 * Hn, 1024, 0, nullptr);

    // LSTM recurrence: step 0 pointwise, steps 1..19 tensor-core
    k_lstm_t0<<<(Bn * Hn + 255) / 256, 256>>>();
    for (int t = 1; t < Tn; t++)
        k_lstm_mma<<<32, 256, L_SMEM>>>(t);

    // logits + mask: out = hs @ fc_w.T + fc_b   (2560 x 12000 x 512)
    mma_gemm<<<tgrid(Bn * Tn, Vn), 256, MG_SMEM>>>(p_hs_h, p_hs_l, p_wfc,
        out, Vn, fc_b, Bn * Tn, Vn, 512, 2, lengths);
}

// round 8
// speedup vs baseline: 6.2335x; 1.1023x over previous
#include <cuda_runtime.h>
#include <cuda_fp16.h>
#include <cstdint>
#include <math.h>

// Problem dims
#define Bn   128
#define Tn   20
#define Vn   12000
#define En   512
#define Hn   512
#define VISn 512

// ===================== PTX helpers (sm_100 baseline) =====================
__device__ __forceinline__ uint32_t smem_u32(const void* p) {
    uint32_t a;
    asm("{ .reg .u64 t; cvta.to.shared.u64 t, %1; cvt.u32.u64 %0, t; }" : "=r"(a) : "l"(p));
    return a;
}
#define CP_ASYNC16(dst, src) \
    asm volatile("cp.async.cg.shared.global [%0], [%1], 16;" :: "r"(dst), "l"(src) : "memory")
#define CP_COMMIT() asm volatile("cp.async.commit_group;" ::: "memory")
#define CP_WAIT1()  asm volatile("cp.async.wait_group 1;" ::: "memory")
#define CP_WAIT2()  asm volatile("cp.async.wait_group 2;" ::: "memory")

__device__ __forceinline__ void ldsm4(uint32_t* r, uint32_t addr) {
    asm volatile("ldmatrix.sync.aligned.m8n8.x4.shared.b16 {%0,%1,%2,%3}, [%4];"
        : "=r"(r[0]), "=r"(r[1]), "=r"(r[2]), "=r"(r[3]) : "r"(addr));
}
__device__ __forceinline__ void mma16816(float* c, const uint32_t* a, const uint32_t* b) {
    asm volatile("mma.sync.aligned.m16n8k16.row.col.f32.f16.f16.f32 "
        "{%0,%1,%2,%3}, {%4,%5,%6,%7}, {%8,%9}, {%0,%1,%2,%3};"
        : "+f"(c[0]), "+f"(c[1]), "+f"(c[2]), "+f"(c[3])
        : "r"(a[0]), "r"(a[1]), "r"(a[2]), "r"(a[3]), "r"(b[0]), "r"(b[1]));
}

// ===================== scratch (device globals) =====================
__device__ float g_fv[Bn * 49 * VISn];
__device__ float g_features_all[Bn * 64 * VISn];
__device__ float g_att_fea[Bn * 64 * VISn];
__device__ float g_att_h[Bn * Tn * VISn];
__device__ float g_xg[Bn * Tn * 4 * Hn];
__device__ float g_c[Bn * Hn];
__device__ float g_bias2[4 * Hn];
__device__ float g_part[8 * Bn * VISn];

// activations: fp16 split pairs (hi, lo)
__device__ __half g_fT_h[Bn * 49 * VISn],   g_fT_l[Bn * 49 * VISn];
__device__ __half g_fall_h[Bn * 64 * VISn], g_fall_l[Bn * 64 * VISn];
__device__ __half g_we_h[Bn * Tn * En],     g_we_l[Bn * Tn * En];
__device__ __half g_x_h[Bn * Tn * 1024],    g_x_l[Bn * Tn * 1024];
__device__ __half g_hs_h[Bn * Tn * Hn],     g_hs_l[Bn * Tn * Hn];
// weights: single fp16
__device__ __half g_wfc1[VISn * VISn];
__device__ __half g_wvw[VISn * VISn];
__device__ __half g_whw[VISn * En];
__device__ __half g_wih[4 * Hn * 1024];
__device__ __half g_wfc[Vn * Hn];
__device__ __half g_whh[4 * Hn * Hn];

__device__ __forceinline__ void split_write16(float v, __half* h, __half* l, long i) {
    __half hi = __float2half_rn(v);
    h[i] = hi;
    l[i] = __float2half_rn(v - __half2float(hi));
}

// ===================== tensor-core GEMM (fp16 2-product) =====================
// C[M,N] = (Ah+Al)[M,K] @ B[N,K]^T, fp32 accum. 128x128 tile, BK=32, 8 warps.
// 3-stage ring -> 92160 B -> 2 CTAs/SM.
#define ROWB   80
#define TILEB  (128 * ROWB)          // 10240 B
#define STAGEB (3 * TILEB)           // 30720 B (Ah, Al, B)
#define G_NSTG 3
#define MG_SMEM (G_NSTG * STAGEB)    // 92160 B

__global__ __launch_bounds__(256, 2)
void mma_gemm(const __half* __restrict__ Ah, const __half* __restrict__ Al,
              const __half* __restrict__ Bw,
              float* __restrict__ C, int ldc, const float* __restrict__ bias,
              int M, int N, int K)
{
    extern __shared__ __align__(16) char smem[];
    const uint32_t sbase = smem_u32(smem);

    const int tid = threadIdx.x, wid = tid >> 5, lane = tid & 31;
    const int m0 = blockIdx.y * 128, n0 = blockIdx.x * 128;
    const int wm = wid & 1, wn = wid >> 1;

    const int NC = K >> 5;

    auto stage_of = [](int c) { return (c % G_NSTG); };

    auto issue = [&](int c) {
        if (c < NC) {
            const long kc = (long)c * 32;
            const uint32_t sb = sbase + stage_of(c) * STAGEB;
            #pragma unroll
            for (int ti = 0; ti < 3; ti++) {
                const __half* S = (ti == 0) ? Ah : (ti == 1) ? Al : Bw;
                const int  rb  = (ti < 2) ? m0 : n0;
                const bool isB = (ti == 2);
                #pragma unroll
                for (int i = 0; i < 2; i++) {
                    int ch = tid + i * 256;
                    int row = ch >> 2, kq = ch & 3;
                    int gr = rb + row;
                    if (isB && gr >= N) gr = N - 1;
                    const __half* src = S + (long)gr * K + kc + kq * 8;
                    CP_ASYNC16(sb + ti * TILEB + row * ROWB + kq * 16, src);
                }
            }
        }
        CP_COMMIT();
    };

    float acc[4][4][4];
    #pragma unroll
    for (int mi = 0; mi < 4; mi++)
        #pragma unroll
        for (int ni = 0; ni < 4; ni++)
            #pragma unroll
            for (int q = 0; q < 4; q++) acc[mi][ni][q] = 0.f;

    const uint32_t a_off = (uint32_t)((wm * 64 + (lane & 15)) * ROWB + (lane >> 4) * 16);
    const uint32_t b_off = (uint32_t)((wn * 32 + ((lane >> 4) & 1) * 8 + (lane & 7)) * ROWB
                                      + ((lane >> 3) & 1) * 16);

    issue(0); issue(1);

    for (int c = 0; c < NC; c++) {
        CP_WAIT1();
        __syncthreads();
        issue(c + 2);

        const uint32_t tb = sbase + stage_of(c) * STAGEB;
        #pragma unroll
        for (int kk = 0; kk < 2; kk++) {
            const uint32_t kba = kk * 32;
            uint32_t ah[4][4], al[4][4], bb[4][2];
            #pragma unroll
            for (int mi = 0; mi < 4; mi++) {
                ldsm4(ah[mi], tb + 0 * TILEB + a_off + mi * 16 * ROWB + kba);
                ldsm4(al[mi], tb + 1 * TILEB + a_off + mi * 16 * ROWB + kba);
            }
            #pragma unroll
            for (int nip = 0; nip < 2; nip++) {
                uint32_t t4[4];
                ldsm4(t4, tb + 2 * TILEB + b_off + nip * 16 * ROWB + kba);
                bb[2*nip][0] = t4[0]; bb[2*nip][1] = t4[1];
                bb[2*nip+1][0] = t4[2]; bb[2*nip+1][1] = t4[3];
            }
            #pragma unroll
            for (int mi = 0; mi < 4; mi++)
                #pragma unroll
                for (int ni = 0; ni < 4; ni++) {
                    mma16816(acc[mi][ni], ah[mi], bb[ni]);
                    mma16816(acc[mi][ni], al[mi], bb[ni]);
                }
        }
        __syncthreads();
    }

    #pragma unroll
    for (int mi = 0; mi < 4; mi++) {
        const int r0 = m0 + wm * 64 + mi * 16 + (lane >> 2);
        const int r1 = r0 + 8;
        #pragma unroll
        for (int ni = 0; ni < 4; ni++) {
            const int col = n0 + wn * 32 + ni * 8 + (lane & 3) * 2;
            if (col >= N) continue;
            float b0 = 0.f, b1 = 0.f;
            if (bias) { b0 = bias[col]; b1 = bias[col + 1]; }
            *(float2*)(C + (long)r0 * ldc + col) = make_float2(acc[mi][ni][0] + b0, acc[mi][ni][1] + b1);
            *(float2*)(C + (long)r1 * ldc + col) = make_float2(acc[mi][ni][2] + b0, acc[mi][ni][3] + b1);
        }
    }
}

// ===================== single-product GEMM for fc (masked epilogue) =====================
// C[M,N] = A[M,K] @ B[N,K]^T + bias, zero where lengths[row/T] < row%T.
// 2 tiles/stage (A, B), 4-stage ring -> 81920 B -> 2 CTAs/SM.
#define S1_STAGEB (2 * TILEB)            // 20480
#define S1_NSTG   4
#define S1_SMEM   (S1_NSTG * S1_STAGEB)  // 81920

__global__ __launch_bounds__(256, 2)
void mma_gemm1(const __half* __restrict__ Ah, const __half* __restrict__ Bw,
               float* __restrict__ C, int ldc, const float* __restrict__ bias,
               int M, int N, int K, const int* __restrict__ lengths)
{
    extern __shared__ __align__(16) char smem[];
    const uint32_t sbase = smem_u32(smem);

    const int tid = threadIdx.x, wid = tid >> 5, lane = tid & 31;
    const int m0 = blockIdx.y * 128, n0 = blockIdx.x * 128;
    const int wm = wid & 1, wn = wid >> 1;

    const int NC = K >> 5;

    auto issue = [&](int c) {
        if (c < NC) {
            const long kc = (long)c * 32;
            const uint32_t sb = sbase + (c & (S1_NSTG - 1)) * S1_STAGEB;
            #pragma unroll
            for (int ti = 0; ti < 2; ti++) {
                const __half* S = (ti == 0) ? Ah : Bw;
                const int  rb  = (ti == 0) ? m0 : n0;
                const bool isB = (ti == 1);
                #pragma unroll
                for (int i = 0; i < 2; i++) {
                    int ch = tid + i * 256;
                    int row = ch >> 2, kq = ch & 3;
                    int gr = rb + row;
                    if (isB && gr >= N) gr = N - 1;
                    const __half* src = S + (long)gr * K + kc + kq * 8;
                    CP_ASYNC16(sb + ti * TILEB + row * ROWB + kq * 16, src);
                }
            }
        }
        CP_COMMIT();
    };

    float acc[4][4][4];
    #pragma unroll
    for (int mi = 0; mi < 4; mi++)
        #pragma unroll
        for (int ni = 0; ni < 4; ni++)
            #pragma unroll
            for (int q = 0; q < 4; q++) acc[mi][ni][q] = 0.f;

    const uint32_t a_off = (uint32_t)((wm * 64 + (lane & 15)) * ROWB + (lane >> 4) * 16);
    const uint32_t b_off = (uint32_t)((wn * 32 + ((lane >> 4) & 1) * 8 + (lane & 7)) * ROWB
                                      + ((lane >> 3) & 1) * 16);

    issue(0); issue(1); issue(2);

    for (int c = 0; c < NC; c++) {
        CP_WAIT2();
        __syncthreads();
        issue(c + 3);

        const uint32_t tb = sbase + (c & (S1_NSTG - 1)) * S1_STAGEB;
        #pragma unroll
        for (int kk = 0; kk < 2; kk++) {
            const uint32_t kba = kk * 32;
            uint32_t ah[4][4], bb[4][2];
            #pragma unroll
            for (int mi = 0; mi < 4; mi++)
                ldsm4(ah[mi], tb + 0 * TILEB + a_off + mi * 16 * ROWB + kba);
            #pragma unroll
            for (int nip = 0; nip < 2; nip++) {
                uint32_t t4[4];
                ldsm4(t4, tb + 1 * TILEB + b_off + nip * 16 * ROWB + kba);
                bb[2*nip][0] = t4[0]; bb[2*nip][1] = t4[1];
                bb[2*nip+1][0] = t4[2]; bb[2*nip+1][1] = t4[3];
            }
            #pragma unroll
            for (int mi = 0; mi < 4; mi++)
                #pragma unroll
                for (int ni = 0; ni < 4; ni++)
                    mma16816(acc[mi][ni], ah[mi], bb[ni]);
        }
        __syncthreads();
    }

    #pragma unroll
    for (int mi = 0; mi < 4; mi++) {
        const int r0 = m0 + wm * 64 + mi * 16 + (lane >> 2);
        const int r1 = r0 + 8;
        const bool keep0 = (lengths[r0 / Tn] >= (r0 % Tn));
        const bool keep1 = (lengths[r1 / Tn] >= (r1 % Tn));
        #pragma unroll
        for (int ni = 0; ni < 4; ni++) {
            const int col = n0 + wn * 32 + ni * 8 + (lane & 3) * 2;
            if (col >= N) continue;
            float b0 = bias[col], b1 = bias[col + 1];
            float v0 = acc[mi][ni][0] + b0, v1 = acc[mi][ni][1] + b1;
            float v2 = acc[mi][ni][2] + b0, v3 = acc[mi][ni][3] + b1;
            if (!keep0) { v0 = 0.f; v1 = 0.f; }
            if (!keep1) { v2 = 0.f; v3 = 0.f; }
            *(float2*)(C + (long)r0 * ldc + col) = make_float2(v0, v1);
            *(float2*)(C + (long)r1 * ldc + col) = make_float2(v2, v3);
        }
    }
}

// ===================== LSTM step t>=1: tensor-core h@w_hh + fused gates =====================
#define L_ATILE (128 * ROWB)                 // 10240
#define L_BTILE (64 * ROWB)                  // 5120
#define L_STAGE (2 * L_ATILE + L_BTILE)      // 25600
#define L_NSTG  4
#define L_SMEM  (L_NSTG * L_STAGE)           // 102400

__global__ __launch_bounds__(256, 1)
void k_lstm_mma(int t)
{
    extern __shared__ __align__(16) char smem[];
    const uint32_t sbase = smem_u32(smem);
    const int tid = threadIdx.x, wid = tid >> 5, lane = tid & 31;
    const int h0 = blockIdx.x * 16;
    const int wm = wid & 1, wn = wid >> 1;       // wn = gate index
    const int NC = 16;

    auto issue = [&](int c) {
        if (c < NC) {
            const long kc = (long)c * 32;
            const uint32_t sb = sbase + (c & (L_NSTG - 1)) * L_STAGE;
            #pragma unroll
            for (int s = 0; s < 2; s++) {        // A: h hi/lo
                const __half* S = s ? g_hs_l : g_hs_h;
                #pragma unroll
                for (int i = 0; i < 2; i++) {
                    int ch = tid + i * 256;
                    int row = ch >> 2, kq = ch & 3;
                    const __half* src = S + ((long)row * Tn + (t - 1)) * Hn + kc + kq * 8;
                    CP_ASYNC16(sb + s * L_ATILE + row * ROWB + kq * 16, src);
                }
            }
            {                                    // B: w_hh, permuted rows
                int row = tid >> 2, kq = tid & 3;
                int j = (row >> 4) * 512 + h0 + (row & 15);
                const __half* src = g_whh + (long)j * Hn + kc + kq * 8;
                CP_ASYNC16(sb + 2 * L_ATILE + row * ROWB + kq * 16, src);
            }
        }
        CP_COMMIT();
    };

    float acc[4][2][4];
    #pragma unroll
    for (int mi = 0; mi < 4; mi++)
        #pragma unroll
        for (int ni = 0; ni < 2; ni++)
            #pragma unroll
            for (int q = 0; q < 4; q++) acc[mi][ni][q] = 0.f;

    const uint32_t a_off = (uint32_t)((wm * 64 + (lane & 15)) * ROWB + (lane >> 4) * 16);
    const uint32_t b_off = (uint32_t)((wn * 16 + ((lane >> 4) & 1) * 8 + (lane & 7)) * ROWB
                                      + ((lane >> 3) & 1) * 16);

    issue(0); issue(1); issue(2);

    for (int c = 0; c < NC; c++) {
        CP_WAIT2();
        __syncthreads();
        issue(c + 3);

        const uint32_t tb = sbase + (c & (L_NSTG - 1)) * L_STAGE;
        #pragma unroll
        for (int kk = 0; kk < 2; kk++) {
            const uint32_t kba = kk * 32;
            uint32_t ah[4][4], al[4][4], bb[2][2];
            #pragma unroll
            for (int mi = 0; mi < 4; mi++) {
                ldsm4(ah[mi], tb + 0 * L_ATILE + a_off + mi * 16 * ROWB + kba);
                ldsm4(al[mi], tb + 1 * L_ATILE + a_off + mi * 16 * ROWB + kba);
            }
            {
                uint32_t t4[4];
                ldsm4(t4, tb + 2 * L_ATILE + b_off + kba);
                bb[0][0] = t4[0]; bb[0][1] = t4[1]; bb[1][0] = t4[2]; bb[1][1] = t4[3];
            }
            #pragma unroll
            for (int mi = 0; mi < 4; mi++)
                #pragma unroll
                for (int ni = 0; ni < 2; ni++) {
                    mma16816(acc[mi][ni], ah[mi], bb[ni]);
                    mma16816(acc[mi][ni], al[mi], bb[ni]);
                }
        }
    }

    // stage gates, fused pointwise
    __syncthreads();
    float* Gs = (float*)smem;                    // [128][68]
    #pragma unroll
    for (int mi = 0; mi < 4; mi++) {
        const int r0 = wm * 64 + mi * 16 + (lane >> 2);
        const int r1 = r0 + 8;
        #pragma unroll
        for (int ni = 0; ni < 2; ni++) {
            const int cl = wn * 16 + ni * 8 + (lane & 3) * 2;
            Gs[r0 * 68 + cl]     = acc[mi][ni][0];
            Gs[r0 * 68 + cl + 1] = acc[mi][ni][1];
            Gs[r1 * 68 + cl]     = acc[mi][ni][2];
            Gs[r1 * 68 + cl + 1] = acc[mi][ni][3];
        }
    }
    __syncthreads();

    for (int p = tid; p < 128 * 16; p += 256) {
        const int b = p >> 4, l = p & 15;
        const int hcol = h0 + l;
        const float* xg = g_xg + ((long)b * Tn + t) * 2048;
        float gi = Gs[b * 68 + 0 * 16 + l] + xg[0 * 512 + hcol];
        float gf = Gs[b * 68 + 1 * 16 + l] + xg[1 * 512 + hcol];
        float gg = Gs[b * 68 + 2 * 16 + l] + xg[2 * 512 + hcol];
        float go = Gs[b * 68 + 3 * 16 + l] + xg[3 * 512 + hcol];
        float co = g_c[b * 512 + hcol];
        float si = 1.f / (1.f + __expf(-gi));
        float sf = 1.f / (1.f + __expf(-gf));
        float so = 1.f / (1.f + __expf(-go));
        float cn = sf * co + si * tanhf(gg);
        float hn = so * tanhf(cn);
        g_c[b * 512 + hcol] = cn;
        split_write16(hn, g_hs_h, g_hs_l, ((long)b * Tn + t) * 512 + hcol);
    }
}

// LSTM step 0
__global__ void k_lstm_t0()
{
    int i = blockIdx.x * blockDim.x + threadIdx.x;
    if (i >= Bn * Hn) return;
    int b = i >> 9, hcol = i & 511;
    const float* xg = g_xg + ((long)b * Tn) * 2048;
    float gi = xg[hcol], gg = xg[1024 + hcol], go = xg[1536 + hcol];
    float si = 1.f / (1.f + __expf(-gi));
    float so = 1.f / (1.f + __expf(-go));
    float cn = si * tanhf(gg);
    float hn = so * tanhf(cn);
    g_c[i] = cn;
    split_write16(hn, g_hs_h, g_hs_l, ((long)b * Tn) * 512 + hcol);
}

// ===================== split-K fp32 GEMM for img (M=128, K=2048) =====================
__global__ __launch_bounds__(256)
void sgemm_splitk(const float* __restrict__ A, const float* __restrict__ Bw)
{
    __shared__ float As[16][64];
    __shared__ float Bs[16][64];
    const int tid = threadIdx.x;
    const int tx = tid & 15, ty = tid >> 4;
    const int n0 = blockIdx.x * 64, m0 = blockIdx.y * 64;
    const int kbase = blockIdx.z * 256;
    const int lr = tid >> 2, lk = (tid & 3) * 4;
    const float* Ap = A  + (long)(m0 + lr) * 2048 + kbase + lk;
    const float* Bp = Bw + (long)(n0 + lr) * 2048 + kbase + lk;

    float acc[4][4] = {};
    for (int k0 = 0; k0 < 256; k0 += 16) {
        float4 avv = *(const float4*)(Ap + k0);
        float4 bvv = *(const float4*)(Bp + k0);
        __syncthreads();
        As[lk+0][lr] = avv.x; As[lk+1][lr] = avv.y; As[lk+2][lr] = avv.z; As[lk+3][lr] = avv.w;
        Bs[lk+0][lr] = bvv.x; Bs[lk+1][lr] = bvv.y; Bs[lk+2][lr] = bvv.z; Bs[lk+3][lr] = bvv.w;
        __syncthreads();
        #pragma unroll
        for (int kk = 0; kk < 16; kk++) {
            float a[4], b[4];
            #pragma unroll
            for (int i = 0; i < 4; i++) a[i] = As[kk][ty * 4 + i];
            #pragma unroll
            for (int j = 0; j < 4; j++) b[j] = Bs[kk][tx * 4 + j];
            #pragma unroll
            for (int i = 0; i < 4; i++)
                #pragma unroll
                for (int j = 0; j < 4; j++) acc[i][j] += a[i] * b[j];
        }
    }
    float* Cp = g_part + (long)blockIdx.z * Bn * VISn;
    #pragma unroll
    for (int i = 0; i < 4; i++)
        #pragma unroll
        for (int j = 0; j < 4; j++)
            Cp[(long)(m0 + ty * 4 + i) * VISn + n0 + tx * 4 + j] = acc[i][j];
}

__global__ void k_img_reduce(const float* __restrict__ img_b) {
    int b = blockIdx.x, v = threadIdx.x;
    float s = img_b[v];
    #pragma unroll
    for (int k = 0; k < 8; k++) s += g_part[((long)k * Bn + b) * VISn + v];
    split_write16(s, g_x_h, g_x_l, (long)(b * Tn) * 1024 + v);
}

// ===================== prep kernels =====================
__global__ void k_bias2(const float* __restrict__ b_ih, const float* __restrict__ b_hh) {
    int i = blockIdx.x * blockDim.x + threadIdx.x;
    if (i < 4 * Hn) g_bias2[i] = b_ih[i] + b_hh[i];
}
// vectorized fp32 -> fp16 conversion (4 elems/thread)
__global__ void k_cvt16(const float* __restrict__ x, __half* __restrict__ h, int n4) {
    int i = blockIdx.x * blockDim.x + threadIdx.x;
    if (i >= n4) return;
    float4 v = ((const float4*)x)[i];
    __half2 a = __floats2half2_rn(v.x, v.y);
    __half2 b = __floats2half2_rn(v.z, v.w);
    ((uint2*)h)[i] = make_uint2(*(uint32_t*)&a, *(uint32_t*)&b);
}
__global__ void k_transpose_f(const float* __restrict__ features) {
    int bp = blockIdx.x;
    int b = bp / 49, p = bp % 49;
    int v = threadIdx.x;
    float val = features[((long)b * 512 + v) * 49 + p];
    split_write16(val, g_fT_h, g_fT_l, (long)bp * 512 + v);
}
__global__ void k_normalize() {
    int row = blockIdx.x;
    int b = row / 49, p = row % 49;
    const float* x = g_fv + (long)row * 512;
    __shared__ float red[8];
    int tid = threadIdx.x, lane = tid & 31, wid = tid >> 5;
    float s = 0.f;
    for (int v = tid; v < 512; v += 256) { float t = x[v]; s += t * t; }
    #pragma unroll
    for (int o = 16; o; o >>= 1) s += __shfl_xor_sync(0xffffffffu, s, o);
    if (lane == 0) red[wid] = s;
    __syncthreads();
    if (tid == 0) {
        float sum = 0.f;
        #pragma unroll
        for (int w = 0; w < 8; w++) sum += red[w];
        red[0] = 1.f / fmaxf(sqrtf(sum), 1e-12f);
    }
    __syncthreads();
    float inv = red[0];
    long o = ((long)b * 64 + p) * 512;
    for (int v = tid; v < 512; v += 256) {
        float val = x[v] * inv;
        g_features_all[o + v] = val;
        split_write16(val, g_fall_h, g_fall_l, o + v);
    }
}
__global__ void k_copy_eng(const float* __restrict__ eng) {
    int bj = blockIdx.x;
    int b = bj / 15, j = bj % 15;
    int v = threadIdx.x;
    float val = eng[(long)bj * 512 + v];
    long o = ((long)b * 64 + 49 + j) * 512 + v;
    g_features_all[o] = val;
    split_write16(val, g_fall_h, g_fall_l, o);
}
__global__ void k_embed(const int* __restrict__ captions, const float* __restrict__ embed_w) {
    int r = blockIdx.x;
    int idx = captions[r];
    float v = embed_w[(long)idx * 512 + threadIdx.x];
    split_write16(v, g_we_h, g_we_l, (long)r * 512 + threadIdx.x);
    split_write16(v, g_x_h,  g_x_l,  (long)r * 1024 + 512 + threadIdx.x);
}

// ===================== fused attention =====================
__global__ __launch_bounds__(512)
void k_attention(const float* __restrict__ att_bias, const float* __restrict__ att_w) {
    int t = blockIdx.x, b = blockIdx.y;
    __shared__ float hh[512], ws[512], sbv[64], sout[64];
    int tid = threadIdx.x, lane = tid & 31, wid = tid >> 5;

    hh[tid] = g_att_h[((long)b * Tn + t) * 512 + tid];
    ws[tid] = att_w[tid];
    if (tid < 64) sbv[tid] = att_bias[tid];
    __syncthreads();

    for (int n = wid; n < 64; n += 16) {
        const float* fea = g_att_fea + ((long)b * 64 + n) * 512;
        float bn = sbv[n], s = 0.f;
        for (int v = lane; v < 512; v += 32)
            s += fmaxf(fea[v] + hh[v] + bn, 0.f) * ws[v];
        #pragma unroll
        for (int o = 16; o; o >>= 1) s += __shfl_xor_sync(0xffffffffu, s, o);
        if (lane == 0) sout[n] = s;
    }
    __syncthreads();

    if (tid == 0) {
        float mx = sout[0];
        for (int n = 1; n < 64; n++) mx = fmaxf(mx, sout[n]);
        float sum = 0.f;
        for (int n = 0; n < 64; n++) { float e = __expf(sout[n] - mx); sout[n] = e; sum += e; }
        float inv = 1.f / sum;
        for (int n = 0; n < 64; n++) sout[n] *= inv;
    }
    __syncthreads();

    float acc = 0.f;
    const float* fa = g_features_all + (long)b * 64 * 512 + tid;
    #pragma unroll 8
    for (int n = 0; n < 64; n++) acc += sout[n] * fa[(long)n * 512];
    split_write16(acc, g_x_h, g_x_l, ((long)b * Tn + (t + 1)) * 1024 + tid);
}

// ===================== launch =====================
static inline dim3 tgrid(int M, int N) { return dim3((N + 127) / 128, M / 128); }

extern "C" void kernel_launch(void* const* d_in, const int* in_sizes, int n_in,
                              void* d_out, int out_size)
{
    const float* feature_0 = (const float*)d_in[0];
    const float* features  = (const float*)d_in[1];
    const float* eng       = (const float*)d_in[2];
    const int*   captions  = (const int*)  d_in[3];
    const int*   lengths   = (const int*)  d_in[4];
    const float* embed_w   = (const float*)d_in[5];
    const float* w_ih      = (const float*)d_in[6];
    const float* w_hh      = (const float*)d_in[7];
    const float* b_ih      = (const float*)d_in[8];
    const float* b_hh      = (const float*)d_in[9];
    const float* fc_w      = (const float*)d_in[10];
    const float* fc_b      = (const float*)d_in[11];
    const float* att_vw_w  = (const float*)d_in[12];
    const float* att_hw_w  = (const float*)d_in[13];
    const float* att_bias  = (const float*)d_in[14];
    const float* att_w_w   = (const float*)d_in[15];
    const float* att_fc_w  = (const float*)d_in[16];
    const float* att_fc_b  = (const float*)d_in[17];
    const float* img_w     = (const float*)d_in[18];
    const float* img_b     = (const float*)d_in[19];
    float* out = (float*)d_out;

    static bool smem_set = false;
    if (!smem_set) {
        cudaFuncSetAttribute(mma_gemm,   cudaFuncAttributeMaxDynamicSharedMemorySize, MG_SMEM);
        cudaFuncSetAttribute(mma_gemm1,  cudaFuncAttributeMaxDynamicSharedMemorySize, S1_SMEM);
        cudaFuncSetAttribute(k_lstm_mma, cudaFuncAttributeMaxDynamicSharedMemorySize, L_SMEM);
        smem_set = true;
    }

    float* p_fv = nullptr;    cudaGetSymbolAddress((void**)&p_fv,    g_fv);
    float* p_ah = nullptr;    cudaGetSymbolAddress((void**)&p_ah,    g_att_h);
    float* p_xg = nullptr;    cudaGetSymbolAddress((void**)&p_xg,    g_xg);
    float* p_bias2 = nullptr; cudaGetSymbolAddress((void**)&p_bias2, g_bias2);
    float* p_afea = nullptr;  cudaGetSymbolAddress((void**)&p_afea,  g_att_fea);
    #define HSYM(p, s) __half* p = nullptr; cudaGetSymbolAddress((void**)&p, s)
    HSYM(p_fT_h, g_fT_h);     HSYM(p_fT_l, g_fT_l);
    HSYM(p_fall_h, g_fall_h); HSYM(p_fall_l, g_fall_l);
    HSYM(p_we_h, g_we_h);     HSYM(p_we_l, g_we_l);
    HSYM(p_x_h, g_x_h);       HSYM(p_x_l, g_x_l);
    HSYM(p_hs_h, g_hs_h);     HSYM(p_hs_l, g_hs_l);
    HSYM(p_wfc1, g_wfc1);     HSYM(p_wvw, g_wvw);
    HSYM(p_whw, g_whw);       HSYM(p_wih, g_wih);
    HSYM(p_wfc, g_wfc);       HSYM(p_whh, g_whh);
    #undef HSYM

    // launches 1-3: dependencies of the att_fc GEMM; #4 = mma_gemm (ncu profile slot)
    k_cvt16<<<(512 * 512 / 4 + 255) / 256, 256>>>(att_fc_w, p_wfc1, 512 * 512 / 4);
    k_transpose_f<<<Bn * 49, 512>>>(features);
    k_bias2<<<(4 * Hn + 255) / 256, 256>>>(b_ih, b_hh);

    // #4: att_fc: fv = fT @ att_fc_w.T + b   (6272 x 512 x 512)
    mma_gemm<<<tgrid(Bn * 49, 512), 256, MG_SMEM>>>(p_fT_h, p_fT_l, p_wfc1,
        p_fv, 512, att_fc_b, Bn * 49, 512, 512);

    // remaining conversions + prep
    k_embed<<<Bn * Tn, 512>>>(captions, embed_w);
    k_cvt16<<<(512 * 512 / 4 + 255) / 256, 256>>>(att_vw_w, p_wvw, 512 * 512 / 4);
    k_cvt16<<<(512 * 512 / 4 + 255) / 256, 256>>>(att_hw_w, p_whw, 512 * 512 / 4);
    k_cvt16<<<(2048 * 1024 / 4 + 255) / 256, 256>>>(w_ih, p_wih, 2048 * 1024 / 4);
    k_cvt16<<<(Vn * 512 / 4 + 255) / 256, 256>>>(fc_w, p_wfc, Vn * 512 / 4);
    k_cvt16<<<(2048 * 512 / 4 + 255) / 256, 256>>>(w_hh, p_whh, 2048 * 512 / 4);
    k_normalize<<<Bn * 49, 256>>>();
    k_copy_eng<<<Bn * 15, 512>>>(eng);

    // img (split-K fp32): feature_0 @ img_w.T -> g_x rows t=0
    sgemm_splitk<<<dim3(8, 2, 8), 256>>>(feature_0, img_w);
    k_img_reduce<<<Bn, 512>>>(img_b);

    // att_fea = features_all @ att_vw_w.T   (8192 x 512 x 512)
    mma_gemm<<<tgrid(Bn * 64, 512), 256, MG_SMEM>>>(p_fall_h, p_fall_l, p_wvw,
        p_afea, 512, nullptr, Bn * 64, 512, 512);

    // att_h = we @ att_hw_w.T   (2560 x 512 x 512)
    mma_gemm<<<tgrid(Bn * Tn, 512), 256, MG_SMEM>>>(p_we_h, p_we_l, p_whw,
        p_ah, 512, nullptr, Bn * Tn, 512, 512);

    // fused attention -> g_x feas part rows t=1..19
    k_attention<<<dim3(Tn - 1, Bn), 512>>>(att_bias, att_w_w);

    // xg = [feas|we] @ w_ih.T + (b_ih+b_hh)   (2560 x 2048 x 1024)
    mma_gemm<<<tgrid(Bn * Tn, 4 * Hn), 256, MG_SMEM>>>(p_x_h, p_x_l, p_wih,
        p_xg, 4 * Hn, p_bias2, Bn * Tn, 4 * Hn, 1024);

    // LSTM recurrence: step 0 pointwise, steps 1..19 tensor-core
    k_lstm_t0<<<(Bn * Hn + 255) / 256, 256>>>();
    for (int t = 1; t < Tn; t++)
        k_lstm_mma<<<32, 256, L_SMEM>>>(t);

    // logits + mask (single-product fp16): out = hs @ fc_w.T + fc_b   (2560 x 12000 x 512)
    mma_gemm1<<<tgrid(Bn * Tn, Vn), 256, S1_SMEM>>>(p_hs_h, p_wfc,
        out, Vn, fc_b, Bn * Tn, Vn, 512, lengths);
}

// round 9
// speedup vs baseline: 6.7684x; 1.0858x over previous
#include <cuda_runtime.h>
#include <cuda_fp16.h>
#include <cstdint>
#include <math.h>

// Problem dims
#define Bn   128
#define Tn   20
#define Vn   12000
#define En   512
#define Hn   512
#define VISn 512

// ===================== PTX helpers (sm_100 baseline) =====================
__device__ __forceinline__ uint32_t smem_u32(const void* p) {
    uint32_t a;
    asm("{ .reg .u64 t; cvta.to.shared.u64 t, %1; cvt.u32.u64 %0, t; }" : "=r"(a) : "l"(p));
    return a;
}
#define CP_ASYNC16(dst, src) \
    asm volatile("cp.async.cg.shared.global [%0], [%1], 16;" :: "r"(dst), "l"(src) : "memory")
#define CP_COMMIT() asm volatile("cp.async.commit_group;" ::: "memory")
#define CP_WAIT0()  asm volatile("cp.async.wait_group 0;" ::: "memory")
#define CP_WAIT1()  asm volatile("cp.async.wait_group 1;" ::: "memory")
#define CP_WAIT2()  asm volatile("cp.async.wait_group 2;" ::: "memory")

__device__ __forceinline__ void ldsm4(uint32_t* r, uint32_t addr) {
    asm volatile("ldmatrix.sync.aligned.m8n8.x4.shared.b16 {%0,%1,%2,%3}, [%4];"
        : "=r"(r[0]), "=r"(r[1]), "=r"(r[2]), "=r"(r[3]) : "r"(addr));
}
__device__ __forceinline__ void mma16816(float* c, const uint32_t* a, const uint32_t* b) {
    asm volatile("mma.sync.aligned.m16n8k16.row.col.f32.f16.f16.f32 "
        "{%0,%1,%2,%3}, {%4,%5,%6,%7}, {%8,%9}, {%0,%1,%2,%3};"
        : "+f"(c[0]), "+f"(c[1]), "+f"(c[2]), "+f"(c[3])
        : "r"(a[0]), "r"(a[1]), "r"(a[2]), "r"(a[3]), "r"(b[0]), "r"(b[1]));
}

// ===================== scratch (device globals) =====================
__device__ float g_fv[Bn * 49 * VISn];
__device__ float g_features_all[Bn * 64 * VISn];
__device__ float g_att_fea[Bn * 64 * VISn];
__device__ float g_att_h[Bn * Tn * VISn];
__device__ float g_scores[Bn * (Tn - 1) * 64];
__device__ float g_xg[Bn * Tn * 4 * Hn];
__device__ float g_c[Bn * Hn];
__device__ float g_bias2[4 * Hn];
__device__ float g_part[8 * Bn * VISn];
__device__ unsigned g_bar;

// activations: fp16 split pairs (hi, lo)
__device__ __half g_fT_h[Bn * 49 * VISn],   g_fT_l[Bn * 49 * VISn];
__device__ __half g_fall_h[Bn * 64 * VISn], g_fall_l[Bn * 64 * VISn];
__device__ __half g_we_h[Bn * Tn * En],     g_we_l[Bn * Tn * En];
__device__ __half g_x_h[Bn * Tn * 1024],    g_x_l[Bn * Tn * 1024];
__device__ __half g_hs_h[Bn * Tn * Hn],     g_hs_l[Bn * Tn * Hn];
// weights: single fp16
__device__ __half g_wfc1[VISn * VISn];
__device__ __half g_wvw[VISn * VISn];
__device__ __half g_whw[VISn * En];
__device__ __half g_wih[4 * Hn * 1024];
__device__ __half g_wfc[Vn * Hn];
__device__ __half g_whh[4 * Hn * Hn];

__device__ __forceinline__ void split_write16(float v, __half* h, __half* l, long i) {
    __half hi = __float2half_rn(v);
    h[i] = hi;
    l[i] = __float2half_rn(v - __half2float(hi));
}

// ===================== tensor-core GEMM (fp16 2-product) =====================
#define ROWB   80
#define TILEB  (128 * ROWB)          // 10240 B
#define STAGEB (3 * TILEB)           // 30720 B (Ah, Al, B)
#define G_NSTG 3
#define MG_SMEM (G_NSTG * STAGEB)    // 92160 B

__global__ __launch_bounds__(256, 2)
void mma_gemm(const __half* __restrict__ Ah, const __half* __restrict__ Al,
              const __half* __restrict__ Bw,
              float* __restrict__ C, int ldc, const float* __restrict__ bias,
              int M, int N, int K)
{
    extern __shared__ __align__(16) char smem[];
    const uint32_t sbase = smem_u32(smem);

    const int tid = threadIdx.x, wid = tid >> 5, lane = tid & 31;
    const int m0 = blockIdx.y * 128, n0 = blockIdx.x * 128;
    const int wm = wid & 1, wn = wid >> 1;

    const int NC = K >> 5;

    auto stage_of = [](int c) { return (c % G_NSTG); };

    auto issue = [&](int c) {
        if (c < NC) {
            const long kc = (long)c * 32;
            const uint32_t sb = sbase + stage_of(c) * STAGEB;
            #pragma unroll
            for (int ti = 0; ti < 3; ti++) {
                const __half* S = (ti == 0) ? Ah : (ti == 1) ? Al : Bw;
                const int  rb  = (ti < 2) ? m0 : n0;
                const bool isB = (ti == 2);
                #pragma unroll
                for (int i = 0; i < 2; i++) {
                    int ch = tid + i * 256;
                    int row = ch >> 2, kq = ch & 3;
                    int gr = rb + row;
                    if (isB && gr >= N) gr = N - 1;
                    const __half* src = S + (long)gr * K + kc + kq * 8;
                    CP_ASYNC16(sb + ti * TILEB + row * ROWB + kq * 16, src);
                }
            }
        }
        CP_COMMIT();
    };

    float acc[4][4][4];
    #pragma unroll
    for (int mi = 0; mi < 4; mi++)
        #pragma unroll
        for (int ni = 0; ni < 4; ni++)
            #pragma unroll
            for (int q = 0; q < 4; q++) acc[mi][ni][q] = 0.f;

    const uint32_t a_off = (uint32_t)((wm * 64 + (lane & 15)) * ROWB + (lane >> 4) * 16);
    const uint32_t b_off = (uint32_t)((wn * 32 + ((lane >> 4) & 1) * 8 + (lane & 7)) * ROWB
                                      + ((lane >> 3) & 1) * 16);

    issue(0); issue(1);

    for (int c = 0; c < NC; c++) {
        CP_WAIT1();
        __syncthreads();
        issue(c + 2);

        const uint32_t tb = sbase + stage_of(c) * STAGEB;
        #pragma unroll
        for (int kk = 0; kk < 2; kk++) {
            const uint32_t kba = kk * 32;
            uint32_t ah[4][4], al[4][4], bb[4][2];
            #pragma unroll
            for (int mi = 0; mi < 4; mi++) {
                ldsm4(ah[mi], tb + 0 * TILEB + a_off + mi * 16 * ROWB + kba);
                ldsm4(al[mi], tb + 1 * TILEB + a_off + mi * 16 * ROWB + kba);
            }
            #pragma unroll
            for (int nip = 0; nip < 2; nip++) {
                uint32_t t4[4];
                ldsm4(t4, tb + 2 * TILEB + b_off + nip * 16 * ROWB + kba);
                bb[2*nip][0] = t4[0]; bb[2*nip][1] = t4[1];
                bb[2*nip+1][0] = t4[2]; bb[2*nip+1][1] = t4[3];
            }
            #pragma unroll
            for (int mi = 0; mi < 4; mi++)
                #pragma unroll
                for (int ni = 0; ni < 4; ni++) {
                    mma16816(acc[mi][ni], ah[mi], bb[ni]);
                    mma16816(acc[mi][ni], al[mi], bb[ni]);
                }
        }
        __syncthreads();
    }

    #pragma unroll
    for (int mi = 0; mi < 4; mi++) {
        const int r0 = m0 + wm * 64 + mi * 16 + (lane >> 2);
        const int r1 = r0 + 8;
        #pragma unroll
        for (int ni = 0; ni < 4; ni++) {
            const int col = n0 + wn * 32 + ni * 8 + (lane & 3) * 2;
            if (col >= N) continue;
            float b0 = 0.f, b1 = 0.f;
            if (bias) { b0 = bias[col]; b1 = bias[col + 1]; }
            *(float2*)(C + (long)r0 * ldc + col) = make_float2(acc[mi][ni][0] + b0, acc[mi][ni][1] + b1);
            *(float2*)(C + (long)r1 * ldc + col) = make_float2(acc[mi][ni][2] + b0, acc[mi][ni][3] + b1);
        }
    }
}

// ===================== single-product GEMM for fc (masked epilogue) =====================
#define S1_STAGEB (2 * TILEB)            // 20480
#define S1_NSTG   4
#define S1_SMEM   (S1_NSTG * S1_STAGEB)  // 81920

__global__ __launch_bounds__(256, 2)
void mma_gemm1(const __half* __restrict__ Ah, const __half* __restrict__ Bw,
               float* __restrict__ C, int ldc, const float* __restrict__ bias,
               int M, int N, int K, const int* __restrict__ lengths)
{
    extern __shared__ __align__(16) char smem[];
    const uint32_t sbase = smem_u32(smem);

    const int tid = threadIdx.x, wid = tid >> 5, lane = tid & 31;
    const int m0 = blockIdx.y * 128, n0 = blockIdx.x * 128;
    const int wm = wid & 1, wn = wid >> 1;

    const int NC = K >> 5;

    auto issue = [&](int c) {
        if (c < NC) {
            const long kc = (long)c * 32;
            const uint32_t sb = sbase + (c & (S1_NSTG - 1)) * S1_STAGEB;
            #pragma unroll
            for (int ti = 0; ti < 2; ti++) {
                const __half* S = (ti == 0) ? Ah : Bw;
                const int  rb  = (ti == 0) ? m0 : n0;
                const bool isB = (ti == 1);
                #pragma unroll
                for (int i = 0; i < 2; i++) {
                    int ch = tid + i * 256;
                    int row = ch >> 2, kq = ch & 3;
                    int gr = rb + row;
                    if (isB && gr >= N) gr = N - 1;
                    const __half* src = S + (long)gr * K + kc + kq * 8;
                    CP_ASYNC16(sb + ti * TILEB + row * ROWB + kq * 16, src);
                }
            }
        }
        CP_COMMIT();
    };

    float acc[4][4][4];
    #pragma unroll
    for (int mi = 0; mi < 4; mi++)
        #pragma unroll
        for (int ni = 0; ni < 4; ni++)
            #pragma unroll
            for (int q = 0; q < 4; q++) acc[mi][ni][q] = 0.f;

    const uint32_t a_off = (uint32_t)((wm * 64 + (lane & 15)) * ROWB + (lane >> 4) * 16);
    const uint32_t b_off = (uint32_t)((wn * 32 + ((lane >> 4) & 1) * 8 + (lane & 7)) * ROWB
                                      + ((lane >> 3) & 1) * 16);

    issue(0); issue(1); issue(2);

    for (int c = 0; c < NC; c++) {
        CP_WAIT2();
        __syncthreads();
        issue(c + 3);

        const uint32_t tb = sbase + (c & (S1_NSTG - 1)) * S1_STAGEB;
        #pragma unroll
        for (int kk = 0; kk < 2; kk++) {
            const uint32_t kba = kk * 32;
            uint32_t ah[4][4], bb[4][2];
            #pragma unroll
            for (int mi = 0; mi < 4; mi++)
                ldsm4(ah[mi], tb + 0 * TILEB + a_off + mi * 16 * ROWB + kba);
            #pragma unroll
            for (int nip = 0; nip < 2; nip++) {
                uint32_t t4[4];
                ldsm4(t4, tb + 1 * TILEB + b_off + nip * 16 * ROWB + kba);
                bb[2*nip][0] = t4[0]; bb[2*nip][1] = t4[1];
                bb[2*nip+1][0] = t4[2]; bb[2*nip+1][1] = t4[3];
            }
            #pragma unroll
            for (int mi = 0; mi < 4; mi++)
                #pragma unroll
                for (int ni = 0; ni < 4; ni++)
                    mma16816(acc[mi][ni], ah[mi], bb[ni]);
        }
        __syncthreads();
    }

    #pragma unroll
    for (int mi = 0; mi < 4; mi++) {
        const int r0 = m0 + wm * 64 + mi * 16 + (lane >> 2);
        const int r1 = r0 + 8;
        const bool keep0 = (lengths[r0 / Tn] >= (r0 % Tn));
        const bool keep1 = (lengths[r1 / Tn] >= (r1 % Tn));
        #pragma unroll
        for (int ni = 0; ni < 4; ni++) {
            const int col = n0 + wn * 32 + ni * 8 + (lane & 3) * 2;
            if (col >= N) continue;
            float b0 = bias[col], b1 = bias[col + 1];
            float v0 = acc[mi][ni][0] + b0, v1 = acc[mi][ni][1] + b1;
            float v2 = acc[mi][ni][2] + b0, v3 = acc[mi][ni][3] + b1;
            if (!keep0) { v0 = 0.f; v1 = 0.f; }
            if (!keep1) { v2 = 0.f; v3 = 0.f; }
            *(float2*)(C + (long)r0 * ldc + col) = make_float2(v0, v1);
            *(float2*)(C + (long)r1 * ldc + col) = make_float2(v2, v3);
        }
    }
}

// ===================== persistent LSTM: all steps t=1..19 in one launch =====================
// 32 CTAs (one per 16 hcols x 4 gates), 256 threads. w_hh slice resident in smem.
// Global spin barrier between steps (all 32 CTAs resident: 1 CTA/SM).
#define LB_ALL   (16 * 64 * ROWB)            // 81920: B for all 16 k-chunks
#define LA_STAGE (2 * TILEB)                 // 20480: A hi+lo per chunk
#define LA_NSTG  4
#define LP_SMEM  (LB_ALL + LA_NSTG * LA_STAGE)   // 163840

__global__ __launch_bounds__(256, 1)
void k_lstm_all()
{
    extern __shared__ __align__(16) char smem[];
    const uint32_t sbase = smem_u32(smem);
    const int tid = threadIdx.x, wid = tid >> 5, lane = tid & 31;
    const int h0 = blockIdx.x * 16;
    const int wm = wid & 1, wn = wid >> 1;       // wn = gate index

    // preload B (w_hh permuted slice) for all 16 chunks: 64 rows x 512 cols
    {
        int row = tid >> 2, kq = tid & 3;
        int j = (row >> 4) * 512 + h0 + (row & 15);
        const __half* base = g_whh + (long)j * Hn + kq * 8;
        #pragma unroll
        for (int c = 0; c < 16; c++)
            CP_ASYNC16(sbase + c * (64 * ROWB) + row * ROWB + kq * 16, base + c * 32);
        CP_COMMIT();
        CP_WAIT0();
    }
    __syncthreads();

    const uint32_t a_off = (uint32_t)((wm * 64 + (lane & 15)) * ROWB + (lane >> 4) * 16);
    const uint32_t b_off = (uint32_t)((wn * 16 + ((lane >> 4) & 1) * 8 + (lane & 7)) * ROWB
                                      + ((lane >> 3) & 1) * 16);
    const uint32_t aring = sbase + LB_ALL;

    for (int t = 1; t < Tn; t++) {
        auto issueA = [&](int c) {
            if (c < 16) {
                const long kc = (long)c * 32;
                const uint32_t sb = aring + (c & (LA_NSTG - 1)) * LA_STAGE;
                #pragma unroll
                for (int s = 0; s < 2; s++) {
                    const __half* S = s ? g_hs_l : g_hs_h;
                    #pragma unroll
                    for (int i = 0; i < 2; i++) {
                        int ch = tid + i * 256;
                        int row = ch >> 2, kq = ch & 3;
                        const __half* src = S + ((long)row * Tn + (t - 1)) * Hn + kc + kq * 8;
                        CP_ASYNC16(sb + s * TILEB + row * ROWB + kq * 16, src);
                    }
                }
            }
            CP_COMMIT();
        };

        float acc[4][2][4];
        #pragma unroll
        for (int mi = 0; mi < 4; mi++)
            #pragma unroll
            for (int ni = 0; ni < 2; ni++)
                #pragma unroll
                for (int q = 0; q < 4; q++) acc[mi][ni][q] = 0.f;

        issueA(0); issueA(1); issueA(2);

        for (int c = 0; c < 16; c++) {
            CP_WAIT2();
            __syncthreads();
            issueA(c + 3);

            const uint32_t ta = aring + (c & (LA_NSTG - 1)) * LA_STAGE;
            const uint32_t tbB = sbase + c * (64 * ROWB);
            #pragma unroll
            for (int kk = 0; kk < 2; kk++) {
                const uint32_t kba = kk * 32;
                uint32_t ah[4][4], al[4][4], bb[2][2];
                #pragma unroll
                for (int mi = 0; mi < 4; mi++) {
                    ldsm4(ah[mi], ta + 0 * TILEB + a_off + mi * 16 * ROWB + kba);
                    ldsm4(al[mi], ta + 1 * TILEB + a_off + mi * 16 * ROWB + kba);
                }
                {
                    uint32_t t4[4];
                    ldsm4(t4, tbB + b_off + kba);
                    bb[0][0] = t4[0]; bb[0][1] = t4[1]; bb[1][0] = t4[2]; bb[1][1] = t4[3];
                }
                #pragma unroll
                for (int mi = 0; mi < 4; mi++)
                    #pragma unroll
                    for (int ni = 0; ni < 2; ni++) {
                        mma16816(acc[mi][ni], ah[mi], bb[ni]);
                        mma16816(acc[mi][ni], al[mi], bb[ni]);
                    }
            }
        }

        // stage gates into smem (overlay A ring; all A consumed), fused pointwise
        __syncthreads();
        float* Gs = (float*)(smem + LB_ALL);     // [128][68] = 34816 B
        #pragma unroll
        for (int mi = 0; mi < 4; mi++) {
            const int r0 = wm * 64 + mi * 16 + (lane >> 2);
            const int r1 = r0 + 8;
            #pragma unroll
            for (int ni = 0; ni < 2; ni++) {
                const int cl = wn * 16 + ni * 8 + (lane & 3) * 2;
                Gs[r0 * 68 + cl]     = acc[mi][ni][0];
                Gs[r0 * 68 + cl + 1] = acc[mi][ni][1];
                Gs[r1 * 68 + cl]     = acc[mi][ni][2];
                Gs[r1 * 68 + cl + 1] = acc[mi][ni][3];
            }
        }
        __syncthreads();

        for (int p = tid; p < 128 * 16; p += 256) {
            const int b = p >> 4, l = p & 15;
            const int hcol = h0 + l;
            const float* xg = g_xg + ((long)b * Tn + t) * 2048;
            float gi = Gs[b * 68 + 0 * 16 + l] + xg[0 * 512 + hcol];
            float gf = Gs[b * 68 + 1 * 16 + l] + xg[1 * 512 + hcol];
            float gg = Gs[b * 68 + 2 * 16 + l] + xg[2 * 512 + hcol];
            float go = Gs[b * 68 + 3 * 16 + l] + xg[3 * 512 + hcol];
            float co = g_c[b * 512 + hcol];
            float si = 1.f / (1.f + __expf(-gi));
            float sf = 1.f / (1.f + __expf(-gf));
            float so = 1.f / (1.f + __expf(-go));
            float cn = sf * co + si * tanhf(gg);
            float hn = so * tanhf(cn);
            g_c[b * 512 + hcol] = cn;
            split_write16(hn, g_hs_h, g_hs_l, ((long)b * Tn + t) * 512 + hcol);
        }

        // global barrier: release h_t, wait for all 32 CTAs
        __syncthreads();
        if (tid == 0) {
            __threadfence();
            atomicAdd(&g_bar, 1u);
            while (*(volatile unsigned*)&g_bar < 32u * (unsigned)t) { }
            __threadfence();
        }
        __syncthreads();
    }
}

// LSTM step 0: h=0, c=0 -> gates = xg only; also resets the global barrier
__global__ void k_lstm_t0()
{
    int i = blockIdx.x * blockDim.x + threadIdx.x;
    if (i == 0) g_bar = 0u;
    if (i >= Bn * Hn) return;
    int b = i >> 9, hcol = i & 511;
    const float* xg = g_xg + ((long)b * Tn) * 2048;
    float gi = xg[hcol], gg = xg[1024 + hcol], go = xg[1536 + hcol];
    float si = 1.f / (1.f + __expf(-gi));
    float so = 1.f / (1.f + __expf(-go));
    float cn = si * tanhf(gg);
    float hn = so * tanhf(cn);
    g_c[i] = cn;
    split_write16(hn, g_hs_h, g_hs_l, ((long)b * Tn) * 512 + hcol);
}

// ===================== split-K fp32 GEMM for img (M=128, K=2048) =====================
__global__ __launch_bounds__(256)
void sgemm_splitk(const float* __restrict__ A, const float* __restrict__ Bw)
{
    __shared__ float As[16][64];
    __shared__ float Bs[16][64];
    const int tid = threadIdx.x;
    const int tx = tid & 15, ty = tid >> 4;
    const int n0 = blockIdx.x * 64, m0 = blockIdx.y * 64;
    const int kbase = blockIdx.z * 256;
    const int lr = tid >> 2, lk = (tid & 3) * 4;
    const float* Ap = A  + (long)(m0 + lr) * 2048 + kbase + lk;
    const float* Bp = Bw + (long)(n0 + lr) * 2048 + kbase + lk;

    float acc[4][4] = {};
    for (int k0 = 0; k0 < 256; k0 += 16) {
        float4 avv = *(const float4*)(Ap + k0);
        float4 bvv = *(const float4*)(Bp + k0);
        __syncthreads();
        As[lk+0][lr] = avv.x; As[lk+1][lr] = avv.y; As[lk+2][lr] = avv.z; As[lk+3][lr] = avv.w;
        Bs[lk+0][lr] = bvv.x; Bs[lk+1][lr] = bvv.y; Bs[lk+2][lr] = bvv.z; Bs[lk+3][lr] = bvv.w;
        __syncthreads();
        #pragma unroll
        for (int kk = 0; kk < 16; kk++) {
            float a[4], b[4];
            #pragma unroll
            for (int i = 0; i < 4; i++) a[i] = As[kk][ty * 4 + i];
            #pragma unroll
            for (int j = 0; j < 4; j++) b[j] = Bs[kk][tx * 4 + j];
            #pragma unroll
            for (int i = 0; i < 4; i++)
                #pragma unroll
                for (int j = 0; j < 4; j++) acc[i][j] += a[i] * b[j];
        }
    }
    float* Cp = g_part + (long)blockIdx.z * Bn * VISn;
    #pragma unroll
    for (int i = 0; i < 4; i++)
        #pragma unroll
        for (int j = 0; j < 4; j++)
            Cp[(long)(m0 + ty * 4 + i) * VISn + n0 + tx * 4 + j] = acc[i][j];
}

__global__ void k_img_reduce(const float* __restrict__ img_b) {
    int b = blockIdx.x, v = threadIdx.x;
    float s = img_b[v];
    #pragma unroll
    for (int k = 0; k < 8; k++) s += g_part[((long)k * Bn + b) * VISn + v];
    split_write16(s, g_x_h, g_x_l, (long)(b * Tn) * 1024 + v);
}

// ===================== prep kernels =====================
__global__ void k_bias2(const float* __restrict__ b_ih, const float* __restrict__ b_hh) {
    int i = blockIdx.x * blockDim.x + threadIdx.x;
    if (i < 4 * Hn) g_bias2[i] = b_ih[i] + b_hh[i];
}
__global__ void k_cvt16(const float* __restrict__ x, __half* __restrict__ h, int n4) {
    int i = blockIdx.x * blockDim.x + threadIdx.x;
    if (i >= n4) return;
    float4 v = ((const float4*)x)[i];
    __half2 a = __floats2half2_rn(v.x, v.y);
    __half2 b = __floats2half2_rn(v.z, v.w);
    ((uint2*)h)[i] = make_uint2(*(uint32_t*)&a, *(uint32_t*)&b);
}
__global__ void k_transpose_f(const float* __restrict__ features) {
    int bp = blockIdx.x;
    int b = bp / 49, p = bp % 49;
    int v = threadIdx.x;
    float val = features[((long)b * 512 + v) * 49 + p];
    split_write16(val, g_fT_h, g_fT_l, (long)bp * 512 + v);
}
__global__ void k_normalize() {
    int row = blockIdx.x;
    int b = row / 49, p = row % 49;
    const float* x = g_fv + (long)row * 512;
    __shared__ float red[8];
    int tid = threadIdx.x, lane = tid & 31, wid = tid >> 5;
    float s = 0.f;
    for (int v = tid; v < 512; v += 256) { float t = x[v]; s += t * t; }
    #pragma unroll
    for (int o = 16; o; o >>= 1) s += __shfl_xor_sync(0xffffffffu, s, o);
    if (lane == 0) red[wid] = s;
    __syncthreads();
    if (tid == 0) {
        float sum = 0.f;
        #pragma unroll
        for (int w = 0; w < 8; w++) sum += red[w];
        red[0] = 1.f / fmaxf(sqrtf(sum), 1e-12f);
    }
    __syncthreads();
    float inv = red[0];
    long o = ((long)b * 64 + p) * 512;
    for (int v = tid; v < 512; v += 256) {
        float val = x[v] * inv;
        g_features_all[o + v] = val;
        split_write16(val, g_fall_h, g_fall_l, o + v);
    }
}
__global__ void k_copy_eng(const float* __restrict__ eng) {
    int bj = blockIdx.x;
    int b = bj / 15, j = bj % 15;
    int v = threadIdx.x;
    float val = eng[(long)bj * 512 + v];
    long o = ((long)b * 64 + 49 + j) * 512 + v;
    g_features_all[o] = val;
    split_write16(val, g_fall_h, g_fall_l, o);
}
__global__ void k_embed(const int* __restrict__ captions, const float* __restrict__ embed_w) {
    int r = blockIdx.x;
    int idx = captions[r];
    float v = embed_w[(long)idx * 512 + threadIdx.x];
    split_write16(v, g_we_h, g_we_l, (long)r * 512 + threadIdx.x);
    split_write16(v, g_x_h,  g_x_l,  (long)r * 1024 + 512 + threadIdx.x);
}

// ===================== attention: scores (block per (b, 8-token chunk)) =====================
__global__ __launch_bounds__(256)
void k_att_scores(const float* __restrict__ att_bias, const float* __restrict__ att_w) {
    const int n0 = blockIdx.x * 8, b = blockIdx.y;
    __shared__ float fea8[8][512];
    __shared__ float ws[512];
    __shared__ float hh[512];
    const int tid = threadIdx.x, lane = tid & 31, wid = tid >> 5;

    for (int v = tid; v < 512; v += 256) ws[v] = att_w[v];
    const float4* fea = (const float4*)(g_att_fea + ((long)b * 64 + n0) * 512);
    for (int i = tid; i < 8 * 128; i += 256)
        ((float4*)&fea8[0][0])[i] = fea[i];
    const float bn = att_bias[n0 + wid];

    for (int t = 0; t < Tn - 1; t++) {
        __syncthreads();
        for (int v = tid; v < 512; v += 256) hh[v] = g_att_h[((long)b * Tn + t) * 512 + v];
        __syncthreads();
        float s = 0.f;
        #pragma unroll 4
        for (int v = lane; v < 512; v += 32)
            s += fmaxf(fea8[wid][v] + hh[v] + bn, 0.f) * ws[v];
        #pragma unroll
        for (int o = 16; o; o >>= 1) s += __shfl_xor_sync(0xffffffffu, s, o);
        if (lane == 0) g_scores[((long)b * (Tn - 1) + t) * 64 + n0 + wid] = s;
    }
}

// ===================== attention: softmax + context (block per b, fall resident) =====================
#define CTX_SMEM (64 * 512 * 4 + 256)
__global__ __launch_bounds__(512)
void k_att_ctx() {
    extern __shared__ float fs[];          // fall_s[64*512], then sout[64]
    float* sout = fs + 64 * 512;
    const int b = blockIdx.x, tid = threadIdx.x, lane = tid & 31, wid = tid >> 5;

    const float4* src = (const float4*)(g_features_all + (long)b * 64 * 512);
    for (int i = tid; i < 64 * 128; i += 512) ((float4*)fs)[i] = src[i];
    __syncthreads();

    for (int t = 0; t < Tn - 1; t++) {
        if (wid == 0) {
            const float* sc = g_scores + ((long)b * (Tn - 1) + t) * 64;
            float s0 = sc[lane], s1 = sc[lane + 32];
            float m = fmaxf(s0, s1);
            #pragma unroll
            for (int o = 16; o; o >>= 1) m = fmaxf(m, __shfl_xor_sync(0xffffffffu, m, o));
            float e0 = __expf(s0 - m), e1 = __expf(s1 - m);
            float sum = e0 + e1;
            #pragma unroll
            for (int o = 16; o; o >>= 1) sum += __shfl_xor_sync(0xffffffffu, sum, o);
            float inv = 1.f / sum;
            sout[lane] = e0 * inv; sout[lane + 32] = e1 * inv;
        }
        __syncthreads();
        float acc = 0.f;
        #pragma unroll 8
        for (int n = 0; n < 64; n++) acc += sout[n] * fs[n * 512 + tid];
        split_write16(acc, g_x_h, g_x_l, ((long)b * Tn + (t + 1)) * 1024 + tid);
        __syncthreads();
    }
}

// ===================== launch =====================
static inline dim3 tgrid(int M, int N) { return dim3((N + 127) / 128, M / 128); }

extern "C" void kernel_launch(void* const* d_in, const int* in_sizes, int n_in,
                              void* d_out, int out_size)
{
    const float* feature_0 = (const float*)d_in[0];
    const float* features  = (const float*)d_in[1];
    const float* eng       = (const float*)d_in[2];
    const int*   captions  = (const int*)  d_in[3];
    const int*   lengths   = (const int*)  d_in[4];
    const float* embed_w   = (const float*)d_in[5];
    const float* w_ih      = (const float*)d_in[6];
    const float* w_hh      = (const float*)d_in[7];
    const float* b_ih      = (const float*)d_in[8];
    const float* b_hh      = (const float*)d_in[9];
    const float* fc_w      = (const float*)d_in[10];
    const float* fc_b      = (const float*)d_in[11];
    const float* att_vw_w  = (const float*)d_in[12];
    const float* att_hw_w  = (const float*)d_in[13];
    const float* att_bias  = (const float*)d_in[14];
    const float* att_w_w   = (const float*)d_in[15];
    const float* att_fc_w  = (const float*)d_in[16];
    const float* att_fc_b  = (const float*)d_in[17];
    const float* img_w     = (const float*)d_in[18];
    const float* img_b     = (const float*)d_in[19];
    float* out = (float*)d_out;

    static bool smem_set = false;
    if (!smem_set) {
        cudaFuncSetAttribute(mma_gemm,   cudaFuncAttributeMaxDynamicSharedMemorySize, MG_SMEM);
        cudaFuncSetAttribute(mma_gemm1,  cudaFuncAttributeMaxDynamicSharedMemorySize, S1_SMEM);
        cudaFuncSetAttribute(k_lstm_all, cudaFuncAttributeMaxDynamicSharedMemorySize, LP_SMEM);
        cudaFuncSetAttribute(k_att_ctx,  cudaFuncAttributeMaxDynamicSharedMemorySize, CTX_SMEM);
        smem_set = true;
    }

    float* p_fv = nullptr;    cudaGetSymbolAddress((void**)&p_fv,    g_fv);
    float* p_ah = nullptr;    cudaGetSymbolAddress((void**)&p_ah,    g_att_h);
    float* p_xg = nullptr;    cudaGetSymbolAddress((void**)&p_xg,    g_xg);
    float* p_bias2 = nullptr; cudaGetSymbolAddress((void**)&p_bias2, g_bias2);
    float* p_afea = nullptr;  cudaGetSymbolAddress((void**)&p_afea,  g_att_fea);
    #define HSYM(p, s) __half* p = nullptr; cudaGetSymbolAddress((void**)&p, s)
    HSYM(p_fT_h, g_fT_h);     HSYM(p_fT_l, g_fT_l);
    HSYM(p_fall_h, g_fall_h); HSYM(p_fall_l, g_fall_l);
    HSYM(p_we_h, g_we_h);     HSYM(p_we_l, g_we_l);
    HSYM(p_x_h, g_x_h);       HSYM(p_x_l, g_x_l);
    HSYM(p_hs_h, g_hs_h);     HSYM(p_hs_l, g_hs_l);
    HSYM(p_wfc1, g_wfc1);     HSYM(p_wvw, g_wvw);
    HSYM(p_whw, g_whw);       HSYM(p_wih, g_wih);
    HSYM(p_wfc, g_wfc);       HSYM(p_whh, g_whh);
    #undef HSYM

    // launches 1-3: deps of the att_fc GEMM; #4 = mma_gemm (ncu profile slot)
    k_cvt16<<<(512 * 512 / 4 + 255) / 256, 256>>>(att_fc_w, p_wfc1, 512 * 512 / 4);
    k_transpose_f<<<Bn * 49, 512>>>(features);
    k_bias2<<<(4 * Hn + 255) / 256, 256>>>(b_ih, b_hh);

    // #4: att_fc: fv = fT @ att_fc_w.T + b   (6272 x 512 x 512)
    mma_gemm<<<tgrid(Bn * 49, 512), 256, MG_SMEM>>>(p_fT_h, p_fT_l, p_wfc1,
        p_fv, 512, att_fc_b, Bn * 49, 512, 512);

    // remaining conversions + prep
    k_embed<<<Bn * Tn, 512>>>(captions, embed_w);
    k_cvt16<<<(512 * 512 / 4 + 255) / 256, 256>>>(att_vw_w, p_wvw, 512 * 512 / 4);
    k_cvt16<<<(512 * 512 / 4 + 255) / 256, 256>>>(att_hw_w, p_whw, 512 * 512 / 4);
    k_cvt16<<<(2048 * 1024 / 4 + 255) / 256, 256>>>(w_ih, p_wih, 2048 * 1024 / 4);
    k_cvt16<<<(Vn * 512 / 4 + 255) / 256, 256>>>(fc_w, p_wfc, Vn * 512 / 4);
    k_cvt16<<<(2048 * 512 / 4 + 255) / 256, 256>>>(w_hh, p_whh, 2048 * 512 / 4);
    k_normalize<<<Bn * 49, 256>>>();
    k_copy_eng<<<Bn * 15, 512>>>(eng);

    // img (split-K fp32): feature_0 @ img_w.T -> g_x rows t=0
    sgemm_splitk<<<dim3(8, 2, 8), 256>>>(feature_0, img_w);
    k_img_reduce<<<Bn, 512>>>(img_b);

    // att_fea = features_all @ att_vw_w.T   (8192 x 512 x 512)
    mma_gemm<<<tgrid(Bn * 64, 512), 256, MG_SMEM>>>(p_fall_h, p_fall_l, p_wvw,
        p_afea, 512, nullptr, Bn * 64, 512, 512);

    // att_h = we @ att_hw_w.T   (2560 x 512 x 512)
    mma_gemm<<<tgrid(Bn * Tn, 512), 256, MG_SMEM>>>(p_we_h, p_we_l, p_whw,
        p_ah, 512, nullptr, Bn * Tn, 512, 512);

    // attention: scores then softmax+context -> g_x rows t=1..19
    k_att_scores<<<dim3(8, Bn), 256>>>(att_bias, att_w_w);
    k_att_ctx<<<Bn, 512, CTX_SMEM>>>();

    // xg = [feas|we] @ w_ih.T + (b_ih+b_hh)   (2560 x 2048 x 1024)
    mma_gemm<<<tgrid(Bn * Tn, 4 * Hn), 256, MG_SMEM>>>(p_x_h, p_x_l, p_wih,
        p_xg, 4 * Hn, p_bias2, Bn * Tn, 4 * Hn, 1024);

    // LSTM: step 0 pointwise (+barrier reset), steps 1..19 in ONE persistent launch
    k_lstm_t0<<<(Bn * Hn + 255) / 256, 256>>>();
    k_lstm_all<<<32, 256, LP_SMEM>>>();

    // logits + mask (single-product fp16): out = hs @ fc_w.T + fc_b   (2560 x 12000 x 512)
    mma_gemm1<<<tgrid(Bn * Tn, Vn), 256, S1_SMEM>>>(p_hs_h, p_wfc,
        out, Vn, fc_b, Bn * Tn, Vn, 512, lengths);
}

// round 10
// speedup vs baseline: 6.9987x; 1.0340x over previous
#include <cuda_runtime.h>
#include <cuda_fp16.h>
#include <cstdint>
#include <math.h>

// Problem dims
#define Bn   128
#define Tn   20
#define Vn   12000
#define En   512
#define Hn   512
#define VISn 512

// ===================== PTX helpers (sm_100 baseline) =====================
__device__ __forceinline__ uint32_t smem_u32(const void* p) {
    uint32_t a;
    asm("{ .reg .u64 t; cvta.to.shared.u64 t, %1; cvt.u32.u64 %0, t; }" : "=r"(a) : "l"(p));
    return a;
}
#define CP_ASYNC16(dst, src) \
    asm volatile("cp.async.cg.shared.global [%0], [%1], 16;" :: "r"(dst), "l"(src) : "memory")
#define CP_COMMIT() asm volatile("cp.async.commit_group;" ::: "memory")
#define CP_WAIT0()  asm volatile("cp.async.wait_group 0;" ::: "memory")
#define CP_WAIT1()  asm volatile("cp.async.wait_group 1;" ::: "memory")
#define CP_WAIT2()  asm volatile("cp.async.wait_group 2;" ::: "memory")

__device__ __forceinline__ void ldsm4(uint32_t* r, uint32_t addr) {
    asm volatile("ldmatrix.sync.aligned.m8n8.x4.shared.b16 {%0,%1,%2,%3}, [%4];"
        : "=r"(r[0]), "=r"(r[1]), "=r"(r[2]), "=r"(r[3]) : "r"(addr));
}
__device__ __forceinline__ void mma16816(float* c, const uint32_t* a, const uint32_t* b) {
    asm volatile("mma.sync.aligned.m16n8k16.row.col.f32.f16.f16.f32 "
        "{%0,%1,%2,%3}, {%4,%5,%6,%7}, {%8,%9}, {%0,%1,%2,%3};"
        : "+f"(c[0]), "+f"(c[1]), "+f"(c[2]), "+f"(c[3])
        : "r"(a[0]), "r"(a[1]), "r"(a[2]), "r"(a[3]), "r"(b[0]), "r"(b[1]));
}

// ===================== scratch (device globals) =====================
__device__ float g_fv[Bn * 49 * VISn];
__device__ float g_features_all[Bn * 64 * VISn];
__device__ float g_att_fea[Bn * 64 * VISn];
__device__ float g_att_h[Bn * Tn * VISn];
__device__ float g_scores[Bn * (Tn - 1) * 64];
__device__ float g_xg[Bn * Tn * 4 * Hn];
__device__ float g_c[Bn * Hn];
__device__ float g_bias2[4 * Hn];
__device__ float g_part[8 * Bn * VISn];
__device__ unsigned g_bar;
__device__ int g_rowmap[Bn * Tn];
__device__ int g_nkept;

// activations: fp16 split pairs (hi, lo)
__device__ __half g_fT_h[Bn * 49 * VISn],   g_fT_l[Bn * 49 * VISn];
__device__ __half g_fall_h[Bn * 64 * VISn], g_fall_l[Bn * 64 * VISn];
__device__ __half g_we_h[Bn * Tn * En],     g_we_l[Bn * Tn * En];
__device__ __half g_x_h[Bn * Tn * 1024],    g_x_l[Bn * Tn * 1024];
__device__ __half g_hs_h[Bn * Tn * Hn],     g_hs_l[Bn * Tn * Hn];
// weights: single fp16
__device__ __half g_wfc1[VISn * VISn];
__device__ __half g_wvw[VISn * VISn];
__device__ __half g_whw[VISn * En];
__device__ __half g_wih[4 * Hn * 1024];
__device__ __half g_wfc[Vn * Hn];
__device__ __half g_whh[4 * Hn * Hn];

__device__ __forceinline__ void split_write16(float v, __half* h, __half* l, long i) {
    __half hi = __float2half_rn(v);
    h[i] = hi;
    l[i] = __float2half_rn(v - __half2float(hi));
}

// ===================== tensor-core GEMM (fp16 2-product) =====================
#define ROWB   80
#define TILEB  (128 * ROWB)          // 10240 B
#define STAGEB (3 * TILEB)           // 30720 B (Ah, Al, B)
#define G_NSTG 3
#define MG_SMEM (G_NSTG * STAGEB)    // 92160 B

__global__ __launch_bounds__(256, 2)
void mma_gemm(const __half* __restrict__ Ah, const __half* __restrict__ Al,
              const __half* __restrict__ Bw,
              float* __restrict__ C, int ldc, const float* __restrict__ bias,
              int M, int N, int K)
{
    extern __shared__ __align__(16) char smem[];
    const uint32_t sbase = smem_u32(smem);

    const int tid = threadIdx.x, wid = tid >> 5, lane = tid & 31;
    const int m0 = blockIdx.y * 128, n0 = blockIdx.x * 128;
    const int wm = wid & 1, wn = wid >> 1;

    const int NC = K >> 5;

    auto stage_of = [](int c) { return (c % G_NSTG); };

    auto issue = [&](int c) {
        if (c < NC) {
            const long kc = (long)c * 32;
            const uint32_t sb = sbase + stage_of(c) * STAGEB;
            #pragma unroll
            for (int ti = 0; ti < 3; ti++) {
                const __half* S = (ti == 0) ? Ah : (ti == 1) ? Al : Bw;
                const int  rb  = (ti < 2) ? m0 : n0;
                const bool isB = (ti == 2);
                #pragma unroll
                for (int i = 0; i < 2; i++) {
                    int ch = tid + i * 256;
                    int row = ch >> 2, kq = ch & 3;
                    int gr = rb + row;
                    if (isB && gr >= N) gr = N - 1;
                    const __half* src = S + (long)gr * K + kc + kq * 8;
                    CP_ASYNC16(sb + ti * TILEB + row * ROWB + kq * 16, src);
                }
            }
        }
        CP_COMMIT();
    };

    float acc[4][4][4];
    #pragma unroll
    for (int mi = 0; mi < 4; mi++)
        #pragma unroll
        for (int ni = 0; ni < 4; ni++)
            #pragma unroll
            for (int q = 0; q < 4; q++) acc[mi][ni][q] = 0.f;

    const uint32_t a_off = (uint32_t)((wm * 64 + (lane & 15)) * ROWB + (lane >> 4) * 16);
    const uint32_t b_off = (uint32_t)((wn * 32 + ((lane >> 4) & 1) * 8 + (lane & 7)) * ROWB
                                      + ((lane >> 3) & 1) * 16);

    issue(0); issue(1);

    for (int c = 0; c < NC; c++) {
        CP_WAIT1();
        __syncthreads();                 // single barrier per chunk (see proof in commit msg)
        issue(c + 2);

        const uint32_t tb = sbase + stage_of(c) * STAGEB;
        #pragma unroll
        for (int kk = 0; kk < 2; kk++) {
            const uint32_t kba = kk * 32;
            uint32_t ah[4][4], al[4][4], bb[4][2];
            #pragma unroll
            for (int mi = 0; mi < 4; mi++) {
                ldsm4(ah[mi], tb + 0 * TILEB + a_off + mi * 16 * ROWB + kba);
                ldsm4(al[mi], tb + 1 * TILEB + a_off + mi * 16 * ROWB + kba);
            }
            #pragma unroll
            for (int nip = 0; nip < 2; nip++) {
                uint32_t t4[4];
                ldsm4(t4, tb + 2 * TILEB + b_off + nip * 16 * ROWB + kba);
                bb[2*nip][0] = t4[0]; bb[2*nip][1] = t4[1];
                bb[2*nip+1][0] = t4[2]; bb[2*nip+1][1] = t4[3];
            }
            #pragma unroll
            for (int mi = 0; mi < 4; mi++)
                #pragma unroll
                for (int ni = 0; ni < 4; ni++) {
                    mma16816(acc[mi][ni], ah[mi], bb[ni]);
                    mma16816(acc[mi][ni], al[mi], bb[ni]);
                }
        }
    }

    #pragma unroll
    for (int mi = 0; mi < 4; mi++) {
        const int r0 = m0 + wm * 64 + mi * 16 + (lane >> 2);
        const int r1 = r0 + 8;
        #pragma unroll
        for (int ni = 0; ni < 4; ni++) {
            const int col = n0 + wn * 32 + ni * 8 + (lane & 3) * 2;
            if (col >= N) continue;
            float b0 = 0.f, b1 = 0.f;
            if (bias) { b0 = bias[col]; b1 = bias[col + 1]; }
            *(float2*)(C + (long)r0 * ldc + col) = make_float2(acc[mi][ni][0] + b0, acc[mi][ni][1] + b1);
            *(float2*)(C + (long)r1 * ldc + col) = make_float2(acc[mi][ni][2] + b0, acc[mi][ni][3] + b1);
        }
    }
}

// ===================== compacted single-product GEMM for fc =====================
// Rows gathered via g_rowmap (kept rows only); epilogue scatters to true rows.
#define S1_STAGEB (2 * TILEB)            // 20480
#define S1_NSTG   4
#define S1_SMEM   (S1_NSTG * S1_STAGEB)  // 81920

__global__ __launch_bounds__(256, 2)
void mma_gemm_fc(const __half* __restrict__ Ah, const __half* __restrict__ Bw,
                 float* __restrict__ C, int ldc, const float* __restrict__ bias,
                 int N, int K)
{
    extern __shared__ __align__(16) char smem[];
    __shared__ int rm[128];
    const uint32_t sbase = smem_u32(smem);

    const int tid = threadIdx.x, wid = tid >> 5, lane = tid & 31;
    const int m0 = blockIdx.y * 128, n0 = blockIdx.x * 128;
    const int wm = wid & 1, wn = wid >> 1;

    const int nkept = g_nkept;
    if (m0 >= nkept) return;

    if (tid < 128) {
        int r = m0 + tid;
        rm[tid] = g_rowmap[r < nkept ? r : (nkept - 1)];
    }
    __syncthreads();

    const int NC = K >> 5;

    auto issue = [&](int c) {
        if (c < NC) {
            const long kc = (long)c * 32;
            const uint32_t sb = sbase + (c & (S1_NSTG - 1)) * S1_STAGEB;
            // A gather
            #pragma unroll
            for (int i = 0; i < 2; i++) {
                int ch = tid + i * 256;
                int row = ch >> 2, kq = ch & 3;
                const __half* src = Ah + (long)rm[row] * K + kc + kq * 8;
                CP_ASYNC16(sb + 0 * TILEB + row * ROWB + kq * 16, src);
            }
            // B
            #pragma unroll
            for (int i = 0; i < 2; i++) {
                int ch = tid + i * 256;
                int row = ch >> 2, kq = ch & 3;
                int gr = n0 + row;
                if (gr >= N) gr = N - 1;
                const __half* src = Bw + (long)gr * K + kc + kq * 8;
                CP_ASYNC16(sb + 1 * TILEB + row * ROWB + kq * 16, src);
            }
        }
        CP_COMMIT();
    };

    float acc[4][4][4];
    #pragma unroll
    for (int mi = 0; mi < 4; mi++)
        #pragma unroll
        for (int ni = 0; ni < 4; ni++)
            #pragma unroll
            for (int q = 0; q < 4; q++) acc[mi][ni][q] = 0.f;

    const uint32_t a_off = (uint32_t)((wm * 64 + (lane & 15)) * ROWB + (lane >> 4) * 16);
    const uint32_t b_off = (uint32_t)((wn * 32 + ((lane >> 4) & 1) * 8 + (lane & 7)) * ROWB
                                      + ((lane >> 3) & 1) * 16);

    issue(0); issue(1); issue(2);

    for (int c = 0; c < NC; c++) {
        CP_WAIT2();
        __syncthreads();
        issue(c + 3);

        const uint32_t tb = sbase + (c & (S1_NSTG - 1)) * S1_STAGEB;
        #pragma unroll
        for (int kk = 0; kk < 2; kk++) {
            const uint32_t kba = kk * 32;
            uint32_t ah[4][4], bb[4][2];
            #pragma unroll
            for (int mi = 0; mi < 4; mi++)
                ldsm4(ah[mi], tb + 0 * TILEB + a_off + mi * 16 * ROWB + kba);
            #pragma unroll
            for (int nip = 0; nip < 2; nip++) {
                uint32_t t4[4];
                ldsm4(t4, tb + 1 * TILEB + b_off + nip * 16 * ROWB + kba);
                bb[2*nip][0] = t4[0]; bb[2*nip][1] = t4[1];
                bb[2*nip+1][0] = t4[2]; bb[2*nip+1][1] = t4[3];
            }
            #pragma unroll
            for (int mi = 0; mi < 4; mi++)
                #pragma unroll
                for (int ni = 0; ni < 4; ni++)
                    mma16816(acc[mi][ni], ah[mi], bb[ni]);
        }
    }

    #pragma unroll
    for (int mi = 0; mi < 4; mi++) {
        const int l0 = wm * 64 + mi * 16 + (lane >> 2);    // local compact row
        const int l1 = l0 + 8;
        const bool v0r = (m0 + l0) < nkept;
        const bool v1r = (m0 + l1) < nkept;
        const long or0 = (long)rm[l0] * ldc;
        const long or1 = (long)rm[l1] * ldc;
        #pragma unroll
        for (int ni = 0; ni < 4; ni++) {
            const int col = n0 + wn * 32 + ni * 8 + (lane & 3) * 2;
            if (col >= N) continue;
            float b0 = bias[col], b1 = bias[col + 1];
            if (v0r) *(float2*)(C + or0 + col) = make_float2(acc[mi][ni][0] + b0, acc[mi][ni][1] + b1);
            if (v1r) *(float2*)(C + or1 + col) = make_float2(acc[mi][ni][2] + b0, acc[mi][ni][3] + b1);
        }
    }
}

// build rowmap of kept rows (lengths[b] >= t) + count
__global__ void k_rowmap(const int* __restrict__ lengths)
{
    __shared__ int cnt[256];
    const int tid = threadIdx.x;
    const int base = tid * 10;
    int flags[10], c = 0;
    #pragma unroll
    for (int i = 0; i < 10; i++) {
        int r = base + i;
        flags[i] = (lengths[r / Tn] >= (r % Tn)) ? 1 : 0;
        c += flags[i];
    }
    cnt[tid] = c;
    __syncthreads();
    for (int off = 1; off < 256; off <<= 1) {
        int v = (tid >= off) ? cnt[tid - off] : 0;
        __syncthreads();
        cnt[tid] += v;
        __syncthreads();
    }
    int pos = cnt[tid] - c;
    #pragma unroll
    for (int i = 0; i < 10; i++) {
        if (flags[i]) g_rowmap[pos++] = base + i;
    }
    if (tid == 255) g_nkept = cnt[255];
}

// zero-fill masked output rows
__global__ void k_zero_masked(const int* __restrict__ lengths, float* __restrict__ out)
{
    const int r = blockIdx.x;
    if (lengths[r / Tn] >= (r % Tn)) return;
    float4* o = (float4*)(out + (long)r * Vn);
    for (int i = threadIdx.x; i < Vn / 4; i += blockDim.x)
        o[i] = make_float4(0.f, 0.f, 0.f, 0.f);
}

// ===================== persistent LSTM: all steps t=1..19 in one launch =====================
#define LB_ALL   (16 * 64 * ROWB)            // 81920: B for all 16 k-chunks
#define LA_STAGE (2 * TILEB)                 // 20480: A hi+lo per chunk
#define LA_NSTG  4
#define LP_SMEM  (LB_ALL + LA_NSTG * LA_STAGE)   // 163840

__global__ __launch_bounds__(256, 1)
void k_lstm_all()
{
    extern __shared__ __align__(16) char smem[];
    const uint32_t sbase = smem_u32(smem);
    const int tid = threadIdx.x, wid = tid >> 5, lane = tid & 31;
    const int h0 = blockIdx.x * 16;
    const int wm = wid & 1, wn = wid >> 1;       // wn = gate index

    {
        int row = tid >> 2, kq = tid & 3;
        int j = (row >> 4) * 512 + h0 + (row & 15);
        const __half* base = g_whh + (long)j * Hn + kq * 8;
        #pragma unroll
        for (int c = 0; c < 16; c++)
            CP_ASYNC16(sbase + c * (64 * ROWB) + row * ROWB + kq * 16, base + c * 32);
        CP_COMMIT();
        CP_WAIT0();
    }
    __syncthreads();

    const uint32_t a_off = (uint32_t)((wm * 64 + (lane & 15)) * ROWB + (lane >> 4) * 16);
    const uint32_t b_off = (uint32_t)((wn * 16 + ((lane >> 4) & 1) * 8 + (lane & 7)) * ROWB
                                      + ((lane >> 3) & 1) * 16);
    const uint32_t aring = sbase + LB_ALL;

    for (int t = 1; t < Tn; t++) {
        auto issueA = [&](int c) {
            if (c < 16) {
                const long kc = (long)c * 32;
                const uint32_t sb = aring + (c & (LA_NSTG - 1)) * LA_STAGE;
                #pragma unroll
                for (int s = 0; s < 2; s++) {
                    const __half* S = s ? g_hs_l : g_hs_h;
                    #pragma unroll
                    for (int i = 0; i < 2; i++) {
                        int ch = tid + i * 256;
                        int row = ch >> 2, kq = ch & 3;
                        const __half* src = S + ((long)row * Tn + (t - 1)) * Hn + kc + kq * 8;
                        CP_ASYNC16(sb + s * TILEB + row * ROWB + kq * 16, src);
                    }
                }
            }
            CP_COMMIT();
        };

        float acc[4][2][4];
        #pragma unroll
        for (int mi = 0; mi < 4; mi++)
            #pragma unroll
            for (int ni = 0; ni < 2; ni++)
                #pragma unroll
                for (int q = 0; q < 4; q++) acc[mi][ni][q] = 0.f;

        issueA(0); issueA(1); issueA(2);

        for (int c = 0; c < 16; c++) {
            CP_WAIT2();
            __syncthreads();
            issueA(c + 3);

            const uint32_t ta = aring + (c & (LA_NSTG - 1)) * LA_STAGE;
            const uint32_t tbB = sbase + c * (64 * ROWB);
            #pragma unroll
            for (int kk = 0; kk < 2; kk++) {
                const uint32_t kba = kk * 32;
                uint32_t ah[4][4], al[4][4], bb[2][2];
                #pragma unroll
                for (int mi = 0; mi < 4; mi++) {
                    ldsm4(ah[mi], ta + 0 * TILEB + a_off + mi * 16 * ROWB + kba);
                    ldsm4(al[mi], ta + 1 * TILEB + a_off + mi * 16 * ROWB + kba);
                }
                {
                    uint32_t t4[4];
                    ldsm4(t4, tbB + b_off + kba);
                    bb[0][0] = t4[0]; bb[0][1] = t4[1]; bb[1][0] = t4[2]; bb[1][1] = t4[3];
                }
                #pragma unroll
                for (int mi = 0; mi < 4; mi++)
                    #pragma unroll
                    for (int ni = 0; ni < 2; ni++) {
                        mma16816(acc[mi][ni], ah[mi], bb[ni]);
                        mma16816(acc[mi][ni], al[mi], bb[ni]);
                    }
            }
        }

        __syncthreads();
        float* Gs = (float*)(smem + LB_ALL);
        #pragma unroll
        for (int mi = 0; mi < 4; mi++) {
            const int r0 = wm * 64 + mi * 16 + (lane >> 2);
            const int r1 = r0 + 8;
            #pragma unroll
            for (int ni = 0; ni < 2; ni++) {
                const int cl = wn * 16 + ni * 8 + (lane & 3) * 2;
                Gs[r0 * 68 + cl]     = acc[mi][ni][0];
                Gs[r0 * 68 + cl + 1] = acc[mi][ni][1];
                Gs[r1 * 68 + cl]     = acc[mi][ni][2];
                Gs[r1 * 68 + cl + 1] = acc[mi][ni][3];
            }
        }
        __syncthreads();

        for (int p = tid; p < 128 * 16; p += 256) {
            const int b = p >> 4, l = p & 15;
            const int hcol = h0 + l;
            const float* xg = g_xg + ((long)b * Tn + t) * 2048;
            float gi = Gs[b * 68 + 0 * 16 + l] + xg[0 * 512 + hcol];
            float gf = Gs[b * 68 + 1 * 16 + l] + xg[1 * 512 + hcol];
            float gg = Gs[b * 68 + 2 * 16 + l] + xg[2 * 512 + hcol];
            float go = Gs[b * 68 + 3 * 16 + l] + xg[3 * 512 + hcol];
            float co = g_c[b * 512 + hcol];
            float si = 1.f / (1.f + __expf(-gi));
            float sf = 1.f / (1.f + __expf(-gf));
            float so = 1.f / (1.f + __expf(-go));
            float cn = sf * co + si * tanhf(gg);
            float hn = so * tanhf(cn);
            g_c[b * 512 + hcol] = cn;
            split_write16(hn, g_hs_h, g_hs_l, ((long)b * Tn + t) * 512 + hcol);
        }

        __syncthreads();
        if (tid == 0) {
            __threadfence();
            atomicAdd(&g_bar, 1u);
            while (*(volatile unsigned*)&g_bar < 32u * (unsigned)t) { }
            __threadfence();
        }
        __syncthreads();
    }
}

__global__ void k_lstm_t0()
{
    int i = blockIdx.x * blockDim.x + threadIdx.x;
    if (i == 0) g_bar = 0u;
    if (i >= Bn * Hn) return;
    int b = i >> 9, hcol = i & 511;
    const float* xg = g_xg + ((long)b * Tn) * 2048;
    float gi = xg[hcol], gg = xg[1024 + hcol], go = xg[1536 + hcol];
    float si = 1.f / (1.f + __expf(-gi));
    float so = 1.f / (1.f + __expf(-go));
    float cn = si * tanhf(gg);
    float hn = so * tanhf(cn);
    g_c[i] = cn;
    split_write16(hn, g_hs_h, g_hs_l, ((long)b * Tn) * 512 + hcol);
}

// ===================== split-K fp32 GEMM for img (M=128, K=2048) =====================
__global__ __launch_bounds__(256)
void sgemm_splitk(const float* __restrict__ A, const float* __restrict__ Bw)
{
    __shared__ float As[16][64];
    __shared__ float Bs[16][64];
    const int tid = threadIdx.x;
    const int tx = tid & 15, ty = tid >> 4;
    const int n0 = blockIdx.x * 64, m0 = blockIdx.y * 64;
    const int kbase = blockIdx.z * 256;
    const int lr = tid >> 2, lk = (tid & 3) * 4;
    const float* Ap = A  + (long)(m0 + lr) * 2048 + kbase + lk;
    const float* Bp = Bw + (long)(n0 + lr) * 2048 + kbase + lk;

    float acc[4][4] = {};
    for (int k0 = 0; k0 < 256; k0 += 16) {
        float4 avv = *(const float4*)(Ap + k0);
        float4 bvv = *(const float4*)(Bp + k0);
        __syncthreads();
        As[lk+0][lr] = avv.x; As[lk+1][lr] = avv.y; As[lk+2][lr] = avv.z; As[lk+3][lr] = avv.w;
        Bs[lk+0][lr] = bvv.x; Bs[lk+1][lr] = bvv.y; Bs[lk+2][lr] = bvv.z; Bs[lk+3][lr] = bvv.w;
        __syncthreads();
        #pragma unroll
        for (int kk = 0; kk < 16; kk++) {
            float a[4], b[4];
            #pragma unroll
            for (int i = 0; i < 4; i++) a[i] = As[kk][ty * 4 + i];
            #pragma unroll
            for (int j = 0; j < 4; j++) b[j] = Bs[kk][tx * 4 + j];
            #pragma unroll
            for (int i = 0; i < 4; i++)
                #pragma unroll
                for (int j = 0; j < 4; j++) acc[i][j] += a[i] * b[j];
        }
    }
    float* Cp = g_part + (long)blockIdx.z * Bn * VISn;
    #pragma unroll
    for (int i = 0; i < 4; i++)
        #pragma unroll
        for (int j = 0; j < 4; j++)
            Cp[(long)(m0 + ty * 4 + i) * VISn + n0 + tx * 4 + j] = acc[i][j];
}

__global__ void k_img_reduce(const float* __restrict__ img_b) {
    int b = blockIdx.x, v = threadIdx.x;
    float s = img_b[v];
    #pragma unroll
    for (int k = 0; k < 8; k++) s += g_part[((long)k * Bn + b) * VISn + v];
    split_write16(s, g_x_h, g_x_l, (long)(b * Tn) * 1024 + v);
}

// ===================== prep kernels =====================
__global__ void k_bias2(const float* __restrict__ b_ih, const float* __restrict__ b_hh) {
    int i = blockIdx.x * blockDim.x + threadIdx.x;
    if (i < 4 * Hn) g_bias2[i] = b_ih[i] + b_hh[i];
}
__global__ void k_cvt16(const float* __restrict__ x, __half* __restrict__ h, int n4) {
    int i = blockIdx.x * blockDim.x + threadIdx.x;
    if (i >= n4) return;
    float4 v = ((const float4*)x)[i];
    __half2 a = __floats2half2_rn(v.x, v.y);
    __half2 b = __floats2half2_rn(v.z, v.w);
    ((uint2*)h)[i] = make_uint2(*(uint32_t*)&a, *(uint32_t*)&b);
}
__global__ void k_transpose_f(const float* __restrict__ features) {
    int bp = blockIdx.x;
    int b = bp / 49, p = bp % 49;
    int v = threadIdx.x;
    float val = features[((long)b * 512 + v) * 49 + p];
    split_write16(val, g_fT_h, g_fT_l, (long)bp * 512 + v);
}
__global__ void k_normalize() {
    int row = blockIdx.x;
    int b = row / 49, p = row % 49;
    const float* x = g_fv + (long)row * 512;
    __shared__ float red[8];
    int tid = threadIdx.x, lane = tid & 31, wid = tid >> 5;
    float s = 0.f;
    for (int v = tid; v < 512; v += 256) { float t = x[v]; s += t * t; }
    #pragma unroll
    for (int o = 16; o; o >>= 1) s += __shfl_xor_sync(0xffffffffu, s, o);
    if (lane == 0) red[wid] = s;
    __syncthreads();
    if (tid == 0) {
        float sum = 0.f;
        #pragma unroll
        for (int w = 0; w < 8; w++) sum += red[w];
        red[0] = 1.f / fmaxf(sqrtf(sum), 1e-12f);
    }
    __syncthreads();
    float inv = red[0];
    long o = ((long)b * 64 + p) * 512;
    for (int v = tid; v < 512; v += 256) {
        float val = x[v] * inv;
        g_features_all[o + v] = val;
        split_write16(val, g_fall_h, g_fall_l, o + v);
    }
}
__global__ void k_copy_eng(const float* __restrict__ eng) {
    int bj = blockIdx.x;
    int b = bj / 15, j = bj % 15;
    int v = threadIdx.x;
    float val = eng[(long)bj * 512 + v];
    long o = ((long)b * 64 + 49 + j) * 512 + v;
    g_features_all[o] = val;
    split_write16(val, g_fall_h, g_fall_l, o);
}
__global__ void k_embed(const int* __restrict__ captions, const float* __restrict__ embed_w) {
    int r = blockIdx.x;
    int idx = captions[r];
    float v = embed_w[(long)idx * 512 + threadIdx.x];
    split_write16(v, g_we_h, g_we_l, (long)r * 512 + threadIdx.x);
    split_write16(v, g_x_h,  g_x_l,  (long)r * 1024 + 512 + threadIdx.x);
}

// ===================== attention: scores =====================
__global__ __launch_bounds__(256)
void k_att_scores(const float* __restrict__ att_bias, const float* __restrict__ att_w) {
    const int n0 = blockIdx.x * 8, b = blockIdx.y;
    __shared__ float fea8[8][512];
    __shared__ float ws[512];
    __shared__ float hh[512];
    const int tid = threadIdx.x, lane = tid & 31, wid = tid >> 5;

    for (int v = tid; v < 512; v += 256) ws[v] = att_w[v];
    const float4* fea = (const float4*)(g_att_fea + ((long)b * 64 + n0) * 512);
    for (int i = tid; i < 8 * 128; i += 256)
        ((float4*)&fea8[0][0])[i] = fea[i];
    const float bn = att_bias[n0 + wid];

    for (int t = 0; t < Tn - 1; t++) {
        __syncthreads();
        for (int v = tid; v < 512; v += 256) hh[v] = g_att_h[((long)b * Tn + t) * 512 + v];
        __syncthreads();
        float s = 0.f;
        #pragma unroll 4
        for (int v = lane; v < 512; v += 32)
            s += fmaxf(fea8[wid][v] + hh[v] + bn, 0.f) * ws[v];
        #pragma unroll
        for (int o = 16; o; o >>= 1) s += __shfl_xor_sync(0xffffffffu, s, o);
        if (lane == 0) g_scores[((long)b * (Tn - 1) + t) * 64 + n0 + wid] = s;
    }
}

// ===================== attention: softmax + context =====================
#define CTX_SMEM (64 * 512 * 4 + 256)
__global__ __launch_bounds__(512)
void k_att_ctx() {
    extern __shared__ float fs[];
    float* sout = fs + 64 * 512;
    const int b = blockIdx.x, tid = threadIdx.x, lane = tid & 31, wid = tid >> 5;

    const float4* src = (const float4*)(g_features_all + (long)b * 64 * 512);
    for (int i = tid; i < 64 * 128; i += 512) ((float4*)fs)[i] = src[i];
    __syncthreads();

    for (int t = 0; t < Tn - 1; t++) {
        if (wid == 0) {
            const float* sc = g_scores + ((long)b * (Tn - 1) + t) * 64;
            float s0 = sc[lane], s1 = sc[lane + 32];
            float m = fmaxf(s0, s1);
            #pragma unroll
            for (int o = 16; o; o >>= 1) m = fmaxf(m, __shfl_xor_sync(0xffffffffu, m, o));
            float e0 = __expf(s0 - m), e1 = __expf(s1 - m);
            float sum = e0 + e1;
            #pragma unroll
            for (int o = 16; o; o >>= 1) sum += __shfl_xor_sync(0xffffffffu, sum, o);
            float inv = 1.f / sum;
            sout[lane] = e0 * inv; sout[lane + 32] = e1 * inv;
        }
        __syncthreads();
        float acc = 0.f;
        #pragma unroll 8
        for (int n = 0; n < 64; n++) acc += sout[n] * fs[n * 512 + tid];
        split_write16(acc, g_x_h, g_x_l, ((long)b * Tn + (t + 1)) * 1024 + tid);
        __syncthreads();
    }
}

// ===================== launch =====================
static inline dim3 tgrid(int M, int N) { return dim3((N + 127) / 128, M / 128); }

extern "C" void kernel_launch(void* const* d_in, const int* in_sizes, int n_in,
                              void* d_out, int out_size)
{
    const float* feature_0 = (const float*)d_in[0];
    const float* features  = (const float*)d_in[1];
    const float* eng       = (const float*)d_in[2];
    const int*   captions  = (const int*)  d_in[3];
    const int*   lengths   = (const int*)  d_in[4];
    const float* embed_w   = (const float*)d_in[5];
    const float* w_ih      = (const float*)d_in[6];
    const float* w_hh      = (const float*)d_in[7];
    const float* b_ih      = (const float*)d_in[8];
    const float* b_hh      = (const float*)d_in[9];
    const float* fc_w      = (const float*)d_in[10];
    const float* fc_b      = (const float*)d_in[11];
    const float* att_vw_w  = (const float*)d_in[12];
    const float* att_hw_w  = (const float*)d_in[13];
    const float* att_bias  = (const float*)d_in[14];
    const float* att_w_w   = (const float*)d_in[15];
    const float* att_fc_w  = (const float*)d_in[16];
    const float* att_fc_b  = (const float*)d_in[17];
    const float* img_w     = (const float*)d_in[18];
    const float* img_b     = (const float*)d_in[19];
    float* out = (float*)d_out;

    static bool smem_set = false;
    if (!smem_set) {
        cudaFuncSetAttribute(mma_gemm,    cudaFuncAttributeMaxDynamicSharedMemorySize, MG_SMEM);
        cudaFuncSetAttribute(mma_gemm_fc, cudaFuncAttributeMaxDynamicSharedMemorySize, S1_SMEM);
        cudaFuncSetAttribute(k_lstm_all,  cudaFuncAttributeMaxDynamicSharedMemorySize, LP_SMEM);
        cudaFuncSetAttribute(k_att_ctx,   cudaFuncAttributeMaxDynamicSharedMemorySize, CTX_SMEM);
        smem_set = true;
    }

    float* p_fv = nullptr;    cudaGetSymbolAddress((void**)&p_fv,    g_fv);
    float* p_ah = nullptr;    cudaGetSymbolAddress((void**)&p_ah,    g_att_h);
    float* p_xg = nullptr;    cudaGetSymbolAddress((void**)&p_xg,    g_xg);
    float* p_bias2 = nullptr; cudaGetSymbolAddress((void**)&p_bias2, g_bias2);
    float* p_afea = nullptr;  cudaGetSymbolAddress((void**)&p_afea,  g_att_fea);
    #define HSYM(p, s) __half* p = nullptr; cudaGetSymbolAddress((void**)&p, s)
    HSYM(p_fT_h, g_fT_h);     HSYM(p_fT_l, g_fT_l);
    HSYM(p_fall_h, g_fall_h); HSYM(p_fall_l, g_fall_l);
    HSYM(p_we_h, g_we_h);     HSYM(p_we_l, g_we_l);
    HSYM(p_x_h, g_x_h);       HSYM(p_x_l, g_x_l);
    HSYM(p_hs_h, g_hs_h);     HSYM(p_hs_l, g_hs_l);
    HSYM(p_wfc1, g_wfc1);     HSYM(p_wvw, g_wvw);
    HSYM(p_whw, g_whw);       HSYM(p_wih, g_wih);
    HSYM(p_wfc, g_wfc);       HSYM(p_whh, g_whh);
    #undef HSYM

    // launches 1-3: deps of the att_fc GEMM; #4 = mma_gemm (ncu profile slot)
    k_cvt16<<<(512 * 512 / 4 + 255) / 256, 256>>>(att_fc_w, p_wfc1, 512 * 512 / 4);
    k_transpose_f<<<Bn * 49, 512>>>(features);
    k_bias2<<<(4 * Hn + 255) / 256, 256>>>(b_ih, b_hh);

    // #4: att_fc: fv = fT @ att_fc_w.T + b   (6272 x 512 x 512)
    mma_gemm<<<tgrid(Bn * 49, 512), 256, MG_SMEM>>>(p_fT_h, p_fT_l, p_wfc1,
        p_fv, 512, att_fc_b, Bn * 49, 512, 512);

    // remaining conversions + prep
    k_embed<<<Bn * Tn, 512>>>(captions, embed_w);
    k_cvt16<<<(512 * 512 / 4 + 255) / 256, 256>>>(att_vw_w, p_wvw, 512 * 512 / 4);
    k_cvt16<<<(512 * 512 / 4 + 255) / 256, 256>>>(att_hw_w, p_whw, 512 * 512 / 4);
    k_cvt16<<<(2048 * 1024 / 4 + 255) / 256, 256>>>(w_ih, p_wih, 2048 * 1024 / 4);
    k_cvt16<<<(Vn * 512 / 4 + 255) / 256, 256>>>(fc_w, p_wfc, Vn * 512 / 4);
    k_cvt16<<<(2048 * 512 / 4 + 255) / 256, 256>>>(w_hh, p_whh, 2048 * 512 / 4);
    k_normalize<<<Bn * 49, 256>>>();
    k_copy_eng<<<Bn * 15, 512>>>(eng);
    k_rowmap<<<1, 256>>>(lengths);
    k_zero_masked<<<Bn * Tn, 256>>>(lengths, out);

    // img (split-K fp32): feature_0 @ img_w.T -> g_x rows t=0
    sgemm_splitk<<<dim3(8, 2, 8), 256>>>(feature_0, img_w);
    k_img_reduce<<<Bn, 512>>>(img_b);

    // att_fea = features_all @ att_vw_w.T   (8192 x 512 x 512)
    mma_gemm<<<tgrid(Bn * 64, 512), 256, MG_SMEM>>>(p_fall_h, p_fall_l, p_wvw,
        p_afea, 512, nullptr, Bn * 64, 512, 512);

    // att_h = we @ att_hw_w.T   (2560 x 512 x 512)
    mma_gemm<<<tgrid(Bn * Tn, 512), 256, MG_SMEM>>>(p_we_h, p_we_l, p_whw,
        p_ah, 512, nullptr, Bn * Tn, 512, 512);

    // attention: scores then softmax+context -> g_x rows t=1..19
    k_att_scores<<<dim3(8, Bn), 256>>>(att_bias, att_w_w);
    k_att_ctx<<<Bn, 512, CTX_SMEM>>>();

    // xg = [feas|we] @ w_ih.T + (b_ih+b_hh)   (2560 x 2048 x 1024)
    mma_gemm<<<tgrid(Bn * Tn, 4 * Hn), 256, MG_SMEM>>>(p_x_h, p_x_l, p_wih,
        p_xg, 4 * Hn, p_bias2, Bn * Tn, 4 * Hn, 1024);

    // LSTM: step 0 pointwise (+barrier reset), steps 1..19 persistent
    k_lstm_t0<<<(Bn * Hn + 255) / 256, 256>>>();
    k_lstm_all<<<32, 256, LP_SMEM>>>();

    // logits (compacted rows only; masked rows pre-zeroed)
    mma_gemm_fc<<<tgrid(Bn * Tn, Vn), 256, S1_SMEM>>>(p_hs_h, p_wfc,
        out, Vn, fc_b, Vn, 512);
}

// round 11
// speedup vs baseline: 7.0726x; 1.0106x over previous
#include <cuda_runtime.h>
#include <cuda_fp16.h>
#include <cstdint>
#include <math.h>

// Problem dims
#define Bn   128
#define Tn   20
#define Vn   12000
#define En   512
#define Hn   512
#define VISn 512

// ===================== PTX helpers (sm_100 baseline) =====================
__device__ __forceinline__ uint32_t smem_u32(const void* p) {
    uint32_t a;
    asm("{ .reg .u64 t; cvta.to.shared.u64 t, %1; cvt.u32.u64 %0, t; }" : "=r"(a) : "l"(p));
    return a;
}
#define CP_ASYNC16(dst, src) \
    asm volatile("cp.async.cg.shared.global [%0], [%1], 16;" :: "r"(dst), "l"(src) : "memory")
#define CP_COMMIT() asm volatile("cp.async.commit_group;" ::: "memory")
#define CP_WAIT0()  asm volatile("cp.async.wait_group 0;" ::: "memory")
#define CP_WAIT1()  asm volatile("cp.async.wait_group 1;" ::: "memory")
#define CP_WAIT2()  asm volatile("cp.async.wait_group 2;" ::: "memory")

__device__ __forceinline__ void ldsm4(uint32_t* r, uint32_t addr) {
    asm volatile("ldmatrix.sync.aligned.m8n8.x4.shared.b16 {%0,%1,%2,%3}, [%4];"
        : "=r"(r[0]), "=r"(r[1]), "=r"(r[2]), "=r"(r[3]) : "r"(addr));
}
__device__ __forceinline__ void mma16816(float* c, const uint32_t* a, const uint32_t* b) {
    asm volatile("mma.sync.aligned.m16n8k16.row.col.f32.f16.f16.f32 "
        "{%0,%1,%2,%3}, {%4,%5,%6,%7}, {%8,%9}, {%0,%1,%2,%3};"
        : "+f"(c[0]), "+f"(c[1]), "+f"(c[2]), "+f"(c[3])
        : "r"(a[0]), "r"(a[1]), "r"(a[2]), "r"(a[3]), "r"(b[0]), "r"(b[1]));
}

// ===================== scratch (device globals) =====================
__device__ float g_fv[Bn * 49 * VISn];
__device__ float g_features_all[Bn * 64 * VISn];
__device__ float g_att_fea[Bn * 64 * VISn];
__device__ float g_att_h[Bn * Tn * VISn];
__device__ float g_scores[Bn * (Tn - 1) * 64];
__device__ float g_xg[Bn * Tn * 4 * Hn];
__device__ float g_c[Bn * Hn];
__device__ float g_bias2[4 * Hn];
__device__ float g_part[8 * Bn * VISn];
__device__ unsigned g_bar;
__device__ int g_rowmap[Bn * Tn];
__device__ int g_nkept;

// activations: fp16 split pairs (hi, lo)
__device__ __half g_fT_h[Bn * 49 * VISn],   g_fT_l[Bn * 49 * VISn];
__device__ __half g_fall_h[Bn * 64 * VISn], g_fall_l[Bn * 64 * VISn];
__device__ __half g_we_h[Bn * Tn * En],     g_we_l[Bn * Tn * En];
__device__ __half g_x_h[Bn * Tn * 1024],    g_x_l[Bn * Tn * 1024];
__device__ __half g_hs_h[Bn * Tn * Hn],     g_hs_l[Bn * Tn * Hn];
// weights: single fp16
__device__ __half g_wfc1[VISn * VISn];
__device__ __half g_wvw[VISn * VISn];
__device__ __half g_whw[VISn * En];
__device__ __half g_wih[4 * Hn * 1024];
__device__ __half g_wfc[Vn * Hn];
__device__ __half g_whh[4 * Hn * Hn];

__device__ __forceinline__ void split_write16(float v, __half* h, __half* l, long i) {
    __half hi = __float2half_rn(v);
    h[i] = hi;
    l[i] = __float2half_rn(v - __half2float(hi));
}

#define ROWB   80
#define ATILE  (64 * ROWB)           // 5120 B (64-row A tile)
#define BTILE  (128 * ROWB)          // 10240 B (128-row B tile)

// ===================== 2-product GEMM: CTA 64x128, 3 CTAs/SM =====================
#define G2_STAGE (2 * ATILE + BTILE) // 20480 (Ah, Al, B)
#define G2_NSTG  3
#define G2_SMEM  (G2_NSTG * G2_STAGE)   // 61440

__global__ __launch_bounds__(256, 3)
void mma_gemm(const __half* __restrict__ Ah, const __half* __restrict__ Al,
              const __half* __restrict__ Bw,
              float* __restrict__ C, int ldc, const float* __restrict__ bias,
              int M, int N, int K)
{
    extern __shared__ __align__(16) char smem[];
    const uint32_t sbase = smem_u32(smem);

    const int tid = threadIdx.x, wid = tid >> 5, lane = tid & 31;
    const int m0 = blockIdx.y * 64, n0 = blockIdx.x * 128;
    const int wm = wid & 1, wn = wid >> 1;

    const int NC = K >> 5;

    auto issue = [&](int c) {
        if (c < NC) {
            const long kc = (long)c * 32;
            const uint32_t sb = sbase + (c % G2_NSTG) * G2_STAGE;
            {   // A hi + lo: 256 chunks each -> 1 per thread
                int row = tid >> 2, kq = tid & 3;
                const long off = (long)(m0 + row) * K + kc + kq * 8;
                CP_ASYNC16(sb + 0 * ATILE + row * ROWB + kq * 16, Ah + off);
                CP_ASYNC16(sb + 1 * ATILE + row * ROWB + kq * 16, Al + off);
            }
            #pragma unroll
            for (int i = 0; i < 2; i++) {   // B: 512 chunks -> 2 per thread
                int ch = tid + i * 256;
                int row = ch >> 2, kq = ch & 3;
                int gr = n0 + row;
                if (gr >= N) gr = N - 1;
                CP_ASYNC16(sb + 2 * ATILE + row * ROWB + kq * 16,
                           Bw + (long)gr * K + kc + kq * 8);
            }
        }
        CP_COMMIT();
    };

    float acc[2][4][4];
    #pragma unroll
    for (int mi = 0; mi < 2; mi++)
        #pragma unroll
        for (int ni = 0; ni < 4; ni++)
            #pragma unroll
            for (int q = 0; q < 4; q++) acc[mi][ni][q] = 0.f;

    const uint32_t a_off = (uint32_t)((wm * 32 + (lane & 15)) * ROWB + (lane >> 4) * 16);
    const uint32_t b_off = (uint32_t)((wn * 32 + ((lane >> 4) & 1) * 8 + (lane & 7)) * ROWB
                                      + ((lane >> 3) & 1) * 16);

    issue(0); issue(1);

    for (int c = 0; c < NC; c++) {
        CP_WAIT1();
        __syncthreads();
        issue(c + 2);

        const uint32_t tb = sbase + (c % G2_NSTG) * G2_STAGE;
        #pragma unroll
        for (int kk = 0; kk < 2; kk++) {
            const uint32_t kba = kk * 32;
            uint32_t ah[2][4], al[2][4], bb[4][2];
            #pragma unroll
            for (int mi = 0; mi < 2; mi++) {
                ldsm4(ah[mi], tb + 0 * ATILE + a_off + mi * 16 * ROWB + kba);
                ldsm4(al[mi], tb + 1 * ATILE + a_off + mi * 16 * ROWB + kba);
            }
            #pragma unroll
            for (int nip = 0; nip < 2; nip++) {
                uint32_t t4[4];
                ldsm4(t4, tb + 2 * ATILE + b_off + nip * 16 * ROWB + kba);
                bb[2*nip][0] = t4[0]; bb[2*nip][1] = t4[1];
                bb[2*nip+1][0] = t4[2]; bb[2*nip+1][1] = t4[3];
            }
            #pragma unroll
            for (int mi = 0; mi < 2; mi++)
                #pragma unroll
                for (int ni = 0; ni < 4; ni++) {
                    mma16816(acc[mi][ni], ah[mi], bb[ni]);
                    mma16816(acc[mi][ni], al[mi], bb[ni]);
                }
        }
    }

    #pragma unroll
    for (int mi = 0; mi < 2; mi++) {
        const int r0 = m0 + wm * 32 + mi * 16 + (lane >> 2);
        const int r1 = r0 + 8;
        #pragma unroll
        for (int ni = 0; ni < 4; ni++) {
            const int col = n0 + wn * 32 + ni * 8 + (lane & 3) * 2;
            if (col >= N) continue;
            float b0 = 0.f, b1 = 0.f;
            if (bias) { b0 = bias[col]; b1 = bias[col + 1]; }
            *(float2*)(C + (long)r0 * ldc + col) = make_float2(acc[mi][ni][0] + b0, acc[mi][ni][1] + b1);
            *(float2*)(C + (long)r1 * ldc + col) = make_float2(acc[mi][ni][2] + b0, acc[mi][ni][3] + b1);
        }
    }
}

// ===================== compacted single-product GEMM for fc: CTA 64x128 =====================
#define S1_STAGE (ATILE + BTILE)         // 15360
#define S1_NSTG  4
#define S1_SMEM  (S1_NSTG * S1_STAGE)    // 61440

__global__ __launch_bounds__(256, 3)
void mma_gemm_fc(const __half* __restrict__ Ah, const __half* __restrict__ Bw,
                 float* __restrict__ C, int ldc, const float* __restrict__ bias,
                 int N, int K)
{
    extern __shared__ __align__(16) char smem[];
    __shared__ int rm[64];
    const uint32_t sbase = smem_u32(smem);

    const int tid = threadIdx.x, wid = tid >> 5, lane = tid & 31;
    const int m0 = blockIdx.y * 64, n0 = blockIdx.x * 128;
    const int wm = wid & 1, wn = wid >> 1;

    const int nkept = g_nkept;
    if (m0 >= nkept) return;

    if (tid < 64) {
        int r = m0 + tid;
        rm[tid] = g_rowmap[r < nkept ? r : (nkept - 1)];
    }
    __syncthreads();

    const int NC = K >> 5;

    auto issue = [&](int c) {
        if (c < NC) {
            const long kc = (long)c * 32;
            const uint32_t sb = sbase + (c & (S1_NSTG - 1)) * S1_STAGE;
            {   // A gather: 1 chunk/thread
                int row = tid >> 2, kq = tid & 3;
                CP_ASYNC16(sb + row * ROWB + kq * 16,
                           Ah + (long)rm[row] * K + kc + kq * 8);
            }
            #pragma unroll
            for (int i = 0; i < 2; i++) {   // B: 2 chunks/thread
                int ch = tid + i * 256;
                int row = ch >> 2, kq = ch & 3;
                int gr = n0 + row;
                if (gr >= N) gr = N - 1;
                CP_ASYNC16(sb + ATILE + row * ROWB + kq * 16,
                           Bw + (long)gr * K + kc + kq * 8);
            }
        }
        CP_COMMIT();
    };

    float acc[2][4][4];
    #pragma unroll
    for (int mi = 0; mi < 2; mi++)
        #pragma unroll
        for (int ni = 0; ni < 4; ni++)
            #pragma unroll
            for (int q = 0; q < 4; q++) acc[mi][ni][q] = 0.f;

    const uint32_t a_off = (uint32_t)((wm * 32 + (lane & 15)) * ROWB + (lane >> 4) * 16);
    const uint32_t b_off = (uint32_t)((wn * 32 + ((lane >> 4) & 1) * 8 + (lane & 7)) * ROWB
                                      + ((lane >> 3) & 1) * 16);

    issue(0); issue(1); issue(2);

    for (int c = 0; c < NC; c++) {
        CP_WAIT2();
        __syncthreads();
        issue(c + 3);

        const uint32_t tb = sbase + (c & (S1_NSTG - 1)) * S1_STAGE;
        #pragma unroll
        for (int kk = 0; kk < 2; kk++) {
            const uint32_t kba = kk * 32;
            uint32_t ah[2][4], bb[4][2];
            #pragma unroll
            for (int mi = 0; mi < 2; mi++)
                ldsm4(ah[mi], tb + a_off + mi * 16 * ROWB + kba);
            #pragma unroll
            for (int nip = 0; nip < 2; nip++) {
                uint32_t t4[4];
                ldsm4(t4, tb + ATILE + b_off + nip * 16 * ROWB + kba);
                bb[2*nip][0] = t4[0]; bb[2*nip][1] = t4[1];
                bb[2*nip+1][0] = t4[2]; bb[2*nip+1][1] = t4[3];
            }
            #pragma unroll
            for (int mi = 0; mi < 2; mi++)
                #pragma unroll
                for (int ni = 0; ni < 4; ni++)
                    mma16816(acc[mi][ni], ah[mi], bb[ni]);
        }
    }

    #pragma unroll
    for (int mi = 0; mi < 2; mi++) {
        const int l0 = wm * 32 + mi * 16 + (lane >> 2);
        const int l1 = l0 + 8;
        const bool v0r = (m0 + l0) < nkept;
        const bool v1r = (m0 + l1) < nkept;
        const long or0 = (long)rm[l0] * ldc;
        const long or1 = (long)rm[l1] * ldc;
        #pragma unroll
        for (int ni = 0; ni < 4; ni++) {
            const int col = n0 + wn * 32 + ni * 8 + (lane & 3) * 2;
            if (col >= N) continue;
            float b0 = bias[col], b1 = bias[col + 1];
            if (v0r) *(float2*)(C + or0 + col) = make_float2(acc[mi][ni][0] + b0, acc[mi][ni][1] + b1);
            if (v1r) *(float2*)(C + or1 + col) = make_float2(acc[mi][ni][2] + b0, acc[mi][ni][3] + b1);
        }
    }
}

// build rowmap of kept rows (lengths[b] >= t) + count
__global__ void k_rowmap(const int* __restrict__ lengths)
{
    __shared__ int cnt[256];
    const int tid = threadIdx.x;
    const int base = tid * 10;
    int flags[10], c = 0;
    #pragma unroll
    for (int i = 0; i < 10; i++) {
        int r = base + i;
        flags[i] = (lengths[r / Tn] >= (r % Tn)) ? 1 : 0;
        c += flags[i];
    }
    cnt[tid] = c;
    __syncthreads();
    for (int off = 1; off < 256; off <<= 1) {
        int v = (tid >= off) ? cnt[tid - off] : 0;
        __syncthreads();
        cnt[tid] += v;
        __syncthreads();
    }
    int pos = cnt[tid] - c;
    #pragma unroll
    for (int i = 0; i < 10; i++) {
        if (flags[i]) g_rowmap[pos++] = base + i;
    }
    if (tid == 255) g_nkept = cnt[255];
}

// zero-fill masked output rows
__global__ void k_zero_masked(const int* __restrict__ lengths, float* __restrict__ out)
{
    const int r = blockIdx.x;
    if (lengths[r / Tn] >= (r % Tn)) return;
    float4* o = (float4*)(out + (long)r * Vn);
    for (int i = threadIdx.x; i < Vn / 4; i += blockDim.x)
        o[i] = make_float4(0.f, 0.f, 0.f, 0.f);
}

// ===================== persistent LSTM: all steps t=1..19 in one launch =====================
#define LB_ALL   (16 * 64 * ROWB)            // 81920
#define LA_STAGE (2 * BTILE)                 // 20480 (h hi/lo, 128 rows)
#define LA_NSTG  4
#define LP_SMEM  (LB_ALL + LA_NSTG * LA_STAGE)   // 163840

__global__ __launch_bounds__(256, 1)
void k_lstm_all()
{
    extern __shared__ __align__(16) char smem[];
    const uint32_t sbase = smem_u32(smem);
    const int tid = threadIdx.x, wid = tid >> 5, lane = tid & 31;
    const int h0 = blockIdx.x * 16;
    const int wm = wid & 1, wn = wid >> 1;       // wn = gate index

    {
        int row = tid >> 2, kq = tid & 3;
        int j = (row >> 4) * 512 + h0 + (row & 15);
        const __half* base = g_whh + (long)j * Hn + kq * 8;
        #pragma unroll
        for (int c = 0; c < 16; c++)
            CP_ASYNC16(sbase + c * (64 * ROWB) + row * ROWB + kq * 16, base + c * 32);
        CP_COMMIT();
        CP_WAIT0();
    }
    __syncthreads();

    const uint32_t a_off = (uint32_t)((wm * 64 + (lane & 15)) * ROWB + (lane >> 4) * 16);
    const uint32_t b_off = (uint32_t)((wn * 16 + ((lane >> 4) & 1) * 8 + (lane & 7)) * ROWB
                                      + ((lane >> 3) & 1) * 16);
    const uint32_t aring = sbase + LB_ALL;

    for (int t = 1; t < Tn; t++) {
        auto issueA = [&](int c) {
            if (c < 16) {
                const long kc = (long)c * 32;
                const uint32_t sb = aring + (c & (LA_NSTG - 1)) * LA_STAGE;
                #pragma unroll
                for (int s = 0; s < 2; s++) {
                    const __half* S = s ? g_hs_l : g_hs_h;
                    #pragma unroll
                    for (int i = 0; i < 2; i++) {
                        int ch = tid + i * 256;
                        int row = ch >> 2, kq = ch & 3;
                        const __half* src = S + ((long)row * Tn + (t - 1)) * Hn + kc + kq * 8;
                        CP_ASYNC16(sb + s * BTILE + row * ROWB + kq * 16, src);
                    }
                }
            }
            CP_COMMIT();
        };

        float acc[4][2][4];
        #pragma unroll
        for (int mi = 0; mi < 4; mi++)
            #pragma unroll
            for (int ni = 0; ni < 2; ni++)
                #pragma unroll
                for (int q = 0; q < 4; q++) acc[mi][ni][q] = 0.f;

        issueA(0); issueA(1); issueA(2);

        for (int c = 0; c < 16; c++) {
            CP_WAIT2();
            __syncthreads();
            issueA(c + 3);

            const uint32_t ta = aring + (c & (LA_NSTG - 1)) * LA_STAGE;
            const uint32_t tbB = sbase + c * (64 * ROWB);
            #pragma unroll
            for (int kk = 0; kk < 2; kk++) {
                const uint32_t kba = kk * 32;
                uint32_t ah[4][4], al[4][4], bb[2][2];
                #pragma unroll
                for (int mi = 0; mi < 4; mi++) {
                    ldsm4(ah[mi], ta + 0 * BTILE + a_off + mi * 16 * ROWB + kba);
                    ldsm4(al[mi], ta + 1 * BTILE + a_off + mi * 16 * ROWB + kba);
                }
                {
                    uint32_t t4[4];
                    ldsm4(t4, tbB + b_off + kba);
                    bb[0][0] = t4[0]; bb[0][1] = t4[1]; bb[1][0] = t4[2]; bb[1][1] = t4[3];
                }
                #pragma unroll
                for (int mi = 0; mi < 4; mi++)
                    #pragma unroll
                    for (int ni = 0; ni < 2; ni++) {
                        mma16816(acc[mi][ni], ah[mi], bb[ni]);
                        mma16816(acc[mi][ni], al[mi], bb[ni]);
                    }
            }
        }

        __syncthreads();
        float* Gs = (float*)(smem + LB_ALL);
        #pragma unroll
        for (int mi = 0; mi < 4; mi++) {
            const int r0 = wm * 64 + mi * 16 + (lane >> 2);
            const int r1 = r0 + 8;
            #pragma unroll
            for (int ni = 0; ni < 2; ni++) {
                const int cl = wn * 16 + ni * 8 + (lane & 3) * 2;
                Gs[r0 * 68 + cl]     = acc[mi][ni][0];
                Gs[r0 * 68 + cl + 1] = acc[mi][ni][1];
                Gs[r1 * 68 + cl]     = acc[mi][ni][2];
                Gs[r1 * 68 + cl + 1] = acc[mi][ni][3];
            }
        }
        __syncthreads();

        for (int p = tid; p < 128 * 16; p += 256) {
            const int b = p >> 4, l = p & 15;
            const int hcol = h0 + l;
            const float* xg = g_xg + ((long)b * Tn + t) * 2048;
            float gi = Gs[b * 68 + 0 * 16 + l] + xg[0 * 512 + hcol];
            float gf = Gs[b * 68 + 1 * 16 + l] + xg[1 * 512 + hcol];
            float gg = Gs[b * 68 + 2 * 16 + l] + xg[2 * 512 + hcol];
            float go = Gs[b * 68 + 3 * 16 + l] + xg[3 * 512 + hcol];
            float co = g_c[b * 512 + hcol];
            float si = 1.f / (1.f + __expf(-gi));
            float sf = 1.f / (1.f + __expf(-gf));
            float so = 1.f / (1.f + __expf(-go));
            float cn = sf * co + si * tanhf(gg);
            float hn = so * tanhf(cn);
            g_c[b * 512 + hcol] = cn;
            split_write16(hn, g_hs_h, g_hs_l, ((long)b * Tn + t) * 512 + hcol);
        }

        __syncthreads();
        if (tid == 0) {
            __threadfence();
            atomicAdd(&g_bar, 1u);
            while (*(volatile unsigned*)&g_bar < 32u * (unsigned)t) { }
            __threadfence();
        }
        __syncthreads();
    }
}

__global__ void k_lstm_t0()
{
    int i = blockIdx.x * blockDim.x + threadIdx.x;
    if (i == 0) g_bar = 0u;
    if (i >= Bn * Hn) return;
    int b = i >> 9, hcol = i & 511;
    const float* xg = g_xg + ((long)b * Tn) * 2048;
    float gi = xg[hcol], gg = xg[1024 + hcol], go = xg[1536 + hcol];
    float si = 1.f / (1.f + __expf(-gi));
    float so = 1.f / (1.f + __expf(-go));
    float cn = si * tanhf(gg);
    float hn = so * tanhf(cn);
    g_c[i] = cn;
    split_write16(hn, g_hs_h, g_hs_l, ((long)b * Tn) * 512 + hcol);
}

// ===================== split-K fp32 GEMM for img (M=128, K=2048) =====================
__global__ __launch_bounds__(256)
void sgemm_splitk(const float* __restrict__ A, const float* __restrict__ Bw)
{
    __shared__ float As[16][64];
    __shared__ float Bs[16][64];
    const int tid = threadIdx.x;
    const int tx = tid & 15, ty = tid >> 4;
    const int n0 = blockIdx.x * 64, m0 = blockIdx.y * 64;
    const int kbase = blockIdx.z * 256;
    const int lr = tid >> 2, lk = (tid & 3) * 4;
    const float* Ap = A  + (long)(m0 + lr) * 2048 + kbase + lk;
    const float* Bp = Bw + (long)(n0 + lr) * 2048 + kbase + lk;

    float acc[4][4] = {};
    for (int k0 = 0; k0 < 256; k0 += 16) {
        float4 avv = *(const float4*)(Ap + k0);
        float4 bvv = *(const float4*)(Bp + k0);
        __syncthreads();
        As[lk+0][lr] = avv.x; As[lk+1][lr] = avv.y; As[lk+2][lr] = avv.z; As[lk+3][lr] = avv.w;
        Bs[lk+0][lr] = bvv.x; Bs[lk+1][lr] = bvv.y; Bs[lk+2][lr] = bvv.z; Bs[lk+3][lr] = bvv.w;
        __syncthreads();
        #pragma unroll
        for (int kk = 0; kk < 16; kk++) {
            float a[4], b[4];
            #pragma unroll
            for (int i = 0; i < 4; i++) a[i] = As[kk][ty * 4 + i];
            #pragma unroll
            for (int j = 0; j < 4; j++) b[j] = Bs[kk][tx * 4 + j];
            #pragma unroll
            for (int i = 0; i < 4; i++)
                #pragma unroll
                for (int j = 0; j < 4; j++) acc[i][j] += a[i] * b[j];
        }
    }
    float* Cp = g_part + (long)blockIdx.z * Bn * VISn;
    #pragma unroll
    for (int i = 0; i < 4; i++)
        #pragma unroll
        for (int j = 0; j < 4; j++)
            Cp[(long)(m0 + ty * 4 + i) * VISn + n0 + tx * 4 + j] = acc[i][j];
}

__global__ void k_img_reduce(const float* __restrict__ img_b) {
    int b = blockIdx.x, v = threadIdx.x;
    float s = img_b[v];
    #pragma unroll
    for (int k = 0; k < 8; k++) s += g_part[((long)k * Bn + b) * VISn + v];
    split_write16(s, g_x_h, g_x_l, (long)(b * Tn) * 1024 + v);
}

// ===================== prep kernels =====================
__global__ void k_bias2(const float* __restrict__ b_ih, const float* __restrict__ b_hh) {
    int i = blockIdx.x * blockDim.x + threadIdx.x;
    if (i < 4 * Hn) g_bias2[i] = b_ih[i] + b_hh[i];
}
__global__ void k_cvt16(const float* __restrict__ x, __half* __restrict__ h, int n4) {
    int i = blockIdx.x * blockDim.x + threadIdx.x;
    if (i >= n4) return;
    float4 v = ((const float4*)x)[i];
    __half2 a = __floats2half2_rn(v.x, v.y);
    __half2 b = __floats2half2_rn(v.z, v.w);
    ((uint2*)h)[i] = make_uint2(*(uint32_t*)&a, *(uint32_t*)&b);
}
__global__ void k_transpose_f(const float* __restrict__ features) {
    int bp = blockIdx.x;
    int b = bp / 49, p = bp % 49;
    int v = threadIdx.x;
    float val = features[((long)b * 512 + v) * 49 + p];
    split_write16(val, g_fT_h, g_fT_l, (long)bp * 512 + v);
}
__global__ void k_normalize() {
    int row = blockIdx.x;
    int b = row / 49, p = row % 49;
    const float* x = g_fv + (long)row * 512;
    __shared__ float red[8];
    int tid = threadIdx.x, lane = tid & 31, wid = tid >> 5;
    float s = 0.f;
    for (int v = tid; v < 512; v += 256) { float t = x[v]; s += t * t; }
    #pragma unroll
    for (int o = 16; o; o >>= 1) s += __shfl_xor_sync(0xffffffffu, s, o);
    if (lane == 0) red[wid] = s;
    __syncthreads();
    if (tid == 0) {
        float sum = 0.f;
        #pragma unroll
        for (int w = 0; w < 8; w++) sum += red[w];
        red[0] = 1.f / fmaxf(sqrtf(sum), 1e-12f);
    }
    __syncthreads();
    float inv = red[0];
    long o = ((long)b * 64 + p) * 512;
    for (int v = tid; v < 512; v += 256) {
        float val = x[v] * inv;
        g_features_all[o + v] = val;
        split_write16(val, g_fall_h, g_fall_l, o + v);
    }
}
__global__ void k_copy_eng(const float* __restrict__ eng) {
    int bj = blockIdx.x;
    int b = bj / 15, j = bj % 15;
    int v = threadIdx.x;
    float val = eng[(long)bj * 512 + v];
    long o = ((long)b * 64 + 49 + j) * 512 + v;
    g_features_all[o] = val;
    split_write16(val, g_fall_h, g_fall_l, o);
}
__global__ void k_embed(const int* __restrict__ captions, const float* __restrict__ embed_w) {
    int r = blockIdx.x;
    int idx = captions[r];
    float v = embed_w[(long)idx * 512 + threadIdx.x];
    split_write16(v, g_we_h, g_we_l, (long)r * 512 + threadIdx.x);
    split_write16(v, g_x_h,  g_x_l,  (long)r * 1024 + 512 + threadIdx.x);
}

// ===================== attention: scores =====================
__global__ __launch_bounds__(256)
void k_att_scores(const float* __restrict__ att_bias, const float* __restrict__ att_w) {
    const int n0 = blockIdx.x * 8, b = blockIdx.y;
    __shared__ float fea8[8][512];
    __shared__ float ws[512];
    __shared__ float hh[512];
    const int tid = threadIdx.x, lane = tid & 31, wid = tid >> 5;

    for (int v = tid; v < 512; v += 256) ws[v] = att_w[v];
    const float4* fea = (const float4*)(g_att_fea + ((long)b * 64 + n0) * 512);
    for (int i = tid; i < 8 * 128; i += 256)
        ((float4*)&fea8[0][0])[i] = fea[i];
    const float bn = att_bias[n0 + wid];

    for (int t = 0; t < Tn - 1; t++) {
        __syncthreads();
        for (int v = tid; v < 512; v += 256) hh[v] = g_att_h[((long)b * Tn + t) * 512 + v];
        __syncthreads();
        float s = 0.f;
        #pragma unroll 4
        for (int v = lane; v < 512; v += 32)
            s += fmaxf(fea8[wid][v] + hh[v] + bn, 0.f) * ws[v];
        #pragma unroll
        for (int o = 16; o; o >>= 1) s += __shfl_xor_sync(0xffffffffu, s, o);
        if (lane == 0) g_scores[((long)b * (Tn - 1) + t) * 64 + n0 + wid] = s;
    }
}

// ===================== attention: softmax + context =====================
#define CTX_SMEM (64 * 512 * 4 + 256)
__global__ __launch_bounds__(512)
void k_att_ctx() {
    extern __shared__ float fs[];
    float* sout = fs + 64 * 512;
    const int b = blockIdx.x, tid = threadIdx.x, lane = tid & 31, wid = tid >> 5;

    const float4* src = (const float4*)(g_features_all + (long)b * 64 * 512);
    for (int i = tid; i < 64 * 128; i += 512) ((float4*)fs)[i] = src[i];
    __syncthreads();

    for (int t = 0; t < Tn - 1; t++) {
        if (wid == 0) {
            const float* sc = g_scores + ((long)b * (Tn - 1) + t) * 64;
            float s0 = sc[lane], s1 = sc[lane + 32];
            float m = fmaxf(s0, s1);
            #pragma unroll
            for (int o = 16; o; o >>= 1) m = fmaxf(m, __shfl_xor_sync(0xffffffffu, m, o));
            float e0 = __expf(s0 - m), e1 = __expf(s1 - m);
            float sum = e0 + e1;
            #pragma unroll
            for (int o = 16; o; o >>= 1) sum += __shfl_xor_sync(0xffffffffu, sum, o);
            float inv = 1.f / sum;
            sout[lane] = e0 * inv; sout[lane + 32] = e1 * inv;
        }
        __syncthreads();
        float acc = 0.f;
        #pragma unroll 8
        for (int n = 0; n < 64; n++) acc += sout[n] * fs[n * 512 + tid];
        split_write16(acc, g_x_h, g_x_l, ((long)b * Tn + (t + 1)) * 1024 + tid);
        __syncthreads();
    }
}

// ===================== launch =====================
static inline dim3 tgrid64(int M, int N) { return dim3((N + 127) / 128, (M + 63) / 64); }

extern "C" void kernel_launch(void* const* d_in, const int* in_sizes, int n_in,
                              void* d_out, int out_size)
{
    const float* feature_0 = (const float*)d_in[0];
    const float* features  = (const float*)d_in[1];
    const float* eng       = (const float*)d_in[2];
    const int*   captions  = (const int*)  d_in[3];
    const int*   lengths   = (const int*)  d_in[4];
    const float* embed_w   = (const float*)d_in[5];
    const float* w_ih      = (const float*)d_in[6];
    const float* w_hh      = (const float*)d_in[7];
    const float* b_ih      = (const float*)d_in[8];
    const float* b_hh      = (const float*)d_in[9];
    const float* fc_w      = (const float*)d_in[10];
    const float* fc_b      = (const float*)d_in[11];
    const float* att_vw_w  = (const float*)d_in[12];
    const float* att_hw_w  = (const float*)d_in[13];
    const float* att_bias  = (const float*)d_in[14];
    const float* att_w_w   = (const float*)d_in[15];
    const float* att_fc_w  = (const float*)d_in[16];
    const float* att_fc_b  = (const float*)d_in[17];
    const float* img_w     = (const float*)d_in[18];
    const float* img_b     = (const float*)d_in[19];
    float* out = (float*)d_out;

    static bool smem_set = false;
    if (!smem_set) {
        cudaFuncSetAttribute(mma_gemm,    cudaFuncAttributeMaxDynamicSharedMemorySize, G2_SMEM);
        cudaFuncSetAttribute(mma_gemm_fc, cudaFuncAttributeMaxDynamicSharedMemorySize, S1_SMEM);
        cudaFuncSetAttribute(k_lstm_all,  cudaFuncAttributeMaxDynamicSharedMemorySize, LP_SMEM);
        cudaFuncSetAttribute(k_att_ctx,   cudaFuncAttributeMaxDynamicSharedMemorySize, CTX_SMEM);
        smem_set = true;
    }

    float* p_fv = nullptr;    cudaGetSymbolAddress((void**)&p_fv,    g_fv);
    float* p_ah = nullptr;    cudaGetSymbolAddress((void**)&p_ah,    g_att_h);
    float* p_xg = nullptr;    cudaGetSymbolAddress((void**)&p_xg,    g_xg);
    float* p_bias2 = nullptr; cudaGetSymbolAddress((void**)&p_bias2, g_bias2);
    float* p_afea = nullptr;  cudaGetSymbolAddress((void**)&p_afea,  g_att_fea);
    #define HSYM(p, s) __half* p = nullptr; cudaGetSymbolAddress((void**)&p, s)
    HSYM(p_fT_h, g_fT_h);     HSYM(p_fT_l, g_fT_l);
    HSYM(p_fall_h, g_fall_h); HSYM(p_fall_l, g_fall_l);
    HSYM(p_we_h, g_we_h);     HSYM(p_we_l, g_we_l);
    HSYM(p_x_h, g_x_h);       HSYM(p_x_l, g_x_l);
    HSYM(p_hs_h, g_hs_h);     HSYM(p_hs_l, g_hs_l);
    HSYM(p_wfc1, g_wfc1);     HSYM(p_wvw, g_wvw);
    HSYM(p_whw, g_whw);       HSYM(p_wih, g_wih);
    HSYM(p_wfc, g_wfc);       HSYM(p_whh, g_whh);
    #undef HSYM

    // launches 1-3: deps of the att_fc GEMM; #4 = mma_gemm (ncu profile slot)
    k_cvt16<<<(512 * 512 / 4 + 255) / 256, 256>>>(att_fc_w, p_wfc1, 512 * 512 / 4);
    k_transpose_f<<<Bn * 49, 512>>>(features);
    k_bias2<<<(4 * Hn + 255) / 256, 256>>>(b_ih, b_hh);

    // #4: att_fc: fv = fT @ att_fc_w.T + b   (6272 x 512 x 512)
    mma_gemm<<<tgrid64(Bn * 49, 512), 256, G2_SMEM>>>(p_fT_h, p_fT_l, p_wfc1,
        p_fv, 512, att_fc_b, Bn * 49, 512, 512);

    // remaining conversions + prep
    k_embed<<<Bn * Tn, 512>>>(captions, embed_w);
    k_cvt16<<<(512 * 512 / 4 + 255) / 256, 256>>>(att_vw_w, p_wvw, 512 * 512 / 4);
    k_cvt16<<<(512 * 512 / 4 + 255) / 256, 256>>>(att_hw_w, p_whw, 512 * 512 / 4);
    k_cvt16<<<(2048 * 1024 / 4 + 255) / 256, 256>>>(w_ih, p_wih, 2048 * 1024 / 4);
    k_cvt16<<<(Vn * 512 / 4 + 255) / 256, 256>>>(fc_w, p_wfc, Vn * 512 / 4);
    k_cvt16<<<(2048 * 512 / 4 + 255) / 256, 256>>>(w_hh, p_whh, 2048 * 512 / 4);
    k_normalize<<<Bn * 49, 256>>>();
    k_copy_eng<<<Bn * 15, 512>>>(eng);
    k_rowmap<<<1, 256>>>(lengths);
    k_zero_masked<<<Bn * Tn, 256>>>(lengths, out);

    // img (split-K fp32): feature_0 @ img_w.T -> g_x rows t=0
    sgemm_splitk<<<dim3(8, 2, 8), 256>>>(feature_0, img_w);
    k_img_reduce<<<Bn, 512>>>(img_b);

    // att_fea = features_all @ att_vw_w.T   (8192 x 512 x 512)
    mma_gemm<<<tgrid64(Bn * 64, 512), 256, G2_SMEM>>>(p_fall_h, p_fall_l, p_wvw,
        p_afea, 512, nullptr, Bn * 64, 512, 512);

    // att_h = we @ att_hw_w.T   (2560 x 512 x 512)
    mma_gemm<<<tgrid64(Bn * Tn, 512), 256, G2_SMEM>>>(p_we_h, p_we_l, p_whw,
        p_ah, 512, nullptr, Bn * Tn, 512, 512);

    // attention: scores then softmax+context -> g_x rows t=1..19
    k_att_scores<<<dim3(8, Bn), 256>>>(att_bias, att_w_w);
    k_att_ctx<<<Bn, 512, CTX_SMEM>>>();

    // xg = [feas|we] @ w_ih.T + (b_ih+b_hh)   (2560 x 2048 x 1024)
    mma_gemm<<<tgrid64(Bn * Tn, 4 * Hn), 256, G2_SMEM>>>(p_x_h, p_x_l, p_wih,
        p_xg, 4 * Hn, p_bias2, Bn * Tn, 4 * Hn, 1024);

    // LSTM: step 0 pointwise (+barrier reset), steps 1..19 persistent
    k_lstm_t0<<<(Bn * Hn + 255) / 256, 256>>>();
    k_lstm_all<<<32, 256, LP_SMEM>>>();

    // logits (compacted rows only; masked rows pre-zeroed)
    mma_gemm_fc<<<tgrid64(Bn * Tn, Vn), 256, S1_SMEM>>>(p_hs_h, p_wfc,
        out, Vn, fc_b, Vn, 512);
}

// round 12
// speedup vs baseline: 7.5935x; 1.0737x over previous
#include <cuda_runtime.h>
#include <cuda_fp16.h>
#include <cstdint>
#include <math.h>

// Problem dims
#define Bn   128
#define Tn   20
#define Vn   12000
#define En   512
#define Hn   512
#define VISn 512

// ===================== PTX helpers (sm_100 baseline) =====================
__device__ __forceinline__ uint32_t smem_u32(const void* p) {
    uint32_t a;
    asm("{ .reg .u64 t; cvta.to.shared.u64 t, %1; cvt.u32.u64 %0, t; }" : "=r"(a) : "l"(p));
    return a;
}
#define CP_ASYNC16(dst, src) \
    asm volatile("cp.async.cg.shared.global [%0], [%1], 16;" :: "r"(dst), "l"(src) : "memory")
#define CP_COMMIT() asm volatile("cp.async.commit_group;" ::: "memory")
#define CP_WAIT0()  asm volatile("cp.async.wait_group 0;" ::: "memory")
#define CP_WAIT1()  asm volatile("cp.async.wait_group 1;" ::: "memory")
#define CP_WAIT2()  asm volatile("cp.async.wait_group 2;" ::: "memory")

__device__ __forceinline__ void ldsm4(uint32_t* r, uint32_t addr) {
    asm volatile("ldmatrix.sync.aligned.m8n8.x4.shared.b16 {%0,%1,%2,%3}, [%4];"
        : "=r"(r[0]), "=r"(r[1]), "=r"(r[2]), "=r"(r[3]) : "r"(addr));
}
__device__ __forceinline__ void mma16816(float* c, const uint32_t* a, const uint32_t* b) {
    asm volatile("mma.sync.aligned.m16n8k16.row.col.f32.f16.f16.f32 "
        "{%0,%1,%2,%3}, {%4,%5,%6,%7}, {%8,%9}, {%0,%1,%2,%3};"
        : "+f"(c[0]), "+f"(c[1]), "+f"(c[2]), "+f"(c[3])
        : "r"(a[0]), "r"(a[1]), "r"(a[2]), "r"(a[3]), "r"(b[0]), "r"(b[1]));
}

// ===================== scratch (device globals) =====================
__device__ float g_fv[Bn * 49 * VISn];
__device__ float g_features_all[Bn * 64 * VISn];
__device__ float g_att_fea[Bn * 64 * VISn];
__device__ float g_att_h[Bn * Tn * VISn];
__device__ float g_scores[Bn * (Tn - 1) * 64];
__device__ float g_xg[Bn * Tn * 4 * Hn];
__device__ float g_c[Bn * Hn];
__device__ float g_bias2[4 * Hn];
__device__ float g_part[8 * Bn * VISn];
__device__ unsigned g_bar;
__device__ int g_rowmap[Bn * Tn];
__device__ int g_nkept;

// activations (single fp16, except hs which stays split for the recurrent path)
__device__ __half g_fT[Bn * 49 * VISn];
__device__ __half g_fall16[Bn * 64 * VISn];
__device__ __half g_we16[Bn * Tn * En];
__device__ __half g_x16[Bn * Tn * 1024];
__device__ __half g_hs_h[Bn * Tn * Hn], g_hs_l[Bn * Tn * Hn];
// weights: single fp16
__device__ __half g_wfc1[VISn * VISn];
__device__ __half g_wvw[VISn * VISn];
__device__ __half g_whw[VISn * En];
__device__ __half g_wih[4 * Hn * 1024];
__device__ __half g_wfc[Vn * Hn];
__device__ __half g_whh[4 * Hn * Hn];

__device__ __forceinline__ void split_write16(float v, __half* h, __half* l, long i) {
    __half hi = __float2half_rn(v);
    h[i] = hi;
    l[i] = __float2half_rn(v - __half2float(hi));
}

#define ROWB   80
#define ATILE  (64 * ROWB)           // 5120 B
#define BTILE  (128 * ROWB)          // 10240 B

// ===================== single-product GEMM: CTA 64x128, 3 CTAs/SM =====================
// C[M,N] = A[M,K] @ B[N,K]^T (+bias). M must be a multiple of 64.
#define S1_STAGE (ATILE + BTILE)         // 15360
#define S1_NSTG  4
#define S1_SMEM  (S1_NSTG * S1_STAGE)    // 61440

__global__ __launch_bounds__(256, 3)
void mma_gemm1(const __half* __restrict__ Ah, const __half* __restrict__ Bw,
               float* __restrict__ C, int ldc, const float* __restrict__ bias,
               int N, int K)
{
    extern __shared__ __align__(16) char smem[];
    const uint32_t sbase = smem_u32(smem);

    const int tid = threadIdx.x, wid = tid >> 5, lane = tid & 31;
    const int m0 = blockIdx.y * 64, n0 = blockIdx.x * 128;
    const int wm = wid & 1, wn = wid >> 1;

    const int NC = K >> 5;

    auto issue = [&](int c) {
        if (c < NC) {
            const long kc = (long)c * 32;
            const uint32_t sb = sbase + (c & (S1_NSTG - 1)) * S1_STAGE;
            {   // A: 1 chunk/thread
                int row = tid >> 2, kq = tid & 3;
                CP_ASYNC16(sb + row * ROWB + kq * 16,
                           Ah + (long)(m0 + row) * K + kc + kq * 8);
            }
            #pragma unroll
            for (int i = 0; i < 2; i++) {   // B: 2 chunks/thread
                int ch = tid + i * 256;
                int row = ch >> 2, kq = ch & 3;
                int gr = n0 + row;
                if (gr >= N) gr = N - 1;
                CP_ASYNC16(sb + ATILE + row * ROWB + kq * 16,
                           Bw + (long)gr * K + kc + kq * 8);
            }
        }
        CP_COMMIT();
    };

    float acc[2][4][4];
    #pragma unroll
    for (int mi = 0; mi < 2; mi++)
        #pragma unroll
        for (int ni = 0; ni < 4; ni++)
            #pragma unroll
            for (int q = 0; q < 4; q++) acc[mi][ni][q] = 0.f;

    const uint32_t a_off = (uint32_t)((wm * 32 + (lane & 15)) * ROWB + (lane >> 4) * 16);
    const uint32_t b_off = (uint32_t)((wn * 32 + ((lane >> 4) & 1) * 8 + (lane & 7)) * ROWB
                                      + ((lane >> 3) & 1) * 16);

    issue(0); issue(1); issue(2);

    for (int c = 0; c < NC; c++) {
        CP_WAIT2();
        __syncthreads();
        issue(c + 3);

        const uint32_t tb = sbase + (c & (S1_NSTG - 1)) * S1_STAGE;
        #pragma unroll
        for (int kk = 0; kk < 2; kk++) {
            const uint32_t kba = kk * 32;
            uint32_t ah[2][4], bb[4][2];
            #pragma unroll
            for (int mi = 0; mi < 2; mi++)
                ldsm4(ah[mi], tb + a_off + mi * 16 * ROWB + kba);
            #pragma unroll
            for (int nip = 0; nip < 2; nip++) {
                uint32_t t4[4];
                ldsm4(t4, tb + ATILE + b_off + nip * 16 * ROWB + kba);
                bb[2*nip][0] = t4[0]; bb[2*nip][1] = t4[1];
                bb[2*nip+1][0] = t4[2]; bb[2*nip+1][1] = t4[3];
            }
            #pragma unroll
            for (int mi = 0; mi < 2; mi++)
                #pragma unroll
                for (int ni = 0; ni < 4; ni++)
                    mma16816(acc[mi][ni], ah[mi], bb[ni]);
        }
    }

    #pragma unroll
    for (int mi = 0; mi < 2; mi++) {
        const int r0 = m0 + wm * 32 + mi * 16 + (lane >> 2);
        const int r1 = r0 + 8;
        #pragma unroll
        for (int ni = 0; ni < 4; ni++) {
            const int col = n0 + wn * 32 + ni * 8 + (lane & 3) * 2;
            if (col >= N) continue;
            float b0 = 0.f, b1 = 0.f;
            if (bias) { b0 = bias[col]; b1 = bias[col + 1]; }
            *(float2*)(C + (long)r0 * ldc + col) = make_float2(acc[mi][ni][0] + b0, acc[mi][ni][1] + b1);
            *(float2*)(C + (long)r1 * ldc + col) = make_float2(acc[mi][ni][2] + b0, acc[mi][ni][3] + b1);
        }
    }
}

// ===================== compacted single-product GEMM for fc =====================
__global__ __launch_bounds__(256, 3)
void mma_gemm_fc(const __half* __restrict__ Ah, const __half* __restrict__ Bw,
                 float* __restrict__ C, int ldc, const float* __restrict__ bias,
                 int N, int K)
{
    extern __shared__ __align__(16) char smem[];
    __shared__ int rm[64];
    const uint32_t sbase = smem_u32(smem);

    const int tid = threadIdx.x, wid = tid >> 5, lane = tid & 31;
    const int m0 = blockIdx.y * 64, n0 = blockIdx.x * 128;
    const int wm = wid & 1, wn = wid >> 1;

    const int nkept = g_nkept;
    if (m0 >= nkept) return;

    if (tid < 64) {
        int r = m0 + tid;
        rm[tid] = g_rowmap[r < nkept ? r : (nkept - 1)];
    }
    __syncthreads();

    const int NC = K >> 5;

    auto issue = [&](int c) {
        if (c < NC) {
            const long kc = (long)c * 32;
            const uint32_t sb = sbase + (c & (S1_NSTG - 1)) * S1_STAGE;
            {
                int row = tid >> 2, kq = tid & 3;
                CP_ASYNC16(sb + row * ROWB + kq * 16,
                           Ah + (long)rm[row] * K + kc + kq * 8);
            }
            #pragma unroll
            for (int i = 0; i < 2; i++) {
                int ch = tid + i * 256;
                int row = ch >> 2, kq = ch & 3;
                int gr = n0 + row;
                if (gr >= N) gr = N - 1;
                CP_ASYNC16(sb + ATILE + row * ROWB + kq * 16,
                           Bw + (long)gr * K + kc + kq * 8);
            }
        }
        CP_COMMIT();
    };

    float acc[2][4][4];
    #pragma unroll
    for (int mi = 0; mi < 2; mi++)
        #pragma unroll
        for (int ni = 0; ni < 4; ni++)
            #pragma unroll
            for (int q = 0; q < 4; q++) acc[mi][ni][q] = 0.f;

    const uint32_t a_off = (uint32_t)((wm * 32 + (lane & 15)) * ROWB + (lane >> 4) * 16);
    const uint32_t b_off = (uint32_t)((wn * 32 + ((lane >> 4) & 1) * 8 + (lane & 7)) * ROWB
                                      + ((lane >> 3) & 1) * 16);

    issue(0); issue(1); issue(2);

    for (int c = 0; c < NC; c++) {
        CP_WAIT2();
        __syncthreads();
        issue(c + 3);

        const uint32_t tb = sbase + (c & (S1_NSTG - 1)) * S1_STAGE;
        #pragma unroll
        for (int kk = 0; kk < 2; kk++) {
            const uint32_t kba = kk * 32;
            uint32_t ah[2][4], bb[4][2];
            #pragma unroll
            for (int mi = 0; mi < 2; mi++)
                ldsm4(ah[mi], tb + a_off + mi * 16 * ROWB + kba);
            #pragma unroll
            for (int nip = 0; nip < 2; nip++) {
                uint32_t t4[4];
                ldsm4(t4, tb + ATILE + b_off + nip * 16 * ROWB + kba);
                bb[2*nip][0] = t4[0]; bb[2*nip][1] = t4[1];
                bb[2*nip+1][0] = t4[2]; bb[2*nip+1][1] = t4[3];
            }
            #pragma unroll
            for (int mi = 0; mi < 2; mi++)
                #pragma unroll
                for (int ni = 0; ni < 4; ni++)
                    mma16816(acc[mi][ni], ah[mi], bb[ni]);
        }
    }

    #pragma unroll
    for (int mi = 0; mi < 2; mi++) {
        const int l0 = wm * 32 + mi * 16 + (lane >> 2);
        const int l1 = l0 + 8;
        const bool v0r = (m0 + l0) < nkept;
        const bool v1r = (m0 + l1) < nkept;
        const long or0 = (long)rm[l0] * ldc;
        const long or1 = (long)rm[l1] * ldc;
        #pragma unroll
        for (int ni = 0; ni < 4; ni++) {
            const int col = n0 + wn * 32 + ni * 8 + (lane & 3) * 2;
            if (col >= N) continue;
            float b0 = bias[col], b1 = bias[col + 1];
            if (v0r) *(float2*)(C + or0 + col) = make_float2(acc[mi][ni][0] + b0, acc[mi][ni][1] + b1);
            if (v1r) *(float2*)(C + or1 + col) = make_float2(acc[mi][ni][2] + b0, acc[mi][ni][3] + b1);
        }
    }
}

// build rowmap of kept rows + count
__global__ void k_rowmap(const int* __restrict__ lengths)
{
    __shared__ int cnt[256];
    const int tid = threadIdx.x;
    const int base = tid * 10;
    int flags[10], c = 0;
    #pragma unroll
    for (int i = 0; i < 10; i++) {
        int r = base + i;
        flags[i] = (lengths[r / Tn] >= (r % Tn)) ? 1 : 0;
        c += flags[i];
    }
    cnt[tid] = c;
    __syncthreads();
    for (int off = 1; off < 256; off <<= 1) {
        int v = (tid >= off) ? cnt[tid - off] : 0;
        __syncthreads();
        cnt[tid] += v;
        __syncthreads();
    }
    int pos = cnt[tid] - c;
    #pragma unroll
    for (int i = 0; i < 10; i++) {
        if (flags[i]) g_rowmap[pos++] = base + i;
    }
    if (tid == 255) g_nkept = cnt[255];
}

__global__ void k_zero_masked(const int* __restrict__ lengths, float* __restrict__ out)
{
    const int r = blockIdx.x;
    if (lengths[r / Tn] >= (r % Tn)) return;
    float4* o = (float4*)(out + (long)r * Vn);
    for (int i = threadIdx.x; i < Vn / 4; i += blockDim.x)
        o[i] = make_float4(0.f, 0.f, 0.f, 0.f);
}

// ===================== persistent LSTM (2-product recurrent path, unchanged) =====================
#define LB_ALL   (16 * 64 * ROWB)            // 81920
#define LA_STAGE (2 * BTILE)                 // 20480
#define LA_NSTG  4
#define LP_SMEM  (LB_ALL + LA_NSTG * LA_STAGE)   // 163840

__global__ __launch_bounds__(256, 1)
void k_lstm_all()
{
    extern __shared__ __align__(16) char smem[];
    const uint32_t sbase = smem_u32(smem);
    const int tid = threadIdx.x, wid = tid >> 5, lane = tid & 31;
    const int h0 = blockIdx.x * 16;
    const int wm = wid & 1, wn = wid >> 1;

    {
        int row = tid >> 2, kq = tid & 3;
        int j = (row >> 4) * 512 + h0 + (row & 15);
        const __half* base = g_whh + (long)j * Hn + kq * 8;
        #pragma unroll
        for (int c = 0; c < 16; c++)
            CP_ASYNC16(sbase + c * (64 * ROWB) + row * ROWB + kq * 16, base + c * 32);
        CP_COMMIT();
        CP_WAIT0();
    }
    __syncthreads();

    const uint32_t a_off = (uint32_t)((wm * 64 + (lane & 15)) * ROWB + (lane >> 4) * 16);
    const uint32_t b_off = (uint32_t)((wn * 16 + ((lane >> 4) & 1) * 8 + (lane & 7)) * ROWB
                                      + ((lane >> 3) & 1) * 16);
    const uint32_t aring = sbase + LB_ALL;

    for (int t = 1; t < Tn; t++) {
        auto issueA = [&](int c) {
            if (c < 16) {
                const long kc = (long)c * 32;
                const uint32_t sb = aring + (c & (LA_NSTG - 1)) * LA_STAGE;
                #pragma unroll
                for (int s = 0; s < 2; s++) {
                    const __half* S = s ? g_hs_l : g_hs_h;
                    #pragma unroll
                    for (int i = 0; i < 2; i++) {
                        int ch = tid + i * 256;
                        int row = ch >> 2, kq = ch & 3;
                        const __half* src = S + ((long)row * Tn + (t - 1)) * Hn + kc + kq * 8;
                        CP_ASYNC16(sb + s * BTILE + row * ROWB + kq * 16, src);
                    }
                }
            }
            CP_COMMIT();
        };

        float acc[4][2][4];
        #pragma unroll
        for (int mi = 0; mi < 4; mi++)
            #pragma unroll
            for (int ni = 0; ni < 2; ni++)
                #pragma unroll
                for (int q = 0; q < 4; q++) acc[mi][ni][q] = 0.f;

        issueA(0); issueA(1); issueA(2);

        for (int c = 0; c < 16; c++) {
            CP_WAIT2();
            __syncthreads();
            issueA(c + 3);

            const uint32_t ta = aring + (c & (LA_NSTG - 1)) * LA_STAGE;
            const uint32_t tbB = sbase + c * (64 * ROWB);
            #pragma unroll
            for (int kk = 0; kk < 2; kk++) {
                const uint32_t kba = kk * 32;
                uint32_t ah[4][4], al[4][4], bb[2][2];
                #pragma unroll
                for (int mi = 0; mi < 4; mi++) {
                    ldsm4(ah[mi], ta + 0 * BTILE + a_off + mi * 16 * ROWB + kba);
                    ldsm4(al[mi], ta + 1 * BTILE + a_off + mi * 16 * ROWB + kba);
                }
                {
                    uint32_t t4[4];
                    ldsm4(t4, tbB + b_off + kba);
                    bb[0][0] = t4[0]; bb[0][1] = t4[1]; bb[1][0] = t4[2]; bb[1][1] = t4[3];
                }
                #pragma unroll
                for (int mi = 0; mi < 4; mi++)
                    #pragma unroll
                    for (int ni = 0; ni < 2; ni++) {
                        mma16816(acc[mi][ni], ah[mi], bb[ni]);
                        mma16816(acc[mi][ni], al[mi], bb[ni]);
                    }
            }
        }

        __syncthreads();
        float* Gs = (float*)(smem + LB_ALL);
        #pragma unroll
        for (int mi = 0; mi < 4; mi++) {
            const int r0 = wm * 64 + mi * 16 + (lane >> 2);
            const int r1 = r0 + 8;
            #pragma unroll
            for (int ni = 0; ni < 2; ni++) {
                const int cl = wn * 16 + ni * 8 + (lane & 3) * 2;
                Gs[r0 * 68 + cl]     = acc[mi][ni][0];
                Gs[r0 * 68 + cl + 1] = acc[mi][ni][1];
                Gs[r1 * 68 + cl]     = acc[mi][ni][2];
                Gs[r1 * 68 + cl + 1] = acc[mi][ni][3];
            }
        }
        __syncthreads();

        for (int p = tid; p < 128 * 16; p += 256) {
            const int b = p >> 4, l = p & 15;
            const int hcol = h0 + l;
            const float* xg = g_xg + ((long)b * Tn + t) * 2048;
            float gi = Gs[b * 68 + 0 * 16 + l] + xg[0 * 512 + hcol];
            float gf = Gs[b * 68 + 1 * 16 + l] + xg[1 * 512 + hcol];
            float gg = Gs[b * 68 + 2 * 16 + l] + xg[2 * 512 + hcol];
            float go = Gs[b * 68 + 3 * 16 + l] + xg[3 * 512 + hcol];
            float co = g_c[b * 512 + hcol];
            float si = 1.f / (1.f + __expf(-gi));
            float sf = 1.f / (1.f + __expf(-gf));
            float so = 1.f / (1.f + __expf(-go));
            float cn = sf * co + si * tanhf(gg);
            float hn = so * tanhf(cn);
            g_c[b * 512 + hcol] = cn;
            split_write16(hn, g_hs_h, g_hs_l, ((long)b * Tn + t) * 512 + hcol);
        }

        __syncthreads();
        if (tid == 0) {
            __threadfence();
            atomicAdd(&g_bar, 1u);
            while (*(volatile unsigned*)&g_bar < 32u * (unsigned)t) { }
            __threadfence();
        }
        __syncthreads();
    }
}

__global__ void k_lstm_t0()
{
    int i = blockIdx.x * blockDim.x + threadIdx.x;
    if (i == 0) g_bar = 0u;
    if (i >= Bn * Hn) return;
    int b = i >> 9, hcol = i & 511;
    const float* xg = g_xg + ((long)b * Tn) * 2048;
    float gi = xg[hcol], gg = xg[1024 + hcol], go = xg[1536 + hcol];
    float si = 1.f / (1.f + __expf(-gi));
    float so = 1.f / (1.f + __expf(-go));
    float cn = si * tanhf(gg);
    float hn = so * tanhf(cn);
    g_c[i] = cn;
    split_write16(hn, g_hs_h, g_hs_l, ((long)b * Tn) * 512 + hcol);
}

// ===================== split-K fp32 GEMM for img =====================
__global__ __launch_bounds__(256)
void sgemm_splitk(const float* __restrict__ A, const float* __restrict__ Bw)
{
    __shared__ float As[16][64];
    __shared__ float Bs[16][64];
    const int tid = threadIdx.x;
    const int tx = tid & 15, ty = tid >> 4;
    const int n0 = blockIdx.x * 64, m0 = blockIdx.y * 64;
    const int kbase = blockIdx.z * 256;
    const int lr = tid >> 2, lk = (tid & 3) * 4;
    const float* Ap = A  + (long)(m0 + lr) * 2048 + kbase + lk;
    const float* Bp = Bw + (long)(n0 + lr) * 2048 + kbase + lk;

    float acc[4][4] = {};
    for (int k0 = 0; k0 < 256; k0 += 16) {
        float4 avv = *(const float4*)(Ap + k0);
        float4 bvv = *(const float4*)(Bp + k0);
        __syncthreads();
        As[lk+0][lr] = avv.x; As[lk+1][lr] = avv.y; As[lk+2][lr] = avv.z; As[lk+3][lr] = avv.w;
        Bs[lk+0][lr] = bvv.x; Bs[lk+1][lr] = bvv.y; Bs[lk+2][lr] = bvv.z; Bs[lk+3][lr] = bvv.w;
        __syncthreads();
        #pragma unroll
        for (int kk = 0; kk < 16; kk++) {
            float a[4], b[4];
            #pragma unroll
            for (int i = 0; i < 4; i++) a[i] = As[kk][ty * 4 + i];
            #pragma unroll
            for (int j = 0; j < 4; j++) b[j] = Bs[kk][tx * 4 + j];
            #pragma unroll
            for (int i = 0; i < 4; i++)
                #pragma unroll
                for (int j = 0; j < 4; j++) acc[i][j] += a[i] * b[j];
        }
    }
    float* Cp = g_part + (long)blockIdx.z * Bn * VISn;
    #pragma unroll
    for (int i = 0; i < 4; i++)
        #pragma unroll
        for (int j = 0; j < 4; j++)
            Cp[(long)(m0 + ty * 4 + i) * VISn + n0 + tx * 4 + j] = acc[i][j];
}

__global__ void k_img_reduce(const float* __restrict__ img_b) {
    int b = blockIdx.x, v = threadIdx.x;
    float s = img_b[v];
    #pragma unroll
    for (int k = 0; k < 8; k++) s += g_part[((long)k * Bn + b) * VISn + v];
    g_x16[(long)(b * Tn) * 1024 + v] = __float2half_rn(s);
}

// ===================== prep kernels =====================
__global__ void k_bias2(const float* __restrict__ b_ih, const float* __restrict__ b_hh) {
    int i = blockIdx.x * blockDim.x + threadIdx.x;
    if (i < 4 * Hn) g_bias2[i] = b_ih[i] + b_hh[i];
}
__global__ void k_cvt16(const float* __restrict__ x, __half* __restrict__ h, int n4) {
    int i = blockIdx.x * blockDim.x + threadIdx.x;
    if (i >= n4) return;
    float4 v = ((const float4*)x)[i];
    __half2 a = __floats2half2_rn(v.x, v.y);
    __half2 b = __floats2half2_rn(v.z, v.w);
    ((uint2*)h)[i] = make_uint2(*(uint32_t*)&a, *(uint32_t*)&b);
}
__global__ void k_transpose_f(const float* __restrict__ features) {
    int bp = blockIdx.x;
    int b = bp / 49, p = bp % 49;
    int v = threadIdx.x;
    g_fT[(long)bp * 512 + v] =
        __float2half_rn(features[((long)b * 512 + v) * 49 + p]);
}
__global__ void k_normalize() {
    int row = blockIdx.x;
    int b = row / 49, p = row % 49;
    const float* x = g_fv + (long)row * 512;
    __shared__ float red[8];
    int tid = threadIdx.x, lane = tid & 31, wid = tid >> 5;
    float s = 0.f;
    for (int v = tid; v < 512; v += 256) { float t = x[v]; s += t * t; }
    #pragma unroll
    for (int o = 16; o; o >>= 1) s += __shfl_xor_sync(0xffffffffu, s, o);
    if (lane == 0) red[wid] = s;
    __syncthreads();
    if (tid == 0) {
        float sum = 0.f;
        #pragma unroll
        for (int w = 0; w < 8; w++) sum += red[w];
        red[0] = 1.f / fmaxf(sqrtf(sum), 1e-12f);
    }
    __syncthreads();
    float inv = red[0];
    long o = ((long)b * 64 + p) * 512;
    for (int v = tid; v < 512; v += 256) {
        float val = x[v] * inv;
        g_features_all[o + v] = val;
        g_fall16[o + v] = __float2half_rn(val);
    }
}
__global__ void k_copy_eng(const float* __restrict__ eng) {
    int bj = blockIdx.x;
    int b = bj / 15, j = bj % 15;
    int v = threadIdx.x;
    float val = eng[(long)bj * 512 + v];
    long o = ((long)b * 64 + 49 + j) * 512 + v;
    g_features_all[o] = val;
    g_fall16[o] = __float2half_rn(val);
}
__global__ void k_embed(const int* __restrict__ captions, const float* __restrict__ embed_w) {
    int r = blockIdx.x;
    int idx = captions[r];
    float v = embed_w[(long)idx * 512 + threadIdx.x];
    __half hv = __float2half_rn(v);
    g_we16[(long)r * 512 + threadIdx.x] = hv;
    g_x16[(long)r * 1024 + 512 + threadIdx.x] = hv;
}

// ===================== attention: scores =====================
__global__ __launch_bounds__(256)
void k_att_scores(const float* __restrict__ att_bias, const float* __restrict__ att_w) {
    const int n0 = blockIdx.x * 8, b = blockIdx.y;
    __shared__ float fea8[8][512];
    __shared__ float ws[512];
    __shared__ float hh[512];
    const int tid = threadIdx.x, lane = tid & 31, wid = tid >> 5;

    for (int v = tid; v < 512; v += 256) ws[v] = att_w[v];
    const float4* fea = (const float4*)(g_att_fea + ((long)b * 64 + n0) * 512);
    for (int i = tid; i < 8 * 128; i += 256)
        ((float4*)&fea8[0][0])[i] = fea[i];
    const float bn = att_bias[n0 + wid];

    for (int t = 0; t < Tn - 1; t++) {
        __syncthreads();
        for (int v = tid; v < 512; v += 256) hh[v] = g_att_h[((long)b * Tn + t) * 512 + v];
        __syncthreads();
        float s = 0.f;
        #pragma unroll 4
        for (int v = lane; v < 512; v += 32)
            s += fmaxf(fea8[wid][v] + hh[v] + bn, 0.f) * ws[v];
        #pragma unroll
        for (int o = 16; o; o >>= 1) s += __shfl_xor_sync(0xffffffffu, s, o);
        if (lane == 0) g_scores[((long)b * (Tn - 1) + t) * 64 + n0 + wid] = s;
    }
}

// ===================== attention: softmax + context =====================
#define CTX_SMEM (64 * 512 * 4 + 256)
__global__ __launch_bounds__(512)
void k_att_ctx() {
    extern __shared__ float fs[];
    float* sout = fs + 64 * 512;
    const int b = blockIdx.x, tid = threadIdx.x, lane = tid & 31, wid = tid >> 5;

    const float4* src = (const float4*)(g_features_all + (long)b * 64 * 512);
    for (int i = tid; i < 64 * 128; i += 512) ((float4*)fs)[i] = src[i];
    __syncthreads();

    for (int t = 0; t < Tn - 1; t++) {
        if (wid == 0) {
            const float* sc = g_scores + ((long)b * (Tn - 1) + t) * 64;
            float s0 = sc[lane], s1 = sc[lane + 32];
            float m = fmaxf(s0, s1);
            #pragma unroll
            for (int o = 16; o; o >>= 1) m = fmaxf(m, __shfl_xor_sync(0xffffffffu, m, o));
            float e0 = __expf(s0 - m), e1 = __expf(s1 - m);
            float sum = e0 + e1;
            #pragma unroll
            for (int o = 16; o; o >>= 1) sum += __shfl_xor_sync(0xffffffffu, sum, o);
            float inv = 1.f / sum;
            sout[lane] = e0 * inv; sout[lane + 32] = e1 * inv;
        }
        __syncthreads();
        float acc = 0.f;
        #pragma unroll 8
        for (int n = 0; n < 64; n++) acc += sout[n] * fs[n * 512 + tid];
        g_x16[((long)b * Tn + (t + 1)) * 1024 + tid] = __float2half_rn(acc);
        __syncthreads();
    }
}

// ===================== launch =====================
static inline dim3 tgrid64(int M, int N) { return dim3((N + 127) / 128, (M + 63) / 64); }

extern "C" void kernel_launch(void* const* d_in, const int* in_sizes, int n_in,
                              void* d_out, int out_size)
{
    const float* feature_0 = (const float*)d_in[0];
    const float* features  = (const float*)d_in[1];
    const float* eng       = (const float*)d_in[2];
    const int*   captions  = (const int*)  d_in[3];
    const int*   lengths   = (const int*)  d_in[4];
    const float* embed_w   = (const float*)d_in[5];
    const float* w_ih      = (const float*)d_in[6];
    const float* w_hh      = (const float*)d_in[7];
    const float* b_ih      = (const float*)d_in[8];
    const float* b_hh      = (const float*)d_in[9];
    const float* fc_w      = (const float*)d_in[10];
    const float* fc_b      = (const float*)d_in[11];
    const float* att_vw_w  = (const float*)d_in[12];
    const float* att_hw_w  = (const float*)d_in[13];
    const float* att_bias  = (const float*)d_in[14];
    const float* att_w_w   = (const float*)d_in[15];
    const float* att_fc_w  = (const float*)d_in[16];
    const float* att_fc_b  = (const float*)d_in[17];
    const float* img_w     = (const float*)d_in[18];
    const float* img_b     = (const float*)d_in[19];
    float* out = (float*)d_out;

    static bool smem_set = false;
    if (!smem_set) {
        cudaFuncSetAttribute(mma_gemm1,   cudaFuncAttributeMaxDynamicSharedMemorySize, S1_SMEM);
        cudaFuncSetAttribute(mma_gemm_fc, cudaFuncAttributeMaxDynamicSharedMemorySize, S1_SMEM);
        cudaFuncSetAttribute(k_lstm_all,  cudaFuncAttributeMaxDynamicSharedMemorySize, LP_SMEM);
        cudaFuncSetAttribute(k_att_ctx,   cudaFuncAttributeMaxDynamicSharedMemorySize, CTX_SMEM);
        smem_set = true;
    }

    float* p_fv = nullptr;    cudaGetSymbolAddress((void**)&p_fv,    g_fv);
    float* p_ah = nullptr;    cudaGetSymbolAddress((void**)&p_ah,    g_att_h);
    float* p_xg = nullptr;    cudaGetSymbolAddress((void**)&p_xg,    g_xg);
    float* p_bias2 = nullptr; cudaGetSymbolAddress((void**)&p_bias2, g_bias2);
    float* p_afea = nullptr;  cudaGetSymbolAddress((void**)&p_afea,  g_att_fea);
    #define HSYM(p, s) __half* p = nullptr; cudaGetSymbolAddress((void**)&p, s)
    HSYM(p_fT, g_fT);
    HSYM(p_fall16, g_fall16);
    HSYM(p_we16, g_we16);
    HSYM(p_x16, g_x16);
    HSYM(p_hs_h, g_hs_h);
    HSYM(p_wfc1, g_wfc1);     HSYM(p_wvw, g_wvw);
    HSYM(p_whw, g_whw);       HSYM(p_wih, g_wih);
    HSYM(p_wfc, g_wfc);       HSYM(p_whh, g_whh);
    #undef HSYM

    // launches 1-3: deps of the att_fc GEMM; #4 = mma_gemm1 (ncu profile slot)
    k_cvt16<<<(512 * 512 / 4 + 255) / 256, 256>>>(att_fc_w, p_wfc1, 512 * 512 / 4);
    k_transpose_f<<<Bn * 49, 512>>>(features);
    k_bias2<<<(4 * Hn + 255) / 256, 256>>>(b_ih, b_hh);

    // #4: att_fc: fv = fT @ att_fc_w.T + b   (6272 x 512 x 512, single product)
    mma_gemm1<<<tgrid64(Bn * 49, 512), 256, S1_SMEM>>>(p_fT, p_wfc1,
        p_fv, 512, att_fc_b, 512, 512);

    // remaining conversions + prep
    k_embed<<<Bn * Tn, 512>>>(captions, embed_w);
    k_cvt16<<<(512 * 512 / 4 + 255) / 256, 256>>>(att_vw_w, p_wvw, 512 * 512 / 4);
    k_cvt16<<<(512 * 512 / 4 + 255) / 256, 256>>>(att_hw_w, p_whw, 512 * 512 / 4);
    k_cvt16<<<(2048 * 1024 / 4 + 255) / 256, 256>>>(w_ih, p_wih, 2048 * 1024 / 4);
    k_cvt16<<<(Vn * 512 / 4 + 255) / 256, 256>>>(fc_w, p_wfc, Vn * 512 / 4);
    k_cvt16<<<(2048 * 512 / 4 + 255) / 256, 256>>>(w_hh, p_whh, 2048 * 512 / 4);
    k_normalize<<<Bn * 49, 256>>>();
    k_copy_eng<<<Bn * 15, 512>>>(eng);
    k_rowmap<<<1, 256>>>(lengths);
    k_zero_masked<<<Bn * Tn, 256>>>(lengths, out);

    // img (split-K fp32): feature_0 @ img_w.T -> g_x16 rows t=0
    sgemm_splitk<<<dim3(8, 2, 8), 256>>>(feature_0, img_w);
    k_img_reduce<<<Bn, 512>>>(img_b);

    // att_fea = features_all @ att_vw_w.T   (8192 x 512 x 512, single product)
    mma_gemm1<<<tgrid64(Bn * 64, 512), 256, S1_SMEM>>>(p_fall16, p_wvw,
        p_afea, 512, nullptr, 512, 512);

    // att_h = we @ att_hw_w.T   (2560 x 512 x 512, single product)
    mma_gemm1<<<tgrid64(Bn * Tn, 512), 256, S1_SMEM>>>(p_we16, p_whw,
        p_ah, 512, nullptr, 512, 512);

    // attention: scores then softmax+context -> g_x16 rows t=1..19
    k_att_scores<<<dim3(8, Bn), 256>>>(att_bias, att_w_w);
    k_att_ctx<<<Bn, 512, CTX_SMEM>>>();

    // xg = [feas|we] @ w_ih.T + (b_ih+b_hh)   (2560 x 2048 x 1024, single product)
    mma_gemm1<<<tgrid64(Bn * Tn, 4 * Hn), 256, S1_SMEM>>>(p_x16, p_wih,
        p_xg, 4 * Hn, p_bias2, 4 * Hn, 1024);

    // LSTM: step 0 pointwise (+barrier reset), steps 1..19 persistent (2-product)
    k_lstm_t0<<<(Bn * Hn + 255) / 256, 256>>>();
    k_lstm_all<<<32, 256, LP_SMEM>>>();

    // logits (compacted rows; masked rows pre-zeroed)
    mma_gemm_fc<<<tgrid64(Bn * Tn, Vn), 256, S1_SMEM>>>(p_hs_h, p_wfc,
        out, Vn, fc_b, Vn, 512);
}

// round 13
// speedup vs baseline: 7.9640x; 1.0488x over previous
#include <cuda_runtime.h>
#include <cuda_fp16.h>
#include <cstdint>
#include <math.h>

// Problem dims
#define Bn   128
#define Tn   20
#define Vn   12000
#define En   512
#define Hn   512
#define VISn 512

// ===================== PTX helpers (sm_100 baseline) =====================
__device__ __forceinline__ uint32_t smem_u32(const void* p) {
    uint32_t a;
    asm("{ .reg .u64 t; cvta.to.shared.u64 t, %1; cvt.u32.u64 %0, t; }" : "=r"(a) : "l"(p));
    return a;
}
#define CP_ASYNC16(dst, src) \
    asm volatile("cp.async.cg.shared.global [%0], [%1], 16;" :: "r"(dst), "l"(src) : "memory")
#define CP_COMMIT() asm volatile("cp.async.commit_group;" ::: "memory")
#define CP_WAIT0()  asm volatile("cp.async.wait_group 0;" ::: "memory")
#define CP_WAIT2()  asm volatile("cp.async.wait_group 2;" ::: "memory")

__device__ __forceinline__ void ldsm4(uint32_t* r, uint32_t addr) {
    asm volatile("ldmatrix.sync.aligned.m8n8.x4.shared.b16 {%0,%1,%2,%3}, [%4];"
        : "=r"(r[0]), "=r"(r[1]), "=r"(r[2]), "=r"(r[3]) : "r"(addr));
}
__device__ __forceinline__ void mma16816(float* c, const uint32_t* a, const uint32_t* b) {
    asm volatile("mma.sync.aligned.m16n8k16.row.col.f32.f16.f16.f32 "
        "{%0,%1,%2,%3}, {%4,%5,%6,%7}, {%8,%9}, {%0,%1,%2,%3};"
        : "+f"(c[0]), "+f"(c[1]), "+f"(c[2]), "+f"(c[3])
        : "r"(a[0]), "r"(a[1]), "r"(a[2]), "r"(a[3]), "r"(b[0]), "r"(b[1]));
}

// ===================== scratch (device globals) =====================
__device__ float g_fv[Bn * 49 * VISn];
__device__ float g_features_all[Bn * 64 * VISn];
__device__ float g_att_fea[Bn * 64 * VISn];
__device__ float g_att_h[Bn * Tn * VISn];
__device__ float g_scores[Bn * (Tn - 1) * 64];
__device__ float g_xg[Bn * Tn * 4 * Hn];
__device__ float g_c[Bn * Hn];
__device__ float g_bias2[4 * Hn];
__device__ float g_part[8 * Bn * VISn];
__device__ unsigned g_bar;
__device__ int g_rowmap[Bn * Tn];
__device__ int g_nkept;

// activations (single fp16, except hs which stays split for the recurrent path)
__device__ __half g_fT[Bn * 49 * VISn];
__device__ __half g_fall16[Bn * 64 * VISn];
__device__ __half g_we16[Bn * Tn * En];
__device__ __half g_x16[Bn * Tn * 1024];
__device__ __half g_hs_h[Bn * Tn * Hn], g_hs_l[Bn * Tn * Hn];
// weights: single fp16
__device__ __half g_wfc1[VISn * VISn];
__device__ __half g_wvw[VISn * VISn];
__device__ __half g_whw[VISn * En];
__device__ __half g_wih[4 * Hn * 1024];
__device__ __half g_wfc[Vn * Hn];
__device__ __half g_whh[4 * Hn * Hn];

__device__ __forceinline__ void split_write16(float v, __half* h, __half* l, long i) {
    __half hi = __float2half_rn(v);
    h[i] = hi;
    l[i] = __float2half_rn(v - __half2float(hi));
}

#define ROWB   80
#define ATILE  (64 * ROWB)           // 5120 B
#define BTILE  (128 * ROWB)          // 10240 B

// ===================== single-product GEMM: CTA 64x128, 3 CTAs/SM =====================
#define S1_STAGE (ATILE + BTILE)         // 15360
#define S1_NSTG  4
#define S1_SMEM  (S1_NSTG * S1_STAGE)    // 61440

__global__ __launch_bounds__(256, 3)
void mma_gemm1(const __half* __restrict__ Ah, const __half* __restrict__ Bw,
               float* __restrict__ C, int ldc, const float* __restrict__ bias,
               int N, int K)
{
    extern __shared__ __align__(16) char smem[];
    const uint32_t sbase = smem_u32(smem);

    const int tid = threadIdx.x, wid = tid >> 5, lane = tid & 31;
    const int m0 = blockIdx.y * 64, n0 = blockIdx.x * 128;
    const int wm = wid & 1, wn = wid >> 1;

    const int NC = K >> 5;

    auto issue = [&](int c) {
        if (c < NC) {
            const long kc = (long)c * 32;
            const uint32_t sb = sbase + (c & (S1_NSTG - 1)) * S1_STAGE;
            {
                int row = tid >> 2, kq = tid & 3;
                CP_ASYNC16(sb + row * ROWB + kq * 16,
                           Ah + (long)(m0 + row) * K + kc + kq * 8);
            }
            #pragma unroll
            for (int i = 0; i < 2; i++) {
                int ch = tid + i * 256;
                int row = ch >> 2, kq = ch & 3;
                int gr = n0 + row;
                if (gr >= N) gr = N - 1;
                CP_ASYNC16(sb + ATILE + row * ROWB + kq * 16,
                           Bw + (long)gr * K + kc + kq * 8);
            }
        }
        CP_COMMIT();
    };

    float acc[2][4][4];
    #pragma unroll
    for (int mi = 0; mi < 2; mi++)
        #pragma unroll
        for (int ni = 0; ni < 4; ni++)
            #pragma unroll
            for (int q = 0; q < 4; q++) acc[mi][ni][q] = 0.f;

    const uint32_t a_off = (uint32_t)((wm * 32 + (lane & 15)) * ROWB + (lane >> 4) * 16);
    const uint32_t b_off = (uint32_t)((wn * 32 + ((lane >> 4) & 1) * 8 + (lane & 7)) * ROWB
                                      + ((lane >> 3) & 1) * 16);

    issue(0); issue(1); issue(2);

    for (int c = 0; c < NC; c++) {
        CP_WAIT2();
        __syncthreads();
        issue(c + 3);

        const uint32_t tb = sbase + (c & (S1_NSTG - 1)) * S1_STAGE;
        #pragma unroll
        for (int kk = 0; kk < 2; kk++) {
            const uint32_t kba = kk * 32;
            uint32_t ah[2][4], bb[4][2];
            #pragma unroll
            for (int mi = 0; mi < 2; mi++)
                ldsm4(ah[mi], tb + a_off + mi * 16 * ROWB + kba);
            #pragma unroll
            for (int nip = 0; nip < 2; nip++) {
                uint32_t t4[4];
                ldsm4(t4, tb + ATILE + b_off + nip * 16 * ROWB + kba);
                bb[2*nip][0] = t4[0]; bb[2*nip][1] = t4[1];
                bb[2*nip+1][0] = t4[2]; bb[2*nip+1][1] = t4[3];
            }
            #pragma unroll
            for (int mi = 0; mi < 2; mi++)
                #pragma unroll
                for (int ni = 0; ni < 4; ni++)
                    mma16816(acc[mi][ni], ah[mi], bb[ni]);
        }
    }

    #pragma unroll
    for (int mi = 0; mi < 2; mi++) {
        const int r0 = m0 + wm * 32 + mi * 16 + (lane >> 2);
        const int r1 = r0 + 8;
        #pragma unroll
        for (int ni = 0; ni < 4; ni++) {
            const int col = n0 + wn * 32 + ni * 8 + (lane & 3) * 2;
            if (col >= N) continue;
            float b0 = 0.f, b1 = 0.f;
            if (bias) { b0 = bias[col]; b1 = bias[col + 1]; }
            *(float2*)(C + (long)r0 * ldc + col) = make_float2(acc[mi][ni][0] + b0, acc[mi][ni][1] + b1);
            *(float2*)(C + (long)r1 * ldc + col) = make_float2(acc[mi][ni][2] + b0, acc[mi][ni][3] + b1);
        }
    }
}

// ===================== compacted single-product GEMM for fc =====================
__global__ __launch_bounds__(256, 3)
void mma_gemm_fc(const __half* __restrict__ Ah, const __half* __restrict__ Bw,
                 float* __restrict__ C, int ldc, const float* __restrict__ bias,
                 int N, int K)
{
    extern __shared__ __align__(16) char smem[];
    __shared__ int rm[64];
    const uint32_t sbase = smem_u32(smem);

    const int tid = threadIdx.x, wid = tid >> 5, lane = tid & 31;
    const int m0 = blockIdx.y * 64, n0 = blockIdx.x * 128;
    const int wm = wid & 1, wn = wid >> 1;

    const int nkept = g_nkept;
    if (m0 >= nkept) return;

    if (tid < 64) {
        int r = m0 + tid;
        rm[tid] = g_rowmap[r < nkept ? r : (nkept - 1)];
    }
    __syncthreads();

    const int NC = K >> 5;

    auto issue = [&](int c) {
        if (c < NC) {
            const long kc = (long)c * 32;
            const uint32_t sb = sbase + (c & (S1_NSTG - 1)) * S1_STAGE;
            {
                int row = tid >> 2, kq = tid & 3;
                CP_ASYNC16(sb + row * ROWB + kq * 16,
                           Ah + (long)rm[row] * K + kc + kq * 8);
            }
            #pragma unroll
            for (int i = 0; i < 2; i++) {
                int ch = tid + i * 256;
                int row = ch >> 2, kq = ch & 3;
                int gr = n0 + row;
                if (gr >= N) gr = N - 1;
                CP_ASYNC16(sb + ATILE + row * ROWB + kq * 16,
                           Bw + (long)gr * K + kc + kq * 8);
            }
        }
        CP_COMMIT();
    };

    float acc[2][4][4];
    #pragma unroll
    for (int mi = 0; mi < 2; mi++)
        #pragma unroll
        for (int ni = 0; ni < 4; ni++)
            #pragma unroll
            for (int q = 0; q < 4; q++) acc[mi][ni][q] = 0.f;

    const uint32_t a_off = (uint32_t)((wm * 32 + (lane & 15)) * ROWB + (lane >> 4) * 16);
    const uint32_t b_off = (uint32_t)((wn * 32 + ((lane >> 4) & 1) * 8 + (lane & 7)) * ROWB
                                      + ((lane >> 3) & 1) * 16);

    issue(0); issue(1); issue(2);

    for (int c = 0; c < NC; c++) {
        CP_WAIT2();
        __syncthreads();
        issue(c + 3);

        const uint32_t tb = sbase + (c & (S1_NSTG - 1)) * S1_STAGE;
        #pragma unroll
        for (int kk = 0; kk < 2; kk++) {
            const uint32_t kba = kk * 32;
            uint32_t ah[2][4], bb[4][2];
            #pragma unroll
            for (int mi = 0; mi < 2; mi++)
                ldsm4(ah[mi], tb + a_off + mi * 16 * ROWB + kba);
            #pragma unroll
            for (int nip = 0; nip < 2; nip++) {
                uint32_t t4[4];
                ldsm4(t4, tb + ATILE + b_off + nip * 16 * ROWB + kba);
                bb[2*nip][0] = t4[0]; bb[2*nip][1] = t4[1];
                bb[2*nip+1][0] = t4[2]; bb[2*nip+1][1] = t4[3];
            }
            #pragma unroll
            for (int mi = 0; mi < 2; mi++)
                #pragma unroll
                for (int ni = 0; ni < 4; ni++)
                    mma16816(acc[mi][ni], ah[mi], bb[ni]);
        }
    }

    #pragma unroll
    for (int mi = 0; mi < 2; mi++) {
        const int l0 = wm * 32 + mi * 16 + (lane >> 2);
        const int l1 = l0 + 8;
        const bool v0r = (m0 + l0) < nkept;
        const bool v1r = (m0 + l1) < nkept;
        const long or0 = (long)rm[l0] * ldc;
        const long or1 = (long)rm[l1] * ldc;
        #pragma unroll
        for (int ni = 0; ni < 4; ni++) {
            const int col = n0 + wn * 32 + ni * 8 + (lane & 3) * 2;
            if (col >= N) continue;
            float b0 = bias[col], b1 = bias[col + 1];
            if (v0r) *(float2*)(C + or0 + col) = make_float2(acc[mi][ni][0] + b0, acc[mi][ni][1] + b1);
            if (v1r) *(float2*)(C + or1 + col) = make_float2(acc[mi][ni][2] + b0, acc[mi][ni][3] + b1);
        }
    }
}

// build rowmap of kept rows + count
__global__ void k_rowmap(const int* __restrict__ lengths)
{
    __shared__ int cnt[256];
    const int tid = threadIdx.x;
    const int base = tid * 10;
    int flags[10], c = 0;
    #pragma unroll
    for (int i = 0; i < 10; i++) {
        int r = base + i;
        flags[i] = (lengths[r / Tn] >= (r % Tn)) ? 1 : 0;
        c += flags[i];
    }
    cnt[tid] = c;
    __syncthreads();
    for (int off = 1; off < 256; off <<= 1) {
        int v = (tid >= off) ? cnt[tid - off] : 0;
        __syncthreads();
        cnt[tid] += v;
        __syncthreads();
    }
    int pos = cnt[tid] - c;
    #pragma unroll
    for (int i = 0; i < 10; i++) {
        if (flags[i]) g_rowmap[pos++] = base + i;
    }
    if (tid == 255) g_nkept = cnt[255];
}

__global__ void k_zero_masked(const int* __restrict__ lengths, float* __restrict__ out)
{
    const int r = blockIdx.x;
    if (lengths[r / Tn] >= (r % Tn)) return;
    float4* o = (float4*)(out + (long)r * Vn);
    for (int i = threadIdx.x; i < Vn / 4; i += blockDim.x)
        o[i] = make_float4(0.f, 0.f, 0.f, 0.f);
}

// ===================== persistent LSTM =====================
#define LB_ALL   (16 * 64 * ROWB)            // 81920
#define LA_STAGE (2 * BTILE)                 // 20480
#define LA_NSTG  4
#define LP_SMEM  (LB_ALL + LA_NSTG * LA_STAGE)   // 163840

__global__ __launch_bounds__(256, 1)
void k_lstm_all()
{
    extern __shared__ __align__(16) char smem[];
    const uint32_t sbase = smem_u32(smem);
    const int tid = threadIdx.x, wid = tid >> 5, lane = tid & 31;
    const int h0 = blockIdx.x * 16;
    const int wm = wid & 1, wn = wid >> 1;

    {
        int row = tid >> 2, kq = tid & 3;
        int j = (row >> 4) * 512 + h0 + (row & 15);
        const __half* base = g_whh + (long)j * Hn + kq * 8;
        #pragma unroll
        for (int c = 0; c < 16; c++)
            CP_ASYNC16(sbase + c * (64 * ROWB) + row * ROWB + kq * 16, base + c * 32);
        CP_COMMIT();
        CP_WAIT0();
    }
    __syncthreads();

    const uint32_t a_off = (uint32_t)((wm * 64 + (lane & 15)) * ROWB + (lane >> 4) * 16);
    const uint32_t b_off = (uint32_t)((wn * 16 + ((lane >> 4) & 1) * 8 + (lane & 7)) * ROWB
                                      + ((lane >> 3) & 1) * 16);
    const uint32_t aring = sbase + LB_ALL;

    for (int t = 1; t < Tn; t++) {
        auto issueA = [&](int c) {
            if (c < 16) {
                const long kc = (long)c * 32;
                const uint32_t sb = aring + (c & (LA_NSTG - 1)) * LA_STAGE;
                #pragma unroll
                for (int s = 0; s < 2; s++) {
                    const __half* S = s ? g_hs_l : g_hs_h;
                    #pragma unroll
                    for (int i = 0; i < 2; i++) {
                        int ch = tid + i * 256;
                        int row = ch >> 2, kq = ch & 3;
                        const __half* src = S + ((long)row * Tn + (t - 1)) * Hn + kc + kq * 8;
                        CP_ASYNC16(sb + s * BTILE + row * ROWB + kq * 16, src);
                    }
                }
            }
            CP_COMMIT();
        };

        float acc[4][2][4];
        #pragma unroll
        for (int mi = 0; mi < 4; mi++)
            #pragma unroll
            for (int ni = 0; ni < 2; ni++)
                #pragma unroll
                for (int q = 0; q < 4; q++) acc[mi][ni][q] = 0.f;

        issueA(0); issueA(1); issueA(2);

        for (int c = 0; c < 16; c++) {
            CP_WAIT2();
            __syncthreads();
            issueA(c + 3);

            const uint32_t ta = aring + (c & (LA_NSTG - 1)) * LA_STAGE;
            const uint32_t tbB = sbase + c * (64 * ROWB);
            #pragma unroll
            for (int kk = 0; kk < 2; kk++) {
                const uint32_t kba = kk * 32;
                uint32_t ah[4][4], al[4][4], bb[2][2];
                #pragma unroll
                for (int mi = 0; mi < 4; mi++) {
                    ldsm4(ah[mi], ta + 0 * BTILE + a_off + mi * 16 * ROWB + kba);
                    ldsm4(al[mi], ta + 1 * BTILE + a_off + mi * 16 * ROWB + kba);
                }
                {
                    uint32_t t4[4];
                    ldsm4(t4, tbB + b_off + kba);
                    bb[0][0] = t4[0]; bb[0][1] = t4[1]; bb[1][0] = t4[2]; bb[1][1] = t4[3];
                }
                #pragma unroll
                for (int mi = 0; mi < 4; mi++)
                    #pragma unroll
                    for (int ni = 0; ni < 2; ni++) {
                        mma16816(acc[mi][ni], ah[mi], bb[ni]);
                        mma16816(acc[mi][ni], al[mi], bb[ni]);
                    }
            }
        }

        __syncthreads();
        float* Gs = (float*)(smem + LB_ALL);
        #pragma unroll
        for (int mi = 0; mi < 4; mi++) {
            const int r0 = wm * 64 + mi * 16 + (lane >> 2);
            const int r1 = r0 + 8;
            #pragma unroll
            for (int ni = 0; ni < 2; ni++) {
                const int cl = wn * 16 + ni * 8 + (lane & 3) * 2;
                Gs[r0 * 68 + cl]     = acc[mi][ni][0];
                Gs[r0 * 68 + cl + 1] = acc[mi][ni][1];
                Gs[r1 * 68 + cl]     = acc[mi][ni][2];
                Gs[r1 * 68 + cl + 1] = acc[mi][ni][3];
            }
        }
        __syncthreads();

        for (int p = tid; p < 128 * 16; p += 256) {
            const int b = p >> 4, l = p & 15;
            const int hcol = h0 + l;
            const float* xg = g_xg + ((long)b * Tn + t) * 2048;
            float gi = Gs[b * 68 + 0 * 16 + l] + xg[0 * 512 + hcol];
            float gf = Gs[b * 68 + 1 * 16 + l] + xg[1 * 512 + hcol];
            float gg = Gs[b * 68 + 2 * 16 + l] + xg[2 * 512 + hcol];
            float go = Gs[b * 68 + 3 * 16 + l] + xg[3 * 512 + hcol];
            float co = g_c[b * 512 + hcol];
            float si = 1.f / (1.f + __expf(-gi));
            float sf = 1.f / (1.f + __expf(-gf));
            float so = 1.f / (1.f + __expf(-go));
            float cn = sf * co + si * tanhf(gg);
            float hn = so * tanhf(cn);
            g_c[b * 512 + hcol] = cn;
            split_write16(hn, g_hs_h, g_hs_l, ((long)b * Tn + t) * 512 + hcol);
        }

        __syncthreads();
        if (tid == 0) {
            __threadfence();
            atomicAdd(&g_bar, 1u);
            while (*(volatile unsigned*)&g_bar < 32u * (unsigned)t) { }
            __threadfence();
        }
        __syncthreads();
    }
}

__global__ void k_lstm_t0()
{
    int i = blockIdx.x * blockDim.x + threadIdx.x;
    if (i == 0) g_bar = 0u;
    if (i >= Bn * Hn) return;
    int b = i >> 9, hcol = i & 511;
    const float* xg = g_xg + ((long)b * Tn) * 2048;
    float gi = xg[hcol], gg = xg[1024 + hcol], go = xg[1536 + hcol];
    float si = 1.f / (1.f + __expf(-gi));
    float so = 1.f / (1.f + __expf(-go));
    float cn = si * tanhf(gg);
    float hn = so * tanhf(cn);
    g_c[i] = cn;
    split_write16(hn, g_hs_h, g_hs_l, ((long)b * Tn) * 512 + hcol);
}

// ===================== split-K fp32 GEMM for img =====================
__global__ __launch_bounds__(256)
void sgemm_splitk(const float* __restrict__ A, const float* __restrict__ Bw)
{
    __shared__ float As[16][64];
    __shared__ float Bs[16][64];
    const int tid = threadIdx.x;
    const int tx = tid & 15, ty = tid >> 4;
    const int n0 = blockIdx.x * 64, m0 = blockIdx.y * 64;
    const int kbase = blockIdx.z * 256;
    const int lr = tid >> 2, lk = (tid & 3) * 4;
    const float* Ap = A  + (long)(m0 + lr) * 2048 + kbase + lk;
    const float* Bp = Bw + (long)(n0 + lr) * 2048 + kbase + lk;

    float acc[4][4] = {};
    for (int k0 = 0; k0 < 256; k0 += 16) {
        float4 avv = *(const float4*)(Ap + k0);
        float4 bvv = *(const float4*)(Bp + k0);
        __syncthreads();
        As[lk+0][lr] = avv.x; As[lk+1][lr] = avv.y; As[lk+2][lr] = avv.z; As[lk+3][lr] = avv.w;
        Bs[lk+0][lr] = bvv.x; Bs[lk+1][lr] = bvv.y; Bs[lk+2][lr] = bvv.z; Bs[lk+3][lr] = bvv.w;
        __syncthreads();
        #pragma unroll
        for (int kk = 0; kk < 16; kk++) {
            float a[4], b[4];
            #pragma unroll
            for (int i = 0; i < 4; i++) a[i] = As[kk][ty * 4 + i];
            #pragma unroll
            for (int j = 0; j < 4; j++) b[j] = Bs[kk][tx * 4 + j];
            #pragma unroll
            for (int i = 0; i < 4; i++)
                #pragma unroll
                for (int j = 0; j < 4; j++) acc[i][j] += a[i] * b[j];
        }
    }
    float* Cp = g_part + (long)blockIdx.z * Bn * VISn;
    #pragma unroll
    for (int i = 0; i < 4; i++)
        #pragma unroll
        for (int j = 0; j < 4; j++)
            Cp[(long)(m0 + ty * 4 + i) * VISn + n0 + tx * 4 + j] = acc[i][j];
}

__global__ void k_img_reduce(const float* __restrict__ img_b) {
    int b = blockIdx.x, v = threadIdx.x;
    float s = img_b[v];
    #pragma unroll
    for (int k = 0; k < 8; k++) s += g_part[((long)k * Bn + b) * VISn + v];
    g_x16[(long)(b * Tn) * 1024 + v] = __float2half_rn(s);
}

// ===================== prep kernels =====================
__global__ void k_bias2(const float* __restrict__ b_ih, const float* __restrict__ b_hh) {
    int i = blockIdx.x * blockDim.x + threadIdx.x;
    if (i < 4 * Hn) g_bias2[i] = b_ih[i] + b_hh[i];
}
__global__ void k_cvt16(const float* __restrict__ x, __half* __restrict__ h, int n4) {
    int i = blockIdx.x * blockDim.x + threadIdx.x;
    if (i >= n4) return;
    float4 v = ((const float4*)x)[i];
    __half2 a = __floats2half2_rn(v.x, v.y);
    __half2 b = __floats2half2_rn(v.z, v.w);
    ((uint2*)h)[i] = make_uint2(*(uint32_t*)&a, *(uint32_t*)&b);
}
__global__ void k_transpose_f(const float* __restrict__ features) {
    int bp = blockIdx.x;
    int b = bp / 49, p = bp % 49;
    int v = threadIdx.x;
    g_fT[(long)bp * 512 + v] =
        __float2half_rn(features[((long)b * 512 + v) * 49 + p]);
}
__global__ void k_normalize() {
    int row = blockIdx.x;
    int b = row / 49, p = row % 49;
    const float* x = g_fv + (long)row * 512;
    __shared__ float red[8];
    int tid = threadIdx.x, lane = tid & 31, wid = tid >> 5;
    float s = 0.f;
    for (int v = tid; v < 512; v += 256) { float t = x[v]; s += t * t; }
    #pragma unroll
    for (int o = 16; o; o >>= 1) s += __shfl_xor_sync(0xffffffffu, s, o);
    if (lane == 0) red[wid] = s;
    __syncthreads();
    if (tid == 0) {
        float sum = 0.f;
        #pragma unroll
        for (int w = 0; w < 8; w++) sum += red[w];
        red[0] = 1.f / fmaxf(sqrtf(sum), 1e-12f);
    }
    __syncthreads();
    float inv = red[0];
    long o = ((long)b * 64 + p) * 512;
    for (int v = tid; v < 512; v += 256) {
        float val = x[v] * inv;
        g_features_all[o + v] = val;
        g_fall16[o + v] = __float2half_rn(val);
    }
}
__global__ void k_copy_eng(const float* __restrict__ eng) {
    int bj = blockIdx.x;
    int b = bj / 15, j = bj % 15;
    int v = threadIdx.x;
    float val = eng[(long)bj * 512 + v];
    long o = ((long)b * 64 + 49 + j) * 512 + v;
    g_features_all[o] = val;
    g_fall16[o] = __float2half_rn(val);
}
__global__ void k_embed(const int* __restrict__ captions, const float* __restrict__ embed_w) {
    int r = blockIdx.x;
    int idx = captions[r];
    float v = embed_w[(long)idx * 512 + threadIdx.x];
    __half hv = __float2half_rn(v);
    g_we16[(long)r * 512 + threadIdx.x] = hv;
    g_x16[(long)r * 1024 + 512 + threadIdx.x] = hv;
}

// ===================== attention: scores =====================
__global__ __launch_bounds__(256)
void k_att_scores(const float* __restrict__ att_bias, const float* __restrict__ att_w) {
    const int n0 = blockIdx.x * 8, b = blockIdx.y;
    __shared__ float fea8[8][512];
    __shared__ float ws[512];
    __shared__ float hh[512];
    const int tid = threadIdx.x, lane = tid & 31, wid = tid >> 5;

    for (int v = tid; v < 512; v += 256) ws[v] = att_w[v];
    const float4* fea = (const float4*)(g_att_fea + ((long)b * 64 + n0) * 512);
    for (int i = tid; i < 8 * 128; i += 256)
        ((float4*)&fea8[0][0])[i] = fea[i];
    const float bn = att_bias[n0 + wid];

    for (int t = 0; t < Tn - 1; t++) {
        __syncthreads();
        for (int v = tid; v < 512; v += 256) hh[v] = g_att_h[((long)b * Tn + t) * 512 + v];
        __syncthreads();
        float s = 0.f;
        #pragma unroll 4
        for (int v = lane; v < 512; v += 32)
            s += fmaxf(fea8[wid][v] + hh[v] + bn, 0.f) * ws[v];
        #pragma unroll
        for (int o = 16; o; o >>= 1) s += __shfl_xor_sync(0xffffffffu, s, o);
        if (lane == 0) g_scores[((long)b * (Tn - 1) + t) * 64 + n0 + wid] = s;
    }
}

// ===================== attention: softmax + context =====================
#define CTX_SMEM (64 * 512 * 4 + 256)
__global__ __launch_bounds__(512)
void k_att_ctx() {
    extern __shared__ float fs[];
    float* sout = fs + 64 * 512;
    const int b = blockIdx.x, tid = threadIdx.x, lane = tid & 31, wid = tid >> 5;

    const float4* src = (const float4*)(g_features_all + (long)b * 64 * 512);
    for (int i = tid; i < 64 * 128; i += 512) ((float4*)fs)[i] = src[i];
    __syncthreads();

    for (int t = 0; t < Tn - 1; t++) {
        if (wid == 0) {
            const float* sc = g_scores + ((long)b * (Tn - 1) + t) * 64;
            float s0 = sc[lane], s1 = sc[lane + 32];
            float m = fmaxf(s0, s1);
            #pragma unroll
            for (int o = 16; o; o >>= 1) m = fmaxf(m, __shfl_xor_sync(0xffffffffu, m, o));
            float e0 = __expf(s0 - m), e1 = __expf(s1 - m);
            float sum = e0 + e1;
            #pragma unroll
            for (int o = 16; o; o >>= 1) sum += __shfl_xor_sync(0xffffffffu, sum, o);
            float inv = 1.f / sum;
            sout[lane] = e0 * inv; sout[lane + 32] = e1 * inv;
        }
        __syncthreads();
        float acc = 0.f;
        #pragma unroll 8
        for (int n = 0; n < 64; n++) acc += sout[n] * fs[n * 512 + tid];
        g_x16[((long)b * Tn + (t + 1)) * 1024 + tid] = __float2half_rn(acc);
        __syncthreads();
    }
}

// ===================== launch =====================
static inline dim3 tgrid64(int M, int N) { return dim3((N + 127) / 128, (M + 63) / 64); }

extern "C" void kernel_launch(void* const* d_in, const int* in_sizes, int n_in,
                              void* d_out, int out_size)
{
    const float* feature_0 = (const float*)d_in[0];
    const float* features  = (const float*)d_in[1];
    const float* eng       = (const float*)d_in[2];
    const int*   captions  = (const int*)  d_in[3];
    const int*   lengths   = (const int*)  d_in[4];
    const float* embed_w   = (const float*)d_in[5];
    const float* w_ih      = (const float*)d_in[6];
    const float* w_hh      = (const float*)d_in[7];
    const float* b_ih      = (const float*)d_in[8];
    const float* b_hh      = (const float*)d_in[9];
    const float* fc_w      = (const float*)d_in[10];
    const float* fc_b      = (const float*)d_in[11];
    const float* att_vw_w  = (const float*)d_in[12];
    const float* att_hw_w  = (const float*)d_in[13];
    const float* att_bias  = (const float*)d_in[14];
    const float* att_w_w   = (const float*)d_in[15];
    const float* att_fc_w  = (const float*)d_in[16];
    const float* att_fc_b  = (const float*)d_in[17];
    const float* img_w     = (const float*)d_in[18];
    const float* img_b     = (const float*)d_in[19];
    float* out = (float*)d_out;

    static bool init_done = false;
    static cudaStream_t s1;
    static cudaEvent_t ev0, ev1, ev3, evEnd;
    if (!init_done) {
        cudaFuncSetAttribute(mma_gemm1,   cudaFuncAttributeMaxDynamicSharedMemorySize, S1_SMEM);
        cudaFuncSetAttribute(mma_gemm_fc, cudaFuncAttributeMaxDynamicSharedMemorySize, S1_SMEM);
        cudaFuncSetAttribute(k_lstm_all,  cudaFuncAttributeMaxDynamicSharedMemorySize, LP_SMEM);
        cudaFuncSetAttribute(k_att_ctx,   cudaFuncAttributeMaxDynamicSharedMemorySize, CTX_SMEM);
        cudaStreamCreateWithFlags(&s1, cudaStreamNonBlocking);
        cudaEventCreateWithFlags(&ev0,   cudaEventDisableTiming);
        cudaEventCreateWithFlags(&ev1,   cudaEventDisableTiming);
        cudaEventCreateWithFlags(&ev3,   cudaEventDisableTiming);
        cudaEventCreateWithFlags(&evEnd, cudaEventDisableTiming);
        init_done = true;
    }

    float* p_fv = nullptr;    cudaGetSymbolAddress((void**)&p_fv,    g_fv);
    float* p_ah = nullptr;    cudaGetSymbolAddress((void**)&p_ah,    g_att_h);
    float* p_xg = nullptr;    cudaGetSymbolAddress((void**)&p_xg,    g_xg);
    float* p_bias2 = nullptr; cudaGetSymbolAddress((void**)&p_bias2, g_bias2);
    float* p_afea = nullptr;  cudaGetSymbolAddress((void**)&p_afea,  g_att_fea);
    #define HSYM(p, s) __half* p = nullptr; cudaGetSymbolAddress((void**)&p, s)
    HSYM(p_fT, g_fT);
    HSYM(p_fall16, g_fall16);
    HSYM(p_we16, g_we16);
    HSYM(p_x16, g_x16);
    HSYM(p_hs_h, g_hs_h);
    HSYM(p_wfc1, g_wfc1);     HSYM(p_wvw, g_wvw);
    HSYM(p_whw, g_whw);       HSYM(p_wih, g_wih);
    HSYM(p_wfc, g_wfc);       HSYM(p_whh, g_whh);
    #undef HSYM

    // ---- fork: side stream s1 handles all off-critical-path work ----
    cudaEventRecord(ev0, 0);
    cudaStreamWaitEvent(s1, ev0, 0);

    // side stream: early deps for att_fea/scores
    k_cvt16<<<(512 * 512 / 4 + 255) / 256, 256, 0, s1>>>(att_vw_w, p_wvw, 512 * 512 / 4);
    k_copy_eng<<<Bn * 15, 512, 0, s1>>>(eng);
    k_embed<<<Bn * Tn, 512, 0, s1>>>(captions, embed_w);
    k_cvt16<<<(512 * 512 / 4 + 255) / 256, 256, 0, s1>>>(att_hw_w, p_whw, 512 * 512 / 4);
    mma_gemm1<<<tgrid64(Bn * Tn, 512), 256, S1_SMEM, s1>>>(p_we16, p_whw,
        p_ah, 512, nullptr, 512, 512);                       // att_h
    cudaEventRecord(ev1, s1);

    // side stream: deps for xg / LSTM
    k_cvt16<<<(2048 * 1024 / 4 + 255) / 256, 256, 0, s1>>>(w_ih, p_wih, 2048 * 1024 / 4);
    sgemm_splitk<<<dim3(8, 2, 8), 256, 0, s1>>>(feature_0, img_w);
    k_img_reduce<<<Bn, 512, 0, s1>>>(img_b);
    k_bias2<<<(4 * Hn + 255) / 256, 256, 0, s1>>>(b_ih, b_hh);
    k_cvt16<<<(2048 * 512 / 4 + 255) / 256, 256, 0, s1>>>(w_hh, p_whh, 2048 * 512 / 4);
    cudaEventRecord(ev3, s1);

    // side stream: deps for fc
    k_cvt16<<<(Vn * 512 / 4 + 255) / 256, 256, 0, s1>>>(fc_w, p_wfc, Vn * 512 / 4);
    k_rowmap<<<1, 256, 0, s1>>>(lengths);
    k_zero_masked<<<Bn * Tn, 256, 0, s1>>>(lengths, out);
    cudaEventRecord(evEnd, s1);

    // ---- main stream: critical chain ----
    k_cvt16<<<(512 * 512 / 4 + 255) / 256, 256>>>(att_fc_w, p_wfc1, 512 * 512 / 4);
    k_transpose_f<<<Bn * 49, 512>>>(features);

    // att_fc: fv = fT @ att_fc_w.T + b
    mma_gemm1<<<tgrid64(Bn * 49, 512), 256, S1_SMEM>>>(p_fT, p_wfc1,
        p_fv, 512, att_fc_b, 512, 512);
    k_normalize<<<Bn * 49, 256>>>();

    cudaStreamWaitEvent(0, ev1, 0);   // wvw, copy_eng, att_h ready

    // att_fea = features_all @ att_vw_w.T
    mma_gemm1<<<tgrid64(Bn * 64, 512), 256, S1_SMEM>>>(p_fall16, p_wvw,
        p_afea, 512, nullptr, 512, 512);

    // attention: scores then softmax+context -> g_x16 rows t=1..19
    k_att_scores<<<dim3(8, Bn), 256>>>(att_bias, att_w_w);
    k_att_ctx<<<Bn, 512, CTX_SMEM>>>();

    cudaStreamWaitEvent(0, ev3, 0);   // wih, img, bias2, whh ready

    // xg = [feas|we] @ w_ih.T + (b_ih+b_hh)
    mma_gemm1<<<tgrid64(Bn * Tn, 4 * Hn), 256, S1_SMEM>>>(p_x16, p_wih,
        p_xg, 4 * Hn, p_bias2, 4 * Hn, 1024);

    // LSTM
    k_lstm_t0<<<(Bn * Hn + 255) / 256, 256>>>();
    k_lstm_all<<<32, 256, LP_SMEM>>>();

    cudaStreamWaitEvent(0, evEnd, 0); // wfc, rowmap, zero_masked done (join side branch)

    // logits (compacted rows; masked rows pre-zeroed)
    mma_gemm_fc<<<tgrid64(Bn * Tn, Vn), 256, S1_SMEM>>>(p_hs_h, p_wfc,
        out, Vn, fc_b, Vn, 512);
}

// round 14
// speedup vs baseline: 7.9881x; 1.0030x over previous
#include <cuda_runtime.h>
#include <cuda_fp16.h>
#include <cstdint>
#include <math.h>

// Problem dims
#define Bn   128
#define Tn   20
#define Vn   12000
#define En   512
#define Hn   512
#define VISn 512

// ===================== PTX helpers (sm_100 baseline) =====================
__device__ __forceinline__ uint32_t smem_u32(const void* p) {
    uint32_t a;
    asm("{ .reg .u64 t; cvta.to.shared.u64 t, %1; cvt.u32.u64 %0, t; }" : "=r"(a) : "l"(p));
    return a;
}
#define CP_ASYNC16(dst, src) \
    asm volatile("cp.async.cg.shared.global [%0], [%1], 16;" :: "r"(dst), "l"(src) : "memory")
#define CP_COMMIT() asm volatile("cp.async.commit_group;" ::: "memory")
#define CP_WAIT0()  asm volatile("cp.async.wait_group 0;" ::: "memory")
#define CP_WAIT2()  asm volatile("cp.async.wait_group 2;" ::: "memory")

__device__ __forceinline__ void ldsm4(uint32_t* r, uint32_t addr) {
    asm volatile("ldmatrix.sync.aligned.m8n8.x4.shared.b16 {%0,%1,%2,%3}, [%4];"
        : "=r"(r[0]), "=r"(r[1]), "=r"(r[2]), "=r"(r[3]) : "r"(addr));
}
__device__ __forceinline__ void mma16816(float* c, const uint32_t* a, const uint32_t* b) {
    asm volatile("mma.sync.aligned.m16n8k16.row.col.f32.f16.f16.f32 "
        "{%0,%1,%2,%3}, {%4,%5,%6,%7}, {%8,%9}, {%0,%1,%2,%3};"
        : "+f"(c[0]), "+f"(c[1]), "+f"(c[2]), "+f"(c[3])
        : "r"(a[0]), "r"(a[1]), "r"(a[2]), "r"(a[3]), "r"(b[0]), "r"(b[1]));
}

// ===================== scratch (device globals) =====================
__device__ float g_fv[Bn * 49 * VISn];
__device__ float g_features_all[Bn * 64 * VISn];
__device__ float g_att_fea[Bn * 64 * VISn];
__device__ float g_att_h[Bn * Tn * VISn];
__device__ float g_scores[Bn * (Tn - 1) * 64];
__device__ float g_xg[Bn * Tn * 4 * Hn];
__device__ float g_c[Bn * Hn];
__device__ float g_bias2[4 * Hn];
__device__ float g_part[8 * Bn * VISn];
__device__ unsigned g_bar;
__device__ int g_rowmap[Bn * Tn];
__device__ int g_nkept;

// activations (single fp16, except hs which stays split for the recurrent path)
__device__ __half g_fT[Bn * 49 * VISn];
__device__ __half g_fall16[Bn * 64 * VISn];
__device__ __half g_we16[Bn * Tn * En];
__device__ __half g_x16[Bn * Tn * 1024];
__device__ __half g_hs_h[Bn * Tn * Hn], g_hs_l[Bn * Tn * Hn];
// weights: single fp16
__device__ __half g_wfc1[VISn * VISn];
__device__ __half g_wvw[VISn * VISn];
__device__ __half g_whw[VISn * En];
__device__ __half g_wih[4 * Hn * 1024];
__device__ __half g_wfc[Vn * Hn];
__device__ __half g_whh[4 * Hn * Hn];

__device__ __forceinline__ void split_write16(float v, __half* h, __half* l, long i) {
    __half hi = __float2half_rn(v);
    h[i] = hi;
    l[i] = __float2half_rn(v - __half2float(hi));
}

#define ROWB   80
#define ATILE  (64 * ROWB)           // 5120 B  (64-row A tile)
#define BTILE  (128 * ROWB)          // 10240 B (128-row tile, LSTM use)
#define B2TILE (256 * ROWB)          // 20480 B (256-row B tile)

// ===================== single-product GEMM: CTA 64x256, 2 CTAs/SM =====================
// C[M,N] = A[M,K] @ B[N,K]^T (+bias). M multiple of 64. Warp tile 32x64.
#define S2_STAGE (ATILE + B2TILE)        // 25600
#define S2_NSTG  4
#define S2_SMEM  (S2_NSTG * S2_STAGE)    // 102400

__global__ __launch_bounds__(256, 2)
void mma_gemm1(const __half* __restrict__ Ah, const __half* __restrict__ Bw,
               float* __restrict__ C, int ldc, const float* __restrict__ bias,
               int N, int K)
{
    extern __shared__ __align__(16) char smem[];
    const uint32_t sbase = smem_u32(smem);

    const int tid = threadIdx.x, wid = tid >> 5, lane = tid & 31;
    const int m0 = blockIdx.y * 64, n0 = blockIdx.x * 256;
    const int wm = wid & 1, wn = wid >> 1;

    const int NC = K >> 5;

    auto issue = [&](int c) {
        if (c < NC) {
            const long kc = (long)c * 32;
            const uint32_t sb = sbase + (c & (S2_NSTG - 1)) * S2_STAGE;
            {   // A: 1 chunk/thread
                int row = tid >> 2, kq = tid & 3;
                CP_ASYNC16(sb + row * ROWB + kq * 16,
                           Ah + (long)(m0 + row) * K + kc + kq * 8);
            }
            #pragma unroll
            for (int i = 0; i < 4; i++) {   // B: 4 chunks/thread (256 rows)
                int ch = tid + i * 256;
                int row = ch >> 2, kq = ch & 3;
                int gr = n0 + row;
                if (gr >= N) gr = N - 1;
                CP_ASYNC16(sb + ATILE + row * ROWB + kq * 16,
                           Bw + (long)gr * K + kc + kq * 8);
            }
        }
        CP_COMMIT();
    };

    float acc[2][8][4];
    #pragma unroll
    for (int mi = 0; mi < 2; mi++)
        #pragma unroll
        for (int ni = 0; ni < 8; ni++)
            #pragma unroll
            for (int q = 0; q < 4; q++) acc[mi][ni][q] = 0.f;

    const uint32_t a_off = (uint32_t)((wm * 32 + (lane & 15)) * ROWB + (lane >> 4) * 16);
    const uint32_t b_off = (uint32_t)((wn * 64 + ((lane >> 4) & 1) * 8 + (lane & 7)) * ROWB
                                      + ((lane >> 3) & 1) * 16);

    issue(0); issue(1); issue(2);

    for (int c = 0; c < NC; c++) {
        CP_WAIT2();
        __syncthreads();
        issue(c + 3);

        const uint32_t tb = sbase + (c & (S2_NSTG - 1)) * S2_STAGE;
        #pragma unroll
        for (int kk = 0; kk < 2; kk++) {
            const uint32_t kba = kk * 32;
            uint32_t ah[2][4], bb[8][2];
            #pragma unroll
            for (int mi = 0; mi < 2; mi++)
                ldsm4(ah[mi], tb + a_off + mi * 16 * ROWB + kba);
            #pragma unroll
            for (int nip = 0; nip < 4; nip++) {
                uint32_t t4[4];
                ldsm4(t4, tb + ATILE + b_off + nip * 16 * ROWB + kba);
                bb[2*nip][0] = t4[0]; bb[2*nip][1] = t4[1];
                bb[2*nip+1][0] = t4[2]; bb[2*nip+1][1] = t4[3];
            }
            #pragma unroll
            for (int mi = 0; mi < 2; mi++)
                #pragma unroll
                for (int ni = 0; ni < 8; ni++)
                    mma16816(acc[mi][ni], ah[mi], bb[ni]);
        }
    }

    #pragma unroll
    for (int mi = 0; mi < 2; mi++) {
        const int r0 = m0 + wm * 32 + mi * 16 + (lane >> 2);
        const int r1 = r0 + 8;
        #pragma unroll
        for (int ni = 0; ni < 8; ni++) {
            const int col = n0 + wn * 64 + ni * 8 + (lane & 3) * 2;
            if (col >= N) continue;
            float b0 = 0.f, b1 = 0.f;
            if (bias) { b0 = bias[col]; b1 = bias[col + 1]; }
            *(float2*)(C + (long)r0 * ldc + col) = make_float2(acc[mi][ni][0] + b0, acc[mi][ni][1] + b1);
            *(float2*)(C + (long)r1 * ldc + col) = make_float2(acc[mi][ni][2] + b0, acc[mi][ni][3] + b1);
        }
    }
}

// ===================== compacted single-product GEMM for fc: CTA 64x256 =====================
__global__ __launch_bounds__(256, 2)
void mma_gemm_fc(const __half* __restrict__ Ah, const __half* __restrict__ Bw,
                 float* __restrict__ C, int ldc, const float* __restrict__ bias,
                 int N, int K)
{
    extern __shared__ __align__(16) char smem[];
    __shared__ int rm[64];
    const uint32_t sbase = smem_u32(smem);

    const int tid = threadIdx.x, wid = tid >> 5, lane = tid & 31;
    const int m0 = blockIdx.y * 64, n0 = blockIdx.x * 256;
    const int wm = wid & 1, wn = wid >> 1;

    const int nkept = g_nkept;
    if (m0 >= nkept) return;

    if (tid < 64) {
        int r = m0 + tid;
        rm[tid] = g_rowmap[r < nkept ? r : (nkept - 1)];
    }
    __syncthreads();

    const int NC = K >> 5;

    auto issue = [&](int c) {
        if (c < NC) {
            const long kc = (long)c * 32;
            const uint32_t sb = sbase + (c & (S2_NSTG - 1)) * S2_STAGE;
            {
                int row = tid >> 2, kq = tid & 3;
                CP_ASYNC16(sb + row * ROWB + kq * 16,
                           Ah + (long)rm[row] * K + kc + kq * 8);
            }
            #pragma unroll
            for (int i = 0; i < 4; i++) {
                int ch = tid + i * 256;
                int row = ch >> 2, kq = ch & 3;
                int gr = n0 + row;
                if (gr >= N) gr = N - 1;
                CP_ASYNC16(sb + ATILE + row * ROWB + kq * 16,
                           Bw + (long)gr * K + kc + kq * 8);
            }
        }
        CP_COMMIT();
    };

    float acc[2][8][4];
    #pragma unroll
    for (int mi = 0; mi < 2; mi++)
        #pragma unroll
        for (int ni = 0; ni < 8; ni++)
            #pragma unroll
            for (int q = 0; q < 4; q++) acc[mi][ni][q] = 0.f;

    const uint32_t a_off = (uint32_t)((wm * 32 + (lane & 15)) * ROWB + (lane >> 4) * 16);
    const uint32_t b_off = (uint32_t)((wn * 64 + ((lane >> 4) & 1) * 8 + (lane & 7)) * ROWB
                                      + ((lane >> 3) & 1) * 16);

    issue(0); issue(1); issue(2);

    for (int c = 0; c < NC; c++) {
        CP_WAIT2();
        __syncthreads();
        issue(c + 3);

        const uint32_t tb = sbase + (c & (S2_NSTG - 1)) * S2_STAGE;
        #pragma unroll
        for (int kk = 0; kk < 2; kk++) {
            const uint32_t kba = kk * 32;
            uint32_t ah[2][4], bb[8][2];
            #pragma unroll
            for (int mi = 0; mi < 2; mi++)
                ldsm4(ah[mi], tb + a_off + mi * 16 * ROWB + kba);
            #pragma unroll
            for (int nip = 0; nip < 4; nip++) {
                uint32_t t4[4];
                ldsm4(t4, tb + ATILE + b_off + nip * 16 * ROWB + kba);
                bb[2*nip][0] = t4[0]; bb[2*nip][1] = t4[1];
                bb[2*nip+1][0] = t4[2]; bb[2*nip+1][1] = t4[3];
            }
            #pragma unroll
            for (int mi = 0; mi < 2; mi++)
                #pragma unroll
                for (int ni = 0; ni < 8; ni++)
                    mma16816(acc[mi][ni], ah[mi], bb[ni]);
        }
    }

    #pragma unroll
    for (int mi = 0; mi < 2; mi++) {
        const int l0 = wm * 32 + mi * 16 + (lane >> 2);
        const int l1 = l0 + 8;
        const bool v0r = (m0 + l0) < nkept;
        const bool v1r = (m0 + l1) < nkept;
        const long or0 = (long)rm[l0] * ldc;
        const long or1 = (long)rm[l1] * ldc;
        #pragma unroll
        for (int ni = 0; ni < 8; ni++) {
            const int col = n0 + wn * 64 + ni * 8 + (lane & 3) * 2;
            if (col >= N) continue;
            float b0 = bias[col], b1 = bias[col + 1];
            if (v0r) *(float2*)(C + or0 + col) = make_float2(acc[mi][ni][0] + b0, acc[mi][ni][1] + b1);
            if (v1r) *(float2*)(C + or1 + col) = make_float2(acc[mi][ni][2] + b0, acc[mi][ni][3] + b1);
        }
    }
}

// build rowmap of kept rows + count
__global__ void k_rowmap(const int* __restrict__ lengths)
{
    __shared__ int cnt[256];
    const int tid = threadIdx.x;
    const int base = tid * 10;
    int flags[10], c = 0;
    #pragma unroll
    for (int i = 0; i < 10; i++) {
        int r = base + i;
        flags[i] = (lengths[r / Tn] >= (r % Tn)) ? 1 : 0;
        c += flags[i];
    }
    cnt[tid] = c;
    __syncthreads();
    for (int off = 1; off < 256; off <<= 1) {
        int v = (tid >= off) ? cnt[tid - off] : 0;
        __syncthreads();
        cnt[tid] += v;
        __syncthreads();
    }
    int pos = cnt[tid] - c;
    #pragma unroll
    for (int i = 0; i < 10; i++) {
        if (flags[i]) g_rowmap[pos++] = base + i;
    }
    if (tid == 255) g_nkept = cnt[255];
}

__global__ void k_zero_masked(const int* __restrict__ lengths, float* __restrict__ out)
{
    const int r = blockIdx.x;
    if (lengths[r / Tn] >= (r % Tn)) return;
    float4* o = (float4*)(out + (long)r * Vn);
    for (int i = threadIdx.x; i < Vn / 4; i += blockDim.x)
        o[i] = make_float4(0.f, 0.f, 0.f, 0.f);
}

// ===================== persistent LSTM =====================
#define LB_ALL   (16 * 64 * ROWB)            // 81920
#define LA_STAGE (2 * BTILE)                 // 20480
#define LA_NSTG  4
#define LP_SMEM  (LB_ALL + LA_NSTG * LA_STAGE)   // 163840

__global__ __launch_bounds__(256, 1)
void k_lstm_all()
{
    extern __shared__ __align__(16) char smem[];
    const uint32_t sbase = smem_u32(smem);
    const int tid = threadIdx.x, wid = tid >> 5, lane = tid & 31;
    const int h0 = blockIdx.x * 16;
    const int wm = wid & 1, wn = wid >> 1;

    {
        int row = tid >> 2, kq = tid & 3;
        int j = (row >> 4) * 512 + h0 + (row & 15);
        const __half* base = g_whh + (long)j * Hn + kq * 8;
        #pragma unroll
        for (int c = 0; c < 16; c++)
            CP_ASYNC16(sbase + c * (64 * ROWB) + row * ROWB + kq * 16, base + c * 32);
        CP_COMMIT();
        CP_WAIT0();
    }
    __syncthreads();

    const uint32_t a_off = (uint32_t)((wm * 64 + (lane & 15)) * ROWB + (lane >> 4) * 16);
    const uint32_t b_off = (uint32_t)((wn * 16 + ((lane >> 4) & 1) * 8 + (lane & 7)) * ROWB
                                      + ((lane >> 3) & 1) * 16);
    const uint32_t aring = sbase + LB_ALL;

    for (int t = 1; t < Tn; t++) {
        auto issueA = [&](int c) {
            if (c < 16) {
                const long kc = (long)c * 32;
                const uint32_t sb = aring + (c & (LA_NSTG - 1)) * LA_STAGE;
                #pragma unroll
                for (int s = 0; s < 2; s++) {
                    const __half* S = s ? g_hs_l : g_hs_h;
                    #pragma unroll
                    for (int i = 0; i < 2; i++) {
                        int ch = tid + i * 256;
                        int row = ch >> 2, kq = ch & 3;
                        const __half* src = S + ((long)row * Tn + (t - 1)) * Hn + kc + kq * 8;
                        CP_ASYNC16(sb + s * BTILE + row * ROWB + kq * 16, src);
                    }
                }
            }
            CP_COMMIT();
        };

        float acc[4][2][4];
        #pragma unroll
        for (int mi = 0; mi < 4; mi++)
            #pragma unroll
            for (int ni = 0; ni < 2; ni++)
                #pragma unroll
                for (int q = 0; q < 4; q++) acc[mi][ni][q] = 0.f;

        issueA(0); issueA(1); issueA(2);

        for (int c = 0; c < 16; c++) {
            CP_WAIT2();
            __syncthreads();
            issueA(c + 3);

            const uint32_t ta = aring + (c & (LA_NSTG - 1)) * LA_STAGE;
            const uint32_t tbB = sbase + c * (64 * ROWB);
            #pragma unroll
            for (int kk = 0; kk < 2; kk++) {
                const uint32_t kba = kk * 32;
                uint32_t ah[4][4], al[4][4], bb[2][2];
                #pragma unroll
                for (int mi = 0; mi < 4; mi++) {
                    ldsm4(ah[mi], ta + 0 * BTILE + a_off + mi * 16 * ROWB + kba);
                    ldsm4(al[mi], ta + 1 * BTILE + a_off + mi * 16 * ROWB + kba);
                }
                {
                    uint32_t t4[4];
                    ldsm4(t4, tbB + b_off + kba);
                    bb[0][0] = t4[0]; bb[0][1] = t4[1]; bb[1][0] = t4[2]; bb[1][1] = t4[3];
                }
                #pragma unroll
                for (int mi = 0; mi < 4; mi++)
                    #pragma unroll
                    for (int ni = 0; ni < 2; ni++) {
                        mma16816(acc[mi][ni], ah[mi], bb[ni]);
                        mma16816(acc[mi][ni], al[mi], bb[ni]);
                    }
            }
        }

        __syncthreads();
        float* Gs = (float*)(smem + LB_ALL);
        #pragma unroll
        for (int mi = 0; mi < 4; mi++) {
            const int r0 = wm * 64 + mi * 16 + (lane >> 2);
            const int r1 = r0 + 8;
            #pragma unroll
            for (int ni = 0; ni < 2; ni++) {
                const int cl = wn * 16 + ni * 8 + (lane & 3) * 2;
                Gs[r0 * 68 + cl]     = acc[mi][ni][0];
                Gs[r0 * 68 + cl + 1] = acc[mi][ni][1];
                Gs[r1 * 68 + cl]     = acc[mi][ni][2];
                Gs[r1 * 68 + cl + 1] = acc[mi][ni][3];
            }
        }
        __syncthreads();

        for (int p = tid; p < 128 * 16; p += 256) {
            const int b = p >> 4, l = p & 15;
            const int hcol = h0 + l;
            const float* xg = g_xg + ((long)b * Tn + t) * 2048;
            float gi = Gs[b * 68 + 0 * 16 + l] + xg[0 * 512 + hcol];
            float gf = Gs[b * 68 + 1 * 16 + l] + xg[1 * 512 + hcol];
            float gg = Gs[b * 68 + 2 * 16 + l] + xg[2 * 512 + hcol];
            float go = Gs[b * 68 + 3 * 16 + l] + xg[3 * 512 + hcol];
            float co = g_c[b * 512 + hcol];
            float si = 1.f / (1.f + __expf(-gi));
            float sf = 1.f / (1.f + __expf(-gf));
            float so = 1.f / (1.f + __expf(-go));
            float cn = sf * co + si * tanhf(gg);
            float hn = so * tanhf(cn);
            g_c[b * 512 + hcol] = cn;
            split_write16(hn, g_hs_h, g_hs_l, ((long)b * Tn + t) * 512 + hcol);
        }

        __syncthreads();
        if (tid == 0) {
            __threadfence();
            atomicAdd(&g_bar, 1u);
            while (*(volatile unsigned*)&g_bar < 32u * (unsigned)t) { }
            __threadfence();
        }
        __syncthreads();
    }
}

__global__ void k_lstm_t0()
{
    int i = blockIdx.x * blockDim.x + threadIdx.x;
    if (i == 0) g_bar = 0u;
    if (i >= Bn * Hn) return;
    int b = i >> 9, hcol = i & 511;
    const float* xg = g_xg + ((long)b * Tn) * 2048;
    float gi = xg[hcol], gg = xg[1024 + hcol], go = xg[1536 + hcol];
    float si = 1.f / (1.f + __expf(-gi));
    float so = 1.f / (1.f + __expf(-go));
    float cn = si * tanhf(gg);
    float hn = so * tanhf(cn);
    g_c[i] = cn;
    split_write16(hn, g_hs_h, g_hs_l, ((long)b * Tn) * 512 + hcol);
}

// ===================== split-K fp32 GEMM for img =====================
__global__ __launch_bounds__(256)
void sgemm_splitk(const float* __restrict__ A, const float* __restrict__ Bw)
{
    __shared__ float As[16][64];
    __shared__ float Bs[16][64];
    const int tid = threadIdx.x;
    const int tx = tid & 15, ty = tid >> 4;
    const int n0 = blockIdx.x * 64, m0 = blockIdx.y * 64;
    const int kbase = blockIdx.z * 256;
    const int lr = tid >> 2, lk = (tid & 3) * 4;
    const float* Ap = A  + (long)(m0 + lr) * 2048 + kbase + lk;
    const float* Bp = Bw + (long)(n0 + lr) * 2048 + kbase + lk;

    float acc[4][4] = {};
    for (int k0 = 0; k0 < 256; k0 += 16) {
        float4 avv = *(const float4*)(Ap + k0);
        float4 bvv = *(const float4*)(Bp + k0);
        __syncthreads();
        As[lk+0][lr] = avv.x; As[lk+1][lr] = avv.y; As[lk+2][lr] = avv.z; As[lk+3][lr] = avv.w;
        Bs[lk+0][lr] = bvv.x; Bs[lk+1][lr] = bvv.y; Bs[lk+2][lr] = bvv.z; Bs[lk+3][lr] = bvv.w;
        __syncthreads();
        #pragma unroll
        for (int kk = 0; kk < 16; kk++) {
            float a[4], b[4];
            #pragma unroll
            for (int i = 0; i < 4; i++) a[i] = As[kk][ty * 4 + i];
            #pragma unroll
            for (int j = 0; j < 4; j++) b[j] = Bs[kk][tx * 4 + j];
            #pragma unroll
            for (int i = 0; i < 4; i++)
                #pragma unroll
                for (int j = 0; j < 4; j++) acc[i][j] += a[i] * b[j];
        }
    }
    float* Cp = g_part + (long)blockIdx.z * Bn * VISn;
    #pragma unroll
    for (int i = 0; i < 4; i++)
        #pragma unroll
        for (int j = 0; j < 4; j++)
            Cp[(long)(m0 + ty * 4 + i) * VISn + n0 + tx * 4 + j] = acc[i][j];
}

__global__ void k_img_reduce(const float* __restrict__ img_b) {
    int b = blockIdx.x, v = threadIdx.x;
    float s = img_b[v];
    #pragma unroll
    for (int k = 0; k < 8; k++) s += g_part[((long)k * Bn + b) * VISn + v];
    g_x16[(long)(b * Tn) * 1024 + v] = __float2half_rn(s);
}

// ===================== prep kernels =====================
__global__ void k_bias2(const float* __restrict__ b_ih, const float* __restrict__ b_hh) {
    int i = blockIdx.x * blockDim.x + threadIdx.x;
    if (i < 4 * Hn) g_bias2[i] = b_ih[i] + b_hh[i];
}
__global__ void k_cvt16(const float* __restrict__ x, __half* __restrict__ h, int n4) {
    int i = blockIdx.x * blockDim.x + threadIdx.x;
    if (i >= n4) return;
    float4 v = ((const float4*)x)[i];
    __half2 a = __floats2half2_rn(v.x, v.y);
    __half2 b = __floats2half2_rn(v.z, v.w);
    ((uint2*)h)[i] = make_uint2(*(uint32_t*)&a, *(uint32_t*)&b);
}
__global__ void k_transpose_f(const float* __restrict__ features) {
    int bp = blockIdx.x;
    int b = bp / 49, p = bp % 49;
    int v = threadIdx.x;
    g_fT[(long)bp * 512 + v] =
        __float2half_rn(features[((long)b * 512 + v) * 49 + p]);
}
__global__ void k_normalize() {
    int row = blockIdx.x;
    int b = row / 49, p = row % 49;
    const float* x = g_fv + (long)row * 512;
    __shared__ float red[8];
    int tid = threadIdx.x, lane = tid & 31, wid = tid >> 5;
    float s = 0.f;
    for (int v = tid; v < 512; v += 256) { float t = x[v]; s += t * t; }
    #pragma unroll
    for (int o = 16; o; o >>= 1) s += __shfl_xor_sync(0xffffffffu, s, o);
    if (lane == 0) red[wid] = s;
    __syncthreads();
    if (tid == 0) {
        float sum = 0.f;
        #pragma unroll
        for (int w = 0; w < 8; w++) sum += red[w];
        red[0] = 1.f / fmaxf(sqrtf(sum), 1e-12f);
    }
    __syncthreads();
    float inv = red[0];
    long o = ((long)b * 64 + p) * 512;
    for (int v = tid; v < 512; v += 256) {
        float val = x[v] * inv;
        g_features_all[o + v] = val;
        g_fall16[o + v] = __float2half_rn(val);
    }
}
__global__ void k_copy_eng(const float* __restrict__ eng) {
    int bj = blockIdx.x;
    int b = bj / 15, j = bj % 15;
    int v = threadIdx.x;
    float val = eng[(long)bj * 512 + v];
    long o = ((long)b * 64 + 49 + j) * 512 + v;
    g_features_all[o] = val;
    g_fall16[o] = __float2half_rn(val);
}
__global__ void k_embed(const int* __restrict__ captions, const float* __restrict__ embed_w) {
    int r = blockIdx.x;
    int idx = captions[r];
    float v = embed_w[(long)idx * 512 + threadIdx.x];
    __half hv = __float2half_rn(v);
    g_we16[(long)r * 512 + threadIdx.x] = hv;
    g_x16[(long)r * 1024 + 512 + threadIdx.x] = hv;
}

// ===================== attention: scores =====================
__global__ __launch_bounds__(256)
void k_att_scores(const float* __restrict__ att_bias, const float* __restrict__ att_w) {
    const int n0 = blockIdx.x * 8, b = blockIdx.y;
    __shared__ float fea8[8][512];
    __shared__ float ws[512];
    __shared__ float hh[512];
    const int tid = threadIdx.x, lane = tid & 31, wid = tid >> 5;

    for (int v = tid; v < 512; v += 256) ws[v] = att_w[v];
    const float4* fea = (const float4*)(g_att_fea + ((long)b * 64 + n0) * 512);
    for (int i = tid; i < 8 * 128; i += 256)
        ((float4*)&fea8[0][0])[i] = fea[i];
    const float bn = att_bias[n0 + wid];

    for (int t = 0; t < Tn - 1; t++) {
        __syncthreads();
        for (int v = tid; v < 512; v += 256) hh[v] = g_att_h[((long)b * Tn + t) * 512 + v];
        __syncthreads();
        float s = 0.f;
        #pragma unroll 4
        for (int v = lane; v < 512; v += 32)
            s += fmaxf(fea8[wid][v] + hh[v] + bn, 0.f) * ws[v];
        #pragma unroll
        for (int o = 16; o; o >>= 1) s += __shfl_xor_sync(0xffffffffu, s, o);
        if (lane == 0) g_scores[((long)b * (Tn - 1) + t) * 64 + n0 + wid] = s;
    }
}

// ===================== attention: softmax + context =====================
#define CTX_SMEM (64 * 512 * 4 + 256)
__global__ __launch_bounds__(512)
void k_att_ctx() {
    extern __shared__ float fs[];
    float* sout = fs + 64 * 512;
    const int b = blockIdx.x, tid = threadIdx.x, lane = tid & 31, wid = tid >> 5;

    const float4* src = (const float4*)(g_features_all + (long)b * 64 * 512);
    for (int i = tid; i < 64 * 128; i += 512) ((float4*)fs)[i] = src[i];
    __syncthreads();

    for (int t = 0; t < Tn - 1; t++) {
        if (wid == 0) {
            const float* sc = g_scores + ((long)b * (Tn - 1) + t) * 64;
            float s0 = sc[lane], s1 = sc[lane + 32];
            float m = fmaxf(s0, s1);
            #pragma unroll
            for (int o = 16; o; o >>= 1) m = fmaxf(m, __shfl_xor_sync(0xffffffffu, m, o));
            float e0 = __expf(s0 - m), e1 = __expf(s1 - m);
            float sum = e0 + e1;
            #pragma unroll
            for (int o = 16; o; o >>= 1) sum += __shfl_xor_sync(0xffffffffu, sum, o);
            float inv = 1.f / sum;
            sout[lane] = e0 * inv; sout[lane + 32] = e1 * inv;
        }
        __syncthreads();
        float acc = 0.f;
        #pragma unroll 8
        for (int n = 0; n < 64; n++) acc += sout[n] * fs[n * 512 + tid];
        g_x16[((long)b * Tn + (t + 1)) * 1024 + tid] = __float2half_rn(acc);
        __syncthreads();
    }
}

// ===================== launch =====================
static inline dim3 tgrid256(int M, int N) { return dim3((N + 255) / 256, (M + 63) / 64); }

extern "C" void kernel_launch(void* const* d_in, const int* in_sizes, int n_in,
                              void* d_out, int out_size)
{
    const float* feature_0 = (const float*)d_in[0];
    const float* features  = (const float*)d_in[1];
    const float* eng       = (const float*)d_in[2];
    const int*   captions  = (const int*)  d_in[3];
    const int*   lengths   = (const int*)  d_in[4];
    const float* embed_w   = (const float*)d_in[5];
    const float* w_ih      = (const float*)d_in[6];
    const float* w_hh      = (const float*)d_in[7];
    const float* b_ih      = (const float*)d_in[8];
    const float* b_hh      = (const float*)d_in[9];
    const float* fc_w      = (const float*)d_in[10];
    const float* fc_b      = (const float*)d_in[11];
    const float* att_vw_w  = (const float*)d_in[12];
    const float* att_hw_w  = (const float*)d_in[13];
    const float* att_bias  = (const float*)d_in[14];
    const float* att_w_w   = (const float*)d_in[15];
    const float* att_fc_w  = (const float*)d_in[16];
    const float* att_fc_b  = (const float*)d_in[17];
    const float* img_w     = (const float*)d_in[18];
    const float* img_b     = (const float*)d_in[19];
    float* out = (float*)d_out;

    static bool init_done = false;
    static cudaStream_t s1;
    static cudaEvent_t ev0, ev1, ev3, evEnd;
    if (!init_done) {
        cudaFuncSetAttribute(mma_gemm1,   cudaFuncAttributeMaxDynamicSharedMemorySize, S2_SMEM);
        cudaFuncSetAttribute(mma_gemm_fc, cudaFuncAttributeMaxDynamicSharedMemorySize, S2_SMEM);
        cudaFuncSetAttribute(k_lstm_all,  cudaFuncAttributeMaxDynamicSharedMemorySize, LP_SMEM);
        cudaFuncSetAttribute(k_att_ctx,   cudaFuncAttributeMaxDynamicSharedMemorySize, CTX_SMEM);
        cudaStreamCreateWithFlags(&s1, cudaStreamNonBlocking);
        cudaEventCreateWithFlags(&ev0,   cudaEventDisableTiming);
        cudaEventCreateWithFlags(&ev1,   cudaEventDisableTiming);
        cudaEventCreateWithFlags(&ev3,   cudaEventDisableTiming);
        cudaEventCreateWithFlags(&evEnd, cudaEventDisableTiming);
        init_done = true;
    }

    float* p_fv = nullptr;    cudaGetSymbolAddress((void**)&p_fv,    g_fv);
    float* p_ah = nullptr;    cudaGetSymbolAddress((void**)&p_ah,    g_att_h);
    float* p_xg = nullptr;    cudaGetSymbolAddress((void**)&p_xg,    g_xg);
    float* p_bias2 = nullptr; cudaGetSymbolAddress((void**)&p_bias2, g_bias2);
    float* p_afea = nullptr;  cudaGetSymbolAddress((void**)&p_afea,  g_att_fea);
    #define HSYM(p, s) __half* p = nullptr; cudaGetSymbolAddress((void**)&p, s)
    HSYM(p_fT, g_fT);
    HSYM(p_fall16, g_fall16);
    HSYM(p_we16, g_we16);
    HSYM(p_x16, g_x16);
    HSYM(p_hs_h, g_hs_h);
    HSYM(p_wfc1, g_wfc1);     HSYM(p_wvw, g_wvw);
    HSYM(p_whw, g_whw);       HSYM(p_wih, g_wih);
    HSYM(p_wfc, g_wfc);       HSYM(p_whh, g_whh);
    #undef HSYM

    // ---- fork: side stream s1 handles all off-critical-path work ----
    cudaEventRecord(ev0, 0);
    cudaStreamWaitEvent(s1, ev0, 0);

    // side stream: early deps for att_fea/scores
    k_cvt16<<<(512 * 512 / 4 + 255) / 256, 256, 0, s1>>>(att_vw_w, p_wvw, 512 * 512 / 4);
    k_copy_eng<<<Bn * 15, 512, 0, s1>>>(eng);
    k_embed<<<Bn * Tn, 512, 0, s1>>>(captions, embed_w);
    k_cvt16<<<(512 * 512 / 4 + 255) / 256, 256, 0, s1>>>(att_hw_w, p_whw, 512 * 512 / 4);
    mma_gemm1<<<tgrid256(Bn * Tn, 512), 256, S2_SMEM, s1>>>(p_we16, p_whw,
        p_ah, 512, nullptr, 512, 512);                       // att_h
    cudaEventRecord(ev1, s1);

    // side stream: deps for xg / LSTM
    k_cvt16<<<(2048 * 1024 / 4 + 255) / 256, 256, 0, s1>>>(w_ih, p_wih, 2048 * 1024 / 4);
    sgemm_splitk<<<dim3(8, 2, 8), 256, 0, s1>>>(feature_0, img_w);
    k_img_reduce<<<Bn, 512, 0, s1>>>(img_b);
    k_bias2<<<(4 * Hn + 255) / 256, 256, 0, s1>>>(b_ih, b_hh);
    k_cvt16<<<(2048 * 512 / 4 + 255) / 256, 256, 0, s1>>>(w_hh, p_whh, 2048 * 512 / 4);
    cudaEventRecord(ev3, s1);

    // side stream: deps for fc
    k_cvt16<<<(Vn * 512 / 4 + 255) / 256, 256, 0, s1>>>(fc_w, p_wfc, Vn * 512 / 4);
    k_rowmap<<<1, 256, 0, s1>>>(lengths);
    k_zero_masked<<<Bn * Tn, 256, 0, s1>>>(lengths, out);
    cudaEventRecord(evEnd, s1);

    // ---- main stream: critical chain ----
    k_cvt16<<<(512 * 512 / 4 + 255) / 256, 256>>>(att_fc_w, p_wfc1, 512 * 512 / 4);
    k_transpose_f<<<Bn * 49, 512>>>(features);

    // att_fc: fv = fT @ att_fc_w.T + b
    mma_gemm1<<<tgrid256(Bn * 49, 512), 256, S2_SMEM>>>(p_fT, p_wfc1,
        p_fv, 512, att_fc_b, 512, 512);
    k_normalize<<<Bn * 49, 256>>>();

    cudaStreamWaitEvent(0, ev1, 0);   // wvw, copy_eng, att_h ready

    // att_fea = features_all @ att_vw_w.T
    mma_gemm1<<<tgrid256(Bn * 64, 512), 256, S2_SMEM>>>(p_fall16, p_wvw,
        p_afea, 512, nullptr, 512, 512);

    // attention: scores then softmax+context -> g_x16 rows t=1..19
    k_att_scores<<<dim3(8, Bn), 256>>>(att_bias, att_w_w);
    k_att_ctx<<<Bn, 512, CTX_SMEM>>>();

    cudaStreamWaitEvent(0, ev3, 0);   // wih, img, bias2, whh ready

    // xg = [feas|we] @ w_ih.T + (b_ih+b_hh)
    mma_gemm1<<<tgrid256(Bn * Tn, 4 * Hn), 256, S2_SMEM>>>(p_x16, p_wih,
        p_xg, 4 * Hn, p_bias2, 4 * Hn, 1024);

    // LSTM
    k_lstm_t0<<<(Bn * Hn + 255) / 256, 256>>>();
    k_lstm_all<<<32, 256, LP_SMEM>>>();

    cudaStreamWaitEvent(0, evEnd, 0); // wfc, rowmap, zero_masked done

    // logits (compacted rows; masked rows pre-zeroed)
    mma_gemm_fc<<<tgrid256(Bn * Tn, Vn), 256, S2_SMEM>>>(p_hs_h, p_wfc,
        out, Vn, fc_b, Vn, 512);
}

// round 15
// speedup vs baseline: 8.4601x; 1.0591x over previous
#include <cuda_runtime.h>
#include <cuda_fp16.h>
#include <cstdint>
#include <math.h>

// Problem dims
#define Bn   128
#define Tn   20
#define Vn   12000
#define En   512
#define Hn   512
#define VISn 512

// ===================== PTX helpers (sm_100 baseline) =====================
__device__ __forceinline__ uint32_t smem_u32(const void* p) {
    uint32_t a;
    asm("{ .reg .u64 t; cvta.to.shared.u64 t, %1; cvt.u32.u64 %0, t; }" : "=r"(a) : "l"(p));
    return a;
}
#define CP_ASYNC16(dst, src) \
    asm volatile("cp.async.cg.shared.global [%0], [%1], 16;" :: "r"(dst), "l"(src) : "memory")
#define CP_COMMIT() asm volatile("cp.async.commit_group;" ::: "memory")
#define CP_WAIT0()  asm volatile("cp.async.wait_group 0;" ::: "memory")
#define CP_WAIT2()  asm volatile("cp.async.wait_group 2;" ::: "memory")

__device__ __forceinline__ void ldsm4(uint32_t* r, uint32_t addr) {
    asm volatile("ldmatrix.sync.aligned.m8n8.x4.shared.b16 {%0,%1,%2,%3}, [%4];"
        : "=r"(r[0]), "=r"(r[1]), "=r"(r[2]), "=r"(r[3]) : "r"(addr));
}
__device__ __forceinline__ void mma16816(float* c, const uint32_t* a, const uint32_t* b) {
    asm volatile("mma.sync.aligned.m16n8k16.row.col.f32.f16.f16.f32 "
        "{%0,%1,%2,%3}, {%4,%5,%6,%7}, {%8,%9}, {%0,%1,%2,%3};"
        : "+f"(c[0]), "+f"(c[1]), "+f"(c[2]), "+f"(c[3])
        : "r"(a[0]), "r"(a[1]), "r"(a[2]), "r"(a[3]), "r"(b[0]), "r"(b[1]));
}

// ===================== scratch (device globals) =====================
__device__ float g_fv[Bn * 49 * VISn];
__device__ float g_features_all[Bn * 64 * VISn];
__device__ float g_att_fea[Bn * 64 * VISn];
__device__ float g_att_h[Bn * Tn * VISn];
__device__ float g_scores[Bn * (Tn - 1) * 64];
__device__ float g_xg[Bn * Tn * 4 * Hn];
__device__ float g_c[Bn * Hn];
__device__ float g_bias2[4 * Hn];
__device__ float g_part[8 * Bn * VISn];
__device__ unsigned g_bar;
__device__ int g_rowmapA[Bn * Tn];
__device__ int g_rowmapB[Bn * Tn];
__device__ int g_nkA;
__device__ int g_nkB;

// activations (single fp16, except hs which stays split for the recurrent path)
__device__ __half g_fT[Bn * 49 * VISn];
__device__ __half g_fall16[Bn * 64 * VISn];
__device__ __half g_we16[Bn * Tn * En];
__device__ __half g_x16[Bn * Tn * 1024];
__device__ __half g_hs_h[Bn * Tn * Hn], g_hs_l[Bn * Tn * Hn];
// weights: single fp16
__device__ __half g_wfc1[VISn * VISn];
__device__ __half g_wvw[VISn * VISn];
__device__ __half g_whw[VISn * En];
__device__ __half g_wih[4 * Hn * 1024];
__device__ __half g_wfc[Vn * Hn];
__device__ __half g_whh[4 * Hn * Hn];

__device__ __forceinline__ void split_write16(float v, __half* h, __half* l, long i) {
    __half hi = __float2half_rn(v);
    h[i] = hi;
    l[i] = __float2half_rn(v - __half2float(hi));
}

#define ROWB   80
#define ATILE  (64 * ROWB)           // 5120 B
#define BTILE  (128 * ROWB)          // 10240 B
#define B2TILE (256 * ROWB)          // 20480 B

// ===================== single-product GEMM: CTA 64x256, 2 CTAs/SM =====================
#define S2_STAGE (ATILE + B2TILE)        // 25600
#define S2_NSTG  4
#define S2_SMEM  (S2_NSTG * S2_STAGE)    // 102400

__global__ __launch_bounds__(256, 2)
void mma_gemm1(const __half* __restrict__ Ah, const __half* __restrict__ Bw,
               float* __restrict__ C, int ldc, const float* __restrict__ bias,
               int N, int K)
{
    extern __shared__ __align__(16) char smem[];
    const uint32_t sbase = smem_u32(smem);

    const int tid = threadIdx.x, wid = tid >> 5, lane = tid & 31;
    const int m0 = blockIdx.y * 64, n0 = blockIdx.x * 256;
    const int wm = wid & 1, wn = wid >> 1;

    const int NC = K >> 5;

    auto issue = [&](int c) {
        if (c < NC) {
            const long kc = (long)c * 32;
            const uint32_t sb = sbase + (c & (S2_NSTG - 1)) * S2_STAGE;
            {
                int row = tid >> 2, kq = tid & 3;
                CP_ASYNC16(sb + row * ROWB + kq * 16,
                           Ah + (long)(m0 + row) * K + kc + kq * 8);
            }
            #pragma unroll
            for (int i = 0; i < 4; i++) {
                int ch = tid + i * 256;
                int row = ch >> 2, kq = ch & 3;
                int gr = n0 + row;
                if (gr >= N) gr = N - 1;
                CP_ASYNC16(sb + ATILE + row * ROWB + kq * 16,
                           Bw + (long)gr * K + kc + kq * 8);
            }
        }
        CP_COMMIT();
    };

    float acc[2][8][4];
    #pragma unroll
    for (int mi = 0; mi < 2; mi++)
        #pragma unroll
        for (int ni = 0; ni < 8; ni++)
            #pragma unroll
            for (int q = 0; q < 4; q++) acc[mi][ni][q] = 0.f;

    const uint32_t a_off = (uint32_t)((wm * 32 + (lane & 15)) * ROWB + (lane >> 4) * 16);
    const uint32_t b_off = (uint32_t)((wn * 64 + ((lane >> 4) & 1) * 8 + (lane & 7)) * ROWB
                                      + ((lane >> 3) & 1) * 16);

    issue(0); issue(1); issue(2);

    for (int c = 0; c < NC; c++) {
        CP_WAIT2();
        __syncthreads();
        issue(c + 3);

        const uint32_t tb = sbase + (c & (S2_NSTG - 1)) * S2_STAGE;
        #pragma unroll
        for (int kk = 0; kk < 2; kk++) {
            const uint32_t kba = kk * 32;
            uint32_t ah[2][4], bb[8][2];
            #pragma unroll
            for (int mi = 0; mi < 2; mi++)
                ldsm4(ah[mi], tb + a_off + mi * 16 * ROWB + kba);
            #pragma unroll
            for (int nip = 0; nip < 4; nip++) {
                uint32_t t4[4];
                ldsm4(t4, tb + ATILE + b_off + nip * 16 * ROWB + kba);
                bb[2*nip][0] = t4[0]; bb[2*nip][1] = t4[1];
                bb[2*nip+1][0] = t4[2]; bb[2*nip+1][1] = t4[3];
            }
            #pragma unroll
            for (int mi = 0; mi < 2; mi++)
                #pragma unroll
                for (int ni = 0; ni < 8; ni++)
                    mma16816(acc[mi][ni], ah[mi], bb[ni]);
        }
    }

    #pragma unroll
    for (int mi = 0; mi < 2; mi++) {
        const int r0 = m0 + wm * 32 + mi * 16 + (lane >> 2);
        const int r1 = r0 + 8;
        #pragma unroll
        for (int ni = 0; ni < 8; ni++) {
            const int col = n0 + wn * 64 + ni * 8 + (lane & 3) * 2;
            if (col >= N) continue;
            float b0 = 0.f, b1 = 0.f;
            if (bias) { b0 = bias[col]; b1 = bias[col + 1]; }
            *(float2*)(C + (long)r0 * ldc + col) = make_float2(acc[mi][ni][0] + b0, acc[mi][ni][1] + b1);
            *(float2*)(C + (long)r1 * ldc + col) = make_float2(acc[mi][ni][2] + b0, acc[mi][ni][3] + b1);
        }
    }
}

// ===================== compacted single-product GEMM for fc (rowmap-parameterized) ============
__global__ __launch_bounds__(256, 2)
void mma_gemm_fc(const __half* __restrict__ Ah, const __half* __restrict__ Bw,
                 float* __restrict__ C, int ldc, const float* __restrict__ bias,
                 int N, int K,
                 const int* __restrict__ rowmap, const int* __restrict__ nkeptp)
{
    extern __shared__ __align__(16) char smem[];
    __shared__ int rm[64];
    const uint32_t sbase = smem_u32(smem);

    const int tid = threadIdx.x, wid = tid >> 5, lane = tid & 31;
    const int m0 = blockIdx.y * 64, n0 = blockIdx.x * 256;
    const int wm = wid & 1, wn = wid >> 1;

    const int nkept = *nkeptp;
    if (m0 >= nkept) return;

    if (tid < 64) {
        int r = m0 + tid;
        rm[tid] = rowmap[r < nkept ? r : (nkept - 1)];
    }
    __syncthreads();

    const int NC = K >> 5;

    auto issue = [&](int c) {
        if (c < NC) {
            const long kc = (long)c * 32;
            const uint32_t sb = sbase + (c & (S2_NSTG - 1)) * S2_STAGE;
            {
                int row = tid >> 2, kq = tid & 3;
                CP_ASYNC16(sb + row * ROWB + kq * 16,
                           Ah + (long)rm[row] * K + kc + kq * 8);
            }
            #pragma unroll
            for (int i = 0; i < 4; i++) {
                int ch = tid + i * 256;
                int row = ch >> 2, kq = ch & 3;
                int gr = n0 + row;
                if (gr >= N) gr = N - 1;
                CP_ASYNC16(sb + ATILE + row * ROWB + kq * 16,
                           Bw + (long)gr * K + kc + kq * 8);
            }
        }
        CP_COMMIT();
    };

    float acc[2][8][4];
    #pragma unroll
    for (int mi = 0; mi < 2; mi++)
        #pragma unroll
        for (int ni = 0; ni < 8; ni++)
            #pragma unroll
            for (int q = 0; q < 4; q++) acc[mi][ni][q] = 0.f;

    const uint32_t a_off = (uint32_t)((wm * 32 + (lane & 15)) * ROWB + (lane >> 4) * 16);
    const uint32_t b_off = (uint32_t)((wn * 64 + ((lane >> 4) & 1) * 8 + (lane & 7)) * ROWB
                                      + ((lane >> 3) & 1) * 16);

    issue(0); issue(1); issue(2);

    for (int c = 0; c < NC; c++) {
        CP_WAIT2();
        __syncthreads();
        issue(c + 3);

        const uint32_t tb = sbase + (c & (S2_NSTG - 1)) * S2_STAGE;
        #pragma unroll
        for (int kk = 0; kk < 2; kk++) {
            const uint32_t kba = kk * 32;
            uint32_t ah[2][4], bb[8][2];
            #pragma unroll
            for (int mi = 0; mi < 2; mi++)
                ldsm4(ah[mi], tb + a_off + mi * 16 * ROWB + kba);
            #pragma unroll
            for (int nip = 0; nip < 4; nip++) {
                uint32_t t4[4];
                ldsm4(t4, tb + ATILE + b_off + nip * 16 * ROWB + kba);
                bb[2*nip][0] = t4[0]; bb[2*nip][1] = t4[1];
                bb[2*nip+1][0] = t4[2]; bb[2*nip+1][1] = t4[3];
            }
            #pragma unroll
            for (int mi = 0; mi < 2; mi++)
                #pragma unroll
                for (int ni = 0; ni < 8; ni++)
                    mma16816(acc[mi][ni], ah[mi], bb[ni]);
        }
    }

    #pragma unroll
    for (int mi = 0; mi < 2; mi++) {
        const int l0 = wm * 32 + mi * 16 + (lane >> 2);
        const int l1 = l0 + 8;
        const bool v0r = (m0 + l0) < nkept;
        const bool v1r = (m0 + l1) < nkept;
        const long or0 = (long)rm[l0] * ldc;
        const long or1 = (long)rm[l1] * ldc;
        #pragma unroll
        for (int ni = 0; ni < 8; ni++) {
            const int col = n0 + wn * 64 + ni * 8 + (lane & 3) * 2;
            if (col >= N) continue;
            float b0 = bias[col], b1 = bias[col + 1];
            if (v0r) *(float2*)(C + or0 + col) = make_float2(acc[mi][ni][0] + b0, acc[mi][ni][1] + b1);
            if (v1r) *(float2*)(C + or1 + col) = make_float2(acc[mi][ni][2] + b0, acc[mi][ni][3] + b1);
        }
    }
}

// build rowmaps of kept rows split by timestep: A = t<=10, B = t>=11
__global__ void k_rowmap(const int* __restrict__ lengths)
{
    __shared__ int cntA[256], cntB[256];
    const int tid = threadIdx.x;
    const int base = tid * 10;
    int fA[10], fB[10];
    int cA = 0, cB = 0;
    #pragma unroll
    for (int i = 0; i < 10; i++) {
        int r = base + i;
        int tt = r % Tn;
        int keep = (lengths[r / Tn] >= tt) ? 1 : 0;
        fA[i] = keep && (tt <= 10);
        fB[i] = keep && (tt >= 11);
        cA += fA[i]; cB += fB[i];
    }
    cntA[tid] = cA; cntB[tid] = cB;
    __syncthreads();
    for (int off = 1; off < 256; off <<= 1) {
        int vA = (tid >= off) ? cntA[tid - off] : 0;
        int vB = (tid >= off) ? cntB[tid - off] : 0;
        __syncthreads();
        cntA[tid] += vA; cntB[tid] += vB;
        __syncthreads();
    }
    int pA = cntA[tid] - cA, pB = cntB[tid] - cB;
    #pragma unroll
    for (int i = 0; i < 10; i++) {
        if (fA[i]) g_rowmapA[pA++] = base + i;
        if (fB[i]) g_rowmapB[pB++] = base + i;
    }
    if (tid == 255) { g_nkA = cntA[255]; g_nkB = cntB[255]; }
}

__global__ void k_zero_masked(const int* __restrict__ lengths, float* __restrict__ out)
{
    const int r = blockIdx.x;
    if (lengths[r / Tn] >= (r % Tn)) return;
    float4* o = (float4*)(out + (long)r * Vn);
    for (int i = threadIdx.x; i < Vn / 4; i += blockDim.x)
        o[i] = make_float4(0.f, 0.f, 0.f, 0.f);
}

// ===================== persistent LSTM (parameterized step range) =====================
#define LB_ALL   (16 * 64 * ROWB)            // 81920
#define LA_STAGE (2 * BTILE)                 // 20480
#define LA_NSTG  4
#define LP_SMEM  (LB_ALL + LA_NSTG * LA_STAGE)   // 163840

__global__ __launch_bounds__(256, 1)
void k_lstm_all(int tbeg, int tend)
{
    extern __shared__ __align__(16) char smem[];
    const uint32_t sbase = smem_u32(smem);
    const int tid = threadIdx.x, wid = tid >> 5, lane = tid & 31;
    const int h0 = blockIdx.x * 16;
    const int wm = wid & 1, wn = wid >> 1;

    {
        int row = tid >> 2, kq = tid & 3;
        int j = (row >> 4) * 512 + h0 + (row & 15);
        const __half* base = g_whh + (long)j * Hn + kq * 8;
        #pragma unroll
        for (int c = 0; c < 16; c++)
            CP_ASYNC16(sbase + c * (64 * ROWB) + row * ROWB + kq * 16, base + c * 32);
        CP_COMMIT();
        CP_WAIT0();
    }
    __syncthreads();

    const uint32_t a_off = (uint32_t)((wm * 64 + (lane & 15)) * ROWB + (lane >> 4) * 16);
    const uint32_t b_off = (uint32_t)((wn * 16 + ((lane >> 4) & 1) * 8 + (lane & 7)) * ROWB
                                      + ((lane >> 3) & 1) * 16);
    const uint32_t aring = sbase + LB_ALL;

    for (int t = tbeg; t < tend; t++) {
        auto issueA = [&](int c) {
            if (c < 16) {
                const long kc = (long)c * 32;
                const uint32_t sb = aring + (c & (LA_NSTG - 1)) * LA_STAGE;
                #pragma unroll
                for (int s = 0; s < 2; s++) {
                    const __half* S = s ? g_hs_l : g_hs_h;
                    #pragma unroll
                    for (int i = 0; i < 2; i++) {
                        int ch = tid + i * 256;
                        int row = ch >> 2, kq = ch & 3;
                        const __half* src = S + ((long)row * Tn + (t - 1)) * Hn + kc + kq * 8;
                        CP_ASYNC16(sb + s * BTILE + row * ROWB + kq * 16, src);
                    }
                }
            }
            CP_COMMIT();
        };

        float acc[4][2][4];
        #pragma unroll
        for (int mi = 0; mi < 4; mi++)
            #pragma unroll
            for (int ni = 0; ni < 2; ni++)
                #pragma unroll
                for (int q = 0; q < 4; q++) acc[mi][ni][q] = 0.f;

        issueA(0); issueA(1); issueA(2);

        for (int c = 0; c < 16; c++) {
            CP_WAIT2();
            __syncthreads();
            issueA(c + 3);

            const uint32_t ta = aring + (c & (LA_NSTG - 1)) * LA_STAGE;
            const uint32_t tbB = sbase + c * (64 * ROWB);
            #pragma unroll
            for (int kk = 0; kk < 2; kk++) {
                const uint32_t kba = kk * 32;
                uint32_t ah[4][4], al[4][4], bb[2][2];
                #pragma unroll
                for (int mi = 0; mi < 4; mi++) {
                    ldsm4(ah[mi], ta + 0 * BTILE + a_off + mi * 16 * ROWB + kba);
                    ldsm4(al[mi], ta + 1 * BTILE + a_off + mi * 16 * ROWB + kba);
                }
                {
                    uint32_t t4[4];
                    ldsm4(t4, tbB + b_off + kba);
                    bb[0][0] = t4[0]; bb[0][1] = t4[1]; bb[1][0] = t4[2]; bb[1][1] = t4[3];
                }
                #pragma unroll
                for (int mi = 0; mi < 4; mi++)
                    #pragma unroll
                    for (int ni = 0; ni < 2; ni++) {
                        mma16816(acc[mi][ni], ah[mi], bb[ni]);
                        mma16816(acc[mi][ni], al[mi], bb[ni]);
                    }
            }
        }

        __syncthreads();
        float* Gs = (float*)(smem + LB_ALL);
        #pragma unroll
        for (int mi = 0; mi < 4; mi++) {
            const int r0 = wm * 64 + mi * 16 + (lane >> 2);
            const int r1 = r0 + 8;
            #pragma unroll
            for (int ni = 0; ni < 2; ni++) {
                const int cl = wn * 16 + ni * 8 + (lane & 3) * 2;
                Gs[r0 * 68 + cl]     = acc[mi][ni][0];
                Gs[r0 * 68 + cl + 1] = acc[mi][ni][1];
                Gs[r1 * 68 + cl]     = acc[mi][ni][2];
                Gs[r1 * 68 + cl + 1] = acc[mi][ni][3];
            }
        }
        __syncthreads();

        for (int p = tid; p < 128 * 16; p += 256) {
            const int b = p >> 4, l = p & 15;
            const int hcol = h0 + l;
            const float* xg = g_xg + ((long)b * Tn + t) * 2048;
            float gi = Gs[b * 68 + 0 * 16 + l] + xg[0 * 512 + hcol];
            float gf = Gs[b * 68 + 1 * 16 + l] + xg[1 * 512 + hcol];
            float gg = Gs[b * 68 + 2 * 16 + l] + xg[2 * 512 + hcol];
            float go = Gs[b * 68 + 3 * 16 + l] + xg[3 * 512 + hcol];
            float co = g_c[b * 512 + hcol];
            float si = 1.f / (1.f + __expf(-gi));
            float sf = 1.f / (1.f + __expf(-gf));
            float so = 1.f / (1.f + __expf(-go));
            float cn = sf * co + si * tanhf(gg);
            float hn = so * tanhf(cn);
            g_c[b * 512 + hcol] = cn;
            split_write16(hn, g_hs_h, g_hs_l, ((long)b * Tn + t) * 512 + hcol);
        }

        __syncthreads();
        if (tid == 0) {
            __threadfence();
            atomicAdd(&g_bar, 1u);
            while (*(volatile unsigned*)&g_bar < 32u * (unsigned)t) { }
            __threadfence();
        }
        __syncthreads();
    }
}

__global__ void k_lstm_t0()
{
    int i = blockIdx.x * blockDim.x + threadIdx.x;
    if (i == 0) g_bar = 0u;
    if (i >= Bn * Hn) return;
    int b = i >> 9, hcol = i & 511;
    const float* xg = g_xg + ((long)b * Tn) * 2048;
    float gi = xg[hcol], gg = xg[1024 + hcol], go = xg[1536 + hcol];
    float si = 1.f / (1.f + __expf(-gi));
    float so = 1.f / (1.f + __expf(-go));
    float cn = si * tanhf(gg);
    float hn = so * tanhf(cn);
    g_c[i] = cn;
    split_write16(hn, g_hs_h, g_hs_l, ((long)b * Tn) * 512 + hcol);
}

// ===================== split-K fp32 GEMM for img =====================
__global__ __launch_bounds__(256)
void sgemm_splitk(const float* __restrict__ A, const float* __restrict__ Bw)
{
    __shared__ float As[16][64];
    __shared__ float Bs[16][64];
    const int tid = threadIdx.x;
    const int tx = tid & 15, ty = tid >> 4;
    const int n0 = blockIdx.x * 64, m0 = blockIdx.y * 64;
    const int kbase = blockIdx.z * 256;
    const int lr = tid >> 2, lk = (tid & 3) * 4;
    const float* Ap = A  + (long)(m0 + lr) * 2048 + kbase + lk;
    const float* Bp = Bw + (long)(n0 + lr) * 2048 + kbase + lk;

    float acc[4][4] = {};
    for (int k0 = 0; k0 < 256; k0 += 16) {
        float4 avv = *(const float4*)(Ap + k0);
        float4 bvv = *(const float4*)(Bp + k0);
        __syncthreads();
        As[lk+0][lr] = avv.x; As[lk+1][lr] = avv.y; As[lk+2][lr] = avv.z; As[lk+3][lr] = avv.w;
        Bs[lk+0][lr] = bvv.x; Bs[lk+1][lr] = bvv.y; Bs[lk+2][lr] = bvv.z; Bs[lk+3][lr] = bvv.w;
        __syncthreads();
        #pragma unroll
        for (int kk = 0; kk < 16; kk++) {
            float a[4], b[4];
            #pragma unroll
            for (int i = 0; i < 4; i++) a[i] = As[kk][ty * 4 + i];
            #pragma unroll
            for (int j = 0; j < 4; j++) b[j] = Bs[kk][tx * 4 + j];
            #pragma unroll
            for (int i = 0; i < 4; i++)
                #pragma unroll
                for (int j = 0; j < 4; j++) acc[i][j] += a[i] * b[j];
        }
    }
    float* Cp = g_part + (long)blockIdx.z * Bn * VISn;
    #pragma unroll
    for (int i = 0; i < 4; i++)
        #pragma unroll
        for (int j = 0; j < 4; j++)
            Cp[(long)(m0 + ty * 4 + i) * VISn + n0 + tx * 4 + j] = acc[i][j];
}

__global__ void k_img_reduce(const float* __restrict__ img_b) {
    int b = blockIdx.x, v = threadIdx.x;
    float s = img_b[v];
    #pragma unroll
    for (int k = 0; k < 8; k++) s += g_part[((long)k * Bn + b) * VISn + v];
    g_x16[(long)(b * Tn) * 1024 + v] = __float2half_rn(s);
}

// ===================== prep kernels =====================
__global__ void k_bias2(const float* __restrict__ b_ih, const float* __restrict__ b_hh) {
    int i = blockIdx.x * blockDim.x + threadIdx.x;
    if (i < 4 * Hn) g_bias2[i] = b_ih[i] + b_hh[i];
}
__global__ void k_cvt16(const float* __restrict__ x, __half* __restrict__ h, int n4) {
    int i = blockIdx.x * blockDim.x + threadIdx.x;
    if (i >= n4) return;
    float4 v = ((const float4*)x)[i];
    __half2 a = __floats2half2_rn(v.x, v.y);
    __half2 b = __floats2half2_rn(v.z, v.w);
    ((uint2*)h)[i] = make_uint2(*(uint32_t*)&a, *(uint32_t*)&b);
}
__global__ void k_transpose_f(const float* __restrict__ features) {
    int bp = blockIdx.x;
    int b = bp / 49, p = bp % 49;
    int v = threadIdx.x;
    g_fT[(long)bp * 512 + v] =
        __float2half_rn(features[((long)b * 512 + v) * 49 + p]);
}
__global__ void k_normalize() {
    int row = blockIdx.x;
    int b = row / 49, p = row % 49;
    const float* x = g_fv + (long)row * 512;
    __shared__ float red[8];
    int tid = threadIdx.x, lane = tid & 31, wid = tid >> 5;
    float s = 0.f;
    for (int v = tid; v < 512; v += 256) { float t = x[v]; s += t * t; }
    #pragma unroll
    for (int o = 16; o; o >>= 1) s += __shfl_xor_sync(0xffffffffu, s, o);
    if (lane == 0) red[wid] = s;
    __syncthreads();
    if (tid == 0) {
        float sum = 0.f;
        #pragma unroll
        for (int w = 0; w < 8; w++) sum += red[w];
        red[0] = 1.f / fmaxf(sqrtf(sum), 1e-12f);
    }
    __syncthreads();
    float inv = red[0];
    long o = ((long)b * 64 + p) * 512;
    for (int v = tid; v < 512; v += 256) {
        float val = x[v] * inv;
        g_features_all[o + v] = val;
        g_fall16[o + v] = __float2half_rn(val);
    }
}
__global__ void k_copy_eng(const float* __restrict__ eng) {
    int bj = blockIdx.x;
    int b = bj / 15, j = bj % 15;
    int v = threadIdx.x;
    float val = eng[(long)bj * 512 + v];
    long o = ((long)b * 64 + 49 + j) * 512 + v;
    g_features_all[o] = val;
    g_fall16[o] = __float2half_rn(val);
}
__global__ void k_embed(const int* __restrict__ captions, const float* __restrict__ embed_w) {
    int r = blockIdx.x;
    int idx = captions[r];
    float v = embed_w[(long)idx * 512 + threadIdx.x];
    __half hv = __float2half_rn(v);
    g_we16[(long)r * 512 + threadIdx.x] = hv;
    g_x16[(long)r * 1024 + 512 + threadIdx.x] = hv;
}

// ===================== attention: scores =====================
__global__ __launch_bounds__(256)
void k_att_scores(const float* __restrict__ att_bias, const float* __restrict__ att_w) {
    const int n0 = blockIdx.x * 8, b = blockIdx.y;
    __shared__ float fea8[8][512];
    __shared__ float ws[512];
    __shared__ float hh[512];
    const int tid = threadIdx.x, lane = tid & 31, wid = tid >> 5;

    for (int v = tid; v < 512; v += 256) ws[v] = att_w[v];
    const float4* fea = (const float4*)(g_att_fea + ((long)b * 64 + n0) * 512);
    for (int i = tid; i < 8 * 128; i += 256)
        ((float4*)&fea8[0][0])[i] = fea[i];
    const float bn = att_bias[n0 + wid];

    for (int t = 0; t < Tn - 1; t++) {
        __syncthreads();
        for (int v = tid; v < 512; v += 256) hh[v] = g_att_h[((long)b * Tn + t) * 512 + v];
        __syncthreads();
        float s = 0.f;
        #pragma unroll 4
        for (int v = lane; v < 512; v += 32)
            s += fmaxf(fea8[wid][v] + hh[v] + bn, 0.f) * ws[v];
        #pragma unroll
        for (int o = 16; o; o >>= 1) s += __shfl_xor_sync(0xffffffffu, s, o);
        if (lane == 0) g_scores[((long)b * (Tn - 1) + t) * 64 + n0 + wid] = s;
    }
}

// ===================== attention: softmax + context =====================
#define CTX_SMEM (64 * 512 * 4 + 256)
__global__ __launch_bounds__(512)
void k_att_ctx() {
    extern __shared__ float fs[];
    float* sout = fs + 64 * 512;
    const int b = blockIdx.x, tid = threadIdx.x, lane = tid & 31, wid = tid >> 5;

    const float4* src = (const float4*)(g_features_all + (long)b * 64 * 512);
    for (int i = tid; i < 64 * 128; i += 512) ((float4*)fs)[i] = src[i];
    __syncthreads();

    for (int t = 0; t < Tn - 1; t++) {
        if (wid == 0) {
            const float* sc = g_scores + ((long)b * (Tn - 1) + t) * 64;
            float s0 = sc[lane], s1 = sc[lane + 32];
            float m = fmaxf(s0, s1);
            #pragma unroll
            for (int o = 16; o; o >>= 1) m = fmaxf(m, __shfl_xor_sync(0xffffffffu, m, o));
            float e0 = __expf(s0 - m), e1 = __expf(s1 - m);
            float sum = e0 + e1;
            #pragma unroll
            for (int o = 16; o; o >>= 1) sum += __shfl_xor_sync(0xffffffffu, sum, o);
            float inv = 1.f / sum;
            sout[lane] = e0 * inv; sout[lane + 32] = e1 * inv;
        }
        __syncthreads();
        float acc = 0.f;
        #pragma unroll 8
        for (int n = 0; n < 64; n++) acc += sout[n] * fs[n * 512 + tid];
        g_x16[((long)b * Tn + (t + 1)) * 1024 + tid] = __float2half_rn(acc);
        __syncthreads();
    }
}

// ===================== launch =====================
static inline dim3 tgrid256(int M, int N) { return dim3((N + 255) / 256, (M + 63) / 64); }

extern "C" void kernel_launch(void* const* d_in, const int* in_sizes, int n_in,
                              void* d_out, int out_size)
{
    const float* feature_0 = (const float*)d_in[0];
    const float* features  = (const float*)d_in[1];
    const float* eng       = (const float*)d_in[2];
    const int*   captions  = (const int*)  d_in[3];
    const int*   lengths   = (const int*)  d_in[4];
    const float* embed_w   = (const float*)d_in[5];
    const float* w_ih      = (const float*)d_in[6];
    const float* w_hh      = (const float*)d_in[7];
    const float* b_ih      = (const float*)d_in[8];
    const float* b_hh      = (const float*)d_in[9];
    const float* fc_w      = (const float*)d_in[10];
    const float* fc_b      = (const float*)d_in[11];
    const float* att_vw_w  = (const float*)d_in[12];
    const float* att_hw_w  = (const float*)d_in[13];
    const float* att_bias  = (const float*)d_in[14];
    const float* att_w_w   = (const float*)d_in[15];
    const float* att_fc_w  = (const float*)d_in[16];
    const float* att_fc_b  = (const float*)d_in[17];
    const float* img_w     = (const float*)d_in[18];
    const float* img_b     = (const float*)d_in[19];
    float* out = (float*)d_out;

    static bool init_done = false;
    static cudaStream_t s1;
    static cudaEvent_t ev0, ev1, ev3, evEnd, evL1, evFcA;
    if (!init_done) {
        cudaFuncSetAttribute(mma_gemm1,   cudaFuncAttributeMaxDynamicSharedMemorySize, S2_SMEM);
        cudaFuncSetAttribute(mma_gemm_fc, cudaFuncAttributeMaxDynamicSharedMemorySize, S2_SMEM);
        cudaFuncSetAttribute(k_lstm_all,  cudaFuncAttributeMaxDynamicSharedMemorySize, LP_SMEM);
        cudaFuncSetAttribute(k_att_ctx,   cudaFuncAttributeMaxDynamicSharedMemorySize, CTX_SMEM);
        cudaStreamCreateWithFlags(&s1, cudaStreamNonBlocking);
        cudaEventCreateWithFlags(&ev0,   cudaEventDisableTiming);
        cudaEventCreateWithFlags(&ev1,   cudaEventDisableTiming);
        cudaEventCreateWithFlags(&ev3,   cudaEventDisableTiming);
        cudaEventCreateWithFlags(&evEnd, cudaEventDisableTiming);
        cudaEventCreateWithFlags(&evL1,  cudaEventDisableTiming);
        cudaEventCreateWithFlags(&evFcA, cudaEventDisableTiming);
        init_done = true;
    }

    float* p_fv = nullptr;    cudaGetSymbolAddress((void**)&p_fv,    g_fv);
    float* p_ah = nullptr;    cudaGetSymbolAddress((void**)&p_ah,    g_att_h);
    float* p_xg = nullptr;    cudaGetSymbolAddress((void**)&p_xg,    g_xg);
    float* p_bias2 = nullptr; cudaGetSymbolAddress((void**)&p_bias2, g_bias2);
    float* p_afea = nullptr;  cudaGetSymbolAddress((void**)&p_afea,  g_att_fea);
    int* p_rmA = nullptr;     cudaGetSymbolAddress((void**)&p_rmA,   g_rowmapA);
    int* p_rmB = nullptr;     cudaGetSymbolAddress((void**)&p_rmB,   g_rowmapB);
    int* p_nkA = nullptr;     cudaGetSymbolAddress((void**)&p_nkA,   g_nkA);
    int* p_nkB = nullptr;     cudaGetSymbolAddress((void**)&p_nkB,   g_nkB);
    #define HSYM(p, s) __half* p = nullptr; cudaGetSymbolAddress((void**)&p, s)
    HSYM(p_fT, g_fT);
    HSYM(p_fall16, g_fall16);
    HSYM(p_we16, g_we16);
    HSYM(p_x16, g_x16);
    HSYM(p_hs_h, g_hs_h);
    HSYM(p_wfc1, g_wfc1);     HSYM(p_wvw, g_wvw);
    HSYM(p_whw, g_whw);       HSYM(p_wih, g_wih);
    HSYM(p_wfc, g_wfc);       HSYM(p_whh, g_whh);
    #undef HSYM

    // ---- fork: side stream s1 handles all off-critical-path work ----
    cudaEventRecord(ev0, 0);
    cudaStreamWaitEvent(s1, ev0, 0);

    // side stream: early deps for att_fea/scores
    k_cvt16<<<(512 * 512 / 4 + 255) / 256, 256, 0, s1>>>(att_vw_w, p_wvw, 512 * 512 / 4);
    k_copy_eng<<<Bn * 15, 512, 0, s1>>>(eng);
    k_embed<<<Bn * Tn, 512, 0, s1>>>(captions, embed_w);
    k_cvt16<<<(512 * 512 / 4 + 255) / 256, 256, 0, s1>>>(att_hw_w, p_whw, 512 * 512 / 4);
    mma_gemm1<<<tgrid256(Bn * Tn, 512), 256, S2_SMEM, s1>>>(p_we16, p_whw,
        p_ah, 512, nullptr, 512, 512);                       // att_h
    cudaEventRecord(ev1, s1);

    // side stream: deps for xg / LSTM
    k_cvt16<<<(2048 * 1024 / 4 + 255) / 256, 256, 0, s1>>>(w_ih, p_wih, 2048 * 1024 / 4);
    sgemm_splitk<<<dim3(8, 2, 8), 256, 0, s1>>>(feature_0, img_w);
    k_img_reduce<<<Bn, 512, 0, s1>>>(img_b);
    k_bias2<<<(4 * Hn + 255) / 256, 256, 0, s1>>>(b_ih, b_hh);
    k_cvt16<<<(2048 * 512 / 4 + 255) / 256, 256, 0, s1>>>(w_hh, p_whh, 2048 * 512 / 4);
    cudaEventRecord(ev3, s1);

    // side stream: deps for fc
    k_cvt16<<<(Vn * 512 / 4 + 255) / 256, 256, 0, s1>>>(fc_w, p_wfc, Vn * 512 / 4);
    k_rowmap<<<1, 256, 0, s1>>>(lengths);
    k_zero_masked<<<Bn * Tn, 256, 0, s1>>>(lengths, out);
    cudaEventRecord(evEnd, s1);

    // ---- main stream: critical chain ----
    k_cvt16<<<(512 * 512 / 4 + 255) / 256, 256>>>(att_fc_w, p_wfc1, 512 * 512 / 4);
    k_transpose_f<<<Bn * 49, 512>>>(features);

    // att_fc: fv = fT @ att_fc_w.T + b
    mma_gemm1<<<tgrid256(Bn * 49, 512), 256, S2_SMEM>>>(p_fT, p_wfc1,
        p_fv, 512, att_fc_b, 512, 512);
    k_normalize<<<Bn * 49, 256>>>();

    cudaStreamWaitEvent(0, ev1, 0);   // wvw, copy_eng, att_h ready

    // att_fea = features_all @ att_vw_w.T
    mma_gemm1<<<tgrid256(Bn * 64, 512), 256, S2_SMEM>>>(p_fall16, p_wvw,
        p_afea, 512, nullptr, 512, 512);

    // attention: scores then softmax+context -> g_x16 rows t=1..19
    k_att_scores<<<dim3(8, Bn), 256>>>(att_bias, att_w_w);
    k_att_ctx<<<Bn, 512, CTX_SMEM>>>();

    cudaStreamWaitEvent(0, ev3, 0);   // wih, img, bias2, whh ready

    // xg = [feas|we] @ w_ih.T + (b_ih+b_hh)
    mma_gemm1<<<tgrid256(Bn * Tn, 4 * Hn), 256, S2_SMEM>>>(p_x16, p_wih,
        p_xg, 4 * Hn, p_bias2, 4 * Hn, 1024);

    // LSTM part 1 (steps 1..10)
    k_lstm_t0<<<(Bn * Hn + 255) / 256, 256>>>();
    k_lstm_all<<<32, 256, LP_SMEM>>>(1, 11);
    cudaEventRecord(evL1, 0);

    // side stream: fcA (rows t<=10) overlaps LSTM part 2 + fcB
    cudaStreamWaitEvent(s1, evL1, 0);   // hs rows t<=10 ready (wfc/rowmap/zero by s1 order)
    mma_gemm_fc<<<tgrid256(128 * 11, Vn), 256, S2_SMEM, s1>>>(p_hs_h, p_wfc,
        out, Vn, fc_b, Vn, 512, p_rmA, p_nkA);
    cudaEventRecord(evFcA, s1);

    // main: LSTM part 2 (steps 11..19), then fcB (rows t>=11)
    k_lstm_all<<<32, 256, LP_SMEM>>>(11, 20);
    cudaStreamWaitEvent(0, evEnd, 0);   // wfc, rowmap, zero_masked done
    mma_gemm_fc<<<tgrid256(128 * 9, Vn), 256, S2_SMEM>>>(p_hs_h, p_wfc,
        out, Vn, fc_b, Vn, 512, p_rmB, p_nkB);

    // join side branch (fcA) before capture end
    cudaStreamWaitEvent(0, evFcA, 0);
}